// round 1
// baseline (speedup 1.0000x reference)
#include <cuda_runtime.h>
#include <cmath>

// Problem constants (fixed by the reference)
#define SQ   2048      // sequence length S
#define DM   512       // d_model D
#define FF   512       // attention dim F (== D)
#define HID  2048      // 4*F
#define VOC  32000     // vocab
#define NL   4         // layers
#define LN_EPS 1e-5f

// ------------------------- scratch (device globals; no runtime alloc) ------
__device__ float g_x  [SQ * DM];   // current activations
__device__ float g_x2 [SQ * DM];   // post-LN1 activations (residual for LN2)
__device__ float g_q  [SQ * FF];
__device__ float g_k  [SQ * FF];
__device__ float g_v  [SQ * FF];
__device__ float g_att[SQ * SQ];
__device__ float g_t  [SQ * FF];
__device__ float g_z  [SQ * FF];
__device__ float g_h  [SQ * HID];
__device__ float g_h2 [SQ * DM];

// ------------------------- SGEMM: 128x128x16 tile, 8x8 per thread ---------
// C[M,N] = alpha * A[M,K] @ op(B) + bias   (op(B)=B [K,N] or B^T with B [N,K])
// All of M, N divisible by 128; K divisible by 16 (true for every call here).
#define BM 128
#define BN 128
#define BK 16

template<int TRANSB>
__global__ void __launch_bounds__(256, 2)
sgemm_kernel(const float* __restrict__ A, const float* __restrict__ B,
             const float* __restrict__ bias, float* __restrict__ C,
             int M, int N, int K, float alpha)
{
    __shared__ float As[BK][BM];
    __shared__ float Bs[BK][BN];

    const int tid = threadIdx.x;      // 0..255
    const int tx  = tid & 15;         // 16 thread-cols
    const int ty  = tid >> 4;         // 16 thread-rows
    const int m0  = blockIdx.y * BM;
    const int n0  = blockIdx.x * BN;

    float acc[8][8];
    #pragma unroll
    for (int i = 0; i < 8; i++)
        #pragma unroll
        for (int j = 0; j < 8; j++) acc[i][j] = 0.f;

    for (int k0 = 0; k0 < K; k0 += BK) {
        // ---- load A tile (BM x BK), store transposed As[k][m]
        #pragma unroll
        for (int r = 0; r < 2; r++) {
            int f   = tid + 256 * r;          // 0..511 float4 slots
            int row = f >> 2;                 // 0..127
            int kc  = (f & 3) << 2;           // 0,4,8,12
            float4 v = *(const float4*)(A + (size_t)(m0 + row) * K + k0 + kc);
            As[kc + 0][row] = v.x;
            As[kc + 1][row] = v.y;
            As[kc + 2][row] = v.z;
            As[kc + 3][row] = v.w;
        }
        // ---- load B tile
        if (!TRANSB) {
            // B is [K,N]; tile BK x BN, float4 along N
            #pragma unroll
            for (int r = 0; r < 2; r++) {
                int f    = tid + 256 * r;
                int krow = f >> 5;            // 0..15
                int nc   = (f & 31) << 2;     // 0..124
                float4 v = *(const float4*)(B + (size_t)(k0 + krow) * N + n0 + nc);
                *(float4*)(&Bs[krow][nc]) = v;
            }
        } else {
            // B is [N,K]; need Bs[k][n] = B[n][k]; float4 along K
            #pragma unroll
            for (int r = 0; r < 2; r++) {
                int f    = tid + 256 * r;
                int nrow = f >> 2;            // 0..127
                int kc   = (f & 3) << 2;      // 0,4,8,12
                float4 v = *(const float4*)(B + (size_t)(n0 + nrow) * K + k0 + kc);
                Bs[kc + 0][nrow] = v.x;
                Bs[kc + 1][nrow] = v.y;
                Bs[kc + 2][nrow] = v.z;
                Bs[kc + 3][nrow] = v.w;
            }
        }
        __syncthreads();

        #pragma unroll
        for (int kk = 0; kk < BK; kk++) {
            float a[8], b[8];
            #pragma unroll
            for (int i = 0; i < 8; i++) a[i] = As[kk][ty * 8 + i];
            #pragma unroll
            for (int j = 0; j < 8; j++) b[j] = Bs[kk][tx * 8 + j];
            #pragma unroll
            for (int i = 0; i < 8; i++)
                #pragma unroll
                for (int j = 0; j < 8; j++)
                    acc[i][j] += a[i] * b[j];
        }
        __syncthreads();
    }

    // ---- epilogue
    #pragma unroll
    for (int i = 0; i < 8; i++) {
        int row = m0 + ty * 8 + i;
        #pragma unroll
        for (int j = 0; j < 8; j += 4) {
            int col = n0 + tx * 8 + j;
            float4 v;
            v.x = acc[i][j + 0] * alpha;
            v.y = acc[i][j + 1] * alpha;
            v.z = acc[i][j + 2] * alpha;
            v.w = acc[i][j + 3] * alpha;
            if (bias) {
                v.x += bias[col + 0];
                v.y += bias[col + 1];
                v.z += bias[col + 2];
                v.w += bias[col + 3];
            }
            *(float4*)(C + (size_t)row * N + col) = v;
        }
    }
}

// ------------------------- causal row softmax on [S,S] ---------------------
__global__ void softmax_causal_kernel(float* __restrict__ att)
{
    const int i = blockIdx.x;
    float* row = att + (size_t)i * SQ;
    const int tid = threadIdx.x;          // 256 threads
    const int n = i + 1;                  // valid columns 0..i

    __shared__ float red[256];

    float m = -1e30f;
    for (int j = tid; j < n; j += 256) m = fmaxf(m, row[j]);
    red[tid] = m; __syncthreads();
    for (int st = 128; st > 0; st >>= 1) {
        if (tid < st) red[tid] = fmaxf(red[tid], red[tid + st]);
        __syncthreads();
    }
    m = red[0]; __syncthreads();

    float s = 0.f;
    for (int j = tid; j < n; j += 256) {
        float e = __expf(row[j] - m);
        row[j] = e;
        s += e;
    }
    red[tid] = s; __syncthreads();
    for (int st = 128; st > 0; st >>= 1) {
        if (tid < st) red[tid] += red[tid + st];
        __syncthreads();
    }
    const float inv = 1.f / red[0];

    for (int j = tid; j < n; j += 256) row[j] *= inv;
    for (int j = n + tid; j < SQ; j += 256) row[j] = 0.f;
}

// ------------------------- fused residual-add + LayerNorm (width 512) ------
__global__ void add_ln_kernel(const float* __restrict__ a,
                              const float* __restrict__ res,
                              const float* __restrict__ g,
                              const float* __restrict__ beta,
                              float* __restrict__ out)
{
    const int row = blockIdx.x;
    const int tid = threadIdx.x;          // 256 threads, 2 elems each (D=512)
    const size_t base = (size_t)row * DM;

    float v0 = a[base + tid]       + res[base + tid];
    float v1 = a[base + tid + 256] + res[base + tid + 256];

    __shared__ float red[256];
    red[tid] = v0 + v1; __syncthreads();
    for (int st = 128; st > 0; st >>= 1) {
        if (tid < st) red[tid] += red[tid + st];
        __syncthreads();
    }
    const float mu = red[0] * (1.0f / DM);
    __syncthreads();

    float d0 = v0 - mu, d1 = v1 - mu;
    red[tid] = d0 * d0 + d1 * d1; __syncthreads();
    for (int st = 128; st > 0; st >>= 1) {
        if (tid < st) red[tid] += red[tid + st];
        __syncthreads();
    }
    const float rstd = rsqrtf(red[0] * (1.0f / DM) + LN_EPS);

    out[base + tid]       = d0 * rstd * g[tid]       + beta[tid];
    out[base + tid + 256] = d1 * rstd * g[tid + 256] + beta[tid + 256];
}

// ------------------------- row softmax over vocab (width 32000) ------------
__global__ void softmax_vocab_kernel(float* __restrict__ x)
{
    const int i = blockIdx.x;
    float* row = x + (size_t)i * VOC;
    const int tid = threadIdx.x;          // 256

    __shared__ float red[256];

    float m = -1e30f;
    for (int j = tid; j < VOC; j += 256) m = fmaxf(m, row[j]);
    red[tid] = m; __syncthreads();
    for (int st = 128; st > 0; st >>= 1) {
        if (tid < st) red[tid] = fmaxf(red[tid], red[tid + st]);
        __syncthreads();
    }
    m = red[0]; __syncthreads();

    float s = 0.f;
    for (int j = tid; j < VOC; j += 256) {
        float e = __expf(row[j] - m);
        row[j] = e;
        s += e;
    }
    red[tid] = s; __syncthreads();
    for (int st = 128; st > 0; st >>= 1) {
        if (tid < st) red[tid] += red[tid + st];
        __syncthreads();
    }
    const float inv = 1.f / red[0];
    for (int j = tid; j < VOC; j += 256) row[j] *= inv;
}

// ------------------------- host launcher -----------------------------------
static inline void gemm_nn(const float* A, const float* B, const float* bias,
                           float* C, int M, int N, int K, float alpha = 1.f)
{
    dim3 grid(N / BN, M / BM);
    sgemm_kernel<0><<<grid, 256>>>(A, B, bias, C, M, N, K, alpha);
}
static inline void gemm_nt(const float* A, const float* B, const float* bias,
                           float* C, int M, int N, int K, float alpha = 1.f)
{
    dim3 grid(N / BN, M / BM);
    sgemm_kernel<1><<<grid, 256>>>(A, B, bias, C, M, N, K, alpha);
}

extern "C" void kernel_launch(void* const* d_in, const int* in_sizes, int n_in,
                              void* d_out, int out_size)
{
    const float* x   = (const float*)d_in[0];
    const float* Wq  = (const float*)d_in[1];
    const float* bq  = (const float*)d_in[2];
    const float* Wk  = (const float*)d_in[3];
    const float* bk  = (const float*)d_in[4];
    const float* Wv  = (const float*)d_in[5];
    const float* bv  = (const float*)d_in[6];
    const float* Wp  = (const float*)d_in[7];
    const float* bp  = (const float*)d_in[8];
    const float* g1  = (const float*)d_in[9];
    const float* be1 = (const float*)d_in[10];
    const float* W1  = (const float*)d_in[11];
    const float* b1  = (const float*)d_in[12];
    const float* W2  = (const float*)d_in[13];
    const float* b2  = (const float*)d_in[14];
    const float* g2  = (const float*)d_in[15];
    const float* be2 = (const float*)d_in[16];
    const float* Wf  = (const float*)d_in[17];
    const float* bf  = (const float*)d_in[18];
    float* out = (float*)d_out;

    float *px, *px2, *pq, *pk, *pv, *patt, *pt, *pz, *ph, *ph2;
    cudaGetSymbolAddress((void**)&px,   g_x);
    cudaGetSymbolAddress((void**)&px2,  g_x2);
    cudaGetSymbolAddress((void**)&pq,   g_q);
    cudaGetSymbolAddress((void**)&pk,   g_k);
    cudaGetSymbolAddress((void**)&pv,   g_v);
    cudaGetSymbolAddress((void**)&patt, g_att);
    cudaGetSymbolAddress((void**)&pt,   g_t);
    cudaGetSymbolAddress((void**)&pz,   g_z);
    cudaGetSymbolAddress((void**)&ph,   g_h);
    cudaGetSymbolAddress((void**)&ph2,  g_h2);

    cudaMemcpyAsync(px, x, (size_t)SQ * DM * sizeof(float),
                    cudaMemcpyDeviceToDevice);

    const float scale = 1.0f / sqrtf((float)FF);

    for (int l = 0; l < NL; l++) {
        const float* Wq_l = Wq + (size_t)l * DM * FF;
        const float* Wk_l = Wk + (size_t)l * DM * FF;
        const float* Wv_l = Wv + (size_t)l * DM * FF;
        const float* Wp_l = Wp + (size_t)l * FF * FF;
        const float* W1_l = W1 + (size_t)l * FF * HID;
        const float* W2_l = W2 + (size_t)l * HID * DM;

        // QKV projections
        gemm_nn(px, Wq_l, bq + (size_t)l * FF, pq, SQ, FF, DM);
        gemm_nn(px, Wk_l, bk + (size_t)l * FF, pk, SQ, FF, DM);
        gemm_nn(px, Wv_l, bv + (size_t)l * FF, pv, SQ, FF, DM);

        // attention scores + causal softmax
        gemm_nt(pq, pk, nullptr, patt, SQ, SQ, FF, scale);
        softmax_causal_kernel<<<SQ, 256>>>(patt);

        // att @ v, output projection
        gemm_nn(patt, pv, nullptr, pt, SQ, FF, SQ);
        gemm_nn(pt, Wp_l, bp + (size_t)l * FF, pz, SQ, FF, FF);

        // LN1(z + x)
        add_ln_kernel<<<SQ, 256>>>(pz, px, g1 + (size_t)l * FF,
                                   be1 + (size_t)l * FF, px2);

        // FFN (no activation, per reference)
        gemm_nn(px2, W1_l, b1 + (size_t)l * HID, ph, SQ, HID, FF);
        gemm_nn(ph, W2_l, b2 + (size_t)l * DM, ph2, SQ, DM, HID);

        // LN2(h + x2) -> x
        add_ln_kernel<<<SQ, 256>>>(ph2, px2, g2 + (size_t)l * DM,
                                   be2 + (size_t)l * DM, px);
    }

    // final head + vocab softmax (in place on d_out)
    gemm_nn(px, Wf, bf, out, SQ, VOC, DM);
    softmax_vocab_kernel<<<SQ, 256>>>(out);

    (void)in_sizes; (void)n_in; (void)out_size;
}

// round 2
// speedup vs baseline: 2.8487x; 2.8487x over previous
#include <cuda_runtime.h>
#include <cuda_bf16.h>
#include <cstdint>
#include <cmath>

// Problem constants
#define SQ   2048
#define DM   512
#define FF   512
#define HID  2048
#define VOC  32000
#define NL   4
#define LN_EPS 1e-5f

// ------------------------- scratch (device globals) ------------------------
__device__ float g_x  [SQ * DM];
__device__ float g_x2 [SQ * DM];
__device__ float g_q  [SQ * FF];
__device__ float g_k  [SQ * FF];
__device__ float g_v  [SQ * FF];
__device__ float g_att[SQ * SQ];
__device__ float g_t  [SQ * FF];
__device__ float g_z  [SQ * FF];
__device__ float g_h  [SQ * HID];
__device__ float g_h2 [SQ * DM];

// ------------------------- PTX wrappers ------------------------------------
__device__ __forceinline__ void ldsm4(uint32_t* r, uint32_t addr) {
    asm volatile("ldmatrix.sync.aligned.m8n8.x4.shared.b16 {%0,%1,%2,%3}, [%4];"
                 : "=r"(r[0]), "=r"(r[1]), "=r"(r[2]), "=r"(r[3]) : "r"(addr));
}
__device__ __forceinline__ void ldsm4t(uint32_t* r, uint32_t addr) {
    asm volatile("ldmatrix.sync.aligned.m8n8.x4.trans.shared.b16 {%0,%1,%2,%3}, [%4];"
                 : "=r"(r[0]), "=r"(r[1]), "=r"(r[2]), "=r"(r[3]) : "r"(addr));
}
__device__ __forceinline__ void mma16816(float* c, const uint32_t* a, const uint32_t* b) {
    asm volatile("mma.sync.aligned.m16n8k16.row.col.f32.bf16.bf16.f32 "
                 "{%0,%1,%2,%3}, {%4,%5,%6,%7}, {%8,%9}, {%0,%1,%2,%3};"
                 : "+f"(c[0]), "+f"(c[1]), "+f"(c[2]), "+f"(c[3])
                 : "r"(a[0]), "r"(a[1]), "r"(a[2]), "r"(a[3]),
                   "r"(b[0]), "r"(b[1]));
}

// split fp32 -> bf16 hi + bf16 lo (error-compensated)
__device__ __forceinline__ void split1(float x, __nv_bfloat16& h, __nv_bfloat16& l) {
    h = __float2bfloat16_rn(x);
    l = __float2bfloat16_rn(x - __bfloat162float(h));
}

struct Ptrs { const float* B; const float* bias; float* C; };

// ------------------------- bf16-split tensor-core GEMM ---------------------
// C[M,N] = alpha * A[M,K] @ op(B) + bias
// TRANSB=0: B is [K,N].  TRANSB=1: B is [N,K] (C = A @ B^T).
// M % 128 == 0, N % BN == 0, K % 32 == 0 (true for all calls here).
template<int BN, int TRANSB>
__global__ void __launch_bounds__(256, 2)
gemm_mma(const float* __restrict__ A, Ptrs p0, Ptrs p1, Ptrs p2,
         int M, int N, int K, float alpha)
{
    constexpr int BM = 128, BK = 32;
    constexpr int ASTR  = BK + 8;                 // 40 halves (conflict-free)
    constexpr int BROWS = TRANSB ? BN : BK;
    constexpr int BSTR  = TRANSB ? (BK + 8) : (BN + 8);
    constexpr int WN = BN / 2;                    // warp n extent (4x2 warp grid)
    constexpr int NT = WN / 8;                    // n tiles per warp

    __shared__ __align__(16) __nv_bfloat16 sA[2][BM][ASTR];
    __shared__ __align__(16) __nv_bfloat16 sB[2][BROWS][BSTR];

    const float* Bp; const float* biasp; float* Cp;
    if (blockIdx.z == 0)      { Bp = p0.B; biasp = p0.bias; Cp = p0.C; }
    else if (blockIdx.z == 1) { Bp = p1.B; biasp = p1.bias; Cp = p1.C; }
    else                      { Bp = p2.B; biasp = p2.bias; Cp = p2.C; }

    const int tid  = threadIdx.x;
    const int lane = tid & 31;
    const int warp = tid >> 5;
    const int wm   = warp >> 1;        // 0..3
    const int wn   = warp & 1;         // 0..1
    const int l7   = lane & 7;
    const int q1   = (lane >> 3) & 1;
    const int q2   = lane >> 4;
    const int m0   = blockIdx.y * BM;
    const int n0   = blockIdx.x * BN;

    float acc[2][NT][4];
    #pragma unroll
    for (int mt = 0; mt < 2; mt++)
        #pragma unroll
        for (int nt = 0; nt < NT; nt++)
            #pragma unroll
            for (int i = 0; i < 4; i++) acc[mt][nt][i] = 0.f;

    const uint32_t sAu = (uint32_t)__cvta_generic_to_shared(&sA[0][0][0]);
    const uint32_t sBu = (uint32_t)__cvta_generic_to_shared(&sB[0][0][0]);
    constexpr uint32_t aPart = BM * ASTR * 2;     // bytes
    constexpr uint32_t bPart = BROWS * BSTR * 2;

    // ldmatrix per-lane base addresses
    const uint32_t aBase = sAu + (uint32_t)(((wm * 32 + l7 + q1 * 8) * ASTR + q2 * 8) * 2);
    uint32_t bBase;
    if (TRANSB)  // sB[n][k]: nrow = wn*WN + l7 (+q2*8, +p*16), kcol = q1*8 (+ks*16)
        bBase = sBu + (uint32_t)(((wn * WN + l7 + q2 * 8) * BSTR + q1 * 8) * 2);
    else         // sB[k][n]: krow = l7 + q1*8 (+ks*16), ncol = wn*WN + q2*8 (+p*16)
        bBase = sBu + (uint32_t)(((l7 + q1 * 8) * BSTR + wn * WN + q2 * 8) * 2);

    for (int k0 = 0; k0 < K; k0 += BK) {
        // ---- stage A tile (BM x BK), split into hi/lo
        #pragma unroll
        for (int r = 0; r < (BM * BK) / (4 * 256); r++) {
            int f = tid + 256 * r;
            int row = f >> 3;
            int kc  = (f & 7) << 2;
            float4 v = *(const float4*)(A + (size_t)(m0 + row) * K + k0 + kc);
            __nv_bfloat16 h0,h1,h2,h3,l0,l1,l2,l3;
            split1(v.x,h0,l0); split1(v.y,h1,l1); split1(v.z,h2,l2); split1(v.w,h3,l3);
            *(__nv_bfloat162*)&sA[0][row][kc]     = __nv_bfloat162{h0,h1};
            *(__nv_bfloat162*)&sA[0][row][kc + 2] = __nv_bfloat162{h2,h3};
            *(__nv_bfloat162*)&sA[1][row][kc]     = __nv_bfloat162{l0,l1};
            *(__nv_bfloat162*)&sA[1][row][kc + 2] = __nv_bfloat162{l2,l3};
        }
        // ---- stage B tile
        if (TRANSB) {
            #pragma unroll
            for (int r = 0; r < (BN * BK) / (4 * 256); r++) {
                int f = tid + 256 * r;
                int row = f >> 3;          // n index
                int kc  = (f & 7) << 2;
                float4 v = *(const float4*)(Bp + (size_t)(n0 + row) * K + k0 + kc);
                __nv_bfloat16 h0,h1,h2,h3,l0,l1,l2,l3;
                split1(v.x,h0,l0); split1(v.y,h1,l1); split1(v.z,h2,l2); split1(v.w,h3,l3);
                *(__nv_bfloat162*)&sB[0][row][kc]     = __nv_bfloat162{h0,h1};
                *(__nv_bfloat162*)&sB[0][row][kc + 2] = __nv_bfloat162{h2,h3};
                *(__nv_bfloat162*)&sB[1][row][kc]     = __nv_bfloat162{l0,l1};
                *(__nv_bfloat162*)&sB[1][row][kc + 2] = __nv_bfloat162{l2,l3};
            }
        } else {
            #pragma unroll
            for (int r = 0; r < (BN * BK) / (4 * 256); r++) {
                int f = tid + 256 * r;
                int krow = f / (BN / 4);
                int nc   = (f % (BN / 4)) << 2;
                float4 v = *(const float4*)(Bp + (size_t)(k0 + krow) * N + n0 + nc);
                __nv_bfloat16 h0,h1,h2,h3,l0,l1,l2,l3;
                split1(v.x,h0,l0); split1(v.y,h1,l1); split1(v.z,h2,l2); split1(v.w,h3,l3);
                *(__nv_bfloat162*)&sB[0][krow][nc]     = __nv_bfloat162{h0,h1};
                *(__nv_bfloat162*)&sB[0][krow][nc + 2] = __nv_bfloat162{h2,h3};
                *(__nv_bfloat162*)&sB[1][krow][nc]     = __nv_bfloat162{l0,l1};
                *(__nv_bfloat162*)&sB[1][krow][nc + 2] = __nv_bfloat162{l2,l3};
            }
        }
        __syncthreads();

        #pragma unroll
        for (int ks = 0; ks < 2; ks++) {
            uint32_t a[2][4], bh[NT][2], bl[NT][2];

            // A hi fragments
            #pragma unroll
            for (int mt = 0; mt < 2; mt++)
                ldsm4(a[mt], aBase + (uint32_t)(mt * 16 * ASTR * 2 + ks * 32));

            // B hi + lo fragments (each x4 covers 2 n-tiles)
            #pragma unroll
            for (int p = 0; p < NT / 2; p++) {
                uint32_t off;
                if (TRANSB) off = (uint32_t)(p * 16 * BSTR * 2 + ks * 32);
                else        off = (uint32_t)(ks * 16 * BSTR * 2 + p * 32);
                uint32_t r4[4];
                if (TRANSB) ldsm4 (r4, bBase + off);
                else        ldsm4t(r4, bBase + off);
                bh[2*p][0]   = r4[0]; bh[2*p][1]   = r4[1];
                bh[2*p+1][0] = r4[2]; bh[2*p+1][1] = r4[3];
                if (TRANSB) ldsm4 (r4, bBase + bPart + off);
                else        ldsm4t(r4, bBase + bPart + off);
                bl[2*p][0]   = r4[0]; bl[2*p][1]   = r4[1];
                bl[2*p+1][0] = r4[2]; bl[2*p+1][1] = r4[3];
            }

            // hi @ hi
            #pragma unroll
            for (int nt = 0; nt < NT; nt++)
                #pragma unroll
                for (int mt = 0; mt < 2; mt++)
                    mma16816(acc[mt][nt], a[mt], bh[nt]);
            // hi @ lo
            #pragma unroll
            for (int nt = 0; nt < NT; nt++)
                #pragma unroll
                for (int mt = 0; mt < 2; mt++)
                    mma16816(acc[mt][nt], a[mt], bl[nt]);
            // lo @ hi (overwrite a with A_lo fragments)
            #pragma unroll
            for (int mt = 0; mt < 2; mt++)
                ldsm4(a[mt], aBase + aPart + (uint32_t)(mt * 16 * ASTR * 2 + ks * 32));
            #pragma unroll
            for (int nt = 0; nt < NT; nt++)
                #pragma unroll
                for (int mt = 0; mt < 2; mt++)
                    mma16816(acc[mt][nt], a[mt], bh[nt]);
        }
        __syncthreads();
    }

    // ---- epilogue
    #pragma unroll
    for (int mt = 0; mt < 2; mt++) {
        int row0 = m0 + wm * 32 + mt * 16 + (lane >> 2);
        #pragma unroll
        for (int nt = 0; nt < NT; nt++) {
            int col = n0 + wn * WN + nt * 8 + ((lane & 3) << 1);
            float b0 = 0.f, b1 = 0.f;
            if (biasp) { b0 = biasp[col]; b1 = biasp[col + 1]; }
            float2 v0, v1;
            v0.x = acc[mt][nt][0] * alpha + b0;
            v0.y = acc[mt][nt][1] * alpha + b1;
            v1.x = acc[mt][nt][2] * alpha + b0;
            v1.y = acc[mt][nt][3] * alpha + b1;
            *(float2*)(Cp + (size_t)row0 * N + col)       = v0;
            *(float2*)(Cp + (size_t)(row0 + 8) * N + col) = v1;
        }
    }
}

// ------------------------- causal row softmax on [S,S] ---------------------
__global__ void softmax_causal_kernel(float* __restrict__ att)
{
    const int i = blockIdx.x;
    float* row = att + (size_t)i * SQ;
    const int tid = threadIdx.x;
    const int n = i + 1;

    __shared__ float red[256];

    float m = -1e30f;
    for (int j = tid; j < n; j += 256) m = fmaxf(m, row[j]);
    red[tid] = m; __syncthreads();
    for (int st = 128; st > 0; st >>= 1) {
        if (tid < st) red[tid] = fmaxf(red[tid], red[tid + st]);
        __syncthreads();
    }
    m = red[0]; __syncthreads();

    float s = 0.f;
    for (int j = tid; j < n; j += 256) {
        float e = __expf(row[j] - m);
        row[j] = e;
        s += e;
    }
    red[tid] = s; __syncthreads();
    for (int st = 128; st > 0; st >>= 1) {
        if (tid < st) red[tid] += red[tid + st];
        __syncthreads();
    }
    const float inv = 1.f / red[0];

    for (int j = tid; j < n; j += 256) row[j] *= inv;
    for (int j = n + tid; j < SQ; j += 256) row[j] = 0.f;
}

// ------------------------- fused residual-add + LayerNorm ------------------
__global__ void add_ln_kernel(const float* __restrict__ a,
                              const float* __restrict__ res,
                              const float* __restrict__ g,
                              const float* __restrict__ beta,
                              float* __restrict__ out)
{
    const int row = blockIdx.x;
    const int tid = threadIdx.x;
    const size_t base = (size_t)row * DM;

    float v0 = a[base + tid]       + res[base + tid];
    float v1 = a[base + tid + 256] + res[base + tid + 256];

    __shared__ float red[256];
    red[tid] = v0 + v1; __syncthreads();
    for (int st = 128; st > 0; st >>= 1) {
        if (tid < st) red[tid] += red[tid + st];
        __syncthreads();
    }
    const float mu = red[0] * (1.0f / DM);
    __syncthreads();

    float d0 = v0 - mu, d1 = v1 - mu;
    red[tid] = d0 * d0 + d1 * d1; __syncthreads();
    for (int st = 128; st > 0; st >>= 1) {
        if (tid < st) red[tid] += red[tid + st];
        __syncthreads();
    }
    const float rstd = rsqrtf(red[0] * (1.0f / DM) + LN_EPS);

    out[base + tid]       = d0 * rstd * g[tid]       + beta[tid];
    out[base + tid + 256] = d1 * rstd * g[tid + 256] + beta[tid + 256];
}

// ------------------------- row softmax over vocab ---------------------------
__global__ void softmax_vocab_kernel(float* __restrict__ x)
{
    const int i = blockIdx.x;
    float* row = x + (size_t)i * VOC;
    const int tid = threadIdx.x;

    __shared__ float red[256];

    float m = -1e30f;
    for (int j = tid; j < VOC; j += 256) m = fmaxf(m, row[j]);
    red[tid] = m; __syncthreads();
    for (int st = 128; st > 0; st >>= 1) {
        if (tid < st) red[tid] = fmaxf(red[tid], red[tid + st]);
        __syncthreads();
    }
    m = red[0]; __syncthreads();

    float s = 0.f;
    for (int j = tid; j < VOC; j += 256) {
        float e = __expf(row[j] - m);
        row[j] = e;
        s += e;
    }
    red[tid] = s; __syncthreads();
    for (int st = 128; st > 0; st >>= 1) {
        if (tid < st) red[tid] += red[tid + st];
        __syncthreads();
    }
    const float inv = 1.f / red[0];
    for (int j = tid; j < VOC; j += 256) row[j] *= inv;
}

// ------------------------- host launchers -----------------------------------
static inline void gemm_nn1(const float* A, const float* B, const float* bias,
                            float* C, int M, int N, int K, float alpha = 1.f)
{
    Ptrs p{B, bias, C};
    if (N % 128 == 0 && N != 512) {
        dim3 grid(N / 128, M / 128, 1);
        gemm_mma<128, 0><<<grid, 256>>>(A, p, p, p, M, N, K, alpha);
    } else {
        dim3 grid(N / 64, M / 128, 1);
        gemm_mma<64, 0><<<grid, 256>>>(A, p, p, p, M, N, K, alpha);
    }
}
static inline void gemm_nn3(const float* A, Ptrs p0, Ptrs p1, Ptrs p2,
                            int M, int N, int K)
{
    dim3 grid(N / 64, M / 128, 3);
    gemm_mma<64, 0><<<grid, 256>>>(A, p0, p1, p2, M, N, K, 1.f);
}
static inline void gemm_nt1(const float* A, const float* B, float* C,
                            int M, int N, int K, float alpha)
{
    Ptrs p{B, nullptr, C};
    dim3 grid(N / 128, M / 128, 1);
    gemm_mma<128, 1><<<grid, 256>>>(A, p, p, p, M, N, K, alpha);
}

extern "C" void kernel_launch(void* const* d_in, const int* in_sizes, int n_in,
                              void* d_out, int out_size)
{
    const float* x   = (const float*)d_in[0];
    const float* Wq  = (const float*)d_in[1];
    const float* bq  = (const float*)d_in[2];
    const float* Wk  = (const float*)d_in[3];
    const float* bk  = (const float*)d_in[4];
    const float* Wv  = (const float*)d_in[5];
    const float* bv  = (const float*)d_in[6];
    const float* Wp  = (const float*)d_in[7];
    const float* bp  = (const float*)d_in[8];
    const float* g1  = (const float*)d_in[9];
    const float* be1 = (const float*)d_in[10];
    const float* W1  = (const float*)d_in[11];
    const float* b1  = (const float*)d_in[12];
    const float* W2  = (const float*)d_in[13];
    const float* b2  = (const float*)d_in[14];
    const float* g2  = (const float*)d_in[15];
    const float* be2 = (const float*)d_in[16];
    const float* Wf  = (const float*)d_in[17];
    const float* bf  = (const float*)d_in[18];
    float* out = (float*)d_out;

    float *px, *px2, *pq, *pk, *pv, *patt, *pt, *pz, *ph, *ph2;
    cudaGetSymbolAddress((void**)&px,   g_x);
    cudaGetSymbolAddress((void**)&px2,  g_x2);
    cudaGetSymbolAddress((void**)&pq,   g_q);
    cudaGetSymbolAddress((void**)&pk,   g_k);
    cudaGetSymbolAddress((void**)&pv,   g_v);
    cudaGetSymbolAddress((void**)&patt, g_att);
    cudaGetSymbolAddress((void**)&pt,   g_t);
    cudaGetSymbolAddress((void**)&pz,   g_z);
    cudaGetSymbolAddress((void**)&ph,   g_h);
    cudaGetSymbolAddress((void**)&ph2,  g_h2);

    cudaMemcpyAsync(px, x, (size_t)SQ * DM * sizeof(float),
                    cudaMemcpyDeviceToDevice);

    const float scale = 1.0f / sqrtf((float)FF);

    for (int l = 0; l < NL; l++) {
        const float* Wq_l = Wq + (size_t)l * DM * FF;
        const float* Wk_l = Wk + (size_t)l * DM * FF;
        const float* Wv_l = Wv + (size_t)l * DM * FF;
        const float* Wp_l = Wp + (size_t)l * FF * FF;
        const float* W1_l = W1 + (size_t)l * FF * HID;
        const float* W2_l = W2 + (size_t)l * HID * DM;

        // QKV projections (batched, one launch)
        Ptrs pQ{Wq_l, bq + (size_t)l * FF, pq};
        Ptrs pK{Wk_l, bk + (size_t)l * FF, pk};
        Ptrs pV{Wv_l, bv + (size_t)l * FF, pv};
        gemm_nn3(px, pQ, pK, pV, SQ, FF, DM);

        // attention scores + causal softmax
        gemm_nt1(pq, pk, patt, SQ, SQ, FF, scale);
        softmax_causal_kernel<<<SQ, 256>>>(patt);

        // att @ v, output projection
        gemm_nn1(patt, pv, nullptr, pt, SQ, FF, SQ);
        gemm_nn1(pt, Wp_l, bp + (size_t)l * FF, pz, SQ, FF, FF);

        // LN1(z + x)
        add_ln_kernel<<<SQ, 256>>>(pz, px, g1 + (size_t)l * FF,
                                   be1 + (size_t)l * FF, px2);

        // FFN
        gemm_nn1(px2, W1_l, b1 + (size_t)l * HID, ph, SQ, HID, FF);
        gemm_nn1(ph, W2_l, b2 + (size_t)l * DM, ph2, SQ, DM, HID);

        // LN2(h + x2) -> x
        add_ln_kernel<<<SQ, 256>>>(ph2, px2, g2 + (size_t)l * DM,
                                   be2 + (size_t)l * DM, px);
    }

    // final head + vocab softmax
    gemm_nn1(px, Wf, bf, out, SQ, VOC, DM);
    softmax_vocab_kernel<<<SQ, 256>>>(out);

    (void)in_sizes; (void)n_in; (void)out_size;
}

// round 3
// speedup vs baseline: 3.1948x; 1.1215x over previous
#include <cuda_runtime.h>
#include <cuda_bf16.h>
#include <cstdint>
#include <cmath>

#define SQ   2048
#define DM   512
#define FF   512
#define HID  2048
#define VOC  32000
#define NL   4
#define LN_EPS 1e-5f

typedef __nv_bfloat16  bf16;
typedef __nv_bfloat162 bf162;

// ------------------------- fp32 scratch ------------------------------------
__device__ float g_x  [SQ * DM];
__device__ float g_x2 [SQ * DM];
__device__ float g_att[SQ * SQ];
__device__ float g_z  [SQ * FF];
__device__ float g_h2 [SQ * DM];

// ------------------------- bf16 hi/lo activations --------------------------
__device__ bf16 g_xh [SQ*DM],  g_xl [SQ*DM];
__device__ bf16 g_x2h[SQ*DM],  g_x2l[SQ*DM];
__device__ bf16 g_qh [SQ*FF],  g_ql [SQ*FF];
__device__ bf16 g_kh [SQ*FF],  g_kl [SQ*FF];
__device__ bf16 g_vh [SQ*FF],  g_vl [SQ*FF];
__device__ bf16 g_ath[SQ*SQ],  g_atl[SQ*SQ];
__device__ bf16 g_th [SQ*FF],  g_tl [SQ*FF];
__device__ bf16 g_hh [SQ*HID], g_hl [SQ*HID];

// ------------------------- bf16 hi/lo weights ------------------------------
__device__ bf16 g_wqh[NL*DM*FF],  g_wql[NL*DM*FF];
__device__ bf16 g_wkh[NL*DM*FF],  g_wkl[NL*DM*FF];
__device__ bf16 g_wvh[NL*DM*FF],  g_wvl[NL*DM*FF];
__device__ bf16 g_wph[NL*FF*FF],  g_wpl[NL*FF*FF];
__device__ bf16 g_w1h[NL*FF*HID], g_w1l[NL*FF*HID];
__device__ bf16 g_w2h[NL*HID*DM], g_w2l[NL*HID*DM];
__device__ bf16 g_wfh[DM*VOC],    g_wfl[DM*VOC];

// ------------------------- PTX wrappers ------------------------------------
__device__ __forceinline__ void ldsm4(uint32_t* r, uint32_t addr) {
    asm volatile("ldmatrix.sync.aligned.m8n8.x4.shared.b16 {%0,%1,%2,%3}, [%4];"
                 : "=r"(r[0]), "=r"(r[1]), "=r"(r[2]), "=r"(r[3]) : "r"(addr));
}
__device__ __forceinline__ void ldsm4t(uint32_t* r, uint32_t addr) {
    asm volatile("ldmatrix.sync.aligned.m8n8.x4.trans.shared.b16 {%0,%1,%2,%3}, [%4];"
                 : "=r"(r[0]), "=r"(r[1]), "=r"(r[2]), "=r"(r[3]) : "r"(addr));
}
__device__ __forceinline__ void mma16816(float* c, const uint32_t* a, const uint32_t* b) {
    asm volatile("mma.sync.aligned.m16n8k16.row.col.f32.bf16.bf16.f32 "
                 "{%0,%1,%2,%3}, {%4,%5,%6,%7}, {%8,%9}, {%0,%1,%2,%3};"
                 : "+f"(c[0]), "+f"(c[1]), "+f"(c[2]), "+f"(c[3])
                 : "r"(a[0]), "r"(a[1]), "r"(a[2]), "r"(a[3]),
                   "r"(b[0]), "r"(b[1]));
}
__device__ __forceinline__ void cpa16(uint32_t s, const void* g) {
    asm volatile("cp.async.cg.shared.global [%0], [%1], 16;\n" :: "r"(s), "l"(g));
}
__device__ __forceinline__ void cpcommit() { asm volatile("cp.async.commit_group;\n"); }
template<int N> __device__ __forceinline__ void cpwait() {
    asm volatile("cp.async.wait_group %0;\n" :: "n"(N));
}

__device__ __forceinline__ void split1(float x, bf16& h, bf16& l) {
    h = __float2bfloat16_rn(x);
    l = __float2bfloat16_rn(x - __bfloat162float(h));
}

// ------------------------- fp32 -> bf16 hi/lo split ------------------------
__global__ void split_kernel(const float* __restrict__ in,
                             bf16* __restrict__ hi, bf16* __restrict__ lo, int n)
{
    int i = (blockIdx.x * blockDim.x + threadIdx.x) * 4;
    if (i >= n) return;
    float4 v = *(const float4*)(in + i);
    bf16 h0,h1,h2,h3,l0,l1,l2,l3;
    split1(v.x,h0,l0); split1(v.y,h1,l1); split1(v.z,h2,l2); split1(v.w,h3,l3);
    *(bf162*)(hi + i)     = bf162{h0,h1};
    *(bf162*)(hi + i + 2) = bf162{h2,h3};
    *(bf162*)(lo + i)     = bf162{l0,l1};
    *(bf162*)(lo + i + 2) = bf162{l2,l3};
}

struct GPtrs { const bf16 *Bh, *Bl; const float* bias; float* C; bf16 *Ch, *Cl; };

// ------------------------- pipelined bf16-split GEMM -----------------------
// C = alpha*A@op(B) + bias.  A given as bf16 hi/lo [M,K].  B bf16 hi/lo.
// TRANSB=0: B [K,N]. TRANSB=1: B [N,K].
// MODE: 0 normal; 1 causal skip (scores, requires TRANSB=1); 2 K bounded at m0+BM.
template<int BN, int TRANSB, int MODE>
__global__ void __launch_bounds__(256)
gemm_bf16(const bf16* __restrict__ Ah, const bf16* __restrict__ Al,
          GPtrs p0, GPtrs p1, GPtrs p2, int M, int N, int K, float alpha)
{
    constexpr int BM = 128, BK = 32, ST = 3;
    constexpr int ASTR   = 40;                  // halves, 16B-aligned stride
    constexpr int A_PART = BM * ASTR;           // halves per (hi|lo) A part
    constexpr int BROWS  = TRANSB ? BN : BK;
    constexpr int BSTR   = TRANSB ? 40 : (BN + 8);
    constexpr int B_PART = BROWS * BSTR;
    constexpr int STAGE  = 2*A_PART + 2*B_PART; // halves per stage
    constexpr int WM  = (BN == 128) ? 2 : 4;    // warp grid: WM x (8/WM)
    constexpr int MT  = BM / (WM * 16);         // m-tiles per warp
    constexpr int NT  = 4;                      // n-tiles per warp (extent 32)

    extern __shared__ bf16 smem[];

    const int m0 = blockIdx.y * BM;
    const int n0 = blockIdx.x * BN;
    if (MODE == 1 && n0 > m0) return;

    GPtrs P = (blockIdx.z == 0) ? p0 : ((blockIdx.z == 1) ? p1 : p2);

    int Keff = K;
    if (MODE == 2) Keff = min(K, m0 + BM);
    const int T = Keff / BK;

    const int tid  = threadIdx.x;
    const int lane = tid & 31;
    const int warp = tid >> 5;
    const int wm = warp % WM;
    const int wn = warp / WM;
    const int l7 = lane & 7, q1 = (lane >> 3) & 1, q2 = lane >> 4;

    auto load_tile = [&](int t, int s) {
        const int k0 = t * BK;
        bf16* sb = smem + s * STAGE;
        // A: 2 parts x 128 rows x 4 chunks(16B) = 1024 copies
        #pragma unroll
        for (int i = 0; i < 4; i++) {
            int f = tid + 256 * i;
            int part = f >> 9;
            int r = (f >> 2) & 127;
            int c = f & 3;
            const bf16* gp = (part ? Al : Ah) + (size_t)(m0 + r) * K + k0 + c * 8;
            cpa16((uint32_t)__cvta_generic_to_shared(sb + part*A_PART + r*ASTR + c*8), gp);
        }
        if (TRANSB) {
            constexpr int CB = BN * 4;          // chunks per part
            #pragma unroll
            for (int i = 0; i < (2 * CB) / 256; i++) {
                int f = tid + 256 * i;
                int part = f / CB, rem = f % CB;
                int r = rem >> 2, c = rem & 3;
                const bf16* gp = (part ? P.Bl : P.Bh) + (size_t)(n0 + r) * K + k0 + c * 8;
                cpa16((uint32_t)__cvta_generic_to_shared(sb + 2*A_PART + part*B_PART + r*BSTR + c*8), gp);
            }
        } else {
            constexpr int CR = BN / 8;
            constexpr int CB = 32 * CR;
            #pragma unroll
            for (int i = 0; i < (2 * CB) / 256; i++) {
                int f = tid + 256 * i;
                int part = f / CB, rem = f % CB;
                int r = rem / CR, c = rem % CR;
                const bf16* gp = (part ? P.Bl : P.Bh) + (size_t)(k0 + r) * N + n0 + c * 8;
                cpa16((uint32_t)__cvta_generic_to_shared(sb + 2*A_PART + part*B_PART + r*BSTR + c*8), gp);
            }
        }
    };

    float acc[MT][NT][4];
    #pragma unroll
    for (int mt = 0; mt < MT; mt++)
        #pragma unroll
        for (int nt = 0; nt < NT; nt++)
            #pragma unroll
            for (int i = 0; i < 4; i++) acc[mt][nt][i] = 0.f;

    const uint32_t smemBase = (uint32_t)__cvta_generic_to_shared(smem);
    const uint32_t aoff = (uint32_t)(((wm*MT*16 + l7 + q1*8) * ASTR + q2*8) * 2);
    uint32_t boff;
    if (TRANSB) boff = (uint32_t)((2*A_PART + (wn*32 + l7 + q2*8) * BSTR + q1*8) * 2);
    else        boff = (uint32_t)((2*A_PART + (l7 + q1*8) * BSTR + wn*32 + q2*8) * 2);

    load_tile(0, 0); cpcommit();
    load_tile(1, 1); cpcommit();

    for (int t = 0; t < T; t++) {
        cpwait<1>();
        __syncthreads();
        if (t + 2 < T) { load_tile(t + 2, (t + 2) % ST); cpcommit(); }

        const uint32_t sbase = smemBase + (uint32_t)((t % ST) * STAGE * 2);

        #pragma unroll
        for (int ks = 0; ks < 2; ks++) {
            uint32_t a[MT][4], bh[NT][2], bl[NT][2];
            #pragma unroll
            for (int mt = 0; mt < MT; mt++)
                ldsm4(a[mt], sbase + aoff + (uint32_t)(mt*16*ASTR*2 + ks*32));
            #pragma unroll
            for (int pp = 0; pp < 2; pp++) {
                uint32_t off = TRANSB ? (uint32_t)(pp*16*BSTR*2 + ks*32)
                                      : (uint32_t)(ks*16*BSTR*2 + pp*32);
                uint32_t r4[4];
                if (TRANSB) ldsm4 (r4, sbase + boff + off);
                else        ldsm4t(r4, sbase + boff + off);
                bh[2*pp][0]   = r4[0]; bh[2*pp][1]   = r4[1];
                bh[2*pp+1][0] = r4[2]; bh[2*pp+1][1] = r4[3];
                if (TRANSB) ldsm4 (r4, sbase + boff + (uint32_t)(B_PART*2) + off);
                else        ldsm4t(r4, sbase + boff + (uint32_t)(B_PART*2) + off);
                bl[2*pp][0]   = r4[0]; bl[2*pp][1]   = r4[1];
                bl[2*pp+1][0] = r4[2]; bl[2*pp+1][1] = r4[3];
            }
            // hi@hi
            #pragma unroll
            for (int nt = 0; nt < NT; nt++)
                #pragma unroll
                for (int mt = 0; mt < MT; mt++)
                    mma16816(acc[mt][nt], a[mt], bh[nt]);
            // hi@lo
            #pragma unroll
            for (int nt = 0; nt < NT; nt++)
                #pragma unroll
                for (int mt = 0; mt < MT; mt++)
                    mma16816(acc[mt][nt], a[mt], bl[nt]);
            // lo@hi
            #pragma unroll
            for (int mt = 0; mt < MT; mt++)
                ldsm4(a[mt], sbase + aoff + (uint32_t)(A_PART*2 + mt*16*ASTR*2 + ks*32));
            #pragma unroll
            for (int nt = 0; nt < NT; nt++)
                #pragma unroll
                for (int mt = 0; mt < MT; mt++)
                    mma16816(acc[mt][nt], a[mt], bh[nt]);
        }
    }

    // ---- epilogue
    #pragma unroll
    for (int mt = 0; mt < MT; mt++) {
        int row0 = m0 + wm*MT*16 + mt*16 + (lane >> 2);
        #pragma unroll
        for (int nt = 0; nt < NT; nt++) {
            int col = n0 + wn*32 + nt*8 + ((lane & 3) << 1);
            float b0 = 0.f, b1 = 0.f;
            if (P.bias) { b0 = P.bias[col]; b1 = P.bias[col + 1]; }
            float c00 = acc[mt][nt][0] * alpha + b0;
            float c01 = acc[mt][nt][1] * alpha + b1;
            float c10 = acc[mt][nt][2] * alpha + b0;
            float c11 = acc[mt][nt][3] * alpha + b1;
            if (P.C) {
                *(float2*)(P.C + (size_t)row0 * N + col)       = float2{c00, c01};
                *(float2*)(P.C + (size_t)(row0 + 8) * N + col) = float2{c10, c11};
            }
            if (P.Ch) {
                bf16 h0,l0,h1,l1;
                split1(c00,h0,l0); split1(c01,h1,l1);
                *(bf162*)(P.Ch + (size_t)row0 * N + col) = bf162{h0,h1};
                *(bf162*)(P.Cl + (size_t)row0 * N + col) = bf162{l0,l1};
                split1(c10,h0,l0); split1(c11,h1,l1);
                *(bf162*)(P.Ch + (size_t)(row0 + 8) * N + col) = bf162{h0,h1};
                *(bf162*)(P.Cl + (size_t)(row0 + 8) * N + col) = bf162{l0,l1};
            }
        }
    }
}

// ------------------------- causal softmax -> bf16 hi/lo --------------------
__global__ void softmax_causal_kernel(const float* __restrict__ att,
                                      bf16* __restrict__ oh, bf16* __restrict__ ol)
{
    const int i = blockIdx.x;
    const float* row = att + (size_t)i * SQ;
    bf16* rh = oh + (size_t)i * SQ;
    bf16* rl = ol + (size_t)i * SQ;
    const int tid = threadIdx.x;
    const int n = i + 1;
    const int fillEnd = ((i >> 7) + 1) << 7;   // zero up to end of 128-block

    __shared__ float red[256];

    float m = -1e30f;
    for (int j = tid; j < n; j += 256) m = fmaxf(m, row[j]);
    red[tid] = m; __syncthreads();
    for (int st = 128; st > 0; st >>= 1) {
        if (tid < st) red[tid] = fmaxf(red[tid], red[tid + st]);
        __syncthreads();
    }
    m = red[0]; __syncthreads();

    float s = 0.f;
    for (int j = tid; j < n; j += 256) s += __expf(row[j] - m);
    red[tid] = s; __syncthreads();
    for (int st = 128; st > 0; st >>= 1) {
        if (tid < st) red[tid] += red[tid + st];
        __syncthreads();
    }
    const float inv = 1.f / red[0];

    for (int j = tid; j < n; j += 256) {
        float e = __expf(row[j] - m) * inv;
        bf16 h, l; split1(e, h, l);
        rh[j] = h; rl[j] = l;
    }
    for (int j = n + tid; j < fillEnd; j += 256) {
        rh[j] = __float2bfloat16_rn(0.f);
        rl[j] = __float2bfloat16_rn(0.f);
    }
}

// ------------------------- residual-add + LayerNorm (+ hi/lo out) ----------
__global__ void add_ln_kernel(const float* __restrict__ a,
                              const float* __restrict__ res,
                              const float* __restrict__ g,
                              const float* __restrict__ beta,
                              float* __restrict__ out,
                              bf16* __restrict__ oh, bf16* __restrict__ ol)
{
    const int row = blockIdx.x;
    const int tid = threadIdx.x;
    const size_t base = (size_t)row * DM;

    float v0 = a[base + tid]       + res[base + tid];
    float v1 = a[base + tid + 256] + res[base + tid + 256];

    __shared__ float red[256];
    red[tid] = v0 + v1; __syncthreads();
    for (int st = 128; st > 0; st >>= 1) {
        if (tid < st) red[tid] += red[tid + st];
        __syncthreads();
    }
    const float mu = red[0] * (1.0f / DM);
    __syncthreads();

    float d0 = v0 - mu, d1 = v1 - mu;
    red[tid] = d0 * d0 + d1 * d1; __syncthreads();
    for (int st = 128; st > 0; st >>= 1) {
        if (tid < st) red[tid] += red[tid + st];
        __syncthreads();
    }
    const float rstd = rsqrtf(red[0] * (1.0f / DM) + LN_EPS);

    float o0 = d0 * rstd * g[tid]       + beta[tid];
    float o1 = d1 * rstd * g[tid + 256] + beta[tid + 256];
    out[base + tid]       = o0;
    out[base + tid + 256] = o1;
    bf16 h, l;
    split1(o0, h, l); oh[base + tid]       = h; ol[base + tid]       = l;
    split1(o1, h, l); oh[base + tid + 256] = h; ol[base + tid + 256] = l;
}

// ------------------------- vocab softmax -----------------------------------
__global__ void softmax_vocab_kernel(float* __restrict__ x)
{
    const int i = blockIdx.x;
    float* row = x + (size_t)i * VOC;
    const int tid = threadIdx.x;

    __shared__ float red[256];

    float m = -1e30f;
    for (int j = tid; j < VOC; j += 256) m = fmaxf(m, row[j]);
    red[tid] = m; __syncthreads();
    for (int st = 128; st > 0; st >>= 1) {
        if (tid < st) red[tid] = fmaxf(red[tid], red[tid + st]);
        __syncthreads();
    }
    m = red[0]; __syncthreads();

    float s = 0.f;
    for (int j = tid; j < VOC; j += 256) {
        float e = __expf(row[j] - m);
        row[j] = e;
        s += e;
    }
    red[tid] = s; __syncthreads();
    for (int st = 128; st > 0; st >>= 1) {
        if (tid < st) red[tid] += red[tid + st];
        __syncthreads();
    }
    const float inv = 1.f / red[0];
    for (int j = tid; j < VOC; j += 256) row[j] *= inv;
}

// ------------------------- host side ---------------------------------------
#define SMEM_64NN  89088
#define SMEM_128NN 113664
#define SMEM_128NT 122880

static inline void do_split(const float* in, bf16* hi, bf16* lo, int n) {
    split_kernel<<<n / 1024, 256>>>(in, hi, lo, n);
}

extern "C" void kernel_launch(void* const* d_in, const int* in_sizes, int n_in,
                              void* d_out, int out_size)
{
    const float* x   = (const float*)d_in[0];
    const float* Wq  = (const float*)d_in[1];
    const float* bq  = (const float*)d_in[2];
    const float* Wk  = (const float*)d_in[3];
    const float* bk  = (const float*)d_in[4];
    const float* Wv  = (const float*)d_in[5];
    const float* bv  = (const float*)d_in[6];
    const float* Wp  = (const float*)d_in[7];
    const float* bp  = (const float*)d_in[8];
    const float* g1  = (const float*)d_in[9];
    const float* be1 = (const float*)d_in[10];
    const float* W1  = (const float*)d_in[11];
    const float* b1  = (const float*)d_in[12];
    const float* W2  = (const float*)d_in[13];
    const float* b2  = (const float*)d_in[14];
    const float* g2  = (const float*)d_in[15];
    const float* be2 = (const float*)d_in[16];
    const float* Wf  = (const float*)d_in[17];
    const float* bf  = (const float*)d_in[18];
    float* out = (float*)d_out;

    cudaFuncSetAttribute(gemm_bf16<64,0,0>,  cudaFuncAttributeMaxDynamicSharedMemorySize, SMEM_64NN);
    cudaFuncSetAttribute(gemm_bf16<64,0,2>,  cudaFuncAttributeMaxDynamicSharedMemorySize, SMEM_64NN);
    cudaFuncSetAttribute(gemm_bf16<128,0,0>, cudaFuncAttributeMaxDynamicSharedMemorySize, SMEM_128NN);
    cudaFuncSetAttribute(gemm_bf16<128,1,1>, cudaFuncAttributeMaxDynamicSharedMemorySize, SMEM_128NT);

    // resolve device globals
    float *px, *px2, *patt, *pz, *ph2;
    cudaGetSymbolAddress((void**)&px,   g_x);
    cudaGetSymbolAddress((void**)&px2,  g_x2);
    cudaGetSymbolAddress((void**)&patt, g_att);
    cudaGetSymbolAddress((void**)&pz,   g_z);
    cudaGetSymbolAddress((void**)&ph2,  g_h2);

    bf16 *xh,*xl,*x2h,*x2l,*qh,*ql,*kh,*kl,*vh,*vl,*ath,*atl,*th,*tl,*hh,*hl;
    cudaGetSymbolAddress((void**)&xh,  g_xh);  cudaGetSymbolAddress((void**)&xl,  g_xl);
    cudaGetSymbolAddress((void**)&x2h, g_x2h); cudaGetSymbolAddress((void**)&x2l, g_x2l);
    cudaGetSymbolAddress((void**)&qh,  g_qh);  cudaGetSymbolAddress((void**)&ql,  g_ql);
    cudaGetSymbolAddress((void**)&kh,  g_kh);  cudaGetSymbolAddress((void**)&kl,  g_kl);
    cudaGetSymbolAddress((void**)&vh,  g_vh);  cudaGetSymbolAddress((void**)&vl,  g_vl);
    cudaGetSymbolAddress((void**)&ath, g_ath); cudaGetSymbolAddress((void**)&atl, g_atl);
    cudaGetSymbolAddress((void**)&th,  g_th);  cudaGetSymbolAddress((void**)&tl,  g_tl);
    cudaGetSymbolAddress((void**)&hh,  g_hh);  cudaGetSymbolAddress((void**)&hl,  g_hl);

    bf16 *wqh,*wql,*wkh,*wkl,*wvh,*wvl,*wph,*wpl,*w1h,*w1l,*w2h,*w2l,*wfh,*wfl;
    cudaGetSymbolAddress((void**)&wqh, g_wqh); cudaGetSymbolAddress((void**)&wql, g_wql);
    cudaGetSymbolAddress((void**)&wkh, g_wkh); cudaGetSymbolAddress((void**)&wkl, g_wkl);
    cudaGetSymbolAddress((void**)&wvh, g_wvh); cudaGetSymbolAddress((void**)&wvl, g_wvl);
    cudaGetSymbolAddress((void**)&wph, g_wph); cudaGetSymbolAddress((void**)&wpl, g_wpl);
    cudaGetSymbolAddress((void**)&w1h, g_w1h); cudaGetSymbolAddress((void**)&w1l, g_w1l);
    cudaGetSymbolAddress((void**)&w2h, g_w2h); cudaGetSymbolAddress((void**)&w2l, g_w2l);
    cudaGetSymbolAddress((void**)&wfh, g_wfh); cudaGetSymbolAddress((void**)&wfl, g_wfl);

    // weight + input splits
    do_split(Wq, wqh, wql, NL*DM*FF);
    do_split(Wk, wkh, wkl, NL*DM*FF);
    do_split(Wv, wvh, wvl, NL*DM*FF);
    do_split(Wp, wph, wpl, NL*FF*FF);
    do_split(W1, w1h, w1l, NL*FF*HID);
    do_split(W2, w2h, w2l, NL*HID*DM);
    do_split(Wf, wfh, wfl, DM*VOC);
    do_split(x,  xh,  xl,  SQ*DM);
    cudaMemcpyAsync(px, x, (size_t)SQ*DM*sizeof(float), cudaMemcpyDeviceToDevice);

    const float scale = 1.0f / sqrtf((float)FF);

    for (int l = 0; l < NL; l++) {
        size_t wOff  = (size_t)l * DM * FF;
        size_t w1Off = (size_t)l * FF * HID;
        size_t w2Off = (size_t)l * HID * DM;

        // QKV (batched over z) — bf16 outputs only
        {
            GPtrs pQ{wqh + wOff, wql + wOff, bq + (size_t)l*FF, nullptr, qh, ql};
            GPtrs pK{wkh + wOff, wkl + wOff, bk + (size_t)l*FF, nullptr, kh, kl};
            GPtrs pV{wvh + wOff, wvl + wOff, bv + (size_t)l*FF, nullptr, vh, vl};
            dim3 grid(FF/64, SQ/128, 3);
            gemm_bf16<64,0,0><<<grid, 256, SMEM_64NN>>>(xh, xl, pQ, pK, pV, SQ, FF, DM, 1.f);
        }
        // scores = q @ k^T * scale (causal-skip), fp32 out
        {
            GPtrs p{kh, kl, nullptr, patt, nullptr, nullptr};
            dim3 grid(SQ/128, SQ/128, 1);
            gemm_bf16<128,1,1><<<grid, 256, SMEM_128NT>>>(qh, ql, p, p, p, SQ, SQ, FF, scale);
        }
        softmax_causal_kernel<<<SQ, 256>>>(patt, ath, atl);
        // t = att @ v (K bounded), bf16 out
        {
            GPtrs p{vh, vl, nullptr, nullptr, th, tl};
            dim3 grid(FF/64, SQ/128, 1);
            gemm_bf16<64,0,2><<<grid, 256, SMEM_64NN>>>(ath, atl, p, p, p, SQ, FF, SQ, 1.f);
        }
        // z = t @ Wp + bp, fp32 out
        {
            GPtrs p{wph + wOff, wpl + wOff, bp + (size_t)l*FF, pz, nullptr, nullptr};
            dim3 grid(FF/64, SQ/128, 1);
            gemm_bf16<64,0,0><<<grid, 256, SMEM_64NN>>>(th, tl, p, p, p, SQ, FF, FF, 1.f);
        }
        // x2 = LN1(z + x), fp32 + hi/lo
        add_ln_kernel<<<SQ, 256>>>(pz, px, g1 + (size_t)l*FF, be1 + (size_t)l*FF,
                                   px2, x2h, x2l);
        // h = x2 @ W1 + b1, bf16 out
        {
            GPtrs p{w1h + w1Off, w1l + w1Off, b1 + (size_t)l*HID, nullptr, hh, hl};
            dim3 grid(HID/128, SQ/128, 1);
            gemm_bf16<128,0,0><<<grid, 256, SMEM_128NN>>>(x2h, x2l, p, p, p, SQ, HID, FF, 1.f);
        }
        // h2 = h @ W2 + b2, fp32 out
        {
            GPtrs p{w2h + w2Off, w2l + w2Off, b2 + (size_t)l*DM, ph2, nullptr, nullptr};
            dim3 grid(DM/64, SQ/128, 1);
            gemm_bf16<64,0,0><<<grid, 256, SMEM_64NN>>>(hh, hl, p, p, p, SQ, DM, HID, 1.f);
        }
        // x = LN2(h2 + x2), fp32 + hi/lo
        add_ln_kernel<<<SQ, 256>>>(ph2, px2, g2 + (size_t)l*DM, be2 + (size_t)l*DM,
                                   px, xh, xl);
    }

    // logits = x @ Wf + bf, then vocab softmax (in place on d_out)
    {
        GPtrs p{wfh, wfl, bf, out, nullptr, nullptr};
        dim3 grid(VOC/128, SQ/128, 1);
        gemm_bf16<128,0,0><<<grid, 256, SMEM_128NN>>>(xh, xl, p, p, p, SQ, VOC, DM, 1.f);
    }
    softmax_vocab_kernel<<<SQ, 256>>>(out);

    (void)in_sizes; (void)n_in; (void)out_size;
}

// round 6
// speedup vs baseline: 3.2243x; 1.0092x over previous
#include <cuda_runtime.h>
#include <cuda_bf16.h>
#include <cstdint>
#include <cmath>

#define SQ   2048
#define DM   512
#define FF   512
#define HID  2048
#define VOC  32000
#define NL   4
#define LN_EPS 1e-5f

typedef __nv_bfloat16  bf16;
typedef __nv_bfloat162 bf162;

// ------------------------- fp32 scratch ------------------------------------
__device__ float g_x  [SQ * DM];
__device__ float g_x2 [SQ * DM];
__device__ float g_att[SQ * SQ];
__device__ float g_z  [SQ * FF];
__device__ float g_h2 [SQ * DM];

// ------------------------- bf16 hi/lo activations --------------------------
__device__ bf16 g_xh [SQ*DM],  g_xl [SQ*DM];
__device__ bf16 g_x2h[SQ*DM],  g_x2l[SQ*DM];
__device__ bf16 g_qh [SQ*FF],  g_ql [SQ*FF];
__device__ bf16 g_kh [SQ*FF],  g_kl [SQ*FF];
__device__ bf16 g_vh [SQ*FF],  g_vl [SQ*FF];
__device__ bf16 g_ath[SQ*SQ],  g_atl[SQ*SQ];
__device__ bf16 g_th [SQ*FF],  g_tl [SQ*FF];
__device__ bf16 g_hh [SQ*HID], g_hl [SQ*HID];

// ------------------------- bf16 hi/lo weights ------------------------------
__device__ bf16 g_wqh[NL*DM*FF],  g_wql[NL*DM*FF];
__device__ bf16 g_wkh[NL*DM*FF],  g_wkl[NL*DM*FF];
__device__ bf16 g_wvh[NL*DM*FF],  g_wvl[NL*DM*FF];
__device__ bf16 g_wph[NL*FF*FF],  g_wpl[NL*FF*FF];
__device__ bf16 g_w1h[NL*FF*HID], g_w1l[NL*FF*HID];
__device__ bf16 g_w2h[NL*HID*DM], g_w2l[NL*HID*DM];
__device__ bf16 g_wfh[DM*VOC],    g_wfl[DM*VOC];

// ------------------------- PTX wrappers ------------------------------------
__device__ __forceinline__ void ldsm4(uint32_t* r, uint32_t addr) {
    asm volatile("ldmatrix.sync.aligned.m8n8.x4.shared.b16 {%0,%1,%2,%3}, [%4];"
                 : "=r"(r[0]), "=r"(r[1]), "=r"(r[2]), "=r"(r[3]) : "r"(addr));
}
__device__ __forceinline__ void ldsm4t(uint32_t* r, uint32_t addr) {
    asm volatile("ldmatrix.sync.aligned.m8n8.x4.trans.shared.b16 {%0,%1,%2,%3}, [%4];"
                 : "=r"(r[0]), "=r"(r[1]), "=r"(r[2]), "=r"(r[3]) : "r"(addr));
}
__device__ __forceinline__ void mma16816(float* c, const uint32_t* a, const uint32_t* b) {
    asm volatile("mma.sync.aligned.m16n8k16.row.col.f32.bf16.bf16.f32 "
                 "{%0,%1,%2,%3}, {%4,%5,%6,%7}, {%8,%9}, {%0,%1,%2,%3};"
                 : "+f"(c[0]), "+f"(c[1]), "+f"(c[2]), "+f"(c[3])
                 : "r"(a[0]), "r"(a[1]), "r"(a[2]), "r"(a[3]),
                   "r"(b[0]), "r"(b[1]));
}
__device__ __forceinline__ void cpa16(uint32_t s, const void* g) {
    asm volatile("cp.async.cg.shared.global [%0], [%1], 16;\n" :: "r"(s), "l"(g));
}
__device__ __forceinline__ void cpcommit() { asm volatile("cp.async.commit_group;\n"); }
template<int N> __device__ __forceinline__ void cpwait() {
    asm volatile("cp.async.wait_group %0;\n" :: "n"(N));
}
__device__ __forceinline__ void split1(float x, bf16& h, bf16& l) {
    h = __float2bfloat16_rn(x);
    l = __float2bfloat16_rn(x - __bfloat162float(h));
}

// ------------------------- fp32 -> bf16 hi/lo split (8 elems/thread) -------
__global__ void split_kernel(const float* __restrict__ in,
                             bf16* __restrict__ hi, bf16* __restrict__ lo, int n)
{
    int i = (blockIdx.x * blockDim.x + threadIdx.x) * 8;
    if (i >= n) return;
    float4 a = *(const float4*)(in + i);
    float4 b = *(const float4*)(in + i + 4);
    bf16 h[8], l[8];
    split1(a.x,h[0],l[0]); split1(a.y,h[1],l[1]);
    split1(a.z,h[2],l[2]); split1(a.w,h[3],l[3]);
    split1(b.x,h[4],l[4]); split1(b.y,h[5],l[5]);
    split1(b.z,h[6],l[6]); split1(b.w,h[7],l[7]);
    *(uint4*)(hi + i) = *(const uint4*)h;
    *(uint4*)(lo + i) = *(const uint4*)l;
}

struct GPtrs { const bf16 *Bh, *Bl; const float* bias; float* C; bf16 *Ch, *Cl; };

// ------------------------- pipelined bf16-split GEMM (BN=64, 2 CTA/SM) -----
// C = alpha*A@op(B) + bias.  A bf16 hi/lo [M,K].  B bf16 hi/lo.
// TRANSB=0: B [K,N]. TRANSB=1: B [N,K].
// MODE: 0 normal; 1 causal block-skip (TRANSB=1); 2 K bounded at m0+128.
template<int TRANSB, int MODE>
__global__ void __launch_bounds__(256, 2)
gemm_bf16(const bf16* __restrict__ Ah, const bf16* __restrict__ Al,
          GPtrs p0, GPtrs p1, GPtrs p2, int M, int N, int K, float alpha)
{
    constexpr int BM = 128, BN = 64, BK = 32, ST = 3;
    constexpr int ASTR   = 40;
    constexpr int A_PART = BM * ASTR;
    constexpr int BROWS  = TRANSB ? BN : BK;
    constexpr int BSTR   = TRANSB ? 40 : (BN + 8);
    constexpr int B_PART = BROWS * BSTR;
    constexpr int STAGE  = 2*A_PART + 2*B_PART;
    constexpr int MT = 2;     // 4 m-warps x 2 m-tiles = 128
    constexpr int NT = 4;     // 2 n-warps x 32 cols

    extern __shared__ bf16 smem[];

    const int m0 = blockIdx.y * BM;
    const int n0 = blockIdx.x * BN;
    if (MODE == 1 && n0 >= m0 + BM) return;

    GPtrs P = (blockIdx.z == 0) ? p0 : ((blockIdx.z == 1) ? p1 : p2);

    int Keff = K;
    if (MODE == 2) Keff = min(K, m0 + BM);
    const int T = Keff / BK;

    const int tid  = threadIdx.x;
    const int lane = tid & 31;
    const int warp = tid >> 5;
    const int wm = warp & 3;
    const int wn = warp >> 2;
    const int l7 = lane & 7, q1 = (lane >> 3) & 1, q2 = lane >> 4;

    auto load_tile = [&](int t, int s) {
        const int k0 = t * BK;
        bf16* sb = smem + s * STAGE;
        #pragma unroll
        for (int i = 0; i < 4; i++) {
            int f = tid + 256 * i;
            int part = f >> 9;
            int r = (f >> 2) & 127;
            int c = f & 3;
            const bf16* gp = (part ? Al : Ah) + (size_t)(m0 + r) * K + k0 + c * 8;
            cpa16((uint32_t)__cvta_generic_to_shared(sb + part*A_PART + r*ASTR + c*8), gp);
        }
        if (TRANSB) {
            constexpr int CB = BN * 4;
            #pragma unroll
            for (int i = 0; i < (2 * CB) / 256; i++) {
                int f = tid + 256 * i;
                int part = f / CB, rem = f % CB;
                int r = rem >> 2, c = rem & 3;
                const bf16* gp = (part ? P.Bl : P.Bh) + (size_t)(n0 + r) * K + k0 + c * 8;
                cpa16((uint32_t)__cvta_generic_to_shared(sb + 2*A_PART + part*B_PART + r*BSTR + c*8), gp);
            }
        } else {
            constexpr int CR = BN / 8;
            constexpr int CB = 32 * CR;
            #pragma unroll
            for (int i = 0; i < (2 * CB) / 256; i++) {
                int f = tid + 256 * i;
                int part = f / CB, rem = f % CB;
                int r = rem / CR, c = rem % CR;
                const bf16* gp = (part ? P.Bl : P.Bh) + (size_t)(k0 + r) * N + n0 + c * 8;
                cpa16((uint32_t)__cvta_generic_to_shared(sb + 2*A_PART + part*B_PART + r*BSTR + c*8), gp);
            }
        }
    };

    float acc[MT][NT][4];
    #pragma unroll
    for (int mt = 0; mt < MT; mt++)
        #pragma unroll
        for (int nt = 0; nt < NT; nt++)
            #pragma unroll
            for (int i = 0; i < 4; i++) acc[mt][nt][i] = 0.f;

    const uint32_t smemBase = (uint32_t)__cvta_generic_to_shared(smem);
    const uint32_t aoff = (uint32_t)(((wm*MT*16 + l7 + q1*8) * ASTR + q2*8) * 2);
    uint32_t boff;
    if (TRANSB) boff = (uint32_t)((2*A_PART + (wn*32 + l7 + q2*8) * BSTR + q1*8) * 2);
    else        boff = (uint32_t)((2*A_PART + (l7 + q1*8) * BSTR + wn*32 + q2*8) * 2);

    load_tile(0, 0); cpcommit();
    if (T > 1) load_tile(1, 1);
    cpcommit();

    for (int t = 0; t < T; t++) {
        cpwait<1>();
        __syncthreads();
        if (t + 2 < T) { load_tile(t + 2, (t + 2) % ST); }
        cpcommit();

        const uint32_t sbase = smemBase + (uint32_t)((t % ST) * STAGE * 2);

        #pragma unroll
        for (int ks = 0; ks < 2; ks++) {
            uint32_t a[MT][4], bh[NT][2], bl[NT][2];
            #pragma unroll
            for (int mt = 0; mt < MT; mt++)
                ldsm4(a[mt], sbase + aoff + (uint32_t)(mt*16*ASTR*2 + ks*32));
            #pragma unroll
            for (int pp = 0; pp < 2; pp++) {
                uint32_t off = TRANSB ? (uint32_t)(pp*16*BSTR*2 + ks*32)
                                      : (uint32_t)(ks*16*BSTR*2 + pp*32);
                uint32_t r4[4];
                if (TRANSB) ldsm4 (r4, sbase + boff + off);
                else        ldsm4t(r4, sbase + boff + off);
                bh[2*pp][0]   = r4[0]; bh[2*pp][1]   = r4[1];
                bh[2*pp+1][0] = r4[2]; bh[2*pp+1][1] = r4[3];
                if (TRANSB) ldsm4 (r4, sbase + boff + (uint32_t)(B_PART*2) + off);
                else        ldsm4t(r4, sbase + boff + (uint32_t)(B_PART*2) + off);
                bl[2*pp][0]   = r4[0]; bl[2*pp][1]   = r4[1];
                bl[2*pp+1][0] = r4[2]; bl[2*pp+1][1] = r4[3];
            }
            // hi@hi
            #pragma unroll
            for (int nt = 0; nt < NT; nt++)
                #pragma unroll
                for (int mt = 0; mt < MT; mt++)
                    mma16816(acc[mt][nt], a[mt], bh[nt]);
            // hi@lo
            #pragma unroll
            for (int nt = 0; nt < NT; nt++)
                #pragma unroll
                for (int mt = 0; mt < MT; mt++)
                    mma16816(acc[mt][nt], a[mt], bl[nt]);
            // lo@hi
            #pragma unroll
            for (int mt = 0; mt < MT; mt++)
                ldsm4(a[mt], sbase + aoff + (uint32_t)(A_PART*2 + mt*16*ASTR*2 + ks*32));
            #pragma unroll
            for (int nt = 0; nt < NT; nt++)
                #pragma unroll
                for (int mt = 0; mt < MT; mt++)
                    mma16816(acc[mt][nt], a[mt], bh[nt]);
        }
    }

    // ---- epilogue
    #pragma unroll
    for (int mt = 0; mt < MT; mt++) {
        int row0 = m0 + wm*MT*16 + mt*16 + (lane >> 2);
        #pragma unroll
        for (int nt = 0; nt < NT; nt++) {
            int col = n0 + wn*32 + nt*8 + ((lane & 3) << 1);
            float b0 = 0.f, b1 = 0.f;
            if (P.bias) { b0 = P.bias[col]; b1 = P.bias[col + 1]; }
            float c00 = acc[mt][nt][0] * alpha + b0;
            float c01 = acc[mt][nt][1] * alpha + b1;
            float c10 = acc[mt][nt][2] * alpha + b0;
            float c11 = acc[mt][nt][3] * alpha + b1;
            if (P.C) {
                *(float2*)(P.C + (size_t)row0 * N + col)       = float2{c00, c01};
                *(float2*)(P.C + (size_t)(row0 + 8) * N + col) = float2{c10, c11};
            }
            if (P.Ch) {
                bf16 h0,l0,h1,l1;
                split1(c00,h0,l0); split1(c01,h1,l1);
                *(bf162*)(P.Ch + (size_t)row0 * N + col) = bf162{h0,h1};
                *(bf162*)(P.Cl + (size_t)row0 * N + col) = bf162{l0,l1};
                split1(c10,h0,l0); split1(c11,h1,l1);
                *(bf162*)(P.Ch + (size_t)(row0 + 8) * N + col) = bf162{h0,h1};
                *(bf162*)(P.Cl + (size_t)(row0 + 8) * N + col) = bf162{l0,l1};
            }
        }
    }
}

// ------------------------- causal softmax (smem row cache) -----------------
__global__ void softmax_causal_kernel(const float* __restrict__ att,
                                      bf16* __restrict__ oh, bf16* __restrict__ ol)
{
    __shared__ float buf[SQ];
    __shared__ float red[256];

    const int i = blockIdx.x;
    const float* row = att + (size_t)i * SQ;
    bf16* rh = oh + (size_t)i * SQ;
    bf16* rl = ol + (size_t)i * SQ;
    const int tid = threadIdx.x;
    const int n = i + 1;
    const int fillEnd = ((i >> 7) + 1) << 7;

    float m = -1e30f;
    for (int j = tid; j < n; j += 256) {
        float v = row[j];
        buf[j] = v;
        m = fmaxf(m, v);
    }
    red[tid] = m; __syncthreads();
    for (int st = 128; st > 0; st >>= 1) {
        if (tid < st) red[tid] = fmaxf(red[tid], red[tid + st]);
        __syncthreads();
    }
    m = red[0]; __syncthreads();

    float s = 0.f;
    for (int j = tid; j < n; j += 256) {
        float e = __expf(buf[j] - m);
        buf[j] = e;
        s += e;
    }
    red[tid] = s; __syncthreads();
    for (int st = 128; st > 0; st >>= 1) {
        if (tid < st) red[tid] += red[tid + st];
        __syncthreads();
    }
    const float inv = 1.f / red[0];

    for (int j = tid; j < n; j += 256) {
        float e = buf[j] * inv;
        bf16 h, l; split1(e, h, l);
        rh[j] = h; rl[j] = l;
    }
    for (int j = n + tid; j < fillEnd; j += 256) {
        rh[j] = __float2bfloat16_rn(0.f);
        rl[j] = __float2bfloat16_rn(0.f);
    }
}

// ------------------------- residual-add + LayerNorm ------------------------
__global__ void add_ln_kernel(const float* __restrict__ a,
                              const float* __restrict__ res,
                              const float* __restrict__ g,
                              const float* __restrict__ beta,
                              float* __restrict__ out,
                              bf16* __restrict__ oh, bf16* __restrict__ ol)
{
    const int row = blockIdx.x;
    const int tid = threadIdx.x;
    const size_t base = (size_t)row * DM;

    float v0 = a[base + tid]       + res[base + tid];
    float v1 = a[base + tid + 256] + res[base + tid + 256];

    __shared__ float red[256];
    red[tid] = v0 + v1; __syncthreads();
    for (int st = 128; st > 0; st >>= 1) {
        if (tid < st) red[tid] += red[tid + st];
        __syncthreads();
    }
    const float mu = red[0] * (1.0f / DM);
    __syncthreads();

    float d0 = v0 - mu, d1 = v1 - mu;
    red[tid] = d0 * d0 + d1 * d1; __syncthreads();
    for (int st = 128; st > 0; st >>= 1) {
        if (tid < st) red[tid] += red[tid + st];
        __syncthreads();
    }
    const float rstd = rsqrtf(red[0] * (1.0f / DM) + LN_EPS);

    float o0 = d0 * rstd * g[tid]       + beta[tid];
    float o1 = d1 * rstd * g[tid + 256] + beta[tid + 256];
    out[base + tid]       = o0;
    out[base + tid + 256] = o1;
    bf16 h, l;
    split1(o0, h, l); oh[base + tid]       = h; ol[base + tid]       = l;
    split1(o1, h, l); oh[base + tid + 256] = h; ol[base + tid + 256] = l;
}

// ------------------------- vocab softmax (online 2-pass) -------------------
__global__ void softmax_vocab_kernel(float* __restrict__ x)
{
    const int i = blockIdx.x;
    float* row = x + (size_t)i * VOC;
    const int tid = threadIdx.x;

    __shared__ float mRed[256];
    __shared__ float sRed[256];

    // pass 1: single read, online max+sum
    float m = -1e30f, s = 0.f;
    for (int j = tid * 4; j < VOC; j += 1024) {
        float4 v = *(const float4*)(row + j);
        float mv = fmaxf(fmaxf(v.x, v.y), fmaxf(v.z, v.w));
        float mo = m;
        m = fmaxf(m, mv);
        s = s * __expf(mo - m)
          + __expf(v.x - m) + __expf(v.y - m)
          + __expf(v.z - m) + __expf(v.w - m);
    }
    mRed[tid] = m; sRed[tid] = s; __syncthreads();
    for (int st = 128; st > 0; st >>= 1) {
        if (tid < st) {
            float m1 = mRed[tid], m2 = mRed[tid + st];
            float M = fmaxf(m1, m2);
            sRed[tid] = sRed[tid] * __expf(m1 - M) + sRed[tid + st] * __expf(m2 - M);
            mRed[tid] = M;
        }
        __syncthreads();
    }
    const float M = mRed[0];
    const float inv = 1.f / sRed[0];

    // pass 2: read + write
    for (int j = tid * 4; j < VOC; j += 1024) {
        float4 v = *(const float4*)(row + j);
        v.x = __expf(v.x - M) * inv;
        v.y = __expf(v.y - M) * inv;
        v.z = __expf(v.z - M) * inv;
        v.w = __expf(v.w - M) * inv;
        *(float4*)(row + j) = v;
    }
}

// ------------------------- host side ---------------------------------------
#define SMEM_NN 89088     // 3*(2*128*40 + 2*32*72)*2
#define SMEM_NT 92160     // 3*(2*128*40 + 2*64*40)*2

static inline void do_split(const float* in, bf16* hi, bf16* lo, int n) {
    split_kernel<<<n / 2048, 256>>>(in, hi, lo, n);
}

extern "C" void kernel_launch(void* const* d_in, const int* in_sizes, int n_in,
                              void* d_out, int out_size)
{
    const float* x   = (const float*)d_in[0];
    const float* Wq  = (const float*)d_in[1];
    const float* bq  = (const float*)d_in[2];
    const float* Wk  = (const float*)d_in[3];
    const float* bk  = (const float*)d_in[4];
    const float* Wv  = (const float*)d_in[5];
    const float* bv  = (const float*)d_in[6];
    const float* Wp  = (const float*)d_in[7];
    const float* bp  = (const float*)d_in[8];
    const float* g1  = (const float*)d_in[9];
    const float* be1 = (const float*)d_in[10];
    const float* W1  = (const float*)d_in[11];
    const float* b1  = (const float*)d_in[12];
    const float* W2  = (const float*)d_in[13];
    const float* b2  = (const float*)d_in[14];
    const float* g2  = (const float*)d_in[15];
    const float* be2 = (const float*)d_in[16];
    const float* Wf  = (const float*)d_in[17];
    const float* bf  = (const float*)d_in[18];
    float* out = (float*)d_out;

    cudaFuncSetAttribute(gemm_bf16<0,0>, cudaFuncAttributeMaxDynamicSharedMemorySize, SMEM_NN);
    cudaFuncSetAttribute(gemm_bf16<0,2>, cudaFuncAttributeMaxDynamicSharedMemorySize, SMEM_NN);
    cudaFuncSetAttribute(gemm_bf16<1,1>, cudaFuncAttributeMaxDynamicSharedMemorySize, SMEM_NT);

    float *px, *px2, *patt, *pz, *ph2;
    cudaGetSymbolAddress((void**)&px,   g_x);
    cudaGetSymbolAddress((void**)&px2,  g_x2);
    cudaGetSymbolAddress((void**)&patt, g_att);
    cudaGetSymbolAddress((void**)&pz,   g_z);
    cudaGetSymbolAddress((void**)&ph2,  g_h2);

    bf16 *xh,*xl,*x2h,*x2l,*qh,*ql,*kh,*kl,*vh,*vl,*ath,*atl,*th,*tl,*hh,*hl;
    cudaGetSymbolAddress((void**)&xh,  g_xh);  cudaGetSymbolAddress((void**)&xl,  g_xl);
    cudaGetSymbolAddress((void**)&x2h, g_x2h); cudaGetSymbolAddress((void**)&x2l, g_x2l);
    cudaGetSymbolAddress((void**)&qh,  g_qh);  cudaGetSymbolAddress((void**)&ql,  g_ql);
    cudaGetSymbolAddress((void**)&kh,  g_kh);  cudaGetSymbolAddress((void**)&kl,  g_kl);
    cudaGetSymbolAddress((void**)&vh,  g_vh);  cudaGetSymbolAddress((void**)&vl,  g_vl);
    cudaGetSymbolAddress((void**)&ath, g_ath); cudaGetSymbolAddress((void**)&atl, g_atl);
    cudaGetSymbolAddress((void**)&th,  g_th);  cudaGetSymbolAddress((void**)&tl,  g_tl);
    cudaGetSymbolAddress((void**)&hh,  g_hh);  cudaGetSymbolAddress((void**)&hl,  g_hl);

    bf16 *wqh,*wql,*wkh,*wkl,*wvh,*wvl,*wph,*wpl,*w1h,*w1l,*w2h,*w2l,*wfh,*wfl;
    cudaGetSymbolAddress((void**)&wqh, g_wqh); cudaGetSymbolAddress((void**)&wql, g_wql);
    cudaGetSymbolAddress((void**)&wkh, g_wkh); cudaGetSymbolAddress((void**)&wkl, g_wkl);
    cudaGetSymbolAddress((void**)&wvh, g_wvh); cudaGetSymbolAddress((void**)&wvl, g_wvl);
    cudaGetSymbolAddress((void**)&wph, g_wph); cudaGetSymbolAddress((void**)&wpl, g_wpl);
    cudaGetSymbolAddress((void**)&w1h, g_w1h); cudaGetSymbolAddress((void**)&w1l, g_w1l);
    cudaGetSymbolAddress((void**)&w2h, g_w2h); cudaGetSymbolAddress((void**)&w2l, g_w2l);
    cudaGetSymbolAddress((void**)&wfh, g_wfh); cudaGetSymbolAddress((void**)&wfl, g_wfl);

    do_split(Wq, wqh, wql, NL*DM*FF);
    do_split(Wk, wkh, wkl, NL*DM*FF);
    do_split(Wv, wvh, wvl, NL*DM*FF);
    do_split(Wp, wph, wpl, NL*FF*FF);
    do_split(W1, w1h, w1l, NL*FF*HID);
    do_split(W2, w2h, w2l, NL*HID*DM);
    do_split(Wf, wfh, wfl, DM*VOC);
    do_split(x,  xh,  xl,  SQ*DM);
    cudaMemcpyAsync(px, x, (size_t)SQ*DM*sizeof(float), cudaMemcpyDeviceToDevice);

    const float scale = 1.0f / sqrtf((float)FF);

    for (int l = 0; l < NL; l++) {
        size_t wOff  = (size_t)l * DM * FF;
        size_t w1Off = (size_t)l * FF * HID;
        size_t w2Off = (size_t)l * HID * DM;

        // QKV (batched over z)
        {
            GPtrs pQ{wqh + wOff, wql + wOff, bq + (size_t)l*FF, nullptr, qh, ql};
            GPtrs pK{wkh + wOff, wkl + wOff, bk + (size_t)l*FF, nullptr, kh, kl};
            GPtrs pV{wvh + wOff, wvl + wOff, bv + (size_t)l*FF, nullptr, vh, vl};
            gemm_bf16<0,0><<<dim3(FF/64, SQ/128, 3), 256, SMEM_NN>>>(xh, xl, pQ, pK, pV, SQ, FF, DM, 1.f);
        }
        // scores = q @ k^T * scale (causal block skip)
        {
            GPtrs p{kh, kl, nullptr, patt, nullptr, nullptr};
            gemm_bf16<1,1><<<dim3(SQ/64, SQ/128, 1), 256, SMEM_NT>>>(qh, ql, p, p, p, SQ, SQ, FF, scale);
        }
        softmax_causal_kernel<<<SQ, 256>>>(patt, ath, atl);
        // t = att @ v (K bounded)
        {
            GPtrs p{vh, vl, nullptr, nullptr, th, tl};
            gemm_bf16<0,2><<<dim3(FF/64, SQ/128, 1), 256, SMEM_NN>>>(ath, atl, p, p, p, SQ, FF, SQ, 1.f);
        }
        // z = t @ Wp + bp
        {
            GPtrs p{wph + wOff, wpl + wOff, bp + (size_t)l*FF, pz, nullptr, nullptr};
            gemm_bf16<0,0><<<dim3(FF/64, SQ/128, 1), 256, SMEM_NN>>>(th, tl, p, p, p, SQ, FF, FF, 1.f);
        }
        add_ln_kernel<<<SQ, 256>>>(pz, px, g1 + (size_t)l*FF, be1 + (size_t)l*FF,
                                   px2, x2h, x2l);
        // h = x2 @ W1 + b1
        {
            GPtrs p{w1h + w1Off, w1l + w1Off, b1 + (size_t)l*HID, nullptr, hh, hl};
            gemm_bf16<0,0><<<dim3(HID/64, SQ/128, 1), 256, SMEM_NN>>>(x2h, x2l, p, p, p, SQ, HID, FF, 1.f);
        }
        // h2 = h @ W2 + b2
        {
            GPtrs p{w2h + w2Off, w2l + w2Off, b2 + (size_t)l*DM, ph2, nullptr, nullptr};
            gemm_bf16<0,0><<<dim3(DM/64, SQ/128, 1), 256, SMEM_NN>>>(hh, hl, p, p, p, SQ, DM, HID, 1.f);
        }
        add_ln_kernel<<<SQ, 256>>>(ph2, px2, g2 + (size_t)l*DM, be2 + (size_t)l*DM,
                                   px, xh, xl);
    }

    // logits + vocab softmax
    {
        GPtrs p{wfh, wfl, bf, out, nullptr, nullptr};
        gemm_bf16<0,0><<<dim3(VOC/64, SQ/128, 1), 256, SMEM_NN>>>(xh, xl, p, p, p, SQ, VOC, DM, 1.f);
    }
    softmax_vocab_kernel<<<SQ, 256>>>(out);

    (void)in_sizes; (void)n_in; (void)out_size;
}

// round 7
// speedup vs baseline: 3.3916x; 1.0519x over previous
#include <cuda_runtime.h>
#include <cuda_bf16.h>
#include <cstdint>
#include <cmath>

#define SQ   2048
#define DM   512
#define FF   512
#define HID  2048
#define VOC  32000
#define NL   4
#define LN_EPS 1e-5f

typedef __nv_bfloat16  bf16;
typedef __nv_bfloat162 bf162;

// ------------------------- fp32 scratch ------------------------------------
__device__ float g_x  [SQ * DM];
__device__ float g_x2 [SQ * DM];
__device__ float g_att[SQ * SQ];
__device__ float g_z  [SQ * FF];
__device__ float g_h2 [SQ * DM];

// ------------------------- bf16 hi/lo activations --------------------------
__device__ bf16 g_xh [SQ*DM],  g_xl [SQ*DM];
__device__ bf16 g_x2h[SQ*DM],  g_x2l[SQ*DM];
__device__ bf16 g_qh [SQ*FF],  g_ql [SQ*FF];
__device__ bf16 g_kh [SQ*FF],  g_kl [SQ*FF];
__device__ bf16 g_vh [SQ*FF],  g_vl [SQ*FF];
__device__ bf16 g_ath[SQ*SQ],  g_atl[SQ*SQ];
__device__ bf16 g_th [SQ*FF],  g_tl [SQ*FF];
__device__ bf16 g_hh [SQ*HID], g_hl [SQ*HID];

// ------------------------- bf16 hi/lo weights ------------------------------
__device__ bf16 g_wqh[NL*DM*FF],  g_wql[NL*DM*FF];
__device__ bf16 g_wkh[NL*DM*FF],  g_wkl[NL*DM*FF];
__device__ bf16 g_wvh[NL*DM*FF],  g_wvl[NL*DM*FF];
__device__ bf16 g_wph[NL*FF*FF],  g_wpl[NL*FF*FF];
__device__ bf16 g_w1h[NL*FF*HID], g_w1l[NL*FF*HID];
__device__ bf16 g_w2h[NL*HID*DM], g_w2l[NL*HID*DM];
__device__ bf16 g_wfh[DM*VOC],    g_wfl[DM*VOC];

// ------------------------- PTX wrappers ------------------------------------
__device__ __forceinline__ void ldsm4(uint32_t* r, uint32_t addr) {
    asm volatile("ldmatrix.sync.aligned.m8n8.x4.shared.b16 {%0,%1,%2,%3}, [%4];"
                 : "=r"(r[0]), "=r"(r[1]), "=r"(r[2]), "=r"(r[3]) : "r"(addr));
}
__device__ __forceinline__ void ldsm4t(uint32_t* r, uint32_t addr) {
    asm volatile("ldmatrix.sync.aligned.m8n8.x4.trans.shared.b16 {%0,%1,%2,%3}, [%4];"
                 : "=r"(r[0]), "=r"(r[1]), "=r"(r[2]), "=r"(r[3]) : "r"(addr));
}
__device__ __forceinline__ void mma16816(float* c, const uint32_t* a, const uint32_t* b) {
    asm volatile("mma.sync.aligned.m16n8k16.row.col.f32.bf16.bf16.f32 "
                 "{%0,%1,%2,%3}, {%4,%5,%6,%7}, {%8,%9}, {%0,%1,%2,%3};"
                 : "+f"(c[0]), "+f"(c[1]), "+f"(c[2]), "+f"(c[3])
                 : "r"(a[0]), "r"(a[1]), "r"(a[2]), "r"(a[3]),
                   "r"(b[0]), "r"(b[1]));
}
__device__ __forceinline__ void cpa16(uint32_t s, const void* g) {
    asm volatile("cp.async.cg.shared.global [%0], [%1], 16;\n" :: "r"(s), "l"(g));
}
__device__ __forceinline__ void cpcommit() { asm volatile("cp.async.commit_group;\n"); }
template<int N> __device__ __forceinline__ void cpwait() {
    asm volatile("cp.async.wait_group %0;\n" :: "n"(N));
}
__device__ __forceinline__ void split1(float x, bf16& h, bf16& l) {
    h = __float2bfloat16_rn(x);
    l = __float2bfloat16_rn(x - __bfloat162float(h));
}

// ------------------------- fp32 -> bf16 hi/lo split (8 elems/thread) -------
__global__ void split_kernel(const float* __restrict__ in,
                             bf16* __restrict__ hi, bf16* __restrict__ lo, int n)
{
    int i = (blockIdx.x * blockDim.x + threadIdx.x) * 8;
    if (i >= n) return;
    float4 a = *(const float4*)(in + i);
    float4 b = *(const float4*)(in + i + 4);
    bf16 h[8], l[8];
    split1(a.x,h[0],l[0]); split1(a.y,h[1],l[1]);
    split1(a.z,h[2],l[2]); split1(a.w,h[3],l[3]);
    split1(b.x,h[4],l[4]); split1(b.y,h[5],l[5]);
    split1(b.z,h[6],l[6]); split1(b.w,h[7],l[7]);
    *(uint4*)(hi + i) = *(const uint4*)h;
    *(uint4*)(lo + i) = *(const uint4*)l;
}

struct GPtrs { const bf16 *Bh, *Bl; const float* bias; float* C; bf16 *Ch, *Cl; };

// ------------------------- BN=64 GEMM (unchanged from R6, passing) ---------
template<int TRANSB, int MODE>
__global__ void __launch_bounds__(256, 2)
gemm_bf16(const bf16* __restrict__ Ah, const bf16* __restrict__ Al,
          GPtrs p0, GPtrs p1, GPtrs p2, int M, int N, int K, float alpha)
{
    constexpr int BM = 128, BN = 64, BK = 32, ST = 3;
    constexpr int ASTR   = 40;
    constexpr int A_PART = BM * ASTR;
    constexpr int BROWS  = TRANSB ? BN : BK;
    constexpr int BSTR   = TRANSB ? 40 : (BN + 8);
    constexpr int B_PART = BROWS * BSTR;
    constexpr int STAGE  = 2*A_PART + 2*B_PART;
    constexpr int MT = 2;
    constexpr int NT = 4;

    extern __shared__ bf16 smem[];

    const int m0 = blockIdx.y * BM;
    const int n0 = blockIdx.x * BN;
    if (MODE == 1 && n0 >= m0 + BM) return;

    GPtrs P = (blockIdx.z == 0) ? p0 : ((blockIdx.z == 1) ? p1 : p2);

    int Keff = K;
    if (MODE == 2) Keff = min(K, m0 + BM);
    const int T = Keff / BK;

    const int tid  = threadIdx.x;
    const int lane = tid & 31;
    const int warp = tid >> 5;
    const int wm = warp & 3;
    const int wn = warp >> 2;
    const int l7 = lane & 7, q1 = (lane >> 3) & 1, q2 = lane >> 4;

    auto load_tile = [&](int t, int s) {
        const int k0 = t * BK;
        bf16* sb = smem + s * STAGE;
        #pragma unroll
        for (int i = 0; i < 4; i++) {
            int f = tid + 256 * i;
            int part = f >> 9;
            int r = (f >> 2) & 127;
            int c = f & 3;
            const bf16* gp = (part ? Al : Ah) + (size_t)(m0 + r) * K + k0 + c * 8;
            cpa16((uint32_t)__cvta_generic_to_shared(sb + part*A_PART + r*ASTR + c*8), gp);
        }
        if (TRANSB) {
            constexpr int CB = BN * 4;
            #pragma unroll
            for (int i = 0; i < (2 * CB) / 256; i++) {
                int f = tid + 256 * i;
                int part = f / CB, rem = f % CB;
                int r = rem >> 2, c = rem & 3;
                const bf16* gp = (part ? P.Bl : P.Bh) + (size_t)(n0 + r) * K + k0 + c * 8;
                cpa16((uint32_t)__cvta_generic_to_shared(sb + 2*A_PART + part*B_PART + r*BSTR + c*8), gp);
            }
        } else {
            constexpr int CR = BN / 8;
            constexpr int CB = 32 * CR;
            #pragma unroll
            for (int i = 0; i < (2 * CB) / 256; i++) {
                int f = tid + 256 * i;
                int part = f / CB, rem = f % CB;
                int r = rem / CR, c = rem % CR;
                const bf16* gp = (part ? P.Bl : P.Bh) + (size_t)(k0 + r) * N + n0 + c * 8;
                cpa16((uint32_t)__cvta_generic_to_shared(sb + 2*A_PART + part*B_PART + r*BSTR + c*8), gp);
            }
        }
    };

    float acc[MT][NT][4];
    #pragma unroll
    for (int mt = 0; mt < MT; mt++)
        #pragma unroll
        for (int nt = 0; nt < NT; nt++)
            #pragma unroll
            for (int i = 0; i < 4; i++) acc[mt][nt][i] = 0.f;

    const uint32_t smemBase = (uint32_t)__cvta_generic_to_shared(smem);
    const uint32_t aoff = (uint32_t)(((wm*MT*16 + l7 + q1*8) * ASTR + q2*8) * 2);
    uint32_t boff;
    if (TRANSB) boff = (uint32_t)((2*A_PART + (wn*32 + l7 + q2*8) * BSTR + q1*8) * 2);
    else        boff = (uint32_t)((2*A_PART + (l7 + q1*8) * BSTR + wn*32 + q2*8) * 2);

    load_tile(0, 0); cpcommit();
    if (T > 1) load_tile(1, 1);
    cpcommit();

    for (int t = 0; t < T; t++) {
        cpwait<1>();
        __syncthreads();
        if (t + 2 < T) { load_tile(t + 2, (t + 2) % ST); }
        cpcommit();

        const uint32_t sbase = smemBase + (uint32_t)((t % ST) * STAGE * 2);

        #pragma unroll
        for (int ks = 0; ks < 2; ks++) {
            uint32_t a[MT][4], bh[NT][2], bl[NT][2];
            #pragma unroll
            for (int mt = 0; mt < MT; mt++)
                ldsm4(a[mt], sbase + aoff + (uint32_t)(mt*16*ASTR*2 + ks*32));
            #pragma unroll
            for (int pp = 0; pp < 2; pp++) {
                uint32_t off = TRANSB ? (uint32_t)(pp*16*BSTR*2 + ks*32)
                                      : (uint32_t)(ks*16*BSTR*2 + pp*32);
                uint32_t r4[4];
                if (TRANSB) ldsm4 (r4, sbase + boff + off);
                else        ldsm4t(r4, sbase + boff + off);
                bh[2*pp][0]   = r4[0]; bh[2*pp][1]   = r4[1];
                bh[2*pp+1][0] = r4[2]; bh[2*pp+1][1] = r4[3];
                if (TRANSB) ldsm4 (r4, sbase + boff + (uint32_t)(B_PART*2) + off);
                else        ldsm4t(r4, sbase + boff + (uint32_t)(B_PART*2) + off);
                bl[2*pp][0]   = r4[0]; bl[2*pp][1]   = r4[1];
                bl[2*pp+1][0] = r4[2]; bl[2*pp+1][1] = r4[3];
            }
            #pragma unroll
            for (int nt = 0; nt < NT; nt++)
                #pragma unroll
                for (int mt = 0; mt < MT; mt++)
                    mma16816(acc[mt][nt], a[mt], bh[nt]);
            #pragma unroll
            for (int nt = 0; nt < NT; nt++)
                #pragma unroll
                for (int mt = 0; mt < MT; mt++)
                    mma16816(acc[mt][nt], a[mt], bl[nt]);
            #pragma unroll
            for (int mt = 0; mt < MT; mt++)
                ldsm4(a[mt], sbase + aoff + (uint32_t)(A_PART*2 + mt*16*ASTR*2 + ks*32));
            #pragma unroll
            for (int nt = 0; nt < NT; nt++)
                #pragma unroll
                for (int mt = 0; mt < MT; mt++)
                    mma16816(acc[mt][nt], a[mt], bh[nt]);
        }
    }

    #pragma unroll
    for (int mt = 0; mt < MT; mt++) {
        int row0 = m0 + wm*MT*16 + mt*16 + (lane >> 2);
        #pragma unroll
        for (int nt = 0; nt < NT; nt++) {
            int col = n0 + wn*32 + nt*8 + ((lane & 3) << 1);
            float b0 = 0.f, b1 = 0.f;
            if (P.bias) { b0 = P.bias[col]; b1 = P.bias[col + 1]; }
            float c00 = acc[mt][nt][0] * alpha + b0;
            float c01 = acc[mt][nt][1] * alpha + b1;
            float c10 = acc[mt][nt][2] * alpha + b0;
            float c11 = acc[mt][nt][3] * alpha + b1;
            if (P.C) {
                *(float2*)(P.C + (size_t)row0 * N + col)       = float2{c00, c01};
                *(float2*)(P.C + (size_t)(row0 + 8) * N + col) = float2{c10, c11};
            }
            if (P.Ch) {
                bf16 h0,l0,h1,l1;
                split1(c00,h0,l0); split1(c01,h1,l1);
                *(bf162*)(P.Ch + (size_t)row0 * N + col) = bf162{h0,h1};
                *(bf162*)(P.Cl + (size_t)row0 * N + col) = bf162{l0,l1};
                split1(c10,h0,l0); split1(c11,h1,l1);
                *(bf162*)(P.Ch + (size_t)(row0 + 8) * N + col) = bf162{h0,h1};
                *(bf162*)(P.Cl + (size_t)(row0 + 8) * N + col) = bf162{l0,l1};
            }
        }
    }
}

// ------------------------- wide-N GEMM: BN=128, NT=8, NN only --------------
// C = A @ B + bias.  B [K,N].  2 CTA/SM (smem 113664B), 48 MMA / 12 ldsm per ks.
__global__ void __launch_bounds__(256, 2)
gemm_bf16w(const bf16* __restrict__ Ah, const bf16* __restrict__ Al,
           GPtrs P, int M, int N, int K)
{
    constexpr int BM = 128, BN = 128, BK = 32, ST = 3;
    constexpr int ASTR   = 40;
    constexpr int A_PART = BM * ASTR;          // 5120 halves
    constexpr int BSTR   = BN + 8;             // 136
    constexpr int B_PART = BK * BSTR;          // 4352 halves
    constexpr int STAGE  = 2*A_PART + 2*B_PART; // 18944 halves
    constexpr int MT = 2;                      // 4 m-warps
    constexpr int NT = 8;                      // 2 n-warps x 64 cols

    extern __shared__ bf16 smem[];

    const int m0 = blockIdx.y * BM;
    const int n0 = blockIdx.x * BN;
    const int T = K / BK;

    const int tid  = threadIdx.x;
    const int lane = tid & 31;
    const int warp = tid >> 5;
    const int wm = warp & 3;
    const int wn = warp >> 2;
    const int l7 = lane & 7, q1 = (lane >> 3) & 1, q2 = lane >> 4;

    auto load_tile = [&](int t, int s) {
        const int k0 = t * BK;
        bf16* sb = smem + s * STAGE;
        #pragma unroll
        for (int i = 0; i < 4; i++) {          // A: 2 parts x 128 x 4 chunks
            int f = tid + 256 * i;
            int part = f >> 9;
            int r = (f >> 2) & 127;
            int c = f & 3;
            const bf16* gp = (part ? Al : Ah) + (size_t)(m0 + r) * K + k0 + c * 8;
            cpa16((uint32_t)__cvta_generic_to_shared(sb + part*A_PART + r*ASTR + c*8), gp);
        }
        #pragma unroll
        for (int i = 0; i < 4; i++) {          // B: 2 parts x 32 x 16 chunks
            int f = tid + 256 * i;
            int part = f >> 9;
            int rem  = f & 511;
            int r = rem >> 4;
            int c = rem & 15;
            const bf16* gp = (part ? P.Bl : P.Bh) + (size_t)(k0 + r) * N + n0 + c * 8;
            cpa16((uint32_t)__cvta_generic_to_shared(sb + 2*A_PART + part*B_PART + r*BSTR + c*8), gp);
        }
    };

    float acc[MT][NT][4];
    #pragma unroll
    for (int mt = 0; mt < MT; mt++)
        #pragma unroll
        for (int nt = 0; nt < NT; nt++)
            #pragma unroll
            for (int i = 0; i < 4; i++) acc[mt][nt][i] = 0.f;

    const uint32_t smemBase = (uint32_t)__cvta_generic_to_shared(smem);
    const uint32_t aoff = (uint32_t)(((wm*MT*16 + l7 + q1*8) * ASTR + q2*8) * 2);
    const uint32_t boff = (uint32_t)((2*A_PART + (l7 + q1*8) * BSTR + wn*64 + q2*8) * 2);

    load_tile(0, 0); cpcommit();
    if (T > 1) load_tile(1, 1);
    cpcommit();

    for (int t = 0; t < T; t++) {
        cpwait<1>();
        __syncthreads();
        if (t + 2 < T) { load_tile(t + 2, (t + 2) % ST); }
        cpcommit();

        const uint32_t sbase = smemBase + (uint32_t)((t % ST) * STAGE * 2);

        #pragma unroll
        for (int ks = 0; ks < 2; ks++) {
            uint32_t a[MT][4], bh[NT][2];
            // A hi
            #pragma unroll
            for (int mt = 0; mt < MT; mt++)
                ldsm4(a[mt], sbase + aoff + (uint32_t)(mt*16*ASTR*2 + ks*32));
            // all B hi (8 n-tiles, 4 ldsm4t)
            #pragma unroll
            for (int pp = 0; pp < 4; pp++) {
                uint32_t r4[4];
                ldsm4t(r4, sbase + boff + (uint32_t)(ks*16*BSTR*2 + pp*32));
                bh[2*pp][0]   = r4[0]; bh[2*pp][1]   = r4[1];
                bh[2*pp+1][0] = r4[2]; bh[2*pp+1][1] = r4[3];
            }
            // hi @ hi (16 MMAs)
            #pragma unroll
            for (int nt = 0; nt < NT; nt++)
                #pragma unroll
                for (int mt = 0; mt < MT; mt++)
                    mma16816(acc[mt][nt], a[mt], bh[nt]);
            // hi @ lo, B lo chunked (2 x 4 tiles)
            #pragma unroll
            for (int ch = 0; ch < 2; ch++) {
                uint32_t bl[4][2];
                #pragma unroll
                for (int pp = 0; pp < 2; pp++) {
                    uint32_t r4[4];
                    ldsm4t(r4, sbase + boff + (uint32_t)(B_PART*2 + ks*16*BSTR*2 + (ch*2+pp)*32));
                    bl[2*pp][0]   = r4[0]; bl[2*pp][1]   = r4[1];
                    bl[2*pp+1][0] = r4[2]; bl[2*pp+1][1] = r4[3];
                }
                #pragma unroll
                for (int j = 0; j < 4; j++)
                    #pragma unroll
                    for (int mt = 0; mt < MT; mt++)
                        mma16816(acc[mt][ch*4 + j], a[mt], bl[j]);
            }
            // lo @ hi (A lo, bh still live)
            #pragma unroll
            for (int mt = 0; mt < MT; mt++)
                ldsm4(a[mt], sbase + aoff + (uint32_t)(A_PART*2 + mt*16*ASTR*2 + ks*32));
            #pragma unroll
            for (int nt = 0; nt < NT; nt++)
                #pragma unroll
                for (int mt = 0; mt < MT; mt++)
                    mma16816(acc[mt][nt], a[mt], bh[nt]);
        }
    }

    #pragma unroll
    for (int mt = 0; mt < MT; mt++) {
        int row0 = m0 + wm*MT*16 + mt*16 + (lane >> 2);
        #pragma unroll
        for (int nt = 0; nt < NT; nt++) {
            int col = n0 + wn*64 + nt*8 + ((lane & 3) << 1);
            float b0 = 0.f, b1 = 0.f;
            if (P.bias) { b0 = P.bias[col]; b1 = P.bias[col + 1]; }
            float c00 = acc[mt][nt][0] + b0;
            float c01 = acc[mt][nt][1] + b1;
            float c10 = acc[mt][nt][2] + b0;
            float c11 = acc[mt][nt][3] + b1;
            if (P.C) {
                *(float2*)(P.C + (size_t)row0 * N + col)       = float2{c00, c01};
                *(float2*)(P.C + (size_t)(row0 + 8) * N + col) = float2{c10, c11};
            }
            if (P.Ch) {
                bf16 h0,l0,h1,l1;
                split1(c00,h0,l0); split1(c01,h1,l1);
                *(bf162*)(P.Ch + (size_t)row0 * N + col) = bf162{h0,h1};
                *(bf162*)(P.Cl + (size_t)row0 * N + col) = bf162{l0,l1};
                split1(c10,h0,l0); split1(c11,h1,l1);
                *(bf162*)(P.Ch + (size_t)(row0 + 8) * N + col) = bf162{h0,h1};
                *(bf162*)(P.Cl + (size_t)(row0 + 8) * N + col) = bf162{l0,l1};
            }
        }
    }
}

// ------------------------- causal softmax (smem row cache) -----------------
__global__ void softmax_causal_kernel(const float* __restrict__ att,
                                      bf16* __restrict__ oh, bf16* __restrict__ ol)
{
    __shared__ float buf[SQ];
    __shared__ float red[256];

    const int i = blockIdx.x;
    const float* row = att + (size_t)i * SQ;
    bf16* rh = oh + (size_t)i * SQ;
    bf16* rl = ol + (size_t)i * SQ;
    const int tid = threadIdx.x;
    const int n = i + 1;
    const int fillEnd = ((i >> 7) + 1) << 7;

    float m = -1e30f;
    for (int j = tid; j < n; j += 256) {
        float v = row[j];
        buf[j] = v;
        m = fmaxf(m, v);
    }
    red[tid] = m; __syncthreads();
    for (int st = 128; st > 0; st >>= 1) {
        if (tid < st) red[tid] = fmaxf(red[tid], red[tid + st]);
        __syncthreads();
    }
    m = red[0]; __syncthreads();

    float s = 0.f;
    for (int j = tid; j < n; j += 256) {
        float e = __expf(buf[j] - m);
        buf[j] = e;
        s += e;
    }
    red[tid] = s; __syncthreads();
    for (int st = 128; st > 0; st >>= 1) {
        if (tid < st) red[tid] += red[tid + st];
        __syncthreads();
    }
    const float inv = 1.f / red[0];

    for (int j = tid; j < n; j += 256) {
        float e = buf[j] * inv;
        bf16 h, l; split1(e, h, l);
        rh[j] = h; rl[j] = l;
    }
    for (int j = n + tid; j < fillEnd; j += 256) {
        rh[j] = __float2bfloat16_rn(0.f);
        rl[j] = __float2bfloat16_rn(0.f);
    }
}

// ------------------------- residual-add + LayerNorm ------------------------
__global__ void add_ln_kernel(const float* __restrict__ a,
                              const float* __restrict__ res,
                              const float* __restrict__ g,
                              const float* __restrict__ beta,
                              float* __restrict__ out,
                              bf16* __restrict__ oh, bf16* __restrict__ ol)
{
    const int row = blockIdx.x;
    const int tid = threadIdx.x;
    const size_t base = (size_t)row * DM;

    float v0 = a[base + tid]       + res[base + tid];
    float v1 = a[base + tid + 256] + res[base + tid + 256];

    __shared__ float red[256];
    red[tid] = v0 + v1; __syncthreads();
    for (int st = 128; st > 0; st >>= 1) {
        if (tid < st) red[tid] += red[tid + st];
        __syncthreads();
    }
    const float mu = red[0] * (1.0f / DM);
    __syncthreads();

    float d0 = v0 - mu, d1 = v1 - mu;
    red[tid] = d0 * d0 + d1 * d1; __syncthreads();
    for (int st = 128; st > 0; st >>= 1) {
        if (tid < st) red[tid] += red[tid + st];
        __syncthreads();
    }
    const float rstd = rsqrtf(red[0] * (1.0f / DM) + LN_EPS);

    float o0 = d0 * rstd * g[tid]       + beta[tid];
    float o1 = d1 * rstd * g[tid + 256] + beta[tid + 256];
    out[base + tid]       = o0;
    out[base + tid + 256] = o1;
    bf16 h, l;
    split1(o0, h, l); oh[base + tid]       = h; ol[base + tid]       = l;
    split1(o1, h, l); oh[base + tid + 256] = h; ol[base + tid + 256] = l;
}

// ------------------------- vocab softmax (online 2-pass) -------------------
__global__ void softmax_vocab_kernel(float* __restrict__ x)
{
    const int i = blockIdx.x;
    float* row = x + (size_t)i * VOC;
    const int tid = threadIdx.x;

    __shared__ float mRed[256];
    __shared__ float sRed[256];

    float m = -1e30f, s = 0.f;
    for (int j = tid * 4; j < VOC; j += 1024) {
        float4 v = *(const float4*)(row + j);
        float mv = fmaxf(fmaxf(v.x, v.y), fmaxf(v.z, v.w));
        float mo = m;
        m = fmaxf(m, mv);
        s = s * __expf(mo - m)
          + __expf(v.x - m) + __expf(v.y - m)
          + __expf(v.z - m) + __expf(v.w - m);
    }
    mRed[tid] = m; sRed[tid] = s; __syncthreads();
    for (int st = 128; st > 0; st >>= 1) {
        if (tid < st) {
            float m1 = mRed[tid], m2 = mRed[tid + st];
            float M = fmaxf(m1, m2);
            sRed[tid] = sRed[tid] * __expf(m1 - M) + sRed[tid + st] * __expf(m2 - M);
            mRed[tid] = M;
        }
        __syncthreads();
    }
    const float M = mRed[0];
    const float inv = 1.f / sRed[0];

    for (int j = tid * 4; j < VOC; j += 1024) {
        float4 v = *(const float4*)(row + j);
        v.x = __expf(v.x - M) * inv;
        v.y = __expf(v.y - M) * inv;
        v.z = __expf(v.z - M) * inv;
        v.w = __expf(v.w - M) * inv;
        *(float4*)(row + j) = v;
    }
}

// ------------------------- host side ---------------------------------------
#define SMEM_NN 89088
#define SMEM_NT 92160
#define SMEM_W  113664    // 3*(2*5120 + 2*4352)*2

static inline void do_split(const float* in, bf16* hi, bf16* lo, int n) {
    split_kernel<<<n / 2048, 256>>>(in, hi, lo, n);
}

extern "C" void kernel_launch(void* const* d_in, const int* in_sizes, int n_in,
                              void* d_out, int out_size)
{
    const float* x   = (const float*)d_in[0];
    const float* Wq  = (const float*)d_in[1];
    const float* bq  = (const float*)d_in[2];
    const float* Wk  = (const float*)d_in[3];
    const float* bk  = (const float*)d_in[4];
    const float* Wv  = (const float*)d_in[5];
    const float* bv  = (const float*)d_in[6];
    const float* Wp  = (const float*)d_in[7];
    const float* bp  = (const float*)d_in[8];
    const float* g1  = (const float*)d_in[9];
    const float* be1 = (const float*)d_in[10];
    const float* W1  = (const float*)d_in[11];
    const float* b1  = (const float*)d_in[12];
    const float* W2  = (const float*)d_in[13];
    const float* b2  = (const float*)d_in[14];
    const float* g2  = (const float*)d_in[15];
    const float* be2 = (const float*)d_in[16];
    const float* Wf  = (const float*)d_in[17];
    const float* bf  = (const float*)d_in[18];
    float* out = (float*)d_out;

    cudaFuncSetAttribute(gemm_bf16<0,0>, cudaFuncAttributeMaxDynamicSharedMemorySize, SMEM_NN);
    cudaFuncSetAttribute(gemm_bf16<0,2>, cudaFuncAttributeMaxDynamicSharedMemorySize, SMEM_NN);
    cudaFuncSetAttribute(gemm_bf16<1,1>, cudaFuncAttributeMaxDynamicSharedMemorySize, SMEM_NT);
    cudaFuncSetAttribute(gemm_bf16w,     cudaFuncAttributeMaxDynamicSharedMemorySize, SMEM_W);

    float *px, *px2, *patt, *pz, *ph2;
    cudaGetSymbolAddress((void**)&px,   g_x);
    cudaGetSymbolAddress((void**)&px2,  g_x2);
    cudaGetSymbolAddress((void**)&patt, g_att);
    cudaGetSymbolAddress((void**)&pz,   g_z);
    cudaGetSymbolAddress((void**)&ph2,  g_h2);

    bf16 *xh,*xl,*x2h,*x2l,*qh,*ql,*kh,*kl,*vh,*vl,*ath,*atl,*th,*tl,*hh,*hl;
    cudaGetSymbolAddress((void**)&xh,  g_xh);  cudaGetSymbolAddress((void**)&xl,  g_xl);
    cudaGetSymbolAddress((void**)&x2h, g_x2h); cudaGetSymbolAddress((void**)&x2l, g_x2l);
    cudaGetSymbolAddress((void**)&qh,  g_qh);  cudaGetSymbolAddress((void**)&ql,  g_ql);
    cudaGetSymbolAddress((void**)&kh,  g_kh);  cudaGetSymbolAddress((void**)&kl,  g_kl);
    cudaGetSymbolAddress((void**)&vh,  g_vh);  cudaGetSymbolAddress((void**)&vl,  g_vl);
    cudaGetSymbolAddress((void**)&ath, g_ath); cudaGetSymbolAddress((void**)&atl, g_atl);
    cudaGetSymbolAddress((void**)&th,  g_th);  cudaGetSymbolAddress((void**)&tl,  g_tl);
    cudaGetSymbolAddress((void**)&hh,  g_hh);  cudaGetSymbolAddress((void**)&hl,  g_hl);

    bf16 *wqh,*wql,*wkh,*wkl,*wvh,*wvl,*wph,*wpl,*w1h,*w1l,*w2h,*w2l,*wfh,*wfl;
    cudaGetSymbolAddress((void**)&wqh, g_wqh); cudaGetSymbolAddress((void**)&wql, g_wql);
    cudaGetSymbolAddress((void**)&wkh, g_wkh); cudaGetSymbolAddress((void**)&wkl, g_wkl);
    cudaGetSymbolAddress((void**)&wvh, g_wvh); cudaGetSymbolAddress((void**)&wvl, g_wvl);
    cudaGetSymbolAddress((void**)&wph, g_wph); cudaGetSymbolAddress((void**)&wpl, g_wpl);
    cudaGetSymbolAddress((void**)&w1h, g_w1h); cudaGetSymbolAddress((void**)&w1l, g_w1l);
    cudaGetSymbolAddress((void**)&w2h, g_w2h); cudaGetSymbolAddress((void**)&w2l, g_w2l);
    cudaGetSymbolAddress((void**)&wfh, g_wfh); cudaGetSymbolAddress((void**)&wfl, g_wfl);

    do_split(Wq, wqh, wql, NL*DM*FF);
    do_split(Wk, wkh, wkl, NL*DM*FF);
    do_split(Wv, wvh, wvl, NL*DM*FF);
    do_split(Wp, wph, wpl, NL*FF*FF);
    do_split(W1, w1h, w1l, NL*FF*HID);
    do_split(W2, w2h, w2l, NL*HID*DM);
    do_split(Wf, wfh, wfl, DM*VOC);
    do_split(x,  xh,  xl,  SQ*DM);
    cudaMemcpyAsync(px, x, (size_t)SQ*DM*sizeof(float), cudaMemcpyDeviceToDevice);

    const float scale = 1.0f / sqrtf((float)FF);

    for (int l = 0; l < NL; l++) {
        size_t wOff  = (size_t)l * DM * FF;
        size_t w1Off = (size_t)l * FF * HID;
        size_t w2Off = (size_t)l * HID * DM;

        // QKV (batched over z)
        {
            GPtrs pQ{wqh + wOff, wql + wOff, bq + (size_t)l*FF, nullptr, qh, ql};
            GPtrs pK{wkh + wOff, wkl + wOff, bk + (size_t)l*FF, nullptr, kh, kl};
            GPtrs pV{wvh + wOff, wvl + wOff, bv + (size_t)l*FF, nullptr, vh, vl};
            gemm_bf16<0,0><<<dim3(FF/64, SQ/128, 3), 256, SMEM_NN>>>(xh, xl, pQ, pK, pV, SQ, FF, DM, 1.f);
        }
        // scores = q @ k^T * scale (causal block skip)
        {
            GPtrs p{kh, kl, nullptr, patt, nullptr, nullptr};
            gemm_bf16<1,1><<<dim3(SQ/64, SQ/128, 1), 256, SMEM_NT>>>(qh, ql, p, p, p, SQ, SQ, FF, scale);
        }
        softmax_causal_kernel<<<SQ, 256>>>(patt, ath, atl);
        // t = att @ v (K bounded)
        {
            GPtrs p{vh, vl, nullptr, nullptr, th, tl};
            gemm_bf16<0,2><<<dim3(FF/64, SQ/128, 1), 256, SMEM_NN>>>(ath, atl, p, p, p, SQ, FF, SQ, 1.f);
        }
        // z = t @ Wp + bp
        {
            GPtrs p{wph + wOff, wpl + wOff, bp + (size_t)l*FF, pz, nullptr, nullptr};
            gemm_bf16<0,0><<<dim3(FF/64, SQ/128, 1), 256, SMEM_NN>>>(th, tl, p, p, p, SQ, FF, FF, 1.f);
        }
        add_ln_kernel<<<SQ, 256>>>(pz, px, g1 + (size_t)l*FF, be1 + (size_t)l*FF,
                                   px2, x2h, x2l);
        // h = x2 @ W1 + b1 (wide)
        {
            GPtrs p{w1h + w1Off, w1l + w1Off, b1 + (size_t)l*HID, nullptr, hh, hl};
            gemm_bf16w<<<dim3(HID/128, SQ/128, 1), 256, SMEM_W>>>(x2h, x2l, p, SQ, HID, FF);
        }
        // h2 = h @ W2 + b2
        {
            GPtrs p{w2h + w2Off, w2l + w2Off, b2 + (size_t)l*DM, ph2, nullptr, nullptr};
            gemm_bf16<0,0><<<dim3(DM/64, SQ/128, 1), 256, SMEM_NN>>>(hh, hl, p, p, p, SQ, DM, HID, 1.f);
        }
        add_ln_kernel<<<SQ, 256>>>(ph2, px2, g2 + (size_t)l*DM, be2 + (size_t)l*DM,
                                   px, xh, xl);
    }

    // logits (wide) + vocab softmax
    {
        GPtrs p{wfh, wfl, bf, out, nullptr, nullptr};
        gemm_bf16w<<<dim3(VOC/128, SQ/128, 1), 256, SMEM_W>>>(xh, xl, p, SQ, VOC, DM);
    }
    softmax_vocab_kernel<<<SQ, 256>>>(out);

    (void)in_sizes; (void)n_in; (void)out_size;
}

// round 8
// speedup vs baseline: 3.4413x; 1.0146x over previous
#include <cuda_runtime.h>
#include <cuda_bf16.h>
#include <cstdint>
#include <cmath>

#define SQ   2048
#define DM   512
#define FF   512
#define HID  2048
#define VOC  32000
#define NL   4
#define LN_EPS 1e-5f
#define NBV  (VOC/128)   // 250 logits n-blocks

typedef __nv_bfloat16  bf16;
typedef __nv_bfloat162 bf162;

// ------------------------- fp32 scratch ------------------------------------
__device__ float g_x  [SQ * DM];
__device__ float g_x2 [SQ * DM];
__device__ float g_att[SQ * SQ];
__device__ float g_z  [SQ * FF];
__device__ float g_h2 [SQ * DM];
__device__ float g_smax[SQ * NBV];
__device__ float g_ssum[SQ * NBV];

// ------------------------- bf16 hi/lo activations --------------------------
__device__ bf16 g_xh [SQ*DM],  g_xl [SQ*DM];
__device__ bf16 g_x2h[SQ*DM],  g_x2l[SQ*DM];
__device__ bf16 g_qh [SQ*FF],  g_ql [SQ*FF];
__device__ bf16 g_kh [SQ*FF],  g_kl [SQ*FF];
__device__ bf16 g_vh [SQ*FF],  g_vl [SQ*FF];
__device__ bf16 g_ath[SQ*SQ],  g_atl[SQ*SQ];
__device__ bf16 g_th [SQ*FF],  g_tl [SQ*FF];
__device__ bf16 g_hh [SQ*HID], g_hl [SQ*HID];

// ------------------------- bf16 hi/lo weights ------------------------------
__device__ bf16 g_wqh[NL*DM*FF],  g_wql[NL*DM*FF];
__device__ bf16 g_wkh[NL*DM*FF],  g_wkl[NL*DM*FF];
__device__ bf16 g_wvh[NL*DM*FF],  g_wvl[NL*DM*FF];
__device__ bf16 g_wph[NL*FF*FF],  g_wpl[NL*FF*FF];
__device__ bf16 g_w1h[NL*FF*HID], g_w1l[NL*FF*HID];
__device__ bf16 g_w2h[NL*HID*DM], g_w2l[NL*HID*DM];
__device__ bf16 g_wfh[DM*VOC],    g_wfl[DM*VOC];

// ------------------------- PTX wrappers ------------------------------------
__device__ __forceinline__ void ldsm4(uint32_t* r, uint32_t addr) {
    asm volatile("ldmatrix.sync.aligned.m8n8.x4.shared.b16 {%0,%1,%2,%3}, [%4];"
                 : "=r"(r[0]), "=r"(r[1]), "=r"(r[2]), "=r"(r[3]) : "r"(addr));
}
__device__ __forceinline__ void ldsm4t(uint32_t* r, uint32_t addr) {
    asm volatile("ldmatrix.sync.aligned.m8n8.x4.trans.shared.b16 {%0,%1,%2,%3}, [%4];"
                 : "=r"(r[0]), "=r"(r[1]), "=r"(r[2]), "=r"(r[3]) : "r"(addr));
}
__device__ __forceinline__ void mma16816(float* c, const uint32_t* a, const uint32_t* b) {
    asm volatile("mma.sync.aligned.m16n8k16.row.col.f32.bf16.bf16.f32 "
                 "{%0,%1,%2,%3}, {%4,%5,%6,%7}, {%8,%9}, {%0,%1,%2,%3};"
                 : "+f"(c[0]), "+f"(c[1]), "+f"(c[2]), "+f"(c[3])
                 : "r"(a[0]), "r"(a[1]), "r"(a[2]), "r"(a[3]),
                   "r"(b[0]), "r"(b[1]));
}
__device__ __forceinline__ void cpa16(uint32_t s, const void* g) {
    asm volatile("cp.async.cg.shared.global [%0], [%1], 16;\n" :: "r"(s), "l"(g));
}
__device__ __forceinline__ void cpcommit() { asm volatile("cp.async.commit_group;\n"); }
template<int N> __device__ __forceinline__ void cpwait() {
    asm volatile("cp.async.wait_group %0;\n" :: "n"(N));
}
__device__ __forceinline__ void split1(float x, bf16& h, bf16& l) {
    h = __float2bfloat16_rn(x);
    l = __float2bfloat16_rn(x - __bfloat162float(h));
}

// ------------------------- small utility kernels ---------------------------
__global__ void copy_kernel(const float* __restrict__ in, float* __restrict__ out, int n)
{
    int i = (blockIdx.x * blockDim.x + threadIdx.x) * 4;
    if (i < n) *(float4*)(out + i) = *(const float4*)(in + i);
}

__global__ void split_kernel(const float* __restrict__ in,
                             bf16* __restrict__ hi, bf16* __restrict__ lo, int n)
{
    int i = (blockIdx.x * blockDim.x + threadIdx.x) * 8;
    if (i >= n) return;
    float4 a = *(const float4*)(in + i);
    float4 b = *(const float4*)(in + i + 4);
    bf16 h[8], l[8];
    split1(a.x,h[0],l[0]); split1(a.y,h[1],l[1]);
    split1(a.z,h[2],l[2]); split1(a.w,h[3],l[3]);
    split1(b.x,h[4],l[4]); split1(b.y,h[5],l[5]);
    split1(b.z,h[6],l[6]); split1(b.w,h[7],l[7]);
    *(uint4*)(hi + i) = *(const uint4*)h;
    *(uint4*)(lo + i) = *(const uint4*)l;
}

struct GPtrs { const bf16 *Bh, *Bl; const float* bias; float* C; bf16 *Ch, *Cl; };

// ------------------------- BN=64 GEMM (proven) ------------------------------
template<int TRANSB, int MODE>
__global__ void __launch_bounds__(256, 2)
gemm_bf16(const bf16* __restrict__ Ah, const bf16* __restrict__ Al,
          GPtrs p0, GPtrs p1, GPtrs p2, int M, int N, int K, float alpha)
{
    constexpr int BM = 128, BN = 64, BK = 32, ST = 3;
    constexpr int ASTR   = 40;
    constexpr int A_PART = BM * ASTR;
    constexpr int BROWS  = TRANSB ? BN : BK;
    constexpr int BSTR   = TRANSB ? 40 : (BN + 8);
    constexpr int B_PART = BROWS * BSTR;
    constexpr int STAGE  = 2*A_PART + 2*B_PART;
    constexpr int MT = 2;
    constexpr int NT = 4;

    extern __shared__ bf16 smem[];

    const int m0 = blockIdx.y * BM;
    const int n0 = blockIdx.x * BN;
    if (MODE == 1 && n0 >= m0 + BM) return;

    GPtrs P = (blockIdx.z == 0) ? p0 : ((blockIdx.z == 1) ? p1 : p2);

    int Keff = K;
    if (MODE == 2) Keff = min(K, m0 + BM);
    const int T = Keff / BK;

    const int tid  = threadIdx.x;
    const int lane = tid & 31;
    const int warp = tid >> 5;
    const int wm = warp & 3;
    const int wn = warp >> 2;
    const int l7 = lane & 7, q1 = (lane >> 3) & 1, q2 = lane >> 4;

    auto load_tile = [&](int t, int s) {
        const int k0 = t * BK;
        bf16* sb = smem + s * STAGE;
        #pragma unroll
        for (int i = 0; i < 4; i++) {
            int f = tid + 256 * i;
            int part = f >> 9;
            int r = (f >> 2) & 127;
            int c = f & 3;
            const bf16* gp = (part ? Al : Ah) + (size_t)(m0 + r) * K + k0 + c * 8;
            cpa16((uint32_t)__cvta_generic_to_shared(sb + part*A_PART + r*ASTR + c*8), gp);
        }
        if (TRANSB) {
            constexpr int CB = BN * 4;
            #pragma unroll
            for (int i = 0; i < (2 * CB) / 256; i++) {
                int f = tid + 256 * i;
                int part = f / CB, rem = f % CB;
                int r = rem >> 2, c = rem & 3;
                const bf16* gp = (part ? P.Bl : P.Bh) + (size_t)(n0 + r) * K + k0 + c * 8;
                cpa16((uint32_t)__cvta_generic_to_shared(sb + 2*A_PART + part*B_PART + r*BSTR + c*8), gp);
            }
        } else {
            constexpr int CR = BN / 8;
            constexpr int CB = 32 * CR;
            #pragma unroll
            for (int i = 0; i < (2 * CB) / 256; i++) {
                int f = tid + 256 * i;
                int part = f / CB, rem = f % CB;
                int r = rem / CR, c = rem % CR;
                const bf16* gp = (part ? P.Bl : P.Bh) + (size_t)(k0 + r) * N + n0 + c * 8;
                cpa16((uint32_t)__cvta_generic_to_shared(sb + 2*A_PART + part*B_PART + r*BSTR + c*8), gp);
            }
        }
    };

    float acc[MT][NT][4];
    #pragma unroll
    for (int mt = 0; mt < MT; mt++)
        #pragma unroll
        for (int nt = 0; nt < NT; nt++)
            #pragma unroll
            for (int i = 0; i < 4; i++) acc[mt][nt][i] = 0.f;

    const uint32_t smemBase = (uint32_t)__cvta_generic_to_shared(smem);
    const uint32_t aoff = (uint32_t)(((wm*MT*16 + l7 + q1*8) * ASTR + q2*8) * 2);
    uint32_t boff;
    if (TRANSB) boff = (uint32_t)((2*A_PART + (wn*32 + l7 + q2*8) * BSTR + q1*8) * 2);
    else        boff = (uint32_t)((2*A_PART + (l7 + q1*8) * BSTR + wn*32 + q2*8) * 2);

    load_tile(0, 0); cpcommit();
    if (T > 1) load_tile(1, 1);
    cpcommit();

    for (int t = 0; t < T; t++) {
        cpwait<1>();
        __syncthreads();
        if (t + 2 < T) { load_tile(t + 2, (t + 2) % ST); }
        cpcommit();

        const uint32_t sbase = smemBase + (uint32_t)((t % ST) * STAGE * 2);

        #pragma unroll
        for (int ks = 0; ks < 2; ks++) {
            uint32_t a[MT][4], bh[NT][2], bl[NT][2];
            #pragma unroll
            for (int mt = 0; mt < MT; mt++)
                ldsm4(a[mt], sbase + aoff + (uint32_t)(mt*16*ASTR*2 + ks*32));
            #pragma unroll
            for (int pp = 0; pp < 2; pp++) {
                uint32_t off = TRANSB ? (uint32_t)(pp*16*BSTR*2 + ks*32)
                                      : (uint32_t)(ks*16*BSTR*2 + pp*32);
                uint32_t r4[4];
                if (TRANSB) ldsm4 (r4, sbase + boff + off);
                else        ldsm4t(r4, sbase + boff + off);
                bh[2*pp][0]   = r4[0]; bh[2*pp][1]   = r4[1];
                bh[2*pp+1][0] = r4[2]; bh[2*pp+1][1] = r4[3];
                if (TRANSB) ldsm4 (r4, sbase + boff + (uint32_t)(B_PART*2) + off);
                else        ldsm4t(r4, sbase + boff + (uint32_t)(B_PART*2) + off);
                bl[2*pp][0]   = r4[0]; bl[2*pp][1]   = r4[1];
                bl[2*pp+1][0] = r4[2]; bl[2*pp+1][1] = r4[3];
            }
            #pragma unroll
            for (int nt = 0; nt < NT; nt++)
                #pragma unroll
                for (int mt = 0; mt < MT; mt++)
                    mma16816(acc[mt][nt], a[mt], bh[nt]);
            #pragma unroll
            for (int nt = 0; nt < NT; nt++)
                #pragma unroll
                for (int mt = 0; mt < MT; mt++)
                    mma16816(acc[mt][nt], a[mt], bl[nt]);
            #pragma unroll
            for (int mt = 0; mt < MT; mt++)
                ldsm4(a[mt], sbase + aoff + (uint32_t)(A_PART*2 + mt*16*ASTR*2 + ks*32));
            #pragma unroll
            for (int nt = 0; nt < NT; nt++)
                #pragma unroll
                for (int mt = 0; mt < MT; mt++)
                    mma16816(acc[mt][nt], a[mt], bh[nt]);
        }
    }

    #pragma unroll
    for (int mt = 0; mt < MT; mt++) {
        int row0 = m0 + wm*MT*16 + mt*16 + (lane >> 2);
        #pragma unroll
        for (int nt = 0; nt < NT; nt++) {
            int col = n0 + wn*32 + nt*8 + ((lane & 3) << 1);
            float b0 = 0.f, b1 = 0.f;
            if (P.bias) { b0 = P.bias[col]; b1 = P.bias[col + 1]; }
            float c00 = acc[mt][nt][0] * alpha + b0;
            float c01 = acc[mt][nt][1] * alpha + b1;
            float c10 = acc[mt][nt][2] * alpha + b0;
            float c11 = acc[mt][nt][3] * alpha + b1;
            if (P.C) {
                *(float2*)(P.C + (size_t)row0 * N + col)       = float2{c00, c01};
                *(float2*)(P.C + (size_t)(row0 + 8) * N + col) = float2{c10, c11};
            }
            if (P.Ch) {
                bf16 h0,l0,h1,l1;
                split1(c00,h0,l0); split1(c01,h1,l1);
                *(bf162*)(P.Ch + (size_t)row0 * N + col) = bf162{h0,h1};
                *(bf162*)(P.Cl + (size_t)row0 * N + col) = bf162{l0,l1};
                split1(c10,h0,l0); split1(c11,h1,l1);
                *(bf162*)(P.Ch + (size_t)(row0 + 8) * N + col) = bf162{h0,h1};
                *(bf162*)(P.Cl + (size_t)(row0 + 8) * N + col) = bf162{l0,l1};
            }
        }
    }
}

// ------------------------- wide-N GEMM: BN=128, M-fast grid, opt stats -----
// grid = (M/128, N/128).  Optionally emits per-(row, n-block) softmax partials.
__global__ void __launch_bounds__(256, 2)
gemm_bf16w(const bf16* __restrict__ Ah, const bf16* __restrict__ Al,
           GPtrs P, float* __restrict__ smax, float* __restrict__ ssum,
           int M, int N, int K)
{
    constexpr int BM = 128, BN = 128, BK = 32, ST = 3;
    constexpr int ASTR   = 40;
    constexpr int A_PART = BM * ASTR;
    constexpr int BSTR   = BN + 8;
    constexpr int B_PART = BK * BSTR;
    constexpr int STAGE  = 2*A_PART + 2*B_PART;
    constexpr int MT = 2;
    constexpr int NT = 8;

    extern __shared__ bf16 smem[];

    const int m0 = blockIdx.x * BM;     // M-fast for L2 B reuse
    const int n0 = blockIdx.y * BN;
    const int T = K / BK;

    const int tid  = threadIdx.x;
    const int lane = tid & 31;
    const int warp = tid >> 5;
    const int wm = warp & 3;
    const int wn = warp >> 2;
    const int l7 = lane & 7, q1 = (lane >> 3) & 1, q2 = lane >> 4;

    auto load_tile = [&](int t, int s) {
        const int k0 = t * BK;
        bf16* sb = smem + s * STAGE;
        #pragma unroll
        for (int i = 0; i < 4; i++) {
            int f = tid + 256 * i;
            int part = f >> 9;
            int r = (f >> 2) & 127;
            int c = f & 3;
            const bf16* gp = (part ? Al : Ah) + (size_t)(m0 + r) * K + k0 + c * 8;
            cpa16((uint32_t)__cvta_generic_to_shared(sb + part*A_PART + r*ASTR + c*8), gp);
        }
        #pragma unroll
        for (int i = 0; i < 4; i++) {
            int f = tid + 256 * i;
            int part = f >> 9;
            int rem  = f & 511;
            int r = rem >> 4;
            int c = rem & 15;
            const bf16* gp = (part ? P.Bl : P.Bh) + (size_t)(k0 + r) * N + n0 + c * 8;
            cpa16((uint32_t)__cvta_generic_to_shared(sb + 2*A_PART + part*B_PART + r*BSTR + c*8), gp);
        }
    };

    float acc[MT][NT][4];
    #pragma unroll
    for (int mt = 0; mt < MT; mt++)
        #pragma unroll
        for (int nt = 0; nt < NT; nt++)
            #pragma unroll
            for (int i = 0; i < 4; i++) acc[mt][nt][i] = 0.f;

    const uint32_t smemBase = (uint32_t)__cvta_generic_to_shared(smem);
    const uint32_t aoff = (uint32_t)(((wm*MT*16 + l7 + q1*8) * ASTR + q2*8) * 2);
    const uint32_t boff = (uint32_t)((2*A_PART + (l7 + q1*8) * BSTR + wn*64 + q2*8) * 2);

    load_tile(0, 0); cpcommit();
    if (T > 1) load_tile(1, 1);
    cpcommit();

    for (int t = 0; t < T; t++) {
        cpwait<1>();
        __syncthreads();
        if (t + 2 < T) { load_tile(t + 2, (t + 2) % ST); }
        cpcommit();

        const uint32_t sbase = smemBase + (uint32_t)((t % ST) * STAGE * 2);

        #pragma unroll
        for (int ks = 0; ks < 2; ks++) {
            uint32_t a[MT][4], bh[NT][2];
            #pragma unroll
            for (int mt = 0; mt < MT; mt++)
                ldsm4(a[mt], sbase + aoff + (uint32_t)(mt*16*ASTR*2 + ks*32));
            #pragma unroll
            for (int pp = 0; pp < 4; pp++) {
                uint32_t r4[4];
                ldsm4t(r4, sbase + boff + (uint32_t)(ks*16*BSTR*2 + pp*32));
                bh[2*pp][0]   = r4[0]; bh[2*pp][1]   = r4[1];
                bh[2*pp+1][0] = r4[2]; bh[2*pp+1][1] = r4[3];
            }
            #pragma unroll
            for (int nt = 0; nt < NT; nt++)
                #pragma unroll
                for (int mt = 0; mt < MT; mt++)
                    mma16816(acc[mt][nt], a[mt], bh[nt]);
            #pragma unroll
            for (int ch = 0; ch < 2; ch++) {
                uint32_t bl[4][2];
                #pragma unroll
                for (int pp = 0; pp < 2; pp++) {
                    uint32_t r4[4];
                    ldsm4t(r4, sbase + boff + (uint32_t)(B_PART*2 + ks*16*BSTR*2 + (ch*2+pp)*32));
                    bl[2*pp][0]   = r4[0]; bl[2*pp][1]   = r4[1];
                    bl[2*pp+1][0] = r4[2]; bl[2*pp+1][1] = r4[3];
                }
                #pragma unroll
                for (int j = 0; j < 4; j++)
                    #pragma unroll
                    for (int mt = 0; mt < MT; mt++)
                        mma16816(acc[mt][ch*4 + j], a[mt], bl[j]);
            }
            #pragma unroll
            for (int mt = 0; mt < MT; mt++)
                ldsm4(a[mt], sbase + aoff + (uint32_t)(A_PART*2 + mt*16*ASTR*2 + ks*32));
            #pragma unroll
            for (int nt = 0; nt < NT; nt++)
                #pragma unroll
                for (int mt = 0; mt < MT; mt++)
                    mma16816(acc[mt][nt], a[mt], bh[nt]);
        }
    }

    // fold bias into acc
    #pragma unroll
    for (int mt = 0; mt < MT; mt++)
        #pragma unroll
        for (int nt = 0; nt < NT; nt++) {
            int col = n0 + wn*64 + nt*8 + ((lane & 3) << 1);
            float b0 = 0.f, b1 = 0.f;
            if (P.bias) { b0 = P.bias[col]; b1 = P.bias[col + 1]; }
            acc[mt][nt][0] += b0; acc[mt][nt][1] += b1;
            acc[mt][nt][2] += b0; acc[mt][nt][3] += b1;
        }

    // store
    #pragma unroll
    for (int mt = 0; mt < MT; mt++) {
        int row0 = m0 + wm*MT*16 + mt*16 + (lane >> 2);
        #pragma unroll
        for (int nt = 0; nt < NT; nt++) {
            int col = n0 + wn*64 + nt*8 + ((lane & 3) << 1);
            if (P.C) {
                *(float2*)(P.C + (size_t)row0 * N + col)       = float2{acc[mt][nt][0], acc[mt][nt][1]};
                *(float2*)(P.C + (size_t)(row0 + 8) * N + col) = float2{acc[mt][nt][2], acc[mt][nt][3]};
            }
            if (P.Ch) {
                bf16 h0,l0,h1,l1;
                split1(acc[mt][nt][0],h0,l0); split1(acc[mt][nt][1],h1,l1);
                *(bf162*)(P.Ch + (size_t)row0 * N + col) = bf162{h0,h1};
                *(bf162*)(P.Cl + (size_t)row0 * N + col) = bf162{l0,l1};
                split1(acc[mt][nt][2],h0,l0); split1(acc[mt][nt][3],h1,l1);
                *(bf162*)(P.Ch + (size_t)(row0 + 8) * N + col) = bf162{h0,h1};
                *(bf162*)(P.Cl + (size_t)(row0 + 8) * N + col) = bf162{l0,l1};
            }
        }
    }

    // optional softmax partial stats: per-row (max over this 128-col block,
    // sumexp relative to that max)
    if (smax) {
        __syncthreads();                     // all warps done with stage smem
        float* sm_m = (float*)smem;          // [128][2]
        float* sm_s = sm_m + 256;
        #pragma unroll
        for (int mt = 0; mt < MT; mt++) {
            float mA = -1e30f, mB = -1e30f;
            #pragma unroll
            for (int nt = 0; nt < NT; nt++) {
                mA = fmaxf(mA, fmaxf(acc[mt][nt][0], acc[mt][nt][1]));
                mB = fmaxf(mB, fmaxf(acc[mt][nt][2], acc[mt][nt][3]));
            }
            mA = fmaxf(mA, __shfl_xor_sync(0xffffffffu, mA, 1));
            mA = fmaxf(mA, __shfl_xor_sync(0xffffffffu, mA, 2));
            mB = fmaxf(mB, __shfl_xor_sync(0xffffffffu, mB, 1));
            mB = fmaxf(mB, __shfl_xor_sync(0xffffffffu, mB, 2));
            float sA = 0.f, sB = 0.f;
            #pragma unroll
            for (int nt = 0; nt < NT; nt++) {
                sA += __expf(acc[mt][nt][0] - mA) + __expf(acc[mt][nt][1] - mA);
                sB += __expf(acc[mt][nt][2] - mB) + __expf(acc[mt][nt][3] - mB);
            }
            sA += __shfl_xor_sync(0xffffffffu, sA, 1);
            sA += __shfl_xor_sync(0xffffffffu, sA, 2);
            sB += __shfl_xor_sync(0xffffffffu, sB, 1);
            sB += __shfl_xor_sync(0xffffffffu, sB, 2);
            if ((lane & 3) == 0) {
                int r = wm*32 + mt*16 + (lane >> 2);
                sm_m[r*2 + wn]       = mA;  sm_s[r*2 + wn]       = sA;
                sm_m[(r+8)*2 + wn]   = mB;  sm_s[(r+8)*2 + wn]   = sB;
            }
        }
        __syncthreads();
        if (tid < 128) {
            float m1 = sm_m[tid*2], m2 = sm_m[tid*2 + 1];
            float Mx = fmaxf(m1, m2);
            float S  = sm_s[tid*2] * __expf(m1 - Mx) + sm_s[tid*2 + 1] * __expf(m2 - Mx);
            int nb = N >> 7;
            smax[(size_t)(m0 + tid) * nb + (n0 >> 7)] = Mx;
            ssum[(size_t)(m0 + tid) * nb + (n0 >> 7)] = S;
        }
    }
}

// ------------------------- causal softmax (smem row cache) -----------------
__global__ void softmax_causal_kernel(const float* __restrict__ att,
                                      bf16* __restrict__ oh, bf16* __restrict__ ol)
{
    __shared__ float buf[SQ];
    __shared__ float red[256];

    const int i = blockIdx.x;
    const float* row = att + (size_t)i * SQ;
    bf16* rh = oh + (size_t)i * SQ;
    bf16* rl = ol + (size_t)i * SQ;
    const int tid = threadIdx.x;
    const int n = i + 1;
    const int fillEnd = ((i >> 7) + 1) << 7;

    float m = -1e30f;
    for (int j = tid; j < n; j += 256) {
        float v = row[j];
        buf[j] = v;
        m = fmaxf(m, v);
    }
    red[tid] = m; __syncthreads();
    for (int st = 128; st > 0; st >>= 1) {
        if (tid < st) red[tid] = fmaxf(red[tid], red[tid + st]);
        __syncthreads();
    }
    m = red[0]; __syncthreads();

    float s = 0.f;
    for (int j = tid; j < n; j += 256) {
        float e = __expf(buf[j] - m);
        buf[j] = e;
        s += e;
    }
    red[tid] = s; __syncthreads();
    for (int st = 128; st > 0; st >>= 1) {
        if (tid < st) red[tid] += red[tid + st];
        __syncthreads();
    }
    const float inv = 1.f / red[0];

    for (int j = tid; j < n; j += 256) {
        float e = buf[j] * inv;
        bf16 h, l; split1(e, h, l);
        rh[j] = h; rl[j] = l;
    }
    for (int j = n + tid; j < fillEnd; j += 256) {
        rh[j] = __float2bfloat16_rn(0.f);
        rl[j] = __float2bfloat16_rn(0.f);
    }
}

// ------------------------- residual-add + LayerNorm ------------------------
__global__ void add_ln_kernel(const float* __restrict__ a,
                              const float* __restrict__ res,
                              const float* __restrict__ g,
                              const float* __restrict__ beta,
                              float* __restrict__ out,
                              bf16* __restrict__ oh, bf16* __restrict__ ol)
{
    const int row = blockIdx.x;
    const int tid = threadIdx.x;
    const size_t base = (size_t)row * DM;

    float v0 = a[base + tid]       + res[base + tid];
    float v1 = a[base + tid + 256] + res[base + tid + 256];

    __shared__ float red[256];
    red[tid] = v0 + v1; __syncthreads();
    for (int st = 128; st > 0; st >>= 1) {
        if (tid < st) red[tid] += red[tid + st];
        __syncthreads();
    }
    const float mu = red[0] * (1.0f / DM);
    __syncthreads();

    float d0 = v0 - mu, d1 = v1 - mu;
    red[tid] = d0 * d0 + d1 * d1; __syncthreads();
    for (int st = 128; st > 0; st >>= 1) {
        if (tid < st) red[tid] += red[tid + st];
        __syncthreads();
    }
    const float rstd = rsqrtf(red[0] * (1.0f / DM) + LN_EPS);

    float o0 = d0 * rstd * g[tid]       + beta[tid];
    float o1 = d1 * rstd * g[tid + 256] + beta[tid + 256];
    out[base + tid]       = o0;
    out[base + tid + 256] = o1;
    bf16 h, l;
    split1(o0, h, l); oh[base + tid]       = h; ol[base + tid]       = l;
    split1(o1, h, l); oh[base + tid + 256] = h; ol[base + tid + 256] = l;
}

// ------------------------- vocab softmax via GEMM partials -----------------
__global__ void softmax_vocab_kernel(float* __restrict__ x,
                                     const float* __restrict__ smax,
                                     const float* __restrict__ ssum)
{
    const int i = blockIdx.x;
    float* row = x + (size_t)i * VOC;
    const int tid = threadIdx.x;

    __shared__ float mRed[256];
    __shared__ float sRed[256];

    // combine per-block partials
    float m = -1e30f, s = 0.f;
    if (tid < NBV) {
        m = smax[(size_t)i * NBV + tid];
        s = ssum[(size_t)i * NBV + tid];
    }
    mRed[tid] = m; sRed[tid] = s; __syncthreads();
    for (int st = 128; st > 0; st >>= 1) {
        if (tid < st) {
            float m1 = mRed[tid], m2 = mRed[tid + st];
            float Mx = fmaxf(m1, m2);
            sRed[tid] = sRed[tid] * __expf(m1 - Mx) + sRed[tid + st] * __expf(m2 - Mx);
            mRed[tid] = Mx;
        }
        __syncthreads();
    }
    const float M = mRed[0];
    const float inv = 1.f / sRed[0];

    // single read+write pass
    for (int j = tid * 4; j < VOC; j += 1024) {
        float4 v = *(const float4*)(row + j);
        v.x = __expf(v.x - M) * inv;
        v.y = __expf(v.y - M) * inv;
        v.z = __expf(v.z - M) * inv;
        v.w = __expf(v.w - M) * inv;
        *(float4*)(row + j) = v;
    }
}

// ------------------------- host side ---------------------------------------
#define SMEM_NN 89088
#define SMEM_NT 92160
#define SMEM_W  113664

static inline void do_split(const float* in, bf16* hi, bf16* lo, int n) {
    split_kernel<<<n / 2048, 256>>>(in, hi, lo, n);
}

extern "C" void kernel_launch(void* const* d_in, const int* in_sizes, int n_in,
                              void* d_out, int out_size)
{
    const float* x   = (const float*)d_in[0];
    const float* Wq  = (const float*)d_in[1];
    const float* bq  = (const float*)d_in[2];
    const float* Wk  = (const float*)d_in[3];
    const float* bk  = (const float*)d_in[4];
    const float* Wv  = (const float*)d_in[5];
    const float* bv  = (const float*)d_in[6];
    const float* Wp  = (const float*)d_in[7];
    const float* bp  = (const float*)d_in[8];
    const float* g1  = (const float*)d_in[9];
    const float* be1 = (const float*)d_in[10];
    const float* W1  = (const float*)d_in[11];
    const float* b1  = (const float*)d_in[12];
    const float* W2  = (const float*)d_in[13];
    const float* b2  = (const float*)d_in[14];
    const float* g2  = (const float*)d_in[15];
    const float* be2 = (const float*)d_in[16];
    const float* Wf  = (const float*)d_in[17];
    const float* bf  = (const float*)d_in[18];
    float* out = (float*)d_out;

    cudaFuncSetAttribute(gemm_bf16<0,0>, cudaFuncAttributeMaxDynamicSharedMemorySize, SMEM_NN);
    cudaFuncSetAttribute(gemm_bf16<0,2>, cudaFuncAttributeMaxDynamicSharedMemorySize, SMEM_NN);
    cudaFuncSetAttribute(gemm_bf16<1,1>, cudaFuncAttributeMaxDynamicSharedMemorySize, SMEM_NT);
    cudaFuncSetAttribute(gemm_bf16w,     cudaFuncAttributeMaxDynamicSharedMemorySize, SMEM_W);

    float *px, *px2, *patt, *pz, *ph2, *psmax, *pssum;
    cudaGetSymbolAddress((void**)&px,    g_x);
    cudaGetSymbolAddress((void**)&px2,   g_x2);
    cudaGetSymbolAddress((void**)&patt,  g_att);
    cudaGetSymbolAddress((void**)&pz,    g_z);
    cudaGetSymbolAddress((void**)&ph2,   g_h2);
    cudaGetSymbolAddress((void**)&psmax, g_smax);
    cudaGetSymbolAddress((void**)&pssum, g_ssum);

    bf16 *xh,*xl,*x2h,*x2l,*qh,*ql,*kh,*kl,*vh,*vl,*ath,*atl,*th,*tl,*hh,*hl;
    cudaGetSymbolAddress((void**)&xh,  g_xh);  cudaGetSymbolAddress((void**)&xl,  g_xl);
    cudaGetSymbolAddress((void**)&x2h, g_x2h); cudaGetSymbolAddress((void**)&x2l, g_x2l);
    cudaGetSymbolAddress((void**)&qh,  g_qh);  cudaGetSymbolAddress((void**)&ql,  g_ql);
    cudaGetSymbolAddress((void**)&kh,  g_kh);  cudaGetSymbolAddress((void**)&kl,  g_kl);
    cudaGetSymbolAddress((void**)&vh,  g_vh);  cudaGetSymbolAddress((void**)&vl,  g_vl);
    cudaGetSymbolAddress((void**)&ath, g_ath); cudaGetSymbolAddress((void**)&atl, g_atl);
    cudaGetSymbolAddress((void**)&th,  g_th);  cudaGetSymbolAddress((void**)&tl,  g_tl);
    cudaGetSymbolAddress((void**)&hh,  g_hh);  cudaGetSymbolAddress((void**)&hl,  g_hl);

    bf16 *wqh,*wql,*wkh,*wkl,*wvh,*wvl,*wph,*wpl,*w1h,*w1l,*w2h,*w2l,*wfh,*wfl;
    cudaGetSymbolAddress((void**)&wqh, g_wqh); cudaGetSymbolAddress((void**)&wql, g_wql);
    cudaGetSymbolAddress((void**)&wkh, g_wkh); cudaGetSymbolAddress((void**)&wkl, g_wkl);
    cudaGetSymbolAddress((void**)&wvh, g_wvh); cudaGetSymbolAddress((void**)&wvl, g_wvl);
    cudaGetSymbolAddress((void**)&wph, g_wph); cudaGetSymbolAddress((void**)&wpl, g_wpl);
    cudaGetSymbolAddress((void**)&w1h, g_w1h); cudaGetSymbolAddress((void**)&w1l, g_w1l);
    cudaGetSymbolAddress((void**)&w2h, g_w2h); cudaGetSymbolAddress((void**)&w2l, g_w2l);
    cudaGetSymbolAddress((void**)&wfh, g_wfh); cudaGetSymbolAddress((void**)&wfl, g_wfl);

    const float scale = 1.0f / sqrtf((float)FF);

    // launches 0-4, so launch #5 = the QKV GEMM (ncu -s 5 -c 1 profiles it)
    do_split(x,  xh,  xl,  SQ*DM);                                   // 0
    do_split(Wq, wqh, wql, NL*DM*FF);                                // 1
    do_split(Wk, wkh, wkl, NL*DM*FF);                                // 2
    do_split(Wv, wvh, wvl, NL*DM*FF);                                // 3
    copy_kernel<<<(SQ*DM)/1024, 256>>>(x, px, SQ*DM);                // 4

    bool firstLayer = true;
    for (int l = 0; l < NL; l++) {
        size_t wOff  = (size_t)l * DM * FF;
        size_t w1Off = (size_t)l * FF * HID;
        size_t w2Off = (size_t)l * HID * DM;

        // QKV (batched over z)                                      // 5 on l=0
        {
            GPtrs pQ{wqh + wOff, wql + wOff, bq + (size_t)l*FF, nullptr, qh, ql};
            GPtrs pK{wkh + wOff, wkl + wOff, bk + (size_t)l*FF, nullptr, kh, kl};
            GPtrs pV{wvh + wOff, wvl + wOff, bv + (size_t)l*FF, nullptr, vh, vl};
            gemm_bf16<0,0><<<dim3(FF/64, SQ/128, 3), 256, SMEM_NN>>>(xh, xl, pQ, pK, pV, SQ, FF, DM, 1.f);
        }
        if (firstLayer) {      // remaining weight splits (needed later on stream)
            do_split(Wp, wph, wpl, NL*FF*FF);
            do_split(W1, w1h, w1l, NL*FF*HID);
            do_split(W2, w2h, w2l, NL*HID*DM);
            do_split(Wf, wfh, wfl, DM*VOC);
            firstLayer = false;
        }
        // scores = q @ k^T * scale (causal block skip)
        {
            GPtrs p{kh, kl, nullptr, patt, nullptr, nullptr};
            gemm_bf16<1,1><<<dim3(SQ/64, SQ/128, 1), 256, SMEM_NT>>>(qh, ql, p, p, p, SQ, SQ, FF, scale);
        }
        softmax_causal_kernel<<<SQ, 256>>>(patt, ath, atl);
        // t = att @ v (K bounded)
        {
            GPtrs p{vh, vl, nullptr, nullptr, th, tl};
            gemm_bf16<0,2><<<dim3(FF/64, SQ/128, 1), 256, SMEM_NN>>>(ath, atl, p, p, p, SQ, FF, SQ, 1.f);
        }
        // z = t @ Wp + bp
        {
            GPtrs p{wph + wOff, wpl + wOff, bp + (size_t)l*FF, pz, nullptr, nullptr};
            gemm_bf16<0,0><<<dim3(FF/64, SQ/128, 1), 256, SMEM_NN>>>(th, tl, p, p, p, SQ, FF, FF, 1.f);
        }
        add_ln_kernel<<<SQ, 256>>>(pz, px, g1 + (size_t)l*FF, be1 + (size_t)l*FF,
                                   px2, x2h, x2l);
        // h = x2 @ W1 + b1 (wide, M-fast)
        {
            GPtrs p{w1h + w1Off, w1l + w1Off, b1 + (size_t)l*HID, nullptr, hh, hl};
            gemm_bf16w<<<dim3(SQ/128, HID/128, 1), 256, SMEM_W>>>(x2h, x2l, p, nullptr, nullptr, SQ, HID, FF);
        }
        // h2 = h @ W2 + b2
        {
            GPtrs p{w2h + w2Off, w2l + w2Off, b2 + (size_t)l*DM, ph2, nullptr, nullptr};
            gemm_bf16<0,0><<<dim3(DM/64, SQ/128, 1), 256, SMEM_NN>>>(hh, hl, p, p, p, SQ, DM, HID, 1.f);
        }
        add_ln_kernel<<<SQ, 256>>>(ph2, px2, g2 + (size_t)l*DM, be2 + (size_t)l*DM,
                                   px, xh, xl);
    }

    // logits (wide, M-fast, with softmax stats) + 1-pass vocab softmax
    {
        GPtrs p{wfh, wfl, bf, out, nullptr, nullptr};
        gemm_bf16w<<<dim3(SQ/128, VOC/128, 1), 256, SMEM_W>>>(xh, xl, p, psmax, pssum, SQ, VOC, DM);
    }
    softmax_vocab_kernel<<<SQ, 256>>>(out, psmax, pssum);

    (void)in_sizes; (void)n_in; (void)out_size;
}

// round 9
// speedup vs baseline: 3.8535x; 1.1198x over previous
#include <cuda_runtime.h>
#include <cuda_bf16.h>
#include <cstdint>
#include <cmath>

#define SQ   2048
#define DM   512
#define FF   512
#define HID  2048
#define VOC  32000
#define NL   4
#define LN_EPS 1e-5f
#define NBV  (VOC/128)

typedef __nv_bfloat16  bf16;
typedef __nv_bfloat162 bf162;

// ------------------------- fp32 scratch ------------------------------------
__device__ float g_x  [SQ * DM];
__device__ float g_xt [SQ * DM];      // tf32-rounded x for logits
__device__ float g_x2 [SQ * DM];
__device__ float g_att[SQ * SQ];
__device__ float g_z  [SQ * FF];
__device__ float g_z2 [SQ * FF];      // split-K partial
__device__ float g_h2 [SQ * DM];
__device__ float g_h2b[SQ * DM];      // split-K partial
__device__ float g_smax[SQ * NBV];
__device__ float g_ssum[SQ * NBV];
__device__ float g_wft[ (size_t)VOC * DM ];   // Wf^T, tf32-rounded, [N][K]

// ------------------------- bf16 hi/lo activations --------------------------
__device__ bf16 g_xh [SQ*DM],  g_xl [SQ*DM];
__device__ bf16 g_x2h[SQ*DM],  g_x2l[SQ*DM];
__device__ bf16 g_qh [SQ*FF],  g_ql [SQ*FF];
__device__ bf16 g_kh [SQ*FF],  g_kl [SQ*FF];
__device__ bf16 g_vh [SQ*FF],  g_vl [SQ*FF];
__device__ bf16 g_ath[SQ*SQ],  g_atl[SQ*SQ];
__device__ bf16 g_th [SQ*FF],  g_tl [SQ*FF];
__device__ bf16 g_hh [SQ*HID], g_hl [SQ*HID];

// ------------------------- bf16 hi/lo weights ------------------------------
__device__ bf16 g_wqh[NL*DM*FF],  g_wql[NL*DM*FF];
__device__ bf16 g_wkh[NL*DM*FF],  g_wkl[NL*DM*FF];
__device__ bf16 g_wvh[NL*DM*FF],  g_wvl[NL*DM*FF];
__device__ bf16 g_wph[NL*FF*FF],  g_wpl[NL*FF*FF];
__device__ bf16 g_w1h[NL*FF*HID], g_w1l[NL*FF*HID];
__device__ bf16 g_w2h[NL*HID*DM], g_w2l[NL*HID*DM];

// ------------------------- PTX wrappers ------------------------------------
__device__ __forceinline__ void ldsm4(uint32_t* r, uint32_t addr) {
    asm volatile("ldmatrix.sync.aligned.m8n8.x4.shared.b16 {%0,%1,%2,%3}, [%4];"
                 : "=r"(r[0]), "=r"(r[1]), "=r"(r[2]), "=r"(r[3]) : "r"(addr));
}
__device__ __forceinline__ void ldsm4t(uint32_t* r, uint32_t addr) {
    asm volatile("ldmatrix.sync.aligned.m8n8.x4.trans.shared.b16 {%0,%1,%2,%3}, [%4];"
                 : "=r"(r[0]), "=r"(r[1]), "=r"(r[2]), "=r"(r[3]) : "r"(addr));
}
__device__ __forceinline__ void mma16816(float* c, const uint32_t* a, const uint32_t* b) {
    asm volatile("mma.sync.aligned.m16n8k16.row.col.f32.bf16.bf16.f32 "
                 "{%0,%1,%2,%3}, {%4,%5,%6,%7}, {%8,%9}, {%0,%1,%2,%3};"
                 : "+f"(c[0]), "+f"(c[1]), "+f"(c[2]), "+f"(c[3])
                 : "r"(a[0]), "r"(a[1]), "r"(a[2]), "r"(a[3]),
                   "r"(b[0]), "r"(b[1]));
}
__device__ __forceinline__ void mma1688tf(float* c, const uint32_t* a, const uint32_t* b) {
    asm volatile("mma.sync.aligned.m16n8k8.row.col.f32.tf32.tf32.f32 "
                 "{%0,%1,%2,%3}, {%4,%5,%6,%7}, {%8,%9}, {%0,%1,%2,%3};"
                 : "+f"(c[0]), "+f"(c[1]), "+f"(c[2]), "+f"(c[3])
                 : "r"(a[0]), "r"(a[1]), "r"(a[2]), "r"(a[3]),
                   "r"(b[0]), "r"(b[1]));
}
__device__ __forceinline__ void cpa16(uint32_t s, const void* g) {
    asm volatile("cp.async.cg.shared.global [%0], [%1], 16;\n" :: "r"(s), "l"(g));
}
__device__ __forceinline__ void cpcommit() { asm volatile("cp.async.commit_group;\n"); }
template<int N> __device__ __forceinline__ void cpwait() {
    asm volatile("cp.async.wait_group %0;\n" :: "n"(N));
}
__device__ __forceinline__ void split1(float x, bf16& h, bf16& l) {
    h = __float2bfloat16_rn(x);
    l = __float2bfloat16_rn(x - __bfloat162float(h));
}
__device__ __forceinline__ float to_tf32(float x) {
    uint32_t u;
    asm("cvt.rna.tf32.f32 %0, %1;" : "=r"(u) : "f"(x));
    return __uint_as_float(u);
}

// ------------------------- utility kernels ---------------------------------
__global__ void copy_kernel(const float* __restrict__ in, float* __restrict__ out, int n)
{
    int i = (blockIdx.x * blockDim.x + threadIdx.x) * 4;
    if (i < n) *(float4*)(out + i) = *(const float4*)(in + i);
}

__global__ void split_kernel(const float* __restrict__ in,
                             bf16* __restrict__ hi, bf16* __restrict__ lo, int n)
{
    int i = (blockIdx.x * blockDim.x + threadIdx.x) * 8;
    if (i >= n) return;
    float4 a = *(const float4*)(in + i);
    float4 b = *(const float4*)(in + i + 4);
    bf16 h[8], l[8];
    split1(a.x,h[0],l[0]); split1(a.y,h[1],l[1]);
    split1(a.z,h[2],l[2]); split1(a.w,h[3],l[3]);
    split1(b.x,h[4],l[4]); split1(b.y,h[5],l[5]);
    split1(b.z,h[6],l[6]); split1(b.w,h[7],l[7]);
    *(uint4*)(hi + i) = *(const uint4*)h;
    *(uint4*)(lo + i) = *(const uint4*)l;
}

// round fp32 -> tf32-valued fp32
__global__ void round_tf32_kernel(const float* __restrict__ in,
                                  float* __restrict__ out, int n)
{
    int i = (blockIdx.x * blockDim.x + threadIdx.x) * 4;
    if (i >= n) return;
    float4 v = *(const float4*)(in + i);
    v.x = to_tf32(v.x); v.y = to_tf32(v.y);
    v.z = to_tf32(v.z); v.w = to_tf32(v.w);
    *(float4*)(out + i) = v;
}

// transpose [Kd,Nd] fp32 -> [Nd,Kd], rounding to tf32
__global__ void transpose_tf32_kernel(const float* __restrict__ in,
                                      float* __restrict__ out, int Kd, int Nd)
{
    __shared__ float t[32][33];
    const int n0 = blockIdx.x * 32, k0 = blockIdx.y * 32;
    const int tx = threadIdx.x, ty = threadIdx.y;   // 32 x 8
    #pragma unroll
    for (int i = 0; i < 4; i++)
        t[ty + 8*i][tx] = in[(size_t)(k0 + ty + 8*i) * Nd + n0 + tx];
    __syncthreads();
    #pragma unroll
    for (int i = 0; i < 4; i++)
        out[(size_t)(n0 + ty + 8*i) * Kd + k0 + tx] = to_tf32(t[tx][ty + 8*i]);
}

struct GPtrs { const bf16 *Bh, *Bl; const float* bias; float* C; bf16 *Ch, *Cl; };

// ------------------------- BN=64 bf16-split GEMM ---------------------------
// MODE: 0 normal; 1 causal block-skip (TRANSB=1); 2 K bounded at m0+128;
//       3 split-K over blockIdx.z (z-half of K, P=p0/p1 selects partial C).
template<int TRANSB, int MODE>
__global__ void __launch_bounds__(256, 2)
gemm_bf16(const bf16* __restrict__ Ah, const bf16* __restrict__ Al,
          GPtrs p0, GPtrs p1, GPtrs p2, int M, int N, int K, float alpha)
{
    constexpr int BM = 128, BN = 64, BK = 32, ST = 3;
    constexpr int ASTR   = 40;
    constexpr int A_PART = BM * ASTR;
    constexpr int BROWS  = TRANSB ? BN : BK;
    constexpr int BSTR   = TRANSB ? 40 : (BN + 8);
    constexpr int B_PART = BROWS * BSTR;
    constexpr int STAGE  = 2*A_PART + 2*B_PART;
    constexpr int MT = 2;
    constexpr int NT = 4;

    extern __shared__ bf16 smem[];

    const int m0 = blockIdx.y * BM;
    const int n0 = blockIdx.x * BN;
    if (MODE == 1 && n0 >= m0 + BM) return;

    GPtrs P = (blockIdx.z == 0) ? p0 : ((blockIdx.z == 1) ? p1 : p2);

    int Keff = K, kOff = 0;
    if (MODE == 2) Keff = min(K, m0 + BM);
    if (MODE == 3) { Keff = K >> 1; kOff = blockIdx.z * Keff; }
    const int T = Keff / BK;

    const int tid  = threadIdx.x;
    const int lane = tid & 31;
    const int warp = tid >> 5;
    const int wm = warp & 3;
    const int wn = warp >> 2;
    const int l7 = lane & 7, q1 = (lane >> 3) & 1, q2 = lane >> 4;

    auto load_tile = [&](int t, int s) {
        const int k0 = kOff + t * BK;
        bf16* sb = smem + s * STAGE;
        #pragma unroll
        for (int i = 0; i < 4; i++) {
            int f = tid + 256 * i;
            int part = f >> 9;
            int r = (f >> 2) & 127;
            int c = f & 3;
            const bf16* gp = (part ? Al : Ah) + (size_t)(m0 + r) * K + k0 + c * 8;
            cpa16((uint32_t)__cvta_generic_to_shared(sb + part*A_PART + r*ASTR + c*8), gp);
        }
        if (TRANSB) {
            constexpr int CB = BN * 4;
            #pragma unroll
            for (int i = 0; i < (2 * CB) / 256; i++) {
                int f = tid + 256 * i;
                int part = f / CB, rem = f % CB;
                int r = rem >> 2, c = rem & 3;
                const bf16* gp = (part ? P.Bl : P.Bh) + (size_t)(n0 + r) * K + k0 + c * 8;
                cpa16((uint32_t)__cvta_generic_to_shared(sb + 2*A_PART + part*B_PART + r*BSTR + c*8), gp);
            }
        } else {
            constexpr int CR = BN / 8;
            constexpr int CB = 32 * CR;
            #pragma unroll
            for (int i = 0; i < (2 * CB) / 256; i++) {
                int f = tid + 256 * i;
                int part = f / CB, rem = f % CB;
                int r = rem / CR, c = rem % CR;
                const bf16* gp = (part ? P.Bl : P.Bh) + (size_t)(k0 + r) * N + n0 + c * 8;
                cpa16((uint32_t)__cvta_generic_to_shared(sb + 2*A_PART + part*B_PART + r*BSTR + c*8), gp);
            }
        }
    };

    float acc[MT][NT][4];
    #pragma unroll
    for (int mt = 0; mt < MT; mt++)
        #pragma unroll
        for (int nt = 0; nt < NT; nt++)
            #pragma unroll
            for (int i = 0; i < 4; i++) acc[mt][nt][i] = 0.f;

    const uint32_t smemBase = (uint32_t)__cvta_generic_to_shared(smem);
    const uint32_t aoff = (uint32_t)(((wm*MT*16 + l7 + q1*8) * ASTR + q2*8) * 2);
    uint32_t boff;
    if (TRANSB) boff = (uint32_t)((2*A_PART + (wn*32 + l7 + q2*8) * BSTR + q1*8) * 2);
    else        boff = (uint32_t)((2*A_PART + (l7 + q1*8) * BSTR + wn*32 + q2*8) * 2);

    load_tile(0, 0); cpcommit();
    if (T > 1) load_tile(1, 1);
    cpcommit();

    for (int t = 0; t < T; t++) {
        cpwait<1>();
        __syncthreads();
        if (t + 2 < T) { load_tile(t + 2, (t + 2) % ST); }
        cpcommit();

        const uint32_t sbase = smemBase + (uint32_t)((t % ST) * STAGE * 2);

        #pragma unroll
        for (int ks = 0; ks < 2; ks++) {
            uint32_t a[MT][4], bh[NT][2], bl[NT][2];
            #pragma unroll
            for (int mt = 0; mt < MT; mt++)
                ldsm4(a[mt], sbase + aoff + (uint32_t)(mt*16*ASTR*2 + ks*32));
            #pragma unroll
            for (int pp = 0; pp < 2; pp++) {
                uint32_t off = TRANSB ? (uint32_t)(pp*16*BSTR*2 + ks*32)
                                      : (uint32_t)(ks*16*BSTR*2 + pp*32);
                uint32_t r4[4];
                if (TRANSB) ldsm4 (r4, sbase + boff + off);
                else        ldsm4t(r4, sbase + boff + off);
                bh[2*pp][0]   = r4[0]; bh[2*pp][1]   = r4[1];
                bh[2*pp+1][0] = r4[2]; bh[2*pp+1][1] = r4[3];
                if (TRANSB) ldsm4 (r4, sbase + boff + (uint32_t)(B_PART*2) + off);
                else        ldsm4t(r4, sbase + boff + (uint32_t)(B_PART*2) + off);
                bl[2*pp][0]   = r4[0]; bl[2*pp][1]   = r4[1];
                bl[2*pp+1][0] = r4[2]; bl[2*pp+1][1] = r4[3];
            }
            #pragma unroll
            for (int nt = 0; nt < NT; nt++)
                #pragma unroll
                for (int mt = 0; mt < MT; mt++)
                    mma16816(acc[mt][nt], a[mt], bh[nt]);
            #pragma unroll
            for (int nt = 0; nt < NT; nt++)
                #pragma unroll
                for (int mt = 0; mt < MT; mt++)
                    mma16816(acc[mt][nt], a[mt], bl[nt]);
            #pragma unroll
            for (int mt = 0; mt < MT; mt++)
                ldsm4(a[mt], sbase + aoff + (uint32_t)(A_PART*2 + mt*16*ASTR*2 + ks*32));
            #pragma unroll
            for (int nt = 0; nt < NT; nt++)
                #pragma unroll
                for (int mt = 0; mt < MT; mt++)
                    mma16816(acc[mt][nt], a[mt], bh[nt]);
        }
    }

    #pragma unroll
    for (int mt = 0; mt < MT; mt++) {
        int row0 = m0 + wm*MT*16 + mt*16 + (lane >> 2);
        #pragma unroll
        for (int nt = 0; nt < NT; nt++) {
            int col = n0 + wn*32 + nt*8 + ((lane & 3) << 1);
            float b0 = 0.f, b1 = 0.f;
            if (P.bias) { b0 = P.bias[col]; b1 = P.bias[col + 1]; }
            float c00 = acc[mt][nt][0] * alpha + b0;
            float c01 = acc[mt][nt][1] * alpha + b1;
            float c10 = acc[mt][nt][2] * alpha + b0;
            float c11 = acc[mt][nt][3] * alpha + b1;
            if (P.C) {
                *(float2*)(P.C + (size_t)row0 * N + col)       = float2{c00, c01};
                *(float2*)(P.C + (size_t)(row0 + 8) * N + col) = float2{c10, c11};
            }
            if (P.Ch) {
                bf16 h0,l0,h1,l1;
                split1(c00,h0,l0); split1(c01,h1,l1);
                *(bf162*)(P.Ch + (size_t)row0 * N + col) = bf162{h0,h1};
                *(bf162*)(P.Cl + (size_t)row0 * N + col) = bf162{l0,l1};
                split1(c10,h0,l0); split1(c11,h1,l1);
                *(bf162*)(P.Ch + (size_t)(row0 + 8) * N + col) = bf162{h0,h1};
                *(bf162*)(P.Cl + (size_t)(row0 + 8) * N + col) = bf162{l0,l1};
            }
        }
    }
}

// ------------------------- wide bf16 GEMM (W1 / FFN up) ---------------------
__global__ void __launch_bounds__(256, 2)
gemm_bf16w(const bf16* __restrict__ Ah, const bf16* __restrict__ Al,
           GPtrs P, int M, int N, int K)
{
    constexpr int BM = 128, BN = 128, BK = 32, ST = 3;
    constexpr int ASTR   = 40;
    constexpr int A_PART = BM * ASTR;
    constexpr int BSTR   = BN + 8;
    constexpr int B_PART = BK * BSTR;
    constexpr int STAGE  = 2*A_PART + 2*B_PART;
    constexpr int MT = 2;
    constexpr int NT = 8;

    extern __shared__ bf16 smem[];

    const int m0 = blockIdx.x * BM;
    const int n0 = blockIdx.y * BN;
    const int T = K / BK;

    const int tid  = threadIdx.x;
    const int lane = tid & 31;
    const int warp = tid >> 5;
    const int wm = warp & 3;
    const int wn = warp >> 2;
    const int l7 = lane & 7, q1 = (lane >> 3) & 1, q2 = lane >> 4;

    auto load_tile = [&](int t, int s) {
        const int k0 = t * BK;
        bf16* sb = smem + s * STAGE;
        #pragma unroll
        for (int i = 0; i < 4; i++) {
            int f = tid + 256 * i;
            int part = f >> 9;
            int r = (f >> 2) & 127;
            int c = f & 3;
            const bf16* gp = (part ? Al : Ah) + (size_t)(m0 + r) * K + k0 + c * 8;
            cpa16((uint32_t)__cvta_generic_to_shared(sb + part*A_PART + r*ASTR + c*8), gp);
        }
        #pragma unroll
        for (int i = 0; i < 4; i++) {
            int f = tid + 256 * i;
            int part = f >> 9;
            int rem  = f & 511;
            int r = rem >> 4;
            int c = rem & 15;
            const bf16* gp = (part ? P.Bl : P.Bh) + (size_t)(k0 + r) * N + n0 + c * 8;
            cpa16((uint32_t)__cvta_generic_to_shared(sb + 2*A_PART + part*B_PART + r*BSTR + c*8), gp);
        }
    };

    float acc[MT][NT][4];
    #pragma unroll
    for (int mt = 0; mt < MT; mt++)
        #pragma unroll
        for (int nt = 0; nt < NT; nt++)
            #pragma unroll
            for (int i = 0; i < 4; i++) acc[mt][nt][i] = 0.f;

    const uint32_t smemBase = (uint32_t)__cvta_generic_to_shared(smem);
    const uint32_t aoff = (uint32_t)(((wm*MT*16 + l7 + q1*8) * ASTR + q2*8) * 2);
    const uint32_t boff = (uint32_t)((2*A_PART + (l7 + q1*8) * BSTR + wn*64 + q2*8) * 2);

    load_tile(0, 0); cpcommit();
    if (T > 1) load_tile(1, 1);
    cpcommit();

    for (int t = 0; t < T; t++) {
        cpwait<1>();
        __syncthreads();
        if (t + 2 < T) { load_tile(t + 2, (t + 2) % ST); }
        cpcommit();

        const uint32_t sbase = smemBase + (uint32_t)((t % ST) * STAGE * 2);

        #pragma unroll
        for (int ks = 0; ks < 2; ks++) {
            uint32_t a[MT][4], bh[NT][2];
            #pragma unroll
            for (int mt = 0; mt < MT; mt++)
                ldsm4(a[mt], sbase + aoff + (uint32_t)(mt*16*ASTR*2 + ks*32));
            #pragma unroll
            for (int pp = 0; pp < 4; pp++) {
                uint32_t r4[4];
                ldsm4t(r4, sbase + boff + (uint32_t)(ks*16*BSTR*2 + pp*32));
                bh[2*pp][0]   = r4[0]; bh[2*pp][1]   = r4[1];
                bh[2*pp+1][0] = r4[2]; bh[2*pp+1][1] = r4[3];
            }
            #pragma unroll
            for (int nt = 0; nt < NT; nt++)
                #pragma unroll
                for (int mt = 0; mt < MT; mt++)
                    mma16816(acc[mt][nt], a[mt], bh[nt]);
            #pragma unroll
            for (int ch = 0; ch < 2; ch++) {
                uint32_t bl[4][2];
                #pragma unroll
                for (int pp = 0; pp < 2; pp++) {
                    uint32_t r4[4];
                    ldsm4t(r4, sbase + boff + (uint32_t)(B_PART*2 + ks*16*BSTR*2 + (ch*2+pp)*32));
                    bl[2*pp][0]   = r4[0]; bl[2*pp][1]   = r4[1];
                    bl[2*pp+1][0] = r4[2]; bl[2*pp+1][1] = r4[3];
                }
                #pragma unroll
                for (int j = 0; j < 4; j++)
                    #pragma unroll
                    for (int mt = 0; mt < MT; mt++)
                        mma16816(acc[mt][ch*4 + j], a[mt], bl[j]);
            }
            #pragma unroll
            for (int mt = 0; mt < MT; mt++)
                ldsm4(a[mt], sbase + aoff + (uint32_t)(A_PART*2 + mt*16*ASTR*2 + ks*32));
            #pragma unroll
            for (int nt = 0; nt < NT; nt++)
                #pragma unroll
                for (int mt = 0; mt < MT; mt++)
                    mma16816(acc[mt][nt], a[mt], bh[nt]);
        }
    }

    #pragma unroll
    for (int mt = 0; mt < MT; mt++) {
        int row0 = m0 + wm*MT*16 + mt*16 + (lane >> 2);
        #pragma unroll
        for (int nt = 0; nt < NT; nt++) {
            int col = n0 + wn*64 + nt*8 + ((lane & 3) << 1);
            float b0 = 0.f, b1 = 0.f;
            if (P.bias) { b0 = P.bias[col]; b1 = P.bias[col + 1]; }
            float c00 = acc[mt][nt][0] + b0;
            float c01 = acc[mt][nt][1] + b1;
            float c10 = acc[mt][nt][2] + b0;
            float c11 = acc[mt][nt][3] + b1;
            if (P.C) {
                *(float2*)(P.C + (size_t)row0 * N + col)       = float2{c00, c01};
                *(float2*)(P.C + (size_t)(row0 + 8) * N + col) = float2{c10, c11};
            }
            if (P.Ch) {
                bf16 h0,l0,h1,l1;
                split1(c00,h0,l0); split1(c01,h1,l1);
                *(bf162*)(P.Ch + (size_t)row0 * N + col) = bf162{h0,h1};
                *(bf162*)(P.Cl + (size_t)row0 * N + col) = bf162{l0,l1};
                split1(c10,h0,l0); split1(c11,h1,l1);
                *(bf162*)(P.Ch + (size_t)(row0 + 8) * N + col) = bf162{h0,h1};
                *(bf162*)(P.Cl + (size_t)(row0 + 8) * N + col) = bf162{l0,l1};
            }
        }
    }
}

// ------------------------- tf32 wide GEMM (logits) --------------------------
// C = A @ B^T + bias.  A [M,K] tf32-valued fp32; B (Wft) [N,K] tf32-valued.
// Single product (error ~4e-4 rel, fine for final softmax).  M-fast grid.
// Fused per-(row, n-block) softmax partials.
__global__ void __launch_bounds__(256, 2)
gemm_tf32w(const float* __restrict__ A, const float* __restrict__ B,
           const float* __restrict__ bias, float* __restrict__ C,
           float* __restrict__ smax, float* __restrict__ ssum,
           int M, int N, int K)
{
    constexpr int BM = 128, BN = 128, BK = 32, ST = 3;
    constexpr int ASTRf = 36;                 // floats
    constexpr int A_PARTf = BM * ASTRf;       // 4608
    constexpr int BSTRf = 36;
    constexpr int B_PARTf = BN * BSTRf;       // 4608
    constexpr int STAGEf = A_PARTf + B_PARTf; // 9216 floats = 36864 B
    constexpr int MT = 2;
    constexpr int NT = 8;

    extern __shared__ float fsmem[];

    const int m0 = blockIdx.x * BM;
    const int n0 = blockIdx.y * BN;
    const int T = K / BK;

    const int tid  = threadIdx.x;
    const int lane = tid & 31;
    const int warp = tid >> 5;
    const int wm = warp & 3;
    const int wn = warp >> 2;
    const int l7 = lane & 7, q1 = (lane >> 3) & 1, q2 = lane >> 4;

    auto load_tile = [&](int t, int s) {
        const int k0 = t * BK;
        float* sb = fsmem + s * STAGEf;
        #pragma unroll
        for (int i = 0; i < 4; i++) {         // A: 128 rows x 8 16B-chunks
            int f = tid + 256 * i;
            int r = f >> 3;
            int c = f & 7;
            cpa16((uint32_t)__cvta_generic_to_shared(sb + r*ASTRf + c*4),
                  A + (size_t)(m0 + r) * K + k0 + c*4);
        }
        #pragma unroll
        for (int i = 0; i < 4; i++) {         // B: 128 n-rows x 8 chunks
            int f = tid + 256 * i;
            int r = f >> 3;
            int c = f & 7;
            cpa16((uint32_t)__cvta_generic_to_shared(sb + A_PARTf + r*BSTRf + c*4),
                  B + (size_t)(n0 + r) * K + k0 + c*4);
        }
    };

    float acc[MT][NT][4];
    #pragma unroll
    for (int mt = 0; mt < MT; mt++)
        #pragma unroll
        for (int nt = 0; nt < NT; nt++)
            #pragma unroll
            for (int i = 0; i < 4; i++) acc[mt][nt][i] = 0.f;

    const uint32_t smemBase = (uint32_t)__cvta_generic_to_shared(fsmem);
    // A frag (fp32-as-b16 ldmatrix.x4): rows l7 + q1*8, fp32 col q2*4
    const uint32_t aoff = (uint32_t)(((wm*MT*16 + l7 + q1*8) * ASTRf + q2*4) * 4);
    // B frag: n-rows l7 + q2*8, fp32 k-col q1*4
    const uint32_t boff = (uint32_t)((A_PARTf + (wn*64 + l7 + q2*8) * BSTRf + q1*4) * 4);

    load_tile(0, 0); cpcommit();
    if (T > 1) load_tile(1, 1);
    cpcommit();

    for (int t = 0; t < T; t++) {
        cpwait<1>();
        __syncthreads();
        if (t + 2 < T) { load_tile(t + 2, (t + 2) % ST); }
        cpcommit();

        const uint32_t sbase = smemBase + (uint32_t)((t % ST) * STAGEf * 4);

        #pragma unroll
        for (int k8 = 0; k8 < 4; k8++) {      // BK=32 -> 4 k8-steps
            uint32_t a[MT][4];
            #pragma unroll
            for (int mt = 0; mt < MT; mt++)
                ldsm4(a[mt], sbase + aoff + (uint32_t)(mt*16*ASTRf*4 + k8*32));
            #pragma unroll
            for (int p = 0; p < NT/2; p++) {
                uint32_t r4[4];
                ldsm4(r4, sbase + boff + (uint32_t)(p*16*BSTRf*4 + k8*32));
                // r4 = {b0(nt0), b1(nt0), b0(nt1), b1(nt1)}
                uint32_t b0[2] = {r4[0], r4[1]};
                uint32_t b1[2] = {r4[2], r4[3]};
                #pragma unroll
                for (int mt = 0; mt < MT; mt++) {
                    mma1688tf(acc[mt][2*p],   a[mt], b0);
                    mma1688tf(acc[mt][2*p+1], a[mt], b1);
                }
            }
        }
    }

    // bias
    #pragma unroll
    for (int mt = 0; mt < MT; mt++)
        #pragma unroll
        for (int nt = 0; nt < NT; nt++) {
            int col = n0 + wn*64 + nt*8 + ((lane & 3) << 1);
            float b0 = 0.f, b1 = 0.f;
            if (bias) { b0 = bias[col]; b1 = bias[col + 1]; }
            acc[mt][nt][0] += b0; acc[mt][nt][1] += b1;
            acc[mt][nt][2] += b0; acc[mt][nt][3] += b1;
        }

    // store
    #pragma unroll
    for (int mt = 0; mt < MT; mt++) {
        int row0 = m0 + wm*MT*16 + mt*16 + (lane >> 2);
        #pragma unroll
        for (int nt = 0; nt < NT; nt++) {
            int col = n0 + wn*64 + nt*8 + ((lane & 3) << 1);
            *(float2*)(C + (size_t)row0 * N + col)       = float2{acc[mt][nt][0], acc[mt][nt][1]};
            *(float2*)(C + (size_t)(row0 + 8) * N + col) = float2{acc[mt][nt][2], acc[mt][nt][3]};
        }
    }

    // fused softmax partials
    if (smax) {
        __syncthreads();
        float* sm_m = fsmem;          // [128][2]
        float* sm_s = fsmem + 256;
        #pragma unroll
        for (int mt = 0; mt < MT; mt++) {
            float mA = -1e30f, mB = -1e30f;
            #pragma unroll
            for (int nt = 0; nt < NT; nt++) {
                mA = fmaxf(mA, fmaxf(acc[mt][nt][0], acc[mt][nt][1]));
                mB = fmaxf(mB, fmaxf(acc[mt][nt][2], acc[mt][nt][3]));
            }
            mA = fmaxf(mA, __shfl_xor_sync(0xffffffffu, mA, 1));
            mA = fmaxf(mA, __shfl_xor_sync(0xffffffffu, mA, 2));
            mB = fmaxf(mB, __shfl_xor_sync(0xffffffffu, mB, 1));
            mB = fmaxf(mB, __shfl_xor_sync(0xffffffffu, mB, 2));
            float sA = 0.f, sB = 0.f;
            #pragma unroll
            for (int nt = 0; nt < NT; nt++) {
                sA += __expf(acc[mt][nt][0] - mA) + __expf(acc[mt][nt][1] - mA);
                sB += __expf(acc[mt][nt][2] - mB) + __expf(acc[mt][nt][3] - mB);
            }
            sA += __shfl_xor_sync(0xffffffffu, sA, 1);
            sA += __shfl_xor_sync(0xffffffffu, sA, 2);
            sB += __shfl_xor_sync(0xffffffffu, sB, 1);
            sB += __shfl_xor_sync(0xffffffffu, sB, 2);
            if ((lane & 3) == 0) {
                int r = wm*32 + mt*16 + (lane >> 2);
                sm_m[r*2 + wn]     = mA;  sm_s[r*2 + wn]     = sA;
                sm_m[(r+8)*2 + wn] = mB;  sm_s[(r+8)*2 + wn] = sB;
            }
        }
        __syncthreads();
        if (tid < 128) {
            float m1 = sm_m[tid*2], m2 = sm_m[tid*2 + 1];
            float Mx = fmaxf(m1, m2);
            float S  = sm_s[tid*2] * __expf(m1 - Mx) + sm_s[tid*2 + 1] * __expf(m2 - Mx);
            int nb = N >> 7;
            smax[(size_t)(m0 + tid) * nb + (n0 >> 7)] = Mx;
            ssum[(size_t)(m0 + tid) * nb + (n0 >> 7)] = S;
        }
    }
}

// ------------------------- causal softmax ----------------------------------
__global__ void softmax_causal_kernel(const float* __restrict__ att,
                                      bf16* __restrict__ oh, bf16* __restrict__ ol)
{
    __shared__ float buf[SQ];
    __shared__ float red[256];

    const int i = blockIdx.x;
    const float* row = att + (size_t)i * SQ;
    bf16* rh = oh + (size_t)i * SQ;
    bf16* rl = ol + (size_t)i * SQ;
    const int tid = threadIdx.x;
    const int n = i + 1;
    const int fillEnd = ((i >> 7) + 1) << 7;

    float m = -1e30f;
    for (int j = tid; j < n; j += 256) {
        float v = row[j];
        buf[j] = v;
        m = fmaxf(m, v);
    }
    red[tid] = m; __syncthreads();
    for (int st = 128; st > 0; st >>= 1) {
        if (tid < st) red[tid] = fmaxf(red[tid], red[tid + st]);
        __syncthreads();
    }
    m = red[0]; __syncthreads();

    float s = 0.f;
    for (int j = tid; j < n; j += 256) {
        float e = __expf(buf[j] - m);
        buf[j] = e;
        s += e;
    }
    red[tid] = s; __syncthreads();
    for (int st = 128; st > 0; st >>= 1) {
        if (tid < st) red[tid] += red[tid + st];
        __syncthreads();
    }
    const float inv = 1.f / red[0];

    for (int j = tid; j < n; j += 256) {
        float e = buf[j] * inv;
        bf16 h, l; split1(e, h, l);
        rh[j] = h; rl[j] = l;
    }
    for (int j = n + tid; j < fillEnd; j += 256) {
        rh[j] = __float2bfloat16_rn(0.f);
        rl[j] = __float2bfloat16_rn(0.f);
    }
}

// ------------------------- residual-add (+2nd partial) + LayerNorm ---------
__global__ void add_ln_kernel(const float* __restrict__ a,
                              const float* __restrict__ a2,
                              const float* __restrict__ res,
                              const float* __restrict__ g,
                              const float* __restrict__ beta,
                              float* __restrict__ out,
                              bf16* __restrict__ oh, bf16* __restrict__ ol)
{
    const int row = blockIdx.x;
    const int tid = threadIdx.x;
    const size_t base = (size_t)row * DM;

    float v0 = a[base + tid]       + res[base + tid];
    float v1 = a[base + tid + 256] + res[base + tid + 256];
    if (a2) {
        v0 += a2[base + tid];
        v1 += a2[base + tid + 256];
    }

    __shared__ float red[256];
    red[tid] = v0 + v1; __syncthreads();
    for (int st = 128; st > 0; st >>= 1) {
        if (tid < st) red[tid] += red[tid + st];
        __syncthreads();
    }
    const float mu = red[0] * (1.0f / DM);
    __syncthreads();

    float d0 = v0 - mu, d1 = v1 - mu;
    red[tid] = d0 * d0 + d1 * d1; __syncthreads();
    for (int st = 128; st > 0; st >>= 1) {
        if (tid < st) red[tid] += red[tid + st];
        __syncthreads();
    }
    const float rstd = rsqrtf(red[0] * (1.0f / DM) + LN_EPS);

    float o0 = d0 * rstd * g[tid]       + beta[tid];
    float o1 = d1 * rstd * g[tid + 256] + beta[tid + 256];
    out[base + tid]       = o0;
    out[base + tid + 256] = o1;
    bf16 h, l;
    split1(o0, h, l); oh[base + tid]       = h; ol[base + tid]       = l;
    split1(o1, h, l); oh[base + tid + 256] = h; ol[base + tid + 256] = l;
}

// ------------------------- vocab softmax via GEMM partials -----------------
__global__ void softmax_vocab_kernel(float* __restrict__ x,
                                     const float* __restrict__ smax,
                                     const float* __restrict__ ssum)
{
    const int i = blockIdx.x;
    float* row = x + (size_t)i * VOC;
    const int tid = threadIdx.x;

    __shared__ float mRed[256];
    __shared__ float sRed[256];

    float m = -1e30f, s = 0.f;
    if (tid < NBV) {
        m = smax[(size_t)i * NBV + tid];
        s = ssum[(size_t)i * NBV + tid];
    }
    mRed[tid] = m; sRed[tid] = s; __syncthreads();
    for (int st = 128; st > 0; st >>= 1) {
        if (tid < st) {
            float m1 = mRed[tid], m2 = mRed[tid + st];
            float Mx = fmaxf(m1, m2);
            sRed[tid] = sRed[tid] * __expf(m1 - Mx) + sRed[tid + st] * __expf(m2 - Mx);
            mRed[tid] = Mx;
        }
        __syncthreads();
    }
    const float M = mRed[0];
    const float inv = 1.f / sRed[0];

    for (int j = tid * 4; j < VOC; j += 1024) {
        float4 v = *(const float4*)(row + j);
        v.x = __expf(v.x - M) * inv;
        v.y = __expf(v.y - M) * inv;
        v.z = __expf(v.z - M) * inv;
        v.w = __expf(v.w - M) * inv;
        *(float4*)(row + j) = v;
    }
}

// ------------------------- host side ---------------------------------------
#define SMEM_NN 89088
#define SMEM_NT 92160
#define SMEM_W  113664
#define SMEM_TF 110592    // 3 * 36864

static inline void do_split(const float* in, bf16* hi, bf16* lo, int n) {
    split_kernel<<<n / 2048, 256>>>(in, hi, lo, n);
}

extern "C" void kernel_launch(void* const* d_in, const int* in_sizes, int n_in,
                              void* d_out, int out_size)
{
    const float* x   = (const float*)d_in[0];
    const float* Wq  = (const float*)d_in[1];
    const float* bq  = (const float*)d_in[2];
    const float* Wk  = (const float*)d_in[3];
    const float* bk  = (const float*)d_in[4];
    const float* Wv  = (const float*)d_in[5];
    const float* bv  = (const float*)d_in[6];
    const float* Wp  = (const float*)d_in[7];
    const float* bp  = (const float*)d_in[8];
    const float* g1  = (const float*)d_in[9];
    const float* be1 = (const float*)d_in[10];
    const float* W1  = (const float*)d_in[11];
    const float* b1  = (const float*)d_in[12];
    const float* W2  = (const float*)d_in[13];
    const float* b2  = (const float*)d_in[14];
    const float* g2  = (const float*)d_in[15];
    const float* be2 = (const float*)d_in[16];
    const float* Wf  = (const float*)d_in[17];
    const float* bf  = (const float*)d_in[18];
    float* out = (float*)d_out;

    cudaFuncSetAttribute(gemm_bf16<0,0>, cudaFuncAttributeMaxDynamicSharedMemorySize, SMEM_NN);
    cudaFuncSetAttribute(gemm_bf16<0,2>, cudaFuncAttributeMaxDynamicSharedMemorySize, SMEM_NN);
    cudaFuncSetAttribute(gemm_bf16<0,3>, cudaFuncAttributeMaxDynamicSharedMemorySize, SMEM_NN);
    cudaFuncSetAttribute(gemm_bf16<1,1>, cudaFuncAttributeMaxDynamicSharedMemorySize, SMEM_NT);
    cudaFuncSetAttribute(gemm_bf16w,     cudaFuncAttributeMaxDynamicSharedMemorySize, SMEM_W);
    cudaFuncSetAttribute(gemm_tf32w,     cudaFuncAttributeMaxDynamicSharedMemorySize, SMEM_TF);

    float *px, *pxt, *px2, *patt, *pz, *pz2, *ph2, *ph2b, *psmax, *pssum, *pwft;
    cudaGetSymbolAddress((void**)&px,    g_x);
    cudaGetSymbolAddress((void**)&pxt,   g_xt);
    cudaGetSymbolAddress((void**)&px2,   g_x2);
    cudaGetSymbolAddress((void**)&patt,  g_att);
    cudaGetSymbolAddress((void**)&pz,    g_z);
    cudaGetSymbolAddress((void**)&pz2,   g_z2);
    cudaGetSymbolAddress((void**)&ph2,   g_h2);
    cudaGetSymbolAddress((void**)&ph2b,  g_h2b);
    cudaGetSymbolAddress((void**)&psmax, g_smax);
    cudaGetSymbolAddress((void**)&pssum, g_ssum);
    cudaGetSymbolAddress((void**)&pwft,  g_wft);

    bf16 *xh,*xl,*x2h,*x2l,*qh,*ql,*kh,*kl,*vh,*vl,*ath,*atl,*th,*tl,*hh,*hl;
    cudaGetSymbolAddress((void**)&xh,  g_xh);  cudaGetSymbolAddress((void**)&xl,  g_xl);
    cudaGetSymbolAddress((void**)&x2h, g_x2h); cudaGetSymbolAddress((void**)&x2l, g_x2l);
    cudaGetSymbolAddress((void**)&qh,  g_qh);  cudaGetSymbolAddress((void**)&ql,  g_ql);
    cudaGetSymbolAddress((void**)&kh,  g_kh);  cudaGetSymbolAddress((void**)&kl,  g_kl);
    cudaGetSymbolAddress((void**)&vh,  g_vh);  cudaGetSymbolAddress((void**)&vl,  g_vl);
    cudaGetSymbolAddress((void**)&ath, g_ath); cudaGetSymbolAddress((void**)&atl, g_atl);
    cudaGetSymbolAddress((void**)&th,  g_th);  cudaGetSymbolAddress((void**)&tl,  g_tl);
    cudaGetSymbolAddress((void**)&hh,  g_hh);  cudaGetSymbolAddress((void**)&hl,  g_hl);

    bf16 *wqh,*wql,*wkh,*wkl,*wvh,*wvl,*wph,*wpl,*w1h,*w1l,*w2h,*w2l;
    cudaGetSymbolAddress((void**)&wqh, g_wqh); cudaGetSymbolAddress((void**)&wql, g_wql);
    cudaGetSymbolAddress((void**)&wkh, g_wkh); cudaGetSymbolAddress((void**)&wkl, g_wkl);
    cudaGetSymbolAddress((void**)&wvh, g_wvh); cudaGetSymbolAddress((void**)&wvl, g_wvl);
    cudaGetSymbolAddress((void**)&wph, g_wph); cudaGetSymbolAddress((void**)&wpl, g_wpl);
    cudaGetSymbolAddress((void**)&w1h, g_w1h); cudaGetSymbolAddress((void**)&w1l, g_w1l);
    cudaGetSymbolAddress((void**)&w2h, g_w2h); cudaGetSymbolAddress((void**)&w2l, g_w2l);

    const float scale = 1.0f / sqrtf((float)FF);

    // preprocessing
    do_split(x,  xh,  xl,  SQ*DM);
    do_split(Wq, wqh, wql, NL*DM*FF);
    do_split(Wk, wkh, wkl, NL*DM*FF);
    do_split(Wv, wvh, wvl, NL*DM*FF);
    copy_kernel<<<(SQ*DM)/1024, 256>>>(x, px, SQ*DM);

    bool firstLayer = true;
    for (int l = 0; l < NL; l++) {
        size_t wOff  = (size_t)l * DM * FF;
        size_t w1Off = (size_t)l * FF * HID;
        size_t w2Off = (size_t)l * HID * DM;

        // QKV (batched over z)
        {
            GPtrs pQ{wqh + wOff, wql + wOff, bq + (size_t)l*FF, nullptr, qh, ql};
            GPtrs pK{wkh + wOff, wkl + wOff, bk + (size_t)l*FF, nullptr, kh, kl};
            GPtrs pV{wvh + wOff, wvl + wOff, bv + (size_t)l*FF, nullptr, vh, vl};
            gemm_bf16<0,0><<<dim3(FF/64, SQ/128, 3), 256, SMEM_NN>>>(xh, xl, pQ, pK, pV, SQ, FF, DM, 1.f);
        }
        if (firstLayer) {    // remaining preprocessing, overlapped after QKV issue
            do_split(Wp, wph, wpl, NL*FF*FF);
            do_split(W1, w1h, w1l, NL*FF*HID);
            do_split(W2, w2h, w2l, NL*HID*DM);
            transpose_tf32_kernel<<<dim3(VOC/32, DM/32), dim3(32,8)>>>(Wf, pwft, DM, VOC);
            firstLayer = false;
        }
        // scores = q @ k^T * scale (causal block skip)
        {
            GPtrs p{kh, kl, nullptr, patt, nullptr, nullptr};
            gemm_bf16<1,1><<<dim3(SQ/64, SQ/128, 1), 256, SMEM_NT>>>(qh, ql, p, p, p, SQ, SQ, FF, scale);
        }
        softmax_causal_kernel<<<SQ, 256>>>(patt, ath, atl);
        // t = att @ v (K bounded)
        {
            GPtrs p{vh, vl, nullptr, nullptr, th, tl};
            gemm_bf16<0,2><<<dim3(FF/64, SQ/128, 1), 256, SMEM_NN>>>(ath, atl, p, p, p, SQ, FF, SQ, 1.f);
        }
        // z = t @ Wp + bp  (split-K=2 -> pz, pz2)
        {
            GPtrs pA{wph + wOff, wpl + wOff, bp + (size_t)l*FF, pz,  nullptr, nullptr};
            GPtrs pB{wph + wOff, wpl + wOff, nullptr,           pz2, nullptr, nullptr};
            gemm_bf16<0,3><<<dim3(FF/64, SQ/128, 2), 256, SMEM_NN>>>(th, tl, pA, pB, pB, SQ, FF, FF, 1.f);
        }
        add_ln_kernel<<<SQ, 256>>>(pz, pz2, px, g1 + (size_t)l*FF, be1 + (size_t)l*FF,
                                   px2, x2h, x2l);
        // h = x2 @ W1 + b1 (wide, M-fast)
        {
            GPtrs p{w1h + w1Off, w1l + w1Off, b1 + (size_t)l*HID, nullptr, hh, hl};
            gemm_bf16w<<<dim3(SQ/128, HID/128, 1), 256, SMEM_W>>>(x2h, x2l, p, SQ, HID, FF);
        }
        // h2 = h @ W2 + b2  (split-K=2 -> ph2, ph2b)
        {
            GPtrs pA{w2h + w2Off, w2l + w2Off, b2 + (size_t)l*DM, ph2,  nullptr, nullptr};
            GPtrs pB{w2h + w2Off, w2l + w2Off, nullptr,           ph2b, nullptr, nullptr};
            gemm_bf16<0,3><<<dim3(DM/64, SQ/128, 2), 256, SMEM_NN>>>(hh, hl, pA, pB, pB, SQ, DM, HID, 1.f);
        }
        add_ln_kernel<<<SQ, 256>>>(ph2, ph2b, px2, g2 + (size_t)l*DM, be2 + (size_t)l*DM,
                                   px, xh, xl);
    }

    // tf32-round the final activations, then tf32 logits GEMM + 1-pass softmax
    round_tf32_kernel<<<(SQ*DM)/1024, 256>>>(px, pxt, SQ*DM);
    gemm_tf32w<<<dim3(SQ/128, VOC/128), 256, SMEM_TF>>>(pxt, pwft, bf, out,
                                                        psmax, pssum, SQ, VOC, DM);
    softmax_vocab_kernel<<<SQ, 256>>>(out, psmax, pssum);

    (void)in_sizes; (void)n_in; (void)out_size;
}

// round 10
// speedup vs baseline: 3.9682x; 1.0298x over previous
#include <cuda_runtime.h>
#include <cuda_bf16.h>
#include <cstdint>
#include <cmath>

#define SQ   2048
#define DM   512
#define FF   512
#define HID  2048
#define VOC  32000
#define NL   4
#define LN_EPS 1e-5f
#define NBV  (VOC/128)

typedef __nv_bfloat16  bf16;
typedef __nv_bfloat162 bf162;

// ------------------------- fp32 scratch ------------------------------------
__device__ float g_x  [SQ * DM];
__device__ float g_xt [SQ * DM];
__device__ float g_x2 [SQ * DM];
__device__ float g_att[SQ * SQ];
__device__ float g_z  [SQ * FF];
__device__ float g_z2 [SQ * FF];
__device__ float g_h2 [SQ * DM];
__device__ float g_h2b[SQ * DM];
__device__ float g_smax[SQ * NBV];
__device__ float g_ssum[SQ * NBV];
__device__ float g_wft[ (size_t)VOC * DM ];

// ------------------------- bf16 hi/lo activations --------------------------
__device__ bf16 g_xh [SQ*DM],  g_xl [SQ*DM];
__device__ bf16 g_x2h[SQ*DM],  g_x2l[SQ*DM];
__device__ bf16 g_qh [SQ*FF],  g_ql [SQ*FF];
__device__ bf16 g_kh [SQ*FF],  g_kl [SQ*FF];
__device__ bf16 g_vh [SQ*FF],  g_vl [SQ*FF];
__device__ bf16 g_ath[SQ*SQ],  g_atl[SQ*SQ];
__device__ bf16 g_th [SQ*FF],  g_tl [SQ*FF];
__device__ bf16 g_hh [SQ*HID], g_hl [SQ*HID];

// ------------------------- bf16 hi/lo weights ------------------------------
__device__ bf16 g_wqh[NL*DM*FF],  g_wql[NL*DM*FF];
__device__ bf16 g_wkh[NL*DM*FF],  g_wkl[NL*DM*FF];
__device__ bf16 g_wvh[NL*DM*FF],  g_wvl[NL*DM*FF];
__device__ bf16 g_wph[NL*FF*FF],  g_wpl[NL*FF*FF];
__device__ bf16 g_w1h[NL*FF*HID], g_w1l[NL*FF*HID];
__device__ bf16 g_w2h[NL*HID*DM], g_w2l[NL*HID*DM];

// ------------------------- PTX wrappers ------------------------------------
__device__ __forceinline__ void ldsm4(uint32_t* r, uint32_t addr) {
    asm volatile("ldmatrix.sync.aligned.m8n8.x4.shared.b16 {%0,%1,%2,%3}, [%4];"
                 : "=r"(r[0]), "=r"(r[1]), "=r"(r[2]), "=r"(r[3]) : "r"(addr));
}
__device__ __forceinline__ void ldsm4t(uint32_t* r, uint32_t addr) {
    asm volatile("ldmatrix.sync.aligned.m8n8.x4.trans.shared.b16 {%0,%1,%2,%3}, [%4];"
                 : "=r"(r[0]), "=r"(r[1]), "=r"(r[2]), "=r"(r[3]) : "r"(addr));
}
__device__ __forceinline__ void mma16816(float* c, const uint32_t* a, const uint32_t* b) {
    asm volatile("mma.sync.aligned.m16n8k16.row.col.f32.bf16.bf16.f32 "
                 "{%0,%1,%2,%3}, {%4,%5,%6,%7}, {%8,%9}, {%0,%1,%2,%3};"
                 : "+f"(c[0]), "+f"(c[1]), "+f"(c[2]), "+f"(c[3])
                 : "r"(a[0]), "r"(a[1]), "r"(a[2]), "r"(a[3]),
                   "r"(b[0]), "r"(b[1]));
}
__device__ __forceinline__ void mma1688tf(float* c, const uint32_t* a, const uint32_t* b) {
    asm volatile("mma.sync.aligned.m16n8k8.row.col.f32.tf32.tf32.f32 "
                 "{%0,%1,%2,%3}, {%4,%5,%6,%7}, {%8,%9}, {%0,%1,%2,%3};"
                 : "+f"(c[0]), "+f"(c[1]), "+f"(c[2]), "+f"(c[3])
                 : "r"(a[0]), "r"(a[1]), "r"(a[2]), "r"(a[3]),
                   "r"(b[0]), "r"(b[1]));
}
__device__ __forceinline__ void cpa16(uint32_t s, const void* g) {
    asm volatile("cp.async.cg.shared.global [%0], [%1], 16;\n" :: "r"(s), "l"(g));
}
__device__ __forceinline__ void cpcommit() { asm volatile("cp.async.commit_group;\n"); }
template<int N> __device__ __forceinline__ void cpwait() {
    asm volatile("cp.async.wait_group %0;\n" :: "n"(N));
}
__device__ __forceinline__ void split1(float x, bf16& h, bf16& l) {
    h = __float2bfloat16_rn(x);
    l = __float2bfloat16_rn(x - __bfloat162float(h));
}
__device__ __forceinline__ float to_tf32(float x) {
    uint32_t u;
    asm("cvt.rna.tf32.f32 %0, %1;" : "=r"(u) : "f"(x));
    return __uint_as_float(u);
}
__device__ __forceinline__ uint32_t pack2(bf16 a, bf16 b) {
    bf162 t{a, b};
    return *(uint32_t*)&t;
}

// ------------------------- utility kernels ---------------------------------
__global__ void copy_kernel(const float* __restrict__ in, float* __restrict__ out, int n)
{
    int i = (blockIdx.x * blockDim.x + threadIdx.x) * 4;
    if (i < n) *(float4*)(out + i) = *(const float4*)(in + i);
}

__global__ void split_kernel(const float* __restrict__ in,
                             bf16* __restrict__ hi, bf16* __restrict__ lo, int n)
{
    int i = (blockIdx.x * blockDim.x + threadIdx.x) * 8;
    if (i >= n) return;
    float4 a = *(const float4*)(in + i);
    float4 b = *(const float4*)(in + i + 4);
    bf16 h[8], l[8];
    split1(a.x,h[0],l[0]); split1(a.y,h[1],l[1]);
    split1(a.z,h[2],l[2]); split1(a.w,h[3],l[3]);
    split1(b.x,h[4],l[4]); split1(b.y,h[5],l[5]);
    split1(b.z,h[6],l[6]); split1(b.w,h[7],l[7]);
    *(uint4*)(hi + i) = *(const uint4*)h;
    *(uint4*)(lo + i) = *(const uint4*)l;
}

// sum two fp32 partials -> bf16 hi/lo
__global__ void add_split_kernel(const float* __restrict__ a, const float* __restrict__ b,
                                 bf16* __restrict__ hi, bf16* __restrict__ lo, int n)
{
    int i = (blockIdx.x * blockDim.x + threadIdx.x) * 4;
    if (i >= n) return;
    float4 va = *(const float4*)(a + i);
    float4 vb = *(const float4*)(b + i);
    va.x += vb.x; va.y += vb.y; va.z += vb.z; va.w += vb.w;
    bf16 h0,h1,h2,h3,l0,l1,l2,l3;
    split1(va.x,h0,l0); split1(va.y,h1,l1); split1(va.z,h2,l2); split1(va.w,h3,l3);
    uint2 ho{pack2(h0,h1), pack2(h2,h3)};
    uint2 lo2{pack2(l0,l1), pack2(l2,l3)};
    *(uint2*)(hi + i) = ho;
    *(uint2*)(lo + i) = lo2;
}

__global__ void round_tf32_kernel(const float* __restrict__ in,
                                  float* __restrict__ out, int n)
{
    int i = (blockIdx.x * blockDim.x + threadIdx.x) * 4;
    if (i >= n) return;
    float4 v = *(const float4*)(in + i);
    v.x = to_tf32(v.x); v.y = to_tf32(v.y);
    v.z = to_tf32(v.z); v.w = to_tf32(v.w);
    *(float4*)(out + i) = v;
}

__global__ void transpose_tf32_kernel(const float* __restrict__ in,
                                      float* __restrict__ out, int Kd, int Nd)
{
    __shared__ float t[32][33];
    const int n0 = blockIdx.x * 32, k0 = blockIdx.y * 32;
    const int tx = threadIdx.x, ty = threadIdx.y;
    #pragma unroll
    for (int i = 0; i < 4; i++)
        t[ty + 8*i][tx] = in[(size_t)(k0 + ty + 8*i) * Nd + n0 + tx];
    __syncthreads();
    #pragma unroll
    for (int i = 0; i < 4; i++)
        out[(size_t)(n0 + ty + 8*i) * Kd + k0 + tx] = to_tf32(t[tx][ty + 8*i]);
}

struct GPtrs { const bf16 *Bh, *Bl; const float* bias; float* C; bf16 *Ch, *Cl; };

// ------------------------- BN=64 bf16-split GEMM ---------------------------
// MODE: 0 normal; 1 causal block-skip (TRANSB=1); 2 K bounded at m0+128;
//       3 split-K=2 over z; 4 K bounded at m0+128 AND split-K=2 over z.
template<int TRANSB, int MODE>
__global__ void __launch_bounds__(256, 2)
gemm_bf16(const bf16* __restrict__ Ah, const bf16* __restrict__ Al,
          GPtrs p0, GPtrs p1, GPtrs p2, int M, int N, int K, float alpha)
{
    constexpr int BM = 128, BN = 64, BK = 32, ST = 3;
    constexpr int ASTR   = 40;
    constexpr int A_PART = BM * ASTR;
    constexpr int BROWS  = TRANSB ? BN : BK;
    constexpr int BSTR   = TRANSB ? 40 : (BN + 8);
    constexpr int B_PART = BROWS * BSTR;
    constexpr int STAGE  = 2*A_PART + 2*B_PART;
    constexpr int MT = 2;
    constexpr int NT = 4;

    extern __shared__ bf16 smem[];

    const int m0 = blockIdx.y * BM;
    const int n0 = blockIdx.x * BN;
    if (MODE == 1 && n0 >= m0 + BM) return;

    GPtrs P = (blockIdx.z == 0) ? p0 : ((blockIdx.z == 1) ? p1 : p2);

    int Keff = K, kOff = 0;
    if (MODE == 2) Keff = min(K, m0 + BM);
    if (MODE == 3) { Keff = K >> 1; kOff = blockIdx.z * Keff; }
    if (MODE == 4) { int kt = min(K, m0 + BM); Keff = kt >> 1; kOff = blockIdx.z * Keff; }
    const int T = Keff / BK;

    const int tid  = threadIdx.x;
    const int lane = tid & 31;
    const int warp = tid >> 5;
    const int wm = warp & 3;
    const int wn = warp >> 2;
    const int l7 = lane & 7, q1 = (lane >> 3) & 1, q2 = lane >> 4;

    auto load_tile = [&](int t, int s) {
        const int k0 = kOff + t * BK;
        bf16* sb = smem + s * STAGE;
        #pragma unroll
        for (int i = 0; i < 4; i++) {
            int f = tid + 256 * i;
            int part = f >> 9;
            int r = (f >> 2) & 127;
            int c = f & 3;
            const bf16* gp = (part ? Al : Ah) + (size_t)(m0 + r) * K + k0 + c * 8;
            cpa16((uint32_t)__cvta_generic_to_shared(sb + part*A_PART + r*ASTR + c*8), gp);
        }
        if (TRANSB) {
            constexpr int CB = BN * 4;
            #pragma unroll
            for (int i = 0; i < (2 * CB) / 256; i++) {
                int f = tid + 256 * i;
                int part = f / CB, rem = f % CB;
                int r = rem >> 2, c = rem & 3;
                const bf16* gp = (part ? P.Bl : P.Bh) + (size_t)(n0 + r) * K + k0 + c * 8;
                cpa16((uint32_t)__cvta_generic_to_shared(sb + 2*A_PART + part*B_PART + r*BSTR + c*8), gp);
            }
        } else {
            constexpr int CR = BN / 8;
            constexpr int CB = 32 * CR;
            #pragma unroll
            for (int i = 0; i < (2 * CB) / 256; i++) {
                int f = tid + 256 * i;
                int part = f / CB, rem = f % CB;
                int r = rem / CR, c = rem % CR;
                const bf16* gp = (part ? P.Bl : P.Bh) + (size_t)(k0 + r) * N + n0 + c * 8;
                cpa16((uint32_t)__cvta_generic_to_shared(sb + 2*A_PART + part*B_PART + r*BSTR + c*8), gp);
            }
        }
    };

    float acc[MT][NT][4];
    #pragma unroll
    for (int mt = 0; mt < MT; mt++)
        #pragma unroll
        for (int nt = 0; nt < NT; nt++)
            #pragma unroll
            for (int i = 0; i < 4; i++) acc[mt][nt][i] = 0.f;

    const uint32_t smemBase = (uint32_t)__cvta_generic_to_shared(smem);
    const uint32_t aoff = (uint32_t)(((wm*MT*16 + l7 + q1*8) * ASTR + q2*8) * 2);
    uint32_t boff;
    if (TRANSB) boff = (uint32_t)((2*A_PART + (wn*32 + l7 + q2*8) * BSTR + q1*8) * 2);
    else        boff = (uint32_t)((2*A_PART + (l7 + q1*8) * BSTR + wn*32 + q2*8) * 2);

    load_tile(0, 0); cpcommit();
    if (T > 1) load_tile(1, 1);
    cpcommit();

    for (int t = 0; t < T; t++) {
        cpwait<1>();
        __syncthreads();
        if (t + 2 < T) { load_tile(t + 2, (t + 2) % ST); }
        cpcommit();

        const uint32_t sbase = smemBase + (uint32_t)((t % ST) * STAGE * 2);

        #pragma unroll
        for (int ks = 0; ks < 2; ks++) {
            uint32_t a[MT][4], bh[NT][2], bl[NT][2];
            #pragma unroll
            for (int mt = 0; mt < MT; mt++)
                ldsm4(a[mt], sbase + aoff + (uint32_t)(mt*16*ASTR*2 + ks*32));
            #pragma unroll
            for (int pp = 0; pp < 2; pp++) {
                uint32_t off = TRANSB ? (uint32_t)(pp*16*BSTR*2 + ks*32)
                                      : (uint32_t)(ks*16*BSTR*2 + pp*32);
                uint32_t r4[4];
                if (TRANSB) ldsm4 (r4, sbase + boff + off);
                else        ldsm4t(r4, sbase + boff + off);
                bh[2*pp][0]   = r4[0]; bh[2*pp][1]   = r4[1];
                bh[2*pp+1][0] = r4[2]; bh[2*pp+1][1] = r4[3];
                if (TRANSB) ldsm4 (r4, sbase + boff + (uint32_t)(B_PART*2) + off);
                else        ldsm4t(r4, sbase + boff + (uint32_t)(B_PART*2) + off);
                bl[2*pp][0]   = r4[0]; bl[2*pp][1]   = r4[1];
                bl[2*pp+1][0] = r4[2]; bl[2*pp+1][1] = r4[3];
            }
            #pragma unroll
            for (int nt = 0; nt < NT; nt++)
                #pragma unroll
                for (int mt = 0; mt < MT; mt++)
                    mma16816(acc[mt][nt], a[mt], bh[nt]);
            #pragma unroll
            for (int nt = 0; nt < NT; nt++)
                #pragma unroll
                for (int mt = 0; mt < MT; mt++)
                    mma16816(acc[mt][nt], a[mt], bl[nt]);
            #pragma unroll
            for (int mt = 0; mt < MT; mt++)
                ldsm4(a[mt], sbase + aoff + (uint32_t)(A_PART*2 + mt*16*ASTR*2 + ks*32));
            #pragma unroll
            for (int nt = 0; nt < NT; nt++)
                #pragma unroll
                for (int mt = 0; mt < MT; mt++)
                    mma16816(acc[mt][nt], a[mt], bh[nt]);
        }
    }

    #pragma unroll
    for (int mt = 0; mt < MT; mt++) {
        int row0 = m0 + wm*MT*16 + mt*16 + (lane >> 2);
        #pragma unroll
        for (int nt = 0; nt < NT; nt++) {
            int col = n0 + wn*32 + nt*8 + ((lane & 3) << 1);
            float b0 = 0.f, b1 = 0.f;
            if (P.bias) { b0 = P.bias[col]; b1 = P.bias[col + 1]; }
            float c00 = acc[mt][nt][0] * alpha + b0;
            float c01 = acc[mt][nt][1] * alpha + b1;
            float c10 = acc[mt][nt][2] * alpha + b0;
            float c11 = acc[mt][nt][3] * alpha + b1;
            if (P.C) {
                *(float2*)(P.C + (size_t)row0 * N + col)       = float2{c00, c01};
                *(float2*)(P.C + (size_t)(row0 + 8) * N + col) = float2{c10, c11};
            }
            if (P.Ch) {
                bf16 h0,l0,h1,l1;
                split1(c00,h0,l0); split1(c01,h1,l1);
                *(bf162*)(P.Ch + (size_t)row0 * N + col) = bf162{h0,h1};
                *(bf162*)(P.Cl + (size_t)row0 * N + col) = bf162{l0,l1};
                split1(c10,h0,l0); split1(c11,h1,l1);
                *(bf162*)(P.Ch + (size_t)(row0 + 8) * N + col) = bf162{h0,h1};
                *(bf162*)(P.Cl + (size_t)(row0 + 8) * N + col) = bf162{l0,l1};
            }
        }
    }
}

// ------------------------- wide bf16 GEMM (W1) ------------------------------
__global__ void __launch_bounds__(256, 2)
gemm_bf16w(const bf16* __restrict__ Ah, const bf16* __restrict__ Al,
           GPtrs P, int M, int N, int K)
{
    constexpr int BM = 128, BN = 128, BK = 32, ST = 3;
    constexpr int ASTR   = 40;
    constexpr int A_PART = BM * ASTR;
    constexpr int BSTR   = BN + 8;
    constexpr int B_PART = BK * BSTR;
    constexpr int STAGE  = 2*A_PART + 2*B_PART;
    constexpr int MT = 2;
    constexpr int NT = 8;

    extern __shared__ bf16 smem[];

    const int m0 = blockIdx.x * BM;
    const int n0 = blockIdx.y * BN;
    const int T = K / BK;

    const int tid  = threadIdx.x;
    const int lane = tid & 31;
    const int warp = tid >> 5;
    const int wm = warp & 3;
    const int wn = warp >> 2;
    const int l7 = lane & 7, q1 = (lane >> 3) & 1, q2 = lane >> 4;

    auto load_tile = [&](int t, int s) {
        const int k0 = t * BK;
        bf16* sb = smem + s * STAGE;
        #pragma unroll
        for (int i = 0; i < 4; i++) {
            int f = tid + 256 * i;
            int part = f >> 9;
            int r = (f >> 2) & 127;
            int c = f & 3;
            const bf16* gp = (part ? Al : Ah) + (size_t)(m0 + r) * K + k0 + c * 8;
            cpa16((uint32_t)__cvta_generic_to_shared(sb + part*A_PART + r*ASTR + c*8), gp);
        }
        #pragma unroll
        for (int i = 0; i < 4; i++) {
            int f = tid + 256 * i;
            int part = f >> 9;
            int rem  = f & 511;
            int r = rem >> 4;
            int c = rem & 15;
            const bf16* gp = (part ? P.Bl : P.Bh) + (size_t)(k0 + r) * N + n0 + c * 8;
            cpa16((uint32_t)__cvta_generic_to_shared(sb + 2*A_PART + part*B_PART + r*BSTR + c*8), gp);
        }
    };

    float acc[MT][NT][4];
    #pragma unroll
    for (int mt = 0; mt < MT; mt++)
        #pragma unroll
        for (int nt = 0; nt < NT; nt++)
            #pragma unroll
            for (int i = 0; i < 4; i++) acc[mt][nt][i] = 0.f;

    const uint32_t smemBase = (uint32_t)__cvta_generic_to_shared(smem);
    const uint32_t aoff = (uint32_t)(((wm*MT*16 + l7 + q1*8) * ASTR + q2*8) * 2);
    const uint32_t boff = (uint32_t)((2*A_PART + (l7 + q1*8) * BSTR + wn*64 + q2*8) * 2);

    load_tile(0, 0); cpcommit();
    if (T > 1) load_tile(1, 1);
    cpcommit();

    for (int t = 0; t < T; t++) {
        cpwait<1>();
        __syncthreads();
        if (t + 2 < T) { load_tile(t + 2, (t + 2) % ST); }
        cpcommit();

        const uint32_t sbase = smemBase + (uint32_t)((t % ST) * STAGE * 2);

        #pragma unroll
        for (int ks = 0; ks < 2; ks++) {
            uint32_t a[MT][4], bh[NT][2];
            #pragma unroll
            for (int mt = 0; mt < MT; mt++)
                ldsm4(a[mt], sbase + aoff + (uint32_t)(mt*16*ASTR*2 + ks*32));
            #pragma unroll
            for (int pp = 0; pp < 4; pp++) {
                uint32_t r4[4];
                ldsm4t(r4, sbase + boff + (uint32_t)(ks*16*BSTR*2 + pp*32));
                bh[2*pp][0]   = r4[0]; bh[2*pp][1]   = r4[1];
                bh[2*pp+1][0] = r4[2]; bh[2*pp+1][1] = r4[3];
            }
            #pragma unroll
            for (int nt = 0; nt < NT; nt++)
                #pragma unroll
                for (int mt = 0; mt < MT; mt++)
                    mma16816(acc[mt][nt], a[mt], bh[nt]);
            #pragma unroll
            for (int ch = 0; ch < 2; ch++) {
                uint32_t bl[4][2];
                #pragma unroll
                for (int pp = 0; pp < 2; pp++) {
                    uint32_t r4[4];
                    ldsm4t(r4, sbase + boff + (uint32_t)(B_PART*2 + ks*16*BSTR*2 + (ch*2+pp)*32));
                    bl[2*pp][0]   = r4[0]; bl[2*pp][1]   = r4[1];
                    bl[2*pp+1][0] = r4[2]; bl[2*pp+1][1] = r4[3];
                }
                #pragma unroll
                for (int j = 0; j < 4; j++)
                    #pragma unroll
                    for (int mt = 0; mt < MT; mt++)
                        mma16816(acc[mt][ch*4 + j], a[mt], bl[j]);
            }
            #pragma unroll
            for (int mt = 0; mt < MT; mt++)
                ldsm4(a[mt], sbase + aoff + (uint32_t)(A_PART*2 + mt*16*ASTR*2 + ks*32));
            #pragma unroll
            for (int nt = 0; nt < NT; nt++)
                #pragma unroll
                for (int mt = 0; mt < MT; mt++)
                    mma16816(acc[mt][nt], a[mt], bh[nt]);
        }
    }

    #pragma unroll
    for (int mt = 0; mt < MT; mt++) {
        int row0 = m0 + wm*MT*16 + mt*16 + (lane >> 2);
        #pragma unroll
        for (int nt = 0; nt < NT; nt++) {
            int col = n0 + wn*64 + nt*8 + ((lane & 3) << 1);
            float b0 = 0.f, b1 = 0.f;
            if (P.bias) { b0 = P.bias[col]; b1 = P.bias[col + 1]; }
            float c00 = acc[mt][nt][0] + b0;
            float c01 = acc[mt][nt][1] + b1;
            float c10 = acc[mt][nt][2] + b0;
            float c11 = acc[mt][nt][3] + b1;
            if (P.C) {
                *(float2*)(P.C + (size_t)row0 * N + col)       = float2{c00, c01};
                *(float2*)(P.C + (size_t)(row0 + 8) * N + col) = float2{c10, c11};
            }
            if (P.Ch) {
                bf16 h0,l0,h1,l1;
                split1(c00,h0,l0); split1(c01,h1,l1);
                *(bf162*)(P.Ch + (size_t)row0 * N + col) = bf162{h0,h1};
                *(bf162*)(P.Cl + (size_t)row0 * N + col) = bf162{l0,l1};
                split1(c10,h0,l0); split1(c11,h1,l1);
                *(bf162*)(P.Ch + (size_t)(row0 + 8) * N + col) = bf162{h0,h1};
                *(bf162*)(P.Cl + (size_t)(row0 + 8) * N + col) = bf162{l0,l1};
            }
        }
    }
}

// ------------------------- tf32 wide GEMM (logits) --------------------------
__global__ void __launch_bounds__(256, 2)
gemm_tf32w(const float* __restrict__ A, const float* __restrict__ B,
           const float* __restrict__ bias, float* __restrict__ C,
           float* __restrict__ smax, float* __restrict__ ssum,
           int M, int N, int K)
{
    constexpr int BM = 128, BN = 128, BK = 32, ST = 3;
    constexpr int ASTRf = 36;
    constexpr int A_PARTf = BM * ASTRf;
    constexpr int BSTRf = 36;
    constexpr int B_PARTf = BN * BSTRf;
    constexpr int STAGEf = A_PARTf + B_PARTf;
    constexpr int MT = 2;
    constexpr int NT = 8;

    extern __shared__ float fsmem[];

    const int m0 = blockIdx.x * BM;
    const int n0 = blockIdx.y * BN;
    const int T = K / BK;

    const int tid  = threadIdx.x;
    const int lane = tid & 31;
    const int warp = tid >> 5;
    const int wm = warp & 3;
    const int wn = warp >> 2;
    const int l7 = lane & 7, q1 = (lane >> 3) & 1, q2 = lane >> 4;

    auto load_tile = [&](int t, int s) {
        const int k0 = t * BK;
        float* sb = fsmem + s * STAGEf;
        #pragma unroll
        for (int i = 0; i < 4; i++) {
            int f = tid + 256 * i;
            int r = f >> 3;
            int c = f & 7;
            cpa16((uint32_t)__cvta_generic_to_shared(sb + r*ASTRf + c*4),
                  A + (size_t)(m0 + r) * K + k0 + c*4);
        }
        #pragma unroll
        for (int i = 0; i < 4; i++) {
            int f = tid + 256 * i;
            int r = f >> 3;
            int c = f & 7;
            cpa16((uint32_t)__cvta_generic_to_shared(sb + A_PARTf + r*BSTRf + c*4),
                  B + (size_t)(n0 + r) * K + k0 + c*4);
        }
    };

    float acc[MT][NT][4];
    #pragma unroll
    for (int mt = 0; mt < MT; mt++)
        #pragma unroll
        for (int nt = 0; nt < NT; nt++)
            #pragma unroll
            for (int i = 0; i < 4; i++) acc[mt][nt][i] = 0.f;

    const uint32_t smemBase = (uint32_t)__cvta_generic_to_shared(fsmem);
    const uint32_t aoff = (uint32_t)(((wm*MT*16 + l7 + q1*8) * ASTRf + q2*4) * 4);
    const uint32_t boff = (uint32_t)((A_PARTf + (wn*64 + l7 + q2*8) * BSTRf + q1*4) * 4);

    load_tile(0, 0); cpcommit();
    if (T > 1) load_tile(1, 1);
    cpcommit();

    for (int t = 0; t < T; t++) {
        cpwait<1>();
        __syncthreads();
        if (t + 2 < T) { load_tile(t + 2, (t + 2) % ST); }
        cpcommit();

        const uint32_t sbase = smemBase + (uint32_t)((t % ST) * STAGEf * 4);

        #pragma unroll
        for (int k8 = 0; k8 < 4; k8++) {
            uint32_t a[MT][4];
            #pragma unroll
            for (int mt = 0; mt < MT; mt++)
                ldsm4(a[mt], sbase + aoff + (uint32_t)(mt*16*ASTRf*4 + k8*32));
            #pragma unroll
            for (int p = 0; p < NT/2; p++) {
                uint32_t r4[4];
                ldsm4(r4, sbase + boff + (uint32_t)(p*16*BSTRf*4 + k8*32));
                uint32_t b0[2] = {r4[0], r4[1]};
                uint32_t b1[2] = {r4[2], r4[3]};
                #pragma unroll
                for (int mt = 0; mt < MT; mt++) {
                    mma1688tf(acc[mt][2*p],   a[mt], b0);
                    mma1688tf(acc[mt][2*p+1], a[mt], b1);
                }
            }
        }
    }

    #pragma unroll
    for (int mt = 0; mt < MT; mt++)
        #pragma unroll
        for (int nt = 0; nt < NT; nt++) {
            int col = n0 + wn*64 + nt*8 + ((lane & 3) << 1);
            float b0 = 0.f, b1 = 0.f;
            if (bias) { b0 = bias[col]; b1 = bias[col + 1]; }
            acc[mt][nt][0] += b0; acc[mt][nt][1] += b1;
            acc[mt][nt][2] += b0; acc[mt][nt][3] += b1;
        }

    #pragma unroll
    for (int mt = 0; mt < MT; mt++) {
        int row0 = m0 + wm*MT*16 + mt*16 + (lane >> 2);
        #pragma unroll
        for (int nt = 0; nt < NT; nt++) {
            int col = n0 + wn*64 + nt*8 + ((lane & 3) << 1);
            *(float2*)(C + (size_t)row0 * N + col)       = float2{acc[mt][nt][0], acc[mt][nt][1]};
            *(float2*)(C + (size_t)(row0 + 8) * N + col) = float2{acc[mt][nt][2], acc[mt][nt][3]};
        }
    }

    if (smax) {
        __syncthreads();
        float* sm_m = fsmem;
        float* sm_s = fsmem + 256;
        #pragma unroll
        for (int mt = 0; mt < MT; mt++) {
            float mA = -1e30f, mB = -1e30f;
            #pragma unroll
            for (int nt = 0; nt < NT; nt++) {
                mA = fmaxf(mA, fmaxf(acc[mt][nt][0], acc[mt][nt][1]));
                mB = fmaxf(mB, fmaxf(acc[mt][nt][2], acc[mt][nt][3]));
            }
            mA = fmaxf(mA, __shfl_xor_sync(0xffffffffu, mA, 1));
            mA = fmaxf(mA, __shfl_xor_sync(0xffffffffu, mA, 2));
            mB = fmaxf(mB, __shfl_xor_sync(0xffffffffu, mB, 1));
            mB = fmaxf(mB, __shfl_xor_sync(0xffffffffu, mB, 2));
            float sA = 0.f, sB = 0.f;
            #pragma unroll
            for (int nt = 0; nt < NT; nt++) {
                sA += __expf(acc[mt][nt][0] - mA) + __expf(acc[mt][nt][1] - mA);
                sB += __expf(acc[mt][nt][2] - mB) + __expf(acc[mt][nt][3] - mB);
            }
            sA += __shfl_xor_sync(0xffffffffu, sA, 1);
            sA += __shfl_xor_sync(0xffffffffu, sA, 2);
            sB += __shfl_xor_sync(0xffffffffu, sB, 1);
            sB += __shfl_xor_sync(0xffffffffu, sB, 2);
            if ((lane & 3) == 0) {
                int r = wm*32 + mt*16 + (lane >> 2);
                sm_m[r*2 + wn]     = mA;  sm_s[r*2 + wn]     = sA;
                sm_m[(r+8)*2 + wn] = mB;  sm_s[(r+8)*2 + wn] = sB;
            }
        }
        __syncthreads();
        if (tid < 128) {
            float m1 = sm_m[tid*2], m2 = sm_m[tid*2 + 1];
            float Mx = fmaxf(m1, m2);
            float S  = sm_s[tid*2] * __expf(m1 - Mx) + sm_s[tid*2 + 1] * __expf(m2 - Mx);
            int nb = N >> 7;
            smax[(size_t)(m0 + tid) * nb + (n0 >> 7)] = Mx;
            ssum[(size_t)(m0 + tid) * nb + (n0 >> 7)] = S;
        }
    }
}

// ------------------------- warp-per-row causal softmax ---------------------
// 8 warps/CTA, warp w handles row blockIdx.x*8 + w.  No __syncthreads.
__global__ void __launch_bounds__(256)
softmax_causal_warp(const float* __restrict__ att,
                    bf16* __restrict__ oh, bf16* __restrict__ ol)
{
    const int warp = threadIdx.x >> 5;
    const int lane = threadIdx.x & 31;
    const int r = blockIdx.x * 8 + warp;
    const float* row = att + (size_t)r * SQ;
    bf16* rh = oh + (size_t)r * SQ;
    bf16* rl = ol + (size_t)r * SQ;
    const int n = r + 1;
    const int fillEnd = ((r >> 7) + 1) << 7;    // multiple of 128

    // pass 1: masked max
    float m = -1e30f;
    for (int j = lane * 4; j < fillEnd; j += 128) {
        float4 v = *(const float4*)(row + j);
        if (j + 0 < n) m = fmaxf(m, v.x);
        if (j + 1 < n) m = fmaxf(m, v.y);
        if (j + 2 < n) m = fmaxf(m, v.z);
        if (j + 3 < n) m = fmaxf(m, v.w);
    }
    #pragma unroll
    for (int st = 16; st > 0; st >>= 1)
        m = fmaxf(m, __shfl_xor_sync(0xffffffffu, m, st));

    // pass 2: masked sum of exp (L1 hit)
    float s = 0.f;
    for (int j = lane * 4; j < fillEnd; j += 128) {
        float4 v = *(const float4*)(row + j);
        if (j + 0 < n) s += __expf(v.x - m);
        if (j + 1 < n) s += __expf(v.y - m);
        if (j + 2 < n) s += __expf(v.z - m);
        if (j + 3 < n) s += __expf(v.w - m);
    }
    #pragma unroll
    for (int st = 16; st > 0; st >>= 1)
        s += __shfl_xor_sync(0xffffffffu, s, st);
    const float inv = 1.f / s;

    // pass 3: write bf16 hi/lo (masked elems -> 0)
    for (int j = lane * 4; j < fillEnd; j += 128) {
        float4 v = *(const float4*)(row + j);
        float e0 = (j + 0 < n) ? __expf(v.x - m) * inv : 0.f;
        float e1 = (j + 1 < n) ? __expf(v.y - m) * inv : 0.f;
        float e2 = (j + 2 < n) ? __expf(v.z - m) * inv : 0.f;
        float e3 = (j + 3 < n) ? __expf(v.w - m) * inv : 0.f;
        bf16 h0,l0,h1,l1,h2,l2,h3,l3;
        split1(e0,h0,l0); split1(e1,h1,l1); split1(e2,h2,l2); split1(e3,h3,l3);
        *(uint2*)(rh + j) = uint2{pack2(h0,h1), pack2(h2,h3)};
        *(uint2*)(rl + j) = uint2{pack2(l0,l1), pack2(l2,l3)};
    }
}

// ------------------------- warp-per-row add+LN ------------------------------
// 8 warps/CTA; row of 512; 16 values per lane in registers.
__global__ void __launch_bounds__(256)
add_ln_warp(const float* __restrict__ a,
            const float* __restrict__ a2,
            const float* __restrict__ res,
            const float* __restrict__ g,
            const float* __restrict__ beta,
            float* __restrict__ out,
            bf16* __restrict__ oh, bf16* __restrict__ ol)
{
    const int warp = threadIdx.x >> 5;
    const int lane = threadIdx.x & 31;
    const int r = blockIdx.x * 8 + warp;
    const size_t base = (size_t)r * DM;

    float v[16];
    float sum = 0.f;
    #pragma unroll
    for (int k = 0; k < 4; k++) {
        int j = lane * 4 + k * 128;
        float4 va = *(const float4*)(a + base + j);
        float4 vr = *(const float4*)(res + base + j);
        va.x += vr.x; va.y += vr.y; va.z += vr.z; va.w += vr.w;
        if (a2) {
            float4 vb = *(const float4*)(a2 + base + j);
            va.x += vb.x; va.y += vb.y; va.z += vb.z; va.w += vb.w;
        }
        v[k*4+0] = va.x; v[k*4+1] = va.y; v[k*4+2] = va.z; v[k*4+3] = va.w;
        sum += va.x + va.y + va.z + va.w;
    }
    #pragma unroll
    for (int st = 16; st > 0; st >>= 1)
        sum += __shfl_xor_sync(0xffffffffu, sum, st);
    const float mu = sum * (1.0f / DM);

    float var = 0.f;
    #pragma unroll
    for (int k = 0; k < 16; k++) {
        float d = v[k] - mu;
        v[k] = d;
        var += d * d;
    }
    #pragma unroll
    for (int st = 16; st > 0; st >>= 1)
        var += __shfl_xor_sync(0xffffffffu, var, st);
    const float rstd = rsqrtf(var * (1.0f / DM) + LN_EPS);

    #pragma unroll
    for (int k = 0; k < 4; k++) {
        int j = lane * 4 + k * 128;
        float4 vg = *(const float4*)(g + j);
        float4 vb = *(const float4*)(beta + j);
        float o0 = v[k*4+0] * rstd * vg.x + vb.x;
        float o1 = v[k*4+1] * rstd * vg.y + vb.y;
        float o2 = v[k*4+2] * rstd * vg.z + vb.z;
        float o3 = v[k*4+3] * rstd * vg.w + vb.w;
        *(float4*)(out + base + j) = float4{o0, o1, o2, o3};
        bf16 h0,l0,h1,l1,h2,l2,h3,l3;
        split1(o0,h0,l0); split1(o1,h1,l1); split1(o2,h2,l2); split1(o3,h3,l3);
        *(uint2*)(oh + base + j) = uint2{pack2(h0,h1), pack2(h2,h3)};
        *(uint2*)(ol + base + j) = uint2{pack2(l0,l1), pack2(l2,l3)};
    }
}

// ------------------------- vocab softmax via GEMM partials -----------------
__global__ void softmax_vocab_kernel(float* __restrict__ x,
                                     const float* __restrict__ smax,
                                     const float* __restrict__ ssum)
{
    const int i = blockIdx.x;
    float* row = x + (size_t)i * VOC;
    const int tid = threadIdx.x;

    __shared__ float mRed[256];
    __shared__ float sRed[256];

    float m = -1e30f, s = 0.f;
    if (tid < NBV) {
        m = smax[(size_t)i * NBV + tid];
        s = ssum[(size_t)i * NBV + tid];
    }
    mRed[tid] = m; sRed[tid] = s; __syncthreads();
    for (int st = 128; st > 0; st >>= 1) {
        if (tid < st) {
            float m1 = mRed[tid], m2 = mRed[tid + st];
            float Mx = fmaxf(m1, m2);
            sRed[tid] = sRed[tid] * __expf(m1 - Mx) + sRed[tid + st] * __expf(m2 - Mx);
            mRed[tid] = Mx;
        }
        __syncthreads();
    }
    const float M = mRed[0];
    const float inv = 1.f / sRed[0];

    for (int j = tid * 4; j < VOC; j += 1024) {
        float4 v = *(const float4*)(row + j);
        v.x = __expf(v.x - M) * inv;
        v.y = __expf(v.y - M) * inv;
        v.z = __expf(v.z - M) * inv;
        v.w = __expf(v.w - M) * inv;
        *(float4*)(row + j) = v;
    }
}

// ------------------------- host side ---------------------------------------
#define SMEM_NN 89088
#define SMEM_NT 92160
#define SMEM_W  113664
#define SMEM_TF 110592

static inline void do_split(const float* in, bf16* hi, bf16* lo, int n) {
    split_kernel<<<n / 2048, 256>>>(in, hi, lo, n);
}

extern "C" void kernel_launch(void* const* d_in, const int* in_sizes, int n_in,
                              void* d_out, int out_size)
{
    const float* x   = (const float*)d_in[0];
    const float* Wq  = (const float*)d_in[1];
    const float* bq  = (const float*)d_in[2];
    const float* Wk  = (const float*)d_in[3];
    const float* bk  = (const float*)d_in[4];
    const float* Wv  = (const float*)d_in[5];
    const float* bv  = (const float*)d_in[6];
    const float* Wp  = (const float*)d_in[7];
    const float* bp  = (const float*)d_in[8];
    const float* g1  = (const float*)d_in[9];
    const float* be1 = (const float*)d_in[10];
    const float* W1  = (const float*)d_in[11];
    const float* b1  = (const float*)d_in[12];
    const float* W2  = (const float*)d_in[13];
    const float* b2  = (const float*)d_in[14];
    const float* g2  = (const float*)d_in[15];
    const float* be2 = (const float*)d_in[16];
    const float* Wf  = (const float*)d_in[17];
    const float* bf  = (const float*)d_in[18];
    float* out = (float*)d_out;

    cudaFuncSetAttribute(gemm_bf16<0,0>, cudaFuncAttributeMaxDynamicSharedMemorySize, SMEM_NN);
    cudaFuncSetAttribute(gemm_bf16<0,3>, cudaFuncAttributeMaxDynamicSharedMemorySize, SMEM_NN);
    cudaFuncSetAttribute(gemm_bf16<0,4>, cudaFuncAttributeMaxDynamicSharedMemorySize, SMEM_NN);
    cudaFuncSetAttribute(gemm_bf16<1,1>, cudaFuncAttributeMaxDynamicSharedMemorySize, SMEM_NT);
    cudaFuncSetAttribute(gemm_bf16w,     cudaFuncAttributeMaxDynamicSharedMemorySize, SMEM_W);
    cudaFuncSetAttribute(gemm_tf32w,     cudaFuncAttributeMaxDynamicSharedMemorySize, SMEM_TF);

    float *px, *pxt, *px2, *patt, *pz, *pz2, *ph2, *ph2b, *psmax, *pssum, *pwft;
    cudaGetSymbolAddress((void**)&px,    g_x);
    cudaGetSymbolAddress((void**)&pxt,   g_xt);
    cudaGetSymbolAddress((void**)&px2,   g_x2);
    cudaGetSymbolAddress((void**)&patt,  g_att);
    cudaGetSymbolAddress((void**)&pz,    g_z);
    cudaGetSymbolAddress((void**)&pz2,   g_z2);
    cudaGetSymbolAddress((void**)&ph2,   g_h2);
    cudaGetSymbolAddress((void**)&ph2b,  g_h2b);
    cudaGetSymbolAddress((void**)&psmax, g_smax);
    cudaGetSymbolAddress((void**)&pssum, g_ssum);
    cudaGetSymbolAddress((void**)&pwft,  g_wft);

    bf16 *xh,*xl,*x2h,*x2l,*qh,*ql,*kh,*kl,*vh,*vl,*ath,*atl,*th,*tl,*hh,*hl;
    cudaGetSymbolAddress((void**)&xh,  g_xh);  cudaGetSymbolAddress((void**)&xl,  g_xl);
    cudaGetSymbolAddress((void**)&x2h, g_x2h); cudaGetSymbolAddress((void**)&x2l, g_x2l);
    cudaGetSymbolAddress((void**)&qh,  g_qh);  cudaGetSymbolAddress((void**)&ql,  g_ql);
    cudaGetSymbolAddress((void**)&kh,  g_kh);  cudaGetSymbolAddress((void**)&kl,  g_kl);
    cudaGetSymbolAddress((void**)&vh,  g_vh);  cudaGetSymbolAddress((void**)&vl,  g_vl);
    cudaGetSymbolAddress((void**)&ath, g_ath); cudaGetSymbolAddress((void**)&atl, g_atl);
    cudaGetSymbolAddress((void**)&th,  g_th);  cudaGetSymbolAddress((void**)&tl,  g_tl);
    cudaGetSymbolAddress((void**)&hh,  g_hh);  cudaGetSymbolAddress((void**)&hl,  g_hl);

    bf16 *wqh,*wql,*wkh,*wkl,*wvh,*wvl,*wph,*wpl,*w1h,*w1l,*w2h,*w2l;
    cudaGetSymbolAddress((void**)&wqh, g_wqh); cudaGetSymbolAddress((void**)&wql, g_wql);
    cudaGetSymbolAddress((void**)&wkh, g_wkh); cudaGetSymbolAddress((void**)&wkl, g_wkl);
    cudaGetSymbolAddress((void**)&wvh, g_wvh); cudaGetSymbolAddress((void**)&wvl, g_wvl);
    cudaGetSymbolAddress((void**)&wph, g_wph); cudaGetSymbolAddress((void**)&wpl, g_wpl);
    cudaGetSymbolAddress((void**)&w1h, g_w1h); cudaGetSymbolAddress((void**)&w1l, g_w1l);
    cudaGetSymbolAddress((void**)&w2h, g_w2h); cudaGetSymbolAddress((void**)&w2l, g_w2l);

    const float scale = 1.0f / sqrtf((float)FF);

    // preprocessing (launches 0-3), then GEMMs land at slots 4/5
    do_split(x,  xh,  xl,  SQ*DM);
    do_split(Wq, wqh, wql, NL*DM*FF);
    do_split(Wk, wkh, wkl, NL*DM*FF);
    do_split(Wv, wvh, wvl, NL*DM*FF);

    bool firstLayer = true;
    for (int l = 0; l < NL; l++) {
        size_t wOff  = (size_t)l * DM * FF;
        size_t w1Off = (size_t)l * FF * HID;
        size_t w2Off = (size_t)l * HID * DM;

        // QKV (batched over z)  -- launch 4 on layer 0
        {
            GPtrs pQ{wqh + wOff, wql + wOff, bq + (size_t)l*FF, nullptr, qh, ql};
            GPtrs pK{wkh + wOff, wkl + wOff, bk + (size_t)l*FF, nullptr, kh, kl};
            GPtrs pV{wvh + wOff, wvl + wOff, bv + (size_t)l*FF, nullptr, vh, vl};
            gemm_bf16<0,0><<<dim3(FF/64, SQ/128, 3), 256, SMEM_NN>>>(xh, xl, pQ, pK, pV, SQ, FF, DM, 1.f);
        }
        // scores = q @ k^T * scale (causal block skip)  -- launch 5 on layer 0
        {
            GPtrs p{kh, kl, nullptr, patt, nullptr, nullptr};
            gemm_bf16<1,1><<<dim3(SQ/64, SQ/128, 1), 256, SMEM_NT>>>(qh, ql, p, p, p, SQ, SQ, FF, scale);
        }
        if (firstLayer) {   // deferred preprocessing (only needed later in the layer)
            copy_kernel<<<(SQ*DM)/1024, 256>>>(x, px, SQ*DM);
            do_split(Wp, wph, wpl, NL*FF*FF);
            do_split(W1, w1h, w1l, NL*FF*HID);
            do_split(W2, w2h, w2l, NL*HID*DM);
            transpose_tf32_kernel<<<dim3(VOC/32, DM/32), dim3(32,8)>>>(Wf, pwft, DM, VOC);
            firstLayer = false;
        }
        softmax_causal_warp<<<SQ/8, 256>>>(patt, ath, atl);
        // t = att @ v  (K bounded + split-K=2 -> pz, pz2 partials)
        {
            GPtrs pA{vh, vl, nullptr, pz,  nullptr, nullptr};
            GPtrs pB{vh, vl, nullptr, pz2, nullptr, nullptr};
            gemm_bf16<0,4><<<dim3(FF/64, SQ/128, 2), 256, SMEM_NN>>>(ath, atl, pA, pB, pB, SQ, FF, SQ, 1.f);
        }
        add_split_kernel<<<(SQ*FF)/1024, 256>>>(pz, pz2, th, tl, SQ*FF);
        // z = t @ Wp + bp  (split-K=2 -> pz, pz2)
        {
            GPtrs pA{wph + wOff, wpl + wOff, bp + (size_t)l*FF, pz,  nullptr, nullptr};
            GPtrs pB{wph + wOff, wpl + wOff, nullptr,           pz2, nullptr, nullptr};
            gemm_bf16<0,3><<<dim3(FF/64, SQ/128, 2), 256, SMEM_NN>>>(th, tl, pA, pB, pB, SQ, FF, FF, 1.f);
        }
        add_ln_warp<<<SQ/8, 256>>>(pz, pz2, px, g1 + (size_t)l*FF, be1 + (size_t)l*FF,
                                   px2, x2h, x2l);
        // h = x2 @ W1 + b1 (wide)
        {
            GPtrs p{w1h + w1Off, w1l + w1Off, b1 + (size_t)l*HID, nullptr, hh, hl};
            gemm_bf16w<<<dim3(SQ/128, HID/128, 1), 256, SMEM_W>>>(x2h, x2l, p, SQ, HID, FF);
        }
        // h2 = h @ W2 + b2  (split-K=2)
        {
            GPtrs pA{w2h + w2Off, w2l + w2Off, b2 + (size_t)l*DM, ph2,  nullptr, nullptr};
            GPtrs pB{w2h + w2Off, w2l + w2Off, nullptr,           ph2b, nullptr, nullptr};
            gemm_bf16<0,3><<<dim3(DM/64, SQ/128, 2), 256, SMEM_NN>>>(hh, hl, pA, pB, pB, SQ, DM, HID, 1.f);
        }
        add_ln_warp<<<SQ/8, 256>>>(ph2, ph2b, px2, g2 + (size_t)l*DM, be2 + (size_t)l*DM,
                                   px, xh, xl);
    }

    // tf32 logits GEMM + 1-pass vocab softmax
    round_tf32_kernel<<<(SQ*DM)/1024, 256>>>(px, pxt, SQ*DM);
    gemm_tf32w<<<dim3(SQ/128, VOC/128), 256, SMEM_TF>>>(pxt, pwft, bf, out,
                                                        psmax, pssum, SQ, VOC, DM);
    softmax_vocab_kernel<<<SQ, 256>>>(out, psmax, pssum);

    (void)in_sizes; (void)n_in; (void)out_size;
}

// round 11
// speedup vs baseline: 4.3374x; 1.0930x over previous
#include <cuda_runtime.h>
#include <cuda_bf16.h>
#include <cstdint>
#include <cmath>

#define SQ   2048
#define DM   512
#define FF   512
#define HID  2048
#define VOC  32000
#define NL   4
#define LN_EPS 1e-5f
#define NBV  (VOC/128)

typedef __nv_bfloat16  bf16;
typedef __nv_bfloat162 bf162;

// ------------------------- fp32 scratch ------------------------------------
__device__ float g_x  [SQ * DM];
__device__ float g_xt [SQ * DM];      // tf32-rounded final x (logits A)
__device__ float g_x2 [SQ * DM];
__device__ float g_x2t[SQ * DM];      // tf32-rounded x2 (W1 A)
__device__ float g_att[SQ * SQ];
__device__ float g_z  [SQ * FF];
__device__ float g_z2 [SQ * FF];
__device__ float g_ht [SQ * HID];     // tf32-rounded h (W2 A)
__device__ float g_c0 [SQ * DM];      // W2 split-K partials
__device__ float g_c1 [SQ * DM];
__device__ float g_c2 [SQ * DM];
__device__ float g_c3 [SQ * DM];
__device__ float g_smax[SQ * NBV];
__device__ float g_ssum[SQ * NBV];
__device__ float g_wft[(size_t)VOC * DM];          // Wf^T tf32 [N,K]
__device__ float g_w1t[(size_t)NL * HID * FF];     // W1^T tf32 [N,K] per layer
__device__ float g_w2t[(size_t)NL * DM * HID];     // W2^T tf32 [N,K] per layer

// ------------------------- bf16 hi/lo activations --------------------------
__device__ bf16 g_xh [SQ*DM],  g_xl [SQ*DM];
__device__ bf16 g_qh [SQ*FF],  g_ql [SQ*FF];
__device__ bf16 g_kh [SQ*FF],  g_kl [SQ*FF];
__device__ bf16 g_vh [SQ*FF],  g_vl [SQ*FF];
__device__ bf16 g_ath[SQ*SQ],  g_atl[SQ*SQ];
__device__ bf16 g_th [SQ*FF],  g_tl [SQ*FF];

// ------------------------- bf16 hi/lo weights ------------------------------
__device__ bf16 g_wqh[NL*DM*FF],  g_wql[NL*DM*FF];
__device__ bf16 g_wkh[NL*DM*FF],  g_wkl[NL*DM*FF];
__device__ bf16 g_wvh[NL*DM*FF],  g_wvl[NL*DM*FF];
__device__ bf16 g_wph[NL*FF*FF],  g_wpl[NL*FF*FF];

// ------------------------- PTX wrappers ------------------------------------
__device__ __forceinline__ void ldsm4(uint32_t* r, uint32_t addr) {
    asm volatile("ldmatrix.sync.aligned.m8n8.x4.shared.b16 {%0,%1,%2,%3}, [%4];"
                 : "=r"(r[0]), "=r"(r[1]), "=r"(r[2]), "=r"(r[3]) : "r"(addr));
}
__device__ __forceinline__ void ldsm4t(uint32_t* r, uint32_t addr) {
    asm volatile("ldmatrix.sync.aligned.m8n8.x4.trans.shared.b16 {%0,%1,%2,%3}, [%4];"
                 : "=r"(r[0]), "=r"(r[1]), "=r"(r[2]), "=r"(r[3]) : "r"(addr));
}
__device__ __forceinline__ void mma16816(float* c, const uint32_t* a, const uint32_t* b) {
    asm volatile("mma.sync.aligned.m16n8k16.row.col.f32.bf16.bf16.f32 "
                 "{%0,%1,%2,%3}, {%4,%5,%6,%7}, {%8,%9}, {%0,%1,%2,%3};"
                 : "+f"(c[0]), "+f"(c[1]), "+f"(c[2]), "+f"(c[3])
                 : "r"(a[0]), "r"(a[1]), "r"(a[2]), "r"(a[3]),
                   "r"(b[0]), "r"(b[1]));
}
__device__ __forceinline__ void mma1688tf(float* c, const uint32_t* a, const uint32_t* b) {
    asm volatile("mma.sync.aligned.m16n8k8.row.col.f32.tf32.tf32.f32 "
                 "{%0,%1,%2,%3}, {%4,%5,%6,%7}, {%8,%9}, {%0,%1,%2,%3};"
                 : "+f"(c[0]), "+f"(c[1]), "+f"(c[2]), "+f"(c[3])
                 : "r"(a[0]), "r"(a[1]), "r"(a[2]), "r"(a[3]),
                   "r"(b[0]), "r"(b[1]));
}
__device__ __forceinline__ void cpa16(uint32_t s, const void* g) {
    asm volatile("cp.async.cg.shared.global [%0], [%1], 16;\n" :: "r"(s), "l"(g));
}
__device__ __forceinline__ void cpcommit() { asm volatile("cp.async.commit_group;\n"); }
template<int N> __device__ __forceinline__ void cpwait() {
    asm volatile("cp.async.wait_group %0;\n" :: "n"(N));
}
__device__ __forceinline__ void split1(float x, bf16& h, bf16& l) {
    h = __float2bfloat16_rn(x);
    l = __float2bfloat16_rn(x - __bfloat162float(h));
}
__device__ __forceinline__ float to_tf32(float x) {
    uint32_t u;
    asm("cvt.rna.tf32.f32 %0, %1;" : "=r"(u) : "f"(x));
    return __uint_as_float(u);
}
__device__ __forceinline__ uint32_t pack2(bf16 a, bf16 b) {
    bf162 t{a, b};
    return *(uint32_t*)&t;
}

// ------------------------- utility kernels ---------------------------------
__global__ void split_kernel(const float* __restrict__ in,
                             bf16* __restrict__ hi, bf16* __restrict__ lo, int n)
{
    int i = (blockIdx.x * blockDim.x + threadIdx.x) * 8;
    if (i >= n) return;
    float4 a = *(const float4*)(in + i);
    float4 b = *(const float4*)(in + i + 4);
    bf16 h[8], l[8];
    split1(a.x,h[0],l[0]); split1(a.y,h[1],l[1]);
    split1(a.z,h[2],l[2]); split1(a.w,h[3],l[3]);
    split1(b.x,h[4],l[4]); split1(b.y,h[5],l[5]);
    split1(b.z,h[6],l[6]); split1(b.w,h[7],l[7]);
    *(uint4*)(hi + i) = *(const uint4*)h;
    *(uint4*)(lo + i) = *(const uint4*)l;
}

__global__ void add_split_kernel(const float* __restrict__ a, const float* __restrict__ b,
                                 bf16* __restrict__ hi, bf16* __restrict__ lo, int n)
{
    int i = (blockIdx.x * blockDim.x + threadIdx.x) * 4;
    if (i >= n) return;
    float4 va = *(const float4*)(a + i);
    float4 vb = *(const float4*)(b + i);
    va.x += vb.x; va.y += vb.y; va.z += vb.z; va.w += vb.w;
    bf16 h0,h1,h2,h3,l0,l1,l2,l3;
    split1(va.x,h0,l0); split1(va.y,h1,l1); split1(va.z,h2,l2); split1(va.w,h3,l3);
    *(uint2*)(hi + i) = uint2{pack2(h0,h1), pack2(h2,h3)};
    *(uint2*)(lo + i) = uint2{pack2(l0,l1), pack2(l2,l3)};
}

// transpose [Kd,Nd] fp32 -> [Nd,Kd], rounding to tf32 (per-z-layer)
__global__ void transpose_tf32_kernel(const float* __restrict__ in,
                                      float* __restrict__ out, int Kd, int Nd)
{
    __shared__ float t[32][33];
    const size_t off = (size_t)blockIdx.z * Kd * Nd;
    const int n0 = blockIdx.x * 32, k0 = blockIdx.y * 32;
    const int tx = threadIdx.x, ty = threadIdx.y;
    #pragma unroll
    for (int i = 0; i < 4; i++)
        t[ty + 8*i][tx] = in[off + (size_t)(k0 + ty + 8*i) * Nd + n0 + tx];
    __syncthreads();
    #pragma unroll
    for (int i = 0; i < 4; i++)
        out[off + (size_t)(n0 + ty + 8*i) * Kd + k0 + tx] = to_tf32(t[tx][ty + 8*i]);
}

struct GPtrs { const bf16 *Bh, *Bl; const float* bias; float* C; bf16 *Ch, *Cl; };

// ------------------------- BN=64 bf16-split GEMM ---------------------------
// MODE: 0 normal; 1 causal block-skip (TRANSB=1); 2 K bounded at m0+128;
//       3 split-K=2 over z; 4 K bounded at m0+128 AND split-K=2 over z.
template<int TRANSB, int MODE>
__global__ void __launch_bounds__(256, 2)
gemm_bf16(const bf16* __restrict__ Ah, const bf16* __restrict__ Al,
          GPtrs p0, GPtrs p1, GPtrs p2, int M, int N, int K, float alpha)
{
    constexpr int BM = 128, BN = 64, BK = 32, ST = 3;
    constexpr int ASTR   = 40;
    constexpr int A_PART = BM * ASTR;
    constexpr int BROWS  = TRANSB ? BN : BK;
    constexpr int BSTR   = TRANSB ? 40 : (BN + 8);
    constexpr int B_PART = BROWS * BSTR;
    constexpr int STAGE  = 2*A_PART + 2*B_PART;
    constexpr int MT = 2;
    constexpr int NT = 4;

    extern __shared__ bf16 smem[];

    const int m0 = blockIdx.y * BM;
    const int n0 = blockIdx.x * BN;
    if (MODE == 1 && n0 >= m0 + BM) return;

    GPtrs P = (blockIdx.z == 0) ? p0 : ((blockIdx.z == 1) ? p1 : p2);

    int Keff = K, kOff = 0;
    if (MODE == 2) Keff = min(K, m0 + BM);
    if (MODE == 3) { Keff = K >> 1; kOff = blockIdx.z * Keff; }
    if (MODE == 4) { int kt = min(K, m0 + BM); Keff = kt >> 1; kOff = blockIdx.z * Keff; }
    const int T = Keff / BK;

    const int tid  = threadIdx.x;
    const int lane = tid & 31;
    const int warp = tid >> 5;
    const int wm = warp & 3;
    const int wn = warp >> 2;
    const int l7 = lane & 7, q1 = (lane >> 3) & 1, q2 = lane >> 4;

    auto load_tile = [&](int t, int s) {
        const int k0 = kOff + t * BK;
        bf16* sb = smem + s * STAGE;
        #pragma unroll
        for (int i = 0; i < 4; i++) {
            int f = tid + 256 * i;
            int part = f >> 9;
            int r = (f >> 2) & 127;
            int c = f & 3;
            const bf16* gp = (part ? Al : Ah) + (size_t)(m0 + r) * K + k0 + c * 8;
            cpa16((uint32_t)__cvta_generic_to_shared(sb + part*A_PART + r*ASTR + c*8), gp);
        }
        if (TRANSB) {
            constexpr int CB = BN * 4;
            #pragma unroll
            for (int i = 0; i < (2 * CB) / 256; i++) {
                int f = tid + 256 * i;
                int part = f / CB, rem = f % CB;
                int r = rem >> 2, c = rem & 3;
                const bf16* gp = (part ? P.Bl : P.Bh) + (size_t)(n0 + r) * K + k0 + c * 8;
                cpa16((uint32_t)__cvta_generic_to_shared(sb + 2*A_PART + part*B_PART + r*BSTR + c*8), gp);
            }
        } else {
            constexpr int CR = BN / 8;
            constexpr int CB = 32 * CR;
            #pragma unroll
            for (int i = 0; i < (2 * CB) / 256; i++) {
                int f = tid + 256 * i;
                int part = f / CB, rem = f % CB;
                int r = rem / CR, c = rem % CR;
                const bf16* gp = (part ? P.Bl : P.Bh) + (size_t)(k0 + r) * N + n0 + c * 8;
                cpa16((uint32_t)__cvta_generic_to_shared(sb + 2*A_PART + part*B_PART + r*BSTR + c*8), gp);
            }
        }
    };

    float acc[MT][NT][4];
    #pragma unroll
    for (int mt = 0; mt < MT; mt++)
        #pragma unroll
        for (int nt = 0; nt < NT; nt++)
            #pragma unroll
            for (int i = 0; i < 4; i++) acc[mt][nt][i] = 0.f;

    const uint32_t smemBase = (uint32_t)__cvta_generic_to_shared(smem);
    const uint32_t aoff = (uint32_t)(((wm*MT*16 + l7 + q1*8) * ASTR + q2*8) * 2);
    uint32_t boff;
    if (TRANSB) boff = (uint32_t)((2*A_PART + (wn*32 + l7 + q2*8) * BSTR + q1*8) * 2);
    else        boff = (uint32_t)((2*A_PART + (l7 + q1*8) * BSTR + wn*32 + q2*8) * 2);

    load_tile(0, 0); cpcommit();
    if (T > 1) load_tile(1, 1);
    cpcommit();

    for (int t = 0; t < T; t++) {
        cpwait<1>();
        __syncthreads();
        if (t + 2 < T) { load_tile(t + 2, (t + 2) % ST); }
        cpcommit();

        const uint32_t sbase = smemBase + (uint32_t)((t % ST) * STAGE * 2);

        #pragma unroll
        for (int ks = 0; ks < 2; ks++) {
            uint32_t a[MT][4], bh[NT][2], bl[NT][2];
            #pragma unroll
            for (int mt = 0; mt < MT; mt++)
                ldsm4(a[mt], sbase + aoff + (uint32_t)(mt*16*ASTR*2 + ks*32));
            #pragma unroll
            for (int pp = 0; pp < 2; pp++) {
                uint32_t off = TRANSB ? (uint32_t)(pp*16*BSTR*2 + ks*32)
                                      : (uint32_t)(ks*16*BSTR*2 + pp*32);
                uint32_t r4[4];
                if (TRANSB) ldsm4 (r4, sbase + boff + off);
                else        ldsm4t(r4, sbase + boff + off);
                bh[2*pp][0]   = r4[0]; bh[2*pp][1]   = r4[1];
                bh[2*pp+1][0] = r4[2]; bh[2*pp+1][1] = r4[3];
                if (TRANSB) ldsm4 (r4, sbase + boff + (uint32_t)(B_PART*2) + off);
                else        ldsm4t(r4, sbase + boff + (uint32_t)(B_PART*2) + off);
                bl[2*pp][0]   = r4[0]; bl[2*pp][1]   = r4[1];
                bl[2*pp+1][0] = r4[2]; bl[2*pp+1][1] = r4[3];
            }
            #pragma unroll
            for (int nt = 0; nt < NT; nt++)
                #pragma unroll
                for (int mt = 0; mt < MT; mt++)
                    mma16816(acc[mt][nt], a[mt], bh[nt]);
            #pragma unroll
            for (int nt = 0; nt < NT; nt++)
                #pragma unroll
                for (int mt = 0; mt < MT; mt++)
                    mma16816(acc[mt][nt], a[mt], bl[nt]);
            #pragma unroll
            for (int mt = 0; mt < MT; mt++)
                ldsm4(a[mt], sbase + aoff + (uint32_t)(A_PART*2 + mt*16*ASTR*2 + ks*32));
            #pragma unroll
            for (int nt = 0; nt < NT; nt++)
                #pragma unroll
                for (int mt = 0; mt < MT; mt++)
                    mma16816(acc[mt][nt], a[mt], bh[nt]);
        }
    }

    #pragma unroll
    for (int mt = 0; mt < MT; mt++) {
        int row0 = m0 + wm*MT*16 + mt*16 + (lane >> 2);
        #pragma unroll
        for (int nt = 0; nt < NT; nt++) {
            int col = n0 + wn*32 + nt*8 + ((lane & 3) << 1);
            float b0 = 0.f, b1 = 0.f;
            if (P.bias) { b0 = P.bias[col]; b1 = P.bias[col + 1]; }
            float c00 = acc[mt][nt][0] * alpha + b0;
            float c01 = acc[mt][nt][1] * alpha + b1;
            float c10 = acc[mt][nt][2] * alpha + b0;
            float c11 = acc[mt][nt][3] * alpha + b1;
            if (P.C) {
                *(float2*)(P.C + (size_t)row0 * N + col)       = float2{c00, c01};
                *(float2*)(P.C + (size_t)(row0 + 8) * N + col) = float2{c10, c11};
            }
            if (P.Ch) {
                bf16 h0,l0,h1,l1;
                split1(c00,h0,l0); split1(c01,h1,l1);
                *(bf162*)(P.Ch + (size_t)row0 * N + col) = bf162{h0,h1};
                *(bf162*)(P.Cl + (size_t)row0 * N + col) = bf162{l0,l1};
                split1(c10,h0,l0); split1(c11,h1,l1);
                *(bf162*)(P.Ch + (size_t)(row0 + 8) * N + col) = bf162{h0,h1};
                *(bf162*)(P.Cl + (size_t)(row0 + 8) * N + col) = bf162{l0,l1};
            }
        }
    }
}

// ------------------------- tf32 GEMM core (shared by all tf32 users) -------
// C = A @ B^T (+bias).  A [M,K] fp32(tf32-valued); B [N,K] tf32-valued.
// KSPLIT: grid.z K-partition; ROUNDC: round output to tf32; STATS: softmax partials.
template<int KSPLIT, int ROUNDC, int STATS>
__global__ void __launch_bounds__(256, 2)
gemm_tf32(const float* __restrict__ A, const float* __restrict__ B,
          const float* __restrict__ bias,
          float* __restrict__ C0, float* __restrict__ C1,
          float* __restrict__ C2, float* __restrict__ C3,
          float* __restrict__ smax, float* __restrict__ ssum,
          int M, int N, int K)
{
    constexpr int BM = 128, BN = 128, BK = 32, ST = 3;
    constexpr int ASTRf = 36;
    constexpr int A_PARTf = BM * ASTRf;
    constexpr int BSTRf = 36;
    constexpr int B_PARTf = BN * BSTRf;
    constexpr int STAGEf = A_PARTf + B_PARTf;
    constexpr int MT = 2;
    constexpr int NT = 8;

    extern __shared__ float fsmem[];

    const int m0 = blockIdx.x * BM;
    const int n0 = blockIdx.y * BN;
    const int keff = K / KSPLIT;
    const int kOff = blockIdx.z * keff;
    const int T = keff / BK;

    float* C = C0;
    if (KSPLIT > 1)
        C = (blockIdx.z == 0) ? C0 : (blockIdx.z == 1) ? C1 : (blockIdx.z == 2) ? C2 : C3;

    const int tid  = threadIdx.x;
    const int lane = tid & 31;
    const int warp = tid >> 5;
    const int wm = warp & 3;
    const int wn = warp >> 2;
    const int l7 = lane & 7, q1 = (lane >> 3) & 1, q2 = lane >> 4;

    auto load_tile = [&](int t, int s) {
        const int k0 = kOff + t * BK;
        float* sb = fsmem + s * STAGEf;
        #pragma unroll
        for (int i = 0; i < 4; i++) {
            int f = tid + 256 * i;
            int r = f >> 3;
            int c = f & 7;
            cpa16((uint32_t)__cvta_generic_to_shared(sb + r*ASTRf + c*4),
                  A + (size_t)(m0 + r) * K + k0 + c*4);
        }
        #pragma unroll
        for (int i = 0; i < 4; i++) {
            int f = tid + 256 * i;
            int r = f >> 3;
            int c = f & 7;
            cpa16((uint32_t)__cvta_generic_to_shared(sb + A_PARTf + r*BSTRf + c*4),
                  B + (size_t)(n0 + r) * K + k0 + c*4);
        }
    };

    float acc[MT][NT][4];
    #pragma unroll
    for (int mt = 0; mt < MT; mt++)
        #pragma unroll
        for (int nt = 0; nt < NT; nt++)
            #pragma unroll
            for (int i = 0; i < 4; i++) acc[mt][nt][i] = 0.f;

    const uint32_t smemBase = (uint32_t)__cvta_generic_to_shared(fsmem);
    const uint32_t aoff = (uint32_t)(((wm*MT*16 + l7 + q1*8) * ASTRf + q2*4) * 4);
    const uint32_t boff = (uint32_t)((A_PARTf + (wn*64 + l7 + q2*8) * BSTRf + q1*4) * 4);

    load_tile(0, 0); cpcommit();
    if (T > 1) load_tile(1, 1);
    cpcommit();

    for (int t = 0; t < T; t++) {
        cpwait<1>();
        __syncthreads();
        if (t + 2 < T) { load_tile(t + 2, (t + 2) % ST); }
        cpcommit();

        const uint32_t sbase = smemBase + (uint32_t)((t % ST) * STAGEf * 4);

        #pragma unroll
        for (int k8 = 0; k8 < 4; k8++) {
            uint32_t a[MT][4];
            #pragma unroll
            for (int mt = 0; mt < MT; mt++)
                ldsm4(a[mt], sbase + aoff + (uint32_t)(mt*16*ASTRf*4 + k8*32));
            #pragma unroll
            for (int p = 0; p < NT/2; p++) {
                uint32_t r4[4];
                ldsm4(r4, sbase + boff + (uint32_t)(p*16*BSTRf*4 + k8*32));
                uint32_t b0[2] = {r4[0], r4[1]};
                uint32_t b1[2] = {r4[2], r4[3]};
                #pragma unroll
                for (int mt = 0; mt < MT; mt++) {
                    mma1688tf(acc[mt][2*p],   a[mt], b0);
                    mma1688tf(acc[mt][2*p+1], a[mt], b1);
                }
            }
        }
    }

    // bias (split-K: only partial 0 carries it)
    if (bias && (KSPLIT == 1 || blockIdx.z == 0)) {
        #pragma unroll
        for (int mt = 0; mt < MT; mt++)
            #pragma unroll
            for (int nt = 0; nt < NT; nt++) {
                int col = n0 + wn*64 + nt*8 + ((lane & 3) << 1);
                acc[mt][nt][0] += bias[col];     acc[mt][nt][1] += bias[col + 1];
                acc[mt][nt][2] += bias[col];     acc[mt][nt][3] += bias[col + 1];
            }
    }

    #pragma unroll
    for (int mt = 0; mt < MT; mt++) {
        int row0 = m0 + wm*MT*16 + mt*16 + (lane >> 2);
        #pragma unroll
        for (int nt = 0; nt < NT; nt++) {
            int col = n0 + wn*64 + nt*8 + ((lane & 3) << 1);
            float c00 = acc[mt][nt][0], c01 = acc[mt][nt][1];
            float c10 = acc[mt][nt][2], c11 = acc[mt][nt][3];
            if (ROUNDC) {
                c00 = to_tf32(c00); c01 = to_tf32(c01);
                c10 = to_tf32(c10); c11 = to_tf32(c11);
            }
            *(float2*)(C + (size_t)row0 * N + col)       = float2{c00, c01};
            *(float2*)(C + (size_t)(row0 + 8) * N + col) = float2{c10, c11};
        }
    }

    if (STATS) {
        __syncthreads();
        float* sm_m = fsmem;
        float* sm_s = fsmem + 256;
        #pragma unroll
        for (int mt = 0; mt < MT; mt++) {
            float mA = -1e30f, mB = -1e30f;
            #pragma unroll
            for (int nt = 0; nt < NT; nt++) {
                mA = fmaxf(mA, fmaxf(acc[mt][nt][0], acc[mt][nt][1]));
                mB = fmaxf(mB, fmaxf(acc[mt][nt][2], acc[mt][nt][3]));
            }
            mA = fmaxf(mA, __shfl_xor_sync(0xffffffffu, mA, 1));
            mA = fmaxf(mA, __shfl_xor_sync(0xffffffffu, mA, 2));
            mB = fmaxf(mB, __shfl_xor_sync(0xffffffffu, mB, 1));
            mB = fmaxf(mB, __shfl_xor_sync(0xffffffffu, mB, 2));
            float sA = 0.f, sB = 0.f;
            #pragma unroll
            for (int nt = 0; nt < NT; nt++) {
                sA += __expf(acc[mt][nt][0] - mA) + __expf(acc[mt][nt][1] - mA);
                sB += __expf(acc[mt][nt][2] - mB) + __expf(acc[mt][nt][3] - mB);
            }
            sA += __shfl_xor_sync(0xffffffffu, sA, 1);
            sA += __shfl_xor_sync(0xffffffffu, sA, 2);
            sB += __shfl_xor_sync(0xffffffffu, sB, 1);
            sB += __shfl_xor_sync(0xffffffffu, sB, 2);
            if ((lane & 3) == 0) {
                int r = wm*32 + mt*16 + (lane >> 2);
                sm_m[r*2 + wn]     = mA;  sm_s[r*2 + wn]     = sA;
                sm_m[(r+8)*2 + wn] = mB;  sm_s[(r+8)*2 + wn] = sB;
            }
        }
        __syncthreads();
        if (tid < 128) {
            float m1 = sm_m[tid*2], m2 = sm_m[tid*2 + 1];
            float Mx = fmaxf(m1, m2);
            float S  = sm_s[tid*2] * __expf(m1 - Mx) + sm_s[tid*2 + 1] * __expf(m2 - Mx);
            int nb = N >> 7;
            smax[(size_t)(m0 + tid) * nb + (n0 >> 7)] = Mx;
            ssum[(size_t)(m0 + tid) * nb + (n0 >> 7)] = S;
        }
    }
}

// ------------------------- warp-per-row causal softmax ---------------------
__global__ void __launch_bounds__(256)
softmax_causal_warp(const float* __restrict__ att,
                    bf16* __restrict__ oh, bf16* __restrict__ ol)
{
    const int warp = threadIdx.x >> 5;
    const int lane = threadIdx.x & 31;
    const int r = blockIdx.x * 8 + warp;
    const float* row = att + (size_t)r * SQ;
    bf16* rh = oh + (size_t)r * SQ;
    bf16* rl = ol + (size_t)r * SQ;
    const int n = r + 1;
    const int fillEnd = ((r >> 7) + 1) << 7;

    float m = -1e30f;
    for (int j = lane * 4; j < fillEnd; j += 128) {
        float4 v = *(const float4*)(row + j);
        if (j + 0 < n) m = fmaxf(m, v.x);
        if (j + 1 < n) m = fmaxf(m, v.y);
        if (j + 2 < n) m = fmaxf(m, v.z);
        if (j + 3 < n) m = fmaxf(m, v.w);
    }
    #pragma unroll
    for (int st = 16; st > 0; st >>= 1)
        m = fmaxf(m, __shfl_xor_sync(0xffffffffu, m, st));

    float s = 0.f;
    for (int j = lane * 4; j < fillEnd; j += 128) {
        float4 v = *(const float4*)(row + j);
        if (j + 0 < n) s += __expf(v.x - m);
        if (j + 1 < n) s += __expf(v.y - m);
        if (j + 2 < n) s += __expf(v.z - m);
        if (j + 3 < n) s += __expf(v.w - m);
    }
    #pragma unroll
    for (int st = 16; st > 0; st >>= 1)
        s += __shfl_xor_sync(0xffffffffu, s, st);
    const float inv = 1.f / s;

    for (int j = lane * 4; j < fillEnd; j += 128) {
        float4 v = *(const float4*)(row + j);
        float e0 = (j + 0 < n) ? __expf(v.x - m) * inv : 0.f;
        float e1 = (j + 1 < n) ? __expf(v.y - m) * inv : 0.f;
        float e2 = (j + 2 < n) ? __expf(v.z - m) * inv : 0.f;
        float e3 = (j + 3 < n) ? __expf(v.w - m) * inv : 0.f;
        bf16 h0,l0,h1,l1,h2,l2,h3,l3;
        split1(e0,h0,l0); split1(e1,h1,l1); split1(e2,h2,l2); split1(e3,h3,l3);
        *(uint2*)(rh + j) = uint2{pack2(h0,h1), pack2(h2,h3)};
        *(uint2*)(rl + j) = uint2{pack2(l0,l1), pack2(l2,l3)};
    }
}

// ------------------------- warp-per-row multi-partial add + LN --------------
// sums a0 (+a1..a3 if non-null) + res, LayerNorm; outputs:
//   out (fp32, always), oh/ol (bf16 hi/lo, optional), xt (tf32-rounded, optional)
__global__ void __launch_bounds__(256)
add_ln_warp(const float* __restrict__ a0, const float* __restrict__ a1,
            const float* __restrict__ a2, const float* __restrict__ a3,
            const float* __restrict__ res,
            const float* __restrict__ g, const float* __restrict__ beta,
            float* __restrict__ out,
            bf16* __restrict__ oh, bf16* __restrict__ ol,
            float* __restrict__ xt)
{
    const int warp = threadIdx.x >> 5;
    const int lane = threadIdx.x & 31;
    const int r = blockIdx.x * 8 + warp;
    const size_t base = (size_t)r * DM;

    float v[16];
    float sum = 0.f;
    #pragma unroll
    for (int k = 0; k < 4; k++) {
        int j = lane * 4 + k * 128;
        float4 va = *(const float4*)(a0 + base + j);
        float4 vr = *(const float4*)(res + base + j);
        va.x += vr.x; va.y += vr.y; va.z += vr.z; va.w += vr.w;
        if (a1) {
            float4 vb = *(const float4*)(a1 + base + j);
            va.x += vb.x; va.y += vb.y; va.z += vb.z; va.w += vb.w;
        }
        if (a2) {
            float4 vb = *(const float4*)(a2 + base + j);
            va.x += vb.x; va.y += vb.y; va.z += vb.z; va.w += vb.w;
        }
        if (a3) {
            float4 vb = *(const float4*)(a3 + base + j);
            va.x += vb.x; va.y += vb.y; va.z += vb.z; va.w += vb.w;
        }
        v[k*4+0] = va.x; v[k*4+1] = va.y; v[k*4+2] = va.z; v[k*4+3] = va.w;
        sum += va.x + va.y + va.z + va.w;
    }
    #pragma unroll
    for (int st = 16; st > 0; st >>= 1)
        sum += __shfl_xor_sync(0xffffffffu, sum, st);
    const float mu = sum * (1.0f / DM);

    float var = 0.f;
    #pragma unroll
    for (int k = 0; k < 16; k++) {
        float d = v[k] - mu;
        v[k] = d;
        var += d * d;
    }
    #pragma unroll
    for (int st = 16; st > 0; st >>= 1)
        var += __shfl_xor_sync(0xffffffffu, var, st);
    const float rstd = rsqrtf(var * (1.0f / DM) + LN_EPS);

    #pragma unroll
    for (int k = 0; k < 4; k++) {
        int j = lane * 4 + k * 128;
        float4 vg = *(const float4*)(g + j);
        float4 vb = *(const float4*)(beta + j);
        float o0 = v[k*4+0] * rstd * vg.x + vb.x;
        float o1 = v[k*4+1] * rstd * vg.y + vb.y;
        float o2 = v[k*4+2] * rstd * vg.z + vb.z;
        float o3 = v[k*4+3] * rstd * vg.w + vb.w;
        *(float4*)(out + base + j) = float4{o0, o1, o2, o3};
        if (oh) {
            bf16 h0,l0,h1,l1,h2,l2,h3,l3;
            split1(o0,h0,l0); split1(o1,h1,l1); split1(o2,h2,l2); split1(o3,h3,l3);
            *(uint2*)(oh + base + j) = uint2{pack2(h0,h1), pack2(h2,h3)};
            *(uint2*)(ol + base + j) = uint2{pack2(l0,l1), pack2(l2,l3)};
        }
        if (xt)
            *(float4*)(xt + base + j) =
                float4{to_tf32(o0), to_tf32(o1), to_tf32(o2), to_tf32(o3)};
    }
}

// ------------------------- vocab softmax via GEMM partials -----------------
__global__ void softmax_vocab_kernel(float* __restrict__ x,
                                     const float* __restrict__ smax,
                                     const float* __restrict__ ssum)
{
    const int i = blockIdx.x;
    float* row = x + (size_t)i * VOC;
    const int tid = threadIdx.x;

    __shared__ float mRed[256];
    __shared__ float sRed[256];

    float m = -1e30f, s = 0.f;
    if (tid < NBV) {
        m = smax[(size_t)i * NBV + tid];
        s = ssum[(size_t)i * NBV + tid];
    }
    mRed[tid] = m; sRed[tid] = s; __syncthreads();
    for (int st = 128; st > 0; st >>= 1) {
        if (tid < st) {
            float m1 = mRed[tid], m2 = mRed[tid + st];
            float Mx = fmaxf(m1, m2);
            sRed[tid] = sRed[tid] * __expf(m1 - Mx) + sRed[tid + st] * __expf(m2 - Mx);
            mRed[tid] = Mx;
        }
        __syncthreads();
    }
    const float M = mRed[0];
    const float inv = 1.f / sRed[0];

    for (int j = tid * 4; j < VOC; j += 1024) {
        float4 v = *(const float4*)(row + j);
        v.x = __expf(v.x - M) * inv;
        v.y = __expf(v.y - M) * inv;
        v.z = __expf(v.z - M) * inv;
        v.w = __expf(v.w - M) * inv;
        *(float4*)(row + j) = v;
    }
}

// ------------------------- host side ---------------------------------------
#define SMEM_NN 89088
#define SMEM_NT 92160
#define SMEM_TF 110592

static inline void do_split(const float* in, bf16* hi, bf16* lo, int n) {
    split_kernel<<<n / 2048, 256>>>(in, hi, lo, n);
}

extern "C" void kernel_launch(void* const* d_in, const int* in_sizes, int n_in,
                              void* d_out, int out_size)
{
    const float* x   = (const float*)d_in[0];
    const float* Wq  = (const float*)d_in[1];
    const float* bq  = (const float*)d_in[2];
    const float* Wk  = (const float*)d_in[3];
    const float* bk  = (const float*)d_in[4];
    const float* Wv  = (const float*)d_in[5];
    const float* bv  = (const float*)d_in[6];
    const float* Wp  = (const float*)d_in[7];
    const float* bp  = (const float*)d_in[8];
    const float* g1  = (const float*)d_in[9];
    const float* be1 = (const float*)d_in[10];
    const float* W1  = (const float*)d_in[11];
    const float* b1  = (const float*)d_in[12];
    const float* W2  = (const float*)d_in[13];
    const float* b2  = (const float*)d_in[14];
    const float* g2  = (const float*)d_in[15];
    const float* be2 = (const float*)d_in[16];
    const float* Wf  = (const float*)d_in[17];
    const float* bf  = (const float*)d_in[18];
    float* out = (float*)d_out;

    cudaFuncSetAttribute(gemm_bf16<0,0>, cudaFuncAttributeMaxDynamicSharedMemorySize, SMEM_NN);
    cudaFuncSetAttribute(gemm_bf16<0,3>, cudaFuncAttributeMaxDynamicSharedMemorySize, SMEM_NN);
    cudaFuncSetAttribute(gemm_bf16<0,4>, cudaFuncAttributeMaxDynamicSharedMemorySize, SMEM_NN);
    cudaFuncSetAttribute(gemm_bf16<1,1>, cudaFuncAttributeMaxDynamicSharedMemorySize, SMEM_NT);
    cudaFuncSetAttribute(gemm_tf32<1,0,1>, cudaFuncAttributeMaxDynamicSharedMemorySize, SMEM_TF);
    cudaFuncSetAttribute(gemm_tf32<1,1,0>, cudaFuncAttributeMaxDynamicSharedMemorySize, SMEM_TF);
    cudaFuncSetAttribute(gemm_tf32<4,0,0>, cudaFuncAttributeMaxDynamicSharedMemorySize, SMEM_TF);

    float *px, *pxt, *px2, *px2t, *patt, *pz, *pz2, *pht;
    float *pc0, *pc1, *pc2, *pc3, *psmax, *pssum, *pwft, *pw1t, *pw2t;
    cudaGetSymbolAddress((void**)&px,    g_x);
    cudaGetSymbolAddress((void**)&pxt,   g_xt);
    cudaGetSymbolAddress((void**)&px2,   g_x2);
    cudaGetSymbolAddress((void**)&px2t,  g_x2t);
    cudaGetSymbolAddress((void**)&patt,  g_att);
    cudaGetSymbolAddress((void**)&pz,    g_z);
    cudaGetSymbolAddress((void**)&pz2,   g_z2);
    cudaGetSymbolAddress((void**)&pht,   g_ht);
    cudaGetSymbolAddress((void**)&pc0,   g_c0);
    cudaGetSymbolAddress((void**)&pc1,   g_c1);
    cudaGetSymbolAddress((void**)&pc2,   g_c2);
    cudaGetSymbolAddress((void**)&pc3,   g_c3);
    cudaGetSymbolAddress((void**)&psmax, g_smax);
    cudaGetSymbolAddress((void**)&pssum, g_ssum);
    cudaGetSymbolAddress((void**)&pwft,  g_wft);
    cudaGetSymbolAddress((void**)&pw1t,  g_w1t);
    cudaGetSymbolAddress((void**)&pw2t,  g_w2t);

    bf16 *xh,*xl,*qh,*ql,*kh,*kl,*vh,*vl,*ath,*atl,*th,*tl;
    cudaGetSymbolAddress((void**)&xh,  g_xh);  cudaGetSymbolAddress((void**)&xl,  g_xl);
    cudaGetSymbolAddress((void**)&qh,  g_qh);  cudaGetSymbolAddress((void**)&ql,  g_ql);
    cudaGetSymbolAddress((void**)&kh,  g_kh);  cudaGetSymbolAddress((void**)&kl,  g_kl);
    cudaGetSymbolAddress((void**)&vh,  g_vh);  cudaGetSymbolAddress((void**)&vl,  g_vl);
    cudaGetSymbolAddress((void**)&ath, g_ath); cudaGetSymbolAddress((void**)&atl, g_atl);
    cudaGetSymbolAddress((void**)&th,  g_th);  cudaGetSymbolAddress((void**)&tl,  g_tl);

    bf16 *wqh,*wql,*wkh,*wkl,*wvh,*wvl,*wph,*wpl;
    cudaGetSymbolAddress((void**)&wqh, g_wqh); cudaGetSymbolAddress((void**)&wql, g_wql);
    cudaGetSymbolAddress((void**)&wkh, g_wkh); cudaGetSymbolAddress((void**)&wkl, g_wkl);
    cudaGetSymbolAddress((void**)&wvh, g_wvh); cudaGetSymbolAddress((void**)&wvl, g_wvl);
    cudaGetSymbolAddress((void**)&wph, g_wph); cudaGetSymbolAddress((void**)&wpl, g_wpl);

    const float scale = 1.0f / sqrtf((float)FF);
    dim3 tb(32, 8);

    // preprocessing
    do_split(x,  xh,  xl,  SQ*DM);
    do_split(Wq, wqh, wql, NL*DM*FF);
    do_split(Wk, wkh, wkl, NL*DM*FF);
    do_split(Wv, wvh, wvl, NL*DM*FF);

    bool firstLayer = true;
    for (int l = 0; l < NL; l++) {
        size_t wOff = (size_t)l * DM * FF;

        // QKV (batched over z)
        {
            GPtrs pQ{wqh + wOff, wql + wOff, bq + (size_t)l*FF, nullptr, qh, ql};
            GPtrs pK{wkh + wOff, wkl + wOff, bk + (size_t)l*FF, nullptr, kh, kl};
            GPtrs pV{wvh + wOff, wvl + wOff, bv + (size_t)l*FF, nullptr, vh, vl};
            gemm_bf16<0,0><<<dim3(FF/64, SQ/128, 3), 256, SMEM_NN>>>(xh, xl, pQ, pK, pV, SQ, FF, DM, 1.f);
        }
        // scores = q @ k^T * scale (causal block skip)
        {
            GPtrs p{kh, kl, nullptr, patt, nullptr, nullptr};
            gemm_bf16<1,1><<<dim3(SQ/64, SQ/128, 1), 256, SMEM_NT>>>(qh, ql, p, p, p, SQ, SQ, FF, scale);
        }
        if (firstLayer) {    // deferred preprocessing, overlapped after issue
            do_split(Wp, wph, wpl, NL*FF*FF);
            transpose_tf32_kernel<<<dim3(HID/32, FF/32, NL), tb>>>(W1, pw1t, FF,  HID);
            transpose_tf32_kernel<<<dim3(DM/32, HID/32, NL), tb>>>(W2, pw2t, HID, DM);
            transpose_tf32_kernel<<<dim3(VOC/32, DM/32, 1),  tb>>>(Wf, pwft, DM,  VOC);
            firstLayer = false;
        }
        softmax_causal_warp<<<SQ/8, 256>>>(patt, ath, atl);
        // t = att @ v  (K bounded + split-K=2)
        {
            GPtrs pA{vh, vl, nullptr, pz,  nullptr, nullptr};
            GPtrs pB{vh, vl, nullptr, pz2, nullptr, nullptr};
            gemm_bf16<0,4><<<dim3(FF/64, SQ/128, 2), 256, SMEM_NN>>>(ath, atl, pA, pB, pB, SQ, FF, SQ, 1.f);
        }
        add_split_kernel<<<(SQ*FF)/1024, 256>>>(pz, pz2, th, tl, SQ*FF);
        // z = t @ Wp + bp  (split-K=2)
        {
            GPtrs pA{wph + wOff, wpl + wOff, bp + (size_t)l*FF, pz,  nullptr, nullptr};
            GPtrs pB{wph + wOff, wpl + wOff, nullptr,           pz2, nullptr, nullptr};
            gemm_bf16<0,3><<<dim3(FF/64, SQ/128, 2), 256, SMEM_NN>>>(th, tl, pA, pB, pB, SQ, FF, FF, 1.f);
        }
        // x2 = LN1(z + x): fp32 px2 + tf32 x2t (for tf32 W1)
        add_ln_warp<<<SQ/8, 256>>>(pz, pz2, nullptr, nullptr,
                                   (l == 0) ? x : px,
                                   g1 + (size_t)l*FF, be1 + (size_t)l*FF,
                                   px2, nullptr, nullptr, px2t);
        // h = x2 @ W1 + b1  (tf32 single-product, tf32-rounded output)
        gemm_tf32<1,1,0><<<dim3(SQ/128, HID/128, 1), 256, SMEM_TF>>>(
            px2t, pw1t + (size_t)l*HID*FF, b1 + (size_t)l*HID,
            pht, nullptr, nullptr, nullptr, nullptr, nullptr, SQ, HID, FF);
        // h2 = h @ W2 + b2  (tf32, split-K=4)
        gemm_tf32<4,0,0><<<dim3(SQ/128, DM/128, 4), 256, SMEM_TF>>>(
            pht, pw2t + (size_t)l*DM*HID, b2 + (size_t)l*DM,
            pc0, pc1, pc2, pc3, nullptr, nullptr, SQ, DM, HID);
        // x = LN2(h2 + x2): fp32 px + bf16 xh/xl; last layer also emits tf32 xt
        add_ln_warp<<<SQ/8, 256>>>(pc0, pc1, pc2, pc3, px2,
                                   g2 + (size_t)l*DM, be2 + (size_t)l*DM,
                                   px,
                                   (l == NL-1) ? nullptr : xh,
                                   (l == NL-1) ? nullptr : xl,
                                   (l == NL-1) ? pxt : nullptr);
    }

    // tf32 logits GEMM (fused softmax partials) + 1-pass vocab softmax
    gemm_tf32<1,0,1><<<dim3(SQ/128, VOC/128, 1), 256, SMEM_TF>>>(
        pxt, pwft, bf, out, nullptr, nullptr, nullptr, psmax, pssum, SQ, VOC, DM);
    softmax_vocab_kernel<<<SQ, 256>>>(out, psmax, pssum);

    (void)in_sizes; (void)n_in; (void)out_size;
}

// round 12
// speedup vs baseline: 4.6445x; 1.0708x over previous
#include <cuda_runtime.h>
#include <cstdint>
#include <cmath>

#define SQ   2048
#define DM   512
#define FF   512
#define HID  2048
#define VOC  32000
#define NL   4
#define LN_EPS 1e-5f
#define NBV  (VOC/128)

// ------------------------- fp32 scratch ------------------------------------
__device__ float g_x  [SQ * DM];      // residual stream (fp32 exact)
__device__ float g_xt [SQ * DM];      // tf32 x (QKV / logits A)
__device__ float g_x2 [SQ * DM];
__device__ float g_x2t[SQ * DM];      // tf32 x2 (W1 A)
__device__ float g_q  [SQ * FF];      // tf32 q
__device__ float g_k  [SQ * FF];      // tf32 k
__device__ float g_v  [SQ * FF];
__device__ float g_vt [FF * SQ];      // tf32 V^T
__device__ float g_att[SQ * SQ];      // scores -> (in-place) tf32 probs
__device__ float g_t  [SQ * FF];      // tf32 t = att@V
__device__ float g_ht [SQ * HID];     // tf32 h
__device__ float g_c0 [SQ * FF];      // split-K partials
__device__ float g_c1 [SQ * FF];
__device__ float g_c2 [SQ * FF];
__device__ float g_c3 [SQ * FF];
__device__ float g_smax[SQ * NBV];
__device__ float g_ssum[SQ * NBV];
// tf32 transposed weights [N,K]
__device__ float g_wqt[(size_t)NL * FF * DM];
__device__ float g_wkt[(size_t)NL * FF * DM];
__device__ float g_wvt[(size_t)NL * FF * DM];
__device__ float g_wpt[(size_t)NL * FF * FF];
__device__ float g_w1t[(size_t)NL * HID * FF];
__device__ float g_w2t[(size_t)NL * DM * HID];
__device__ float g_wft[(size_t)VOC * DM];

// ------------------------- PTX helpers -------------------------------------
__device__ __forceinline__ void ldsm4(uint32_t* r, uint32_t addr) {
    asm volatile("ldmatrix.sync.aligned.m8n8.x4.shared.b16 {%0,%1,%2,%3}, [%4];"
                 : "=r"(r[0]), "=r"(r[1]), "=r"(r[2]), "=r"(r[3]) : "r"(addr));
}
__device__ __forceinline__ void mma1688tf(float* c, const uint32_t* a, const uint32_t* b) {
    asm volatile("mma.sync.aligned.m16n8k8.row.col.f32.tf32.tf32.f32 "
                 "{%0,%1,%2,%3}, {%4,%5,%6,%7}, {%8,%9}, {%0,%1,%2,%3};"
                 : "+f"(c[0]), "+f"(c[1]), "+f"(c[2]), "+f"(c[3])
                 : "r"(a[0]), "r"(a[1]), "r"(a[2]), "r"(a[3]),
                   "r"(b[0]), "r"(b[1]));
}
__device__ __forceinline__ void cpa16(uint32_t s, const void* g) {
    asm volatile("cp.async.cg.shared.global [%0], [%1], 16;\n" :: "r"(s), "l"(g));
}
__device__ __forceinline__ void cpcommit() { asm volatile("cp.async.commit_group;\n"); }
template<int N> __device__ __forceinline__ void cpwait() {
    asm volatile("cp.async.wait_group %0;\n" :: "n"(N));
}
__device__ __forceinline__ float to_tf32(float x) {
    uint32_t u;
    asm("cvt.rna.tf32.f32 %0, %1;" : "=r"(u) : "f"(x));
    return __uint_as_float(u);
}

// ------------------------- utility kernels ---------------------------------
__global__ void round_tf32_kernel(const float* __restrict__ in,
                                  float* __restrict__ out, int n)
{
    int i = (blockIdx.x * blockDim.x + threadIdx.x) * 4;
    if (i >= n) return;
    float4 v = *(const float4*)(in + i);
    v.x = to_tf32(v.x); v.y = to_tf32(v.y);
    v.z = to_tf32(v.z); v.w = to_tf32(v.w);
    *(float4*)(out + i) = v;
}

// transpose [Kd,Nd] fp32 -> [Nd,Kd], rounding to tf32 (per-z-layer)
__global__ void transpose_tf32_kernel(const float* __restrict__ in,
                                      float* __restrict__ out, int Kd, int Nd)
{
    __shared__ float t[32][33];
    const size_t off = (size_t)blockIdx.z * Kd * Nd;
    const int n0 = blockIdx.x * 32, k0 = blockIdx.y * 32;
    const int tx = threadIdx.x, ty = threadIdx.y;
    #pragma unroll
    for (int i = 0; i < 4; i++)
        t[ty + 8*i][tx] = in[off + (size_t)(k0 + ty + 8*i) * Nd + n0 + tx];
    __syncthreads();
    #pragma unroll
    for (int i = 0; i < 4; i++)
        out[off + (size_t)(n0 + ty + 8*i) * Kd + k0 + tx] = to_tf32(t[tx][ty + 8*i]);
}

// out = tf32(a0+a1+a2+a3)
__global__ void add4_tf32_kernel(const float* __restrict__ a0, const float* __restrict__ a1,
                                 const float* __restrict__ a2, const float* __restrict__ a3,
                                 float* __restrict__ out, int n)
{
    int i = (blockIdx.x * blockDim.x + threadIdx.x) * 4;
    if (i >= n) return;
    float4 v0 = *(const float4*)(a0 + i);
    float4 v1 = *(const float4*)(a1 + i);
    float4 v2 = *(const float4*)(a2 + i);
    float4 v3 = *(const float4*)(a3 + i);
    float4 o;
    o.x = to_tf32(v0.x + v1.x + v2.x + v3.x);
    o.y = to_tf32(v0.y + v1.y + v2.y + v3.y);
    o.z = to_tf32(v0.z + v1.z + v2.z + v3.z);
    o.w = to_tf32(v0.w + v1.w + v2.w + v3.w);
    *(float4*)(out + i) = o;
}

struct TfP { const float* B; const float* bias; float* C; };

// ------------------------- unified tf32 GEMM -------------------------------
// C = alpha * A @ B^T + bias.  A [M,K] tf32-valued fp32; B [N,K] tf32-valued.
// Grid: (M/128, N/128, z).
// MODE 0: z selects batch {p0,p1,p2} (full K).
// MODE 1: causal block-skip (n0 > m0 -> return), p0 only.
// MODE 2: K bounded at m0+128, split over z (C = pz.C, B/bias = p0).
// MODE 3: split-K over z (C = pz.C, B/bias = p0).
// ROUNDC: round outputs to tf32.  STATS: emit per-(row,n-block) softmax partials.
template<int MODE, int ROUNDC, int STATS>
__global__ void __launch_bounds__(256, 2)
gemm_tf32(const float* __restrict__ A, TfP p0, TfP p1, TfP p2, TfP p3,
          float* __restrict__ smax, float* __restrict__ ssum,
          int M, int N, int K, float alpha)
{
    constexpr int BM = 128, BN = 128, BK = 32, ST = 3;
    constexpr int ASTRf = 36;
    constexpr int A_PARTf = BM * ASTRf;
    constexpr int BSTRf = 36;
    constexpr int B_PARTf = BN * BSTRf;
    constexpr int STAGEf = A_PARTf + B_PARTf;
    constexpr int MT = 2;
    constexpr int NT = 8;

    extern __shared__ float fsmem[];

    const int m0 = blockIdx.x * BM;
    const int n0 = blockIdx.y * BN;
    if (MODE == 1 && n0 > m0) return;

    TfP P = p0;
    if (MODE == 0)
        P = (blockIdx.z == 0) ? p0 : ((blockIdx.z == 1) ? p1 : p2);
    float* C = P.C;
    if (MODE >= 2)
        C = (blockIdx.z == 0) ? p0.C : (blockIdx.z == 1) ? p1.C
          : (blockIdx.z == 2) ? p2.C : p3.C;
    const float* bias = P.bias;
    if (MODE >= 2 && blockIdx.z != 0) bias = nullptr;

    int Keff = K, kOff = 0;
    if (MODE == 2) { int kt = min(K, m0 + BM); Keff = kt / gridDim.z; kOff = blockIdx.z * Keff; }
    if (MODE == 3) { Keff = K / gridDim.z; kOff = blockIdx.z * Keff; }
    const int T = Keff / BK;

    const int tid  = threadIdx.x;
    const int lane = tid & 31;
    const int warp = tid >> 5;
    const int wm = warp & 3;
    const int wn = warp >> 2;
    const int l7 = lane & 7, q1 = (lane >> 3) & 1, q2 = lane >> 4;

    auto load_tile = [&](int t, int s) {
        const int k0 = kOff + t * BK;
        float* sb = fsmem + s * STAGEf;
        #pragma unroll
        for (int i = 0; i < 4; i++) {
            int f = tid + 256 * i;
            int r = f >> 3;
            int c = f & 7;
            cpa16((uint32_t)__cvta_generic_to_shared(sb + r*ASTRf + c*4),
                  A + (size_t)(m0 + r) * K + k0 + c*4);
        }
        #pragma unroll
        for (int i = 0; i < 4; i++) {
            int f = tid + 256 * i;
            int r = f >> 3;
            int c = f & 7;
            cpa16((uint32_t)__cvta_generic_to_shared(sb + A_PARTf + r*BSTRf + c*4),
                  P.B + (size_t)(n0 + r) * K + k0 + c*4);
        }
    };

    float acc[MT][NT][4];
    #pragma unroll
    for (int mt = 0; mt < MT; mt++)
        #pragma unroll
        for (int nt = 0; nt < NT; nt++)
            #pragma unroll
            for (int i = 0; i < 4; i++) acc[mt][nt][i] = 0.f;

    const uint32_t smemBase = (uint32_t)__cvta_generic_to_shared(fsmem);
    const uint32_t aoff = (uint32_t)(((wm*MT*16 + l7 + q1*8) * ASTRf + q2*4) * 4);
    const uint32_t boff = (uint32_t)((A_PARTf + (wn*64 + l7 + q2*8) * BSTRf + q1*4) * 4);

    load_tile(0, 0); cpcommit();
    if (T > 1) load_tile(1, 1);
    cpcommit();

    for (int t = 0; t < T; t++) {
        cpwait<1>();
        __syncthreads();
        if (t + 2 < T) { load_tile(t + 2, (t + 2) % ST); }
        cpcommit();

        const uint32_t sbase = smemBase + (uint32_t)((t % ST) * STAGEf * 4);

        #pragma unroll
        for (int k8 = 0; k8 < 4; k8++) {
            uint32_t a[MT][4];
            #pragma unroll
            for (int mt = 0; mt < MT; mt++)
                ldsm4(a[mt], sbase + aoff + (uint32_t)(mt*16*ASTRf*4 + k8*32));
            #pragma unroll
            for (int p = 0; p < NT/2; p++) {
                uint32_t r4[4];
                ldsm4(r4, sbase + boff + (uint32_t)(p*16*BSTRf*4 + k8*32));
                uint32_t b0[2] = {r4[0], r4[1]};
                uint32_t b1[2] = {r4[2], r4[3]};
                #pragma unroll
                for (int mt = 0; mt < MT; mt++) {
                    mma1688tf(acc[mt][2*p],   a[mt], b0);
                    mma1688tf(acc[mt][2*p+1], a[mt], b1);
                }
            }
        }
    }

    // fold alpha + bias into acc
    #pragma unroll
    for (int mt = 0; mt < MT; mt++)
        #pragma unroll
        for (int nt = 0; nt < NT; nt++) {
            int col = n0 + wn*64 + nt*8 + ((lane & 3) << 1);
            float b0 = 0.f, b1 = 0.f;
            if (bias) { b0 = bias[col]; b1 = bias[col + 1]; }
            acc[mt][nt][0] = acc[mt][nt][0] * alpha + b0;
            acc[mt][nt][1] = acc[mt][nt][1] * alpha + b1;
            acc[mt][nt][2] = acc[mt][nt][2] * alpha + b0;
            acc[mt][nt][3] = acc[mt][nt][3] * alpha + b1;
        }

    #pragma unroll
    for (int mt = 0; mt < MT; mt++) {
        int row0 = m0 + wm*MT*16 + mt*16 + (lane >> 2);
        #pragma unroll
        for (int nt = 0; nt < NT; nt++) {
            int col = n0 + wn*64 + nt*8 + ((lane & 3) << 1);
            float c00 = acc[mt][nt][0], c01 = acc[mt][nt][1];
            float c10 = acc[mt][nt][2], c11 = acc[mt][nt][3];
            if (ROUNDC) {
                c00 = to_tf32(c00); c01 = to_tf32(c01);
                c10 = to_tf32(c10); c11 = to_tf32(c11);
            }
            *(float2*)(C + (size_t)row0 * N + col)       = float2{c00, c01};
            *(float2*)(C + (size_t)(row0 + 8) * N + col) = float2{c10, c11};
        }
    }

    if (STATS) {
        __syncthreads();
        float* sm_m = fsmem;
        float* sm_s = fsmem + 256;
        #pragma unroll
        for (int mt = 0; mt < MT; mt++) {
            float mA = -1e30f, mB = -1e30f;
            #pragma unroll
            for (int nt = 0; nt < NT; nt++) {
                mA = fmaxf(mA, fmaxf(acc[mt][nt][0], acc[mt][nt][1]));
                mB = fmaxf(mB, fmaxf(acc[mt][nt][2], acc[mt][nt][3]));
            }
            mA = fmaxf(mA, __shfl_xor_sync(0xffffffffu, mA, 1));
            mA = fmaxf(mA, __shfl_xor_sync(0xffffffffu, mA, 2));
            mB = fmaxf(mB, __shfl_xor_sync(0xffffffffu, mB, 1));
            mB = fmaxf(mB, __shfl_xor_sync(0xffffffffu, mB, 2));
            float sA = 0.f, sB = 0.f;
            #pragma unroll
            for (int nt = 0; nt < NT; nt++) {
                sA += __expf(acc[mt][nt][0] - mA) + __expf(acc[mt][nt][1] - mA);
                sB += __expf(acc[mt][nt][2] - mB) + __expf(acc[mt][nt][3] - mB);
            }
            sA += __shfl_xor_sync(0xffffffffu, sA, 1);
            sA += __shfl_xor_sync(0xffffffffu, sA, 2);
            sB += __shfl_xor_sync(0xffffffffu, sB, 1);
            sB += __shfl_xor_sync(0xffffffffu, sB, 2);
            if ((lane & 3) == 0) {
                int r = wm*32 + mt*16 + (lane >> 2);
                sm_m[r*2 + wn]     = mA;  sm_s[r*2 + wn]     = sA;
                sm_m[(r+8)*2 + wn] = mB;  sm_s[(r+8)*2 + wn] = sB;
            }
        }
        __syncthreads();
        if (tid < 128) {
            float m1 = sm_m[tid*2], m2 = sm_m[tid*2 + 1];
            float Mx = fmaxf(m1, m2);
            float S  = sm_s[tid*2] * __expf(m1 - Mx) + sm_s[tid*2 + 1] * __expf(m2 - Mx);
            int nb = N >> 7;
            smax[(size_t)(m0 + tid) * nb + (n0 >> 7)] = Mx;
            ssum[(size_t)(m0 + tid) * nb + (n0 >> 7)] = S;
        }
    }
}

// ------------------------- warp-per-row causal softmax (in place) ----------
__global__ void __launch_bounds__(256)
softmax_causal_warp(float* __restrict__ att)
{
    const int warp = threadIdx.x >> 5;
    const int lane = threadIdx.x & 31;
    const int r = blockIdx.x * 8 + warp;
    float* row = att + (size_t)r * SQ;
    const int n = r + 1;
    const int fillEnd = ((r >> 7) + 1) << 7;

    float m = -1e30f;
    for (int j = lane * 4; j < fillEnd; j += 128) {
        float4 v = *(const float4*)(row + j);
        if (j + 0 < n) m = fmaxf(m, v.x);
        if (j + 1 < n) m = fmaxf(m, v.y);
        if (j + 2 < n) m = fmaxf(m, v.z);
        if (j + 3 < n) m = fmaxf(m, v.w);
    }
    #pragma unroll
    for (int st = 16; st > 0; st >>= 1)
        m = fmaxf(m, __shfl_xor_sync(0xffffffffu, m, st));

    float s = 0.f;
    for (int j = lane * 4; j < fillEnd; j += 128) {
        float4 v = *(const float4*)(row + j);
        if (j + 0 < n) s += __expf(v.x - m);
        if (j + 1 < n) s += __expf(v.y - m);
        if (j + 2 < n) s += __expf(v.z - m);
        if (j + 3 < n) s += __expf(v.w - m);
    }
    #pragma unroll
    for (int st = 16; st > 0; st >>= 1)
        s += __shfl_xor_sync(0xffffffffu, s, st);
    const float inv = 1.f / s;

    for (int j = lane * 4; j < fillEnd; j += 128) {
        float4 v = *(const float4*)(row + j);
        v.x = (j + 0 < n) ? to_tf32(__expf(v.x - m) * inv) : 0.f;
        v.y = (j + 1 < n) ? to_tf32(__expf(v.y - m) * inv) : 0.f;
        v.z = (j + 2 < n) ? to_tf32(__expf(v.z - m) * inv) : 0.f;
        v.w = (j + 3 < n) ? to_tf32(__expf(v.w - m) * inv) : 0.f;
        *(float4*)(row + j) = v;
    }
}

// ------------------------- warp-per-row 4-partial add + LN -----------------
// x = LN(a0+a1+a2+a3 + res); outputs fp32 (residual) + tf32 (GEMM operand).
__global__ void __launch_bounds__(256)
add_ln_warp(const float* __restrict__ a0, const float* __restrict__ a1,
            const float* __restrict__ a2, const float* __restrict__ a3,
            const float* __restrict__ res,
            const float* __restrict__ g, const float* __restrict__ beta,
            float* __restrict__ out, float* __restrict__ xt)
{
    const int warp = threadIdx.x >> 5;
    const int lane = threadIdx.x & 31;
    const int r = blockIdx.x * 8 + warp;
    const size_t base = (size_t)r * DM;

    float v[16];
    float sum = 0.f;
    #pragma unroll
    for (int k = 0; k < 4; k++) {
        int j = lane * 4 + k * 128;
        float4 va = *(const float4*)(a0 + base + j);
        float4 v1 = *(const float4*)(a1 + base + j);
        float4 v2 = *(const float4*)(a2 + base + j);
        float4 v3 = *(const float4*)(a3 + base + j);
        float4 vr = *(const float4*)(res + base + j);
        va.x += v1.x + v2.x + v3.x + vr.x;
        va.y += v1.y + v2.y + v3.y + vr.y;
        va.z += v1.z + v2.z + v3.z + vr.z;
        va.w += v1.w + v2.w + v3.w + vr.w;
        v[k*4+0] = va.x; v[k*4+1] = va.y; v[k*4+2] = va.z; v[k*4+3] = va.w;
        sum += va.x + va.y + va.z + va.w;
    }
    #pragma unroll
    for (int st = 16; st > 0; st >>= 1)
        sum += __shfl_xor_sync(0xffffffffu, sum, st);
    const float mu = sum * (1.0f / DM);

    float var = 0.f;
    #pragma unroll
    for (int k = 0; k < 16; k++) {
        float d = v[k] - mu;
        v[k] = d;
        var += d * d;
    }
    #pragma unroll
    for (int st = 16; st > 0; st >>= 1)
        var += __shfl_xor_sync(0xffffffffu, var, st);
    const float rstd = rsqrtf(var * (1.0f / DM) + LN_EPS);

    #pragma unroll
    for (int k = 0; k < 4; k++) {
        int j = lane * 4 + k * 128;
        float4 vg = *(const float4*)(g + j);
        float4 vb = *(const float4*)(beta + j);
        float o0 = v[k*4+0] * rstd * vg.x + vb.x;
        float o1 = v[k*4+1] * rstd * vg.y + vb.y;
        float o2 = v[k*4+2] * rstd * vg.z + vb.z;
        float o3 = v[k*4+3] * rstd * vg.w + vb.w;
        *(float4*)(out + base + j) = float4{o0, o1, o2, o3};
        *(float4*)(xt + base + j) =
            float4{to_tf32(o0), to_tf32(o1), to_tf32(o2), to_tf32(o3)};
    }
}

// ------------------------- vocab softmax via GEMM partials -----------------
__global__ void softmax_vocab_kernel(float* __restrict__ x,
                                     const float* __restrict__ smax,
                                     const float* __restrict__ ssum)
{
    const int i = blockIdx.x;
    float* row = x + (size_t)i * VOC;
    const int tid = threadIdx.x;

    __shared__ float mRed[256];
    __shared__ float sRed[256];

    float m = -1e30f, s = 0.f;
    if (tid < NBV) {
        m = smax[(size_t)i * NBV + tid];
        s = ssum[(size_t)i * NBV + tid];
    }
    mRed[tid] = m; sRed[tid] = s; __syncthreads();
    for (int st = 128; st > 0; st >>= 1) {
        if (tid < st) {
            float m1 = mRed[tid], m2 = mRed[tid + st];
            float Mx = fmaxf(m1, m2);
            sRed[tid] = sRed[tid] * __expf(m1 - Mx) + sRed[tid + st] * __expf(m2 - Mx);
            mRed[tid] = Mx;
        }
        __syncthreads();
    }
    const float M = mRed[0];
    const float inv = 1.f / sRed[0];

    for (int j = tid * 4; j < VOC; j += 1024) {
        float4 v = *(const float4*)(row + j);
        v.x = __expf(v.x - M) * inv;
        v.y = __expf(v.y - M) * inv;
        v.z = __expf(v.z - M) * inv;
        v.w = __expf(v.w - M) * inv;
        *(float4*)(row + j) = v;
    }
}

// ------------------------- host side ---------------------------------------
#define SMEM_TF 110592

extern "C" void kernel_launch(void* const* d_in, const int* in_sizes, int n_in,
                              void* d_out, int out_size)
{
    const float* x   = (const float*)d_in[0];
    const float* Wq  = (const float*)d_in[1];
    const float* bq  = (const float*)d_in[2];
    const float* Wk  = (const float*)d_in[3];
    const float* bk  = (const float*)d_in[4];
    const float* Wv  = (const float*)d_in[5];
    const float* bv  = (const float*)d_in[6];
    const float* Wp  = (const float*)d_in[7];
    const float* bp  = (const float*)d_in[8];
    const float* g1  = (const float*)d_in[9];
    const float* be1 = (const float*)d_in[10];
    const float* W1  = (const float*)d_in[11];
    const float* b1  = (const float*)d_in[12];
    const float* W2  = (const float*)d_in[13];
    const float* b2  = (const float*)d_in[14];
    const float* g2  = (const float*)d_in[15];
    const float* be2 = (const float*)d_in[16];
    const float* Wf  = (const float*)d_in[17];
    const float* bf  = (const float*)d_in[18];
    float* out = (float*)d_out;

    cudaFuncSetAttribute(gemm_tf32<0,1,0>, cudaFuncAttributeMaxDynamicSharedMemorySize, SMEM_TF);
    cudaFuncSetAttribute(gemm_tf32<1,0,0>, cudaFuncAttributeMaxDynamicSharedMemorySize, SMEM_TF);
    cudaFuncSetAttribute(gemm_tf32<2,0,0>, cudaFuncAttributeMaxDynamicSharedMemorySize, SMEM_TF);
    cudaFuncSetAttribute(gemm_tf32<3,0,0>, cudaFuncAttributeMaxDynamicSharedMemorySize, SMEM_TF);
    cudaFuncSetAttribute(gemm_tf32<0,0,1>, cudaFuncAttributeMaxDynamicSharedMemorySize, SMEM_TF);

    float *px, *pxt, *px2, *px2t, *pq, *pk, *pv, *pvt, *patt, *pt, *pht;
    float *pc0, *pc1, *pc2, *pc3, *psmax, *pssum;
    float *pwqt, *pwkt, *pwvt, *pwpt, *pw1t, *pw2t, *pwft;
    cudaGetSymbolAddress((void**)&px,    g_x);
    cudaGetSymbolAddress((void**)&pxt,   g_xt);
    cudaGetSymbolAddress((void**)&px2,   g_x2);
    cudaGetSymbolAddress((void**)&px2t,  g_x2t);
    cudaGetSymbolAddress((void**)&pq,    g_q);
    cudaGetSymbolAddress((void**)&pk,    g_k);
    cudaGetSymbolAddress((void**)&pv,    g_v);
    cudaGetSymbolAddress((void**)&pvt,   g_vt);
    cudaGetSymbolAddress((void**)&patt,  g_att);
    cudaGetSymbolAddress((void**)&pt,    g_t);
    cudaGetSymbolAddress((void**)&pht,   g_ht);
    cudaGetSymbolAddress((void**)&pc0,   g_c0);
    cudaGetSymbolAddress((void**)&pc1,   g_c1);
    cudaGetSymbolAddress((void**)&pc2,   g_c2);
    cudaGetSymbolAddress((void**)&pc3,   g_c3);
    cudaGetSymbolAddress((void**)&psmax, g_smax);
    cudaGetSymbolAddress((void**)&pssum, g_ssum);
    cudaGetSymbolAddress((void**)&pwqt,  g_wqt);
    cudaGetSymbolAddress((void**)&pwkt,  g_wkt);
    cudaGetSymbolAddress((void**)&pwvt,  g_wvt);
    cudaGetSymbolAddress((void**)&pwpt,  g_wpt);
    cudaGetSymbolAddress((void**)&pw1t,  g_w1t);
    cudaGetSymbolAddress((void**)&pw2t,  g_w2t);
    cudaGetSymbolAddress((void**)&pwft,  g_wft);

    const float scale = 1.0f / sqrtf((float)FF);
    dim3 tb(32, 8);
    TfP z{nullptr, nullptr, nullptr};

    // preprocessing needed for first QKV
    round_tf32_kernel<<<(SQ*DM)/1024, 256>>>(x, pxt, SQ*DM);
    transpose_tf32_kernel<<<dim3(FF/32, DM/32, NL), tb>>>(Wq, pwqt, DM, FF);
    transpose_tf32_kernel<<<dim3(FF/32, DM/32, NL), tb>>>(Wk, pwkt, DM, FF);
    transpose_tf32_kernel<<<dim3(FF/32, DM/32, NL), tb>>>(Wv, pwvt, DM, FF);

    bool firstLayer = true;
    for (int l = 0; l < NL; l++) {
        size_t wOff = (size_t)l * DM * FF;

        // QKV (batched over z, tf32-rounded outputs)
        {
            TfP pQ{pwqt + wOff, bq + (size_t)l*FF, pq};
            TfP pK{pwkt + wOff, bk + (size_t)l*FF, pk};
            TfP pV{pwvt + wOff, bv + (size_t)l*FF, pv};
            gemm_tf32<0,1,0><<<dim3(SQ/128, FF/128, 3), 256, SMEM_TF>>>(
                pxt, pQ, pK, pV, z, nullptr, nullptr, SQ, FF, DM, 1.f);
        }
        // scores = q @ k^T * scale (causal skip), fp32 out
        {
            TfP p{pk, nullptr, patt};
            gemm_tf32<1,0,0><<<dim3(SQ/128, SQ/128, 1), 256, SMEM_TF>>>(
                pq, p, z, z, z, nullptr, nullptr, SQ, SQ, FF, scale);
        }
        if (firstLayer) {   // deferred preprocessing (overlaps with above)
            transpose_tf32_kernel<<<dim3(FF/32, FF/32, NL),  tb>>>(Wp, pwpt, FF,  FF);
            transpose_tf32_kernel<<<dim3(HID/32, FF/32, NL), tb>>>(W1, pw1t, FF,  HID);
            transpose_tf32_kernel<<<dim3(DM/32, HID/32, NL), tb>>>(W2, pw2t, HID, DM);
            transpose_tf32_kernel<<<dim3(VOC/32, DM/32, 1),  tb>>>(Wf, pwft, DM,  VOC);
            firstLayer = false;
        }
        // V^T (tf32) for att@V
        transpose_tf32_kernel<<<dim3(FF/32, SQ/32, 1), tb>>>(pv, pvt, SQ, FF);
        // causal softmax (in place, tf32 probs)
        softmax_causal_warp<<<SQ/8, 256>>>(patt);
        // t = att @ V  (K bounded at m0+128, split-K=4)
        {
            TfP pA{pvt, nullptr, pc0};
            TfP pB{nullptr, nullptr, pc1};
            TfP pC{nullptr, nullptr, pc2};
            TfP pD{nullptr, nullptr, pc3};
            gemm_tf32<2,0,0><<<dim3(SQ/128, FF/128, 4), 256, SMEM_TF>>>(
                patt, pA, pB, pC, pD, nullptr, nullptr, SQ, FF, SQ, 1.f);
        }
        add4_tf32_kernel<<<(SQ*FF)/1024, 256>>>(pc0, pc1, pc2, pc3, pt, SQ*FF);
        // zout = t @ Wp + bp  (split-K=4, partials -> LN1)
        {
            TfP pA{pwpt + (size_t)l*FF*FF, bp + (size_t)l*FF, pc0};
            TfP pB{nullptr, nullptr, pc1};
            TfP pC{nullptr, nullptr, pc2};
            TfP pD{nullptr, nullptr, pc3};
            gemm_tf32<3,0,0><<<dim3(SQ/128, FF/128, 4), 256, SMEM_TF>>>(
                pt, pA, pB, pC, pD, nullptr, nullptr, SQ, FF, FF, 1.f);
        }
        add_ln_warp<<<SQ/8, 256>>>(pc0, pc1, pc2, pc3, (l == 0) ? x : px,
                                   g1 + (size_t)l*FF, be1 + (size_t)l*FF,
                                   px2, px2t);
        // h = x2 @ W1 + b1 (tf32-rounded out)
        {
            TfP p{pw1t + (size_t)l*HID*FF, b1 + (size_t)l*HID, pht};
            gemm_tf32<0,1,0><<<dim3(SQ/128, HID/128, 1), 256, SMEM_TF>>>(
                px2t, p, z, z, z, nullptr, nullptr, SQ, HID, FF, 1.f);
        }
        // h2 = h @ W2 + b2 (split-K=4)
        {
            TfP pA{pw2t + (size_t)l*DM*HID, b2 + (size_t)l*DM, pc0};
            TfP pB{nullptr, nullptr, pc1};
            TfP pC{nullptr, nullptr, pc2};
            TfP pD{nullptr, nullptr, pc3};
            gemm_tf32<3,0,0><<<dim3(SQ/128, DM/128, 4), 256, SMEM_TF>>>(
                pht, pA, pB, pC, pD, nullptr, nullptr, SQ, DM, HID, 1.f);
        }
        add_ln_warp<<<SQ/8, 256>>>(pc0, pc1, pc2, pc3, px2,
                                   g2 + (size_t)l*DM, be2 + (size_t)l*DM,
                                   px, pxt);
    }

    // logits (fused softmax partials) + 1-pass vocab softmax
    {
        TfP p{pwft, bf, out};
        gemm_tf32<0,0,1><<<dim3(SQ/128, VOC/128, 1), 256, SMEM_TF>>>(
            pxt, p, z, z, z, psmax, pssum, SQ, VOC, DM, 1.f);
    }
    softmax_vocab_kernel<<<SQ, 256>>>(out, psmax, pssum);

    (void)in_sizes; (void)n_in; (void)out_size;
}

// round 13
// speedup vs baseline: 6.7474x; 1.4528x over previous
#include <cuda_runtime.h>
#include <cuda_fp16.h>
#include <cstdint>
#include <cmath>

#define SQ   2048
#define DM   512
#define FF   512
#define HID  2048
#define VOC  32000
#define NL   4
#define LN_EPS 1e-5f
#define NBV  (VOC/128)

typedef __half  f16;
typedef __half2 f162;

// ------------------------- fp32 scratch ------------------------------------
__device__ float g_x  [SQ * DM];      // residual stream (fp32 exact)
__device__ float g_x2 [SQ * DM];
__device__ float g_att[SQ * SQ];      // fp32 scores
__device__ float g_c0 [SQ * FF];      // split-K partials
__device__ float g_c1 [SQ * FF];
__device__ float g_c2 [SQ * FF];
__device__ float g_c3 [SQ * FF];
__device__ float g_smax[SQ * NBV];
__device__ float g_ssum[SQ * NBV];

// ------------------------- fp16 operands -----------------------------------
__device__ f16 g_xh [SQ*DM];          // x (QKV / logits A)
__device__ f16 g_x2h[SQ*DM];          // x2 (W1 A)
__device__ f16 g_q  [SQ*FF];
__device__ f16 g_k  [SQ*FF];
__device__ f16 g_v  [SQ*FF];
__device__ f16 g_vt [FF*SQ];          // V^T
__device__ f16 g_ath[SQ*SQ];          // probs
__device__ f16 g_t  [SQ*FF];
__device__ f16 g_h  [SQ*HID];
// fp16 transposed weights [N,K]
__device__ f16 g_wqt[(size_t)NL * FF * DM];
__device__ f16 g_wkt[(size_t)NL * FF * DM];
__device__ f16 g_wvt[(size_t)NL * FF * DM];
__device__ f16 g_wpt[(size_t)NL * FF * FF];
__device__ f16 g_w1t[(size_t)NL * HID * FF];
__device__ f16 g_w2t[(size_t)NL * DM * HID];
__device__ f16 g_wft[(size_t)VOC * DM];

// ------------------------- PTX helpers -------------------------------------
__device__ __forceinline__ void ldsm4(uint32_t* r, uint32_t addr) {
    asm volatile("ldmatrix.sync.aligned.m8n8.x4.shared.b16 {%0,%1,%2,%3}, [%4];"
                 : "=r"(r[0]), "=r"(r[1]), "=r"(r[2]), "=r"(r[3]) : "r"(addr));
}
__device__ __forceinline__ void mma16816h(float* c, const uint32_t* a, const uint32_t* b) {
    asm volatile("mma.sync.aligned.m16n8k16.row.col.f32.f16.f16.f32 "
                 "{%0,%1,%2,%3}, {%4,%5,%6,%7}, {%8,%9}, {%0,%1,%2,%3};"
                 : "+f"(c[0]), "+f"(c[1]), "+f"(c[2]), "+f"(c[3])
                 : "r"(a[0]), "r"(a[1]), "r"(a[2]), "r"(a[3]),
                   "r"(b[0]), "r"(b[1]));
}
__device__ __forceinline__ void cpa16(uint32_t s, const void* g) {
    asm volatile("cp.async.cg.shared.global [%0], [%1], 16;\n" :: "r"(s), "l"(g));
}
__device__ __forceinline__ void cpcommit() { asm volatile("cp.async.commit_group;\n"); }
template<int N> __device__ __forceinline__ void cpwait() {
    asm volatile("cp.async.wait_group %0;\n" :: "n"(N));
}

// ------------------------- utility kernels ---------------------------------
__global__ void f32_to_f16_kernel(const float* __restrict__ in,
                                  f16* __restrict__ out, int n)
{
    int i = (blockIdx.x * blockDim.x + threadIdx.x) * 8;
    if (i >= n) return;
    float4 a = *(const float4*)(in + i);
    float4 b = *(const float4*)(in + i + 4);
    f162 o[4];
    o[0] = __floats2half2_rn(a.x, a.y);
    o[1] = __floats2half2_rn(a.z, a.w);
    o[2] = __floats2half2_rn(b.x, b.y);
    o[3] = __floats2half2_rn(b.z, b.w);
    *(uint4*)(out + i) = *(const uint4*)o;
}

// transpose [Kd,Nd] fp32 -> [Nd,Kd] fp16 (per-z-layer)
__global__ void transpose_f16_kernel(const float* __restrict__ in,
                                     f16* __restrict__ out, int Kd, int Nd)
{
    __shared__ float t[32][33];
    const size_t off = (size_t)blockIdx.z * Kd * Nd;
    const int n0 = blockIdx.x * 32, k0 = blockIdx.y * 32;
    const int tx = threadIdx.x, ty = threadIdx.y;
    #pragma unroll
    for (int i = 0; i < 4; i++)
        t[ty + 8*i][tx] = in[off + (size_t)(k0 + ty + 8*i) * Nd + n0 + tx];
    __syncthreads();
    #pragma unroll
    for (int i = 0; i < 4; i++)
        out[off + (size_t)(n0 + ty + 8*i) * Kd + k0 + tx] = __float2half_rn(t[tx][ty + 8*i]);
}

// transpose fp16 [Kd,Nd] -> fp16 [Nd,Kd] (V^T)
__global__ void transpose_h2h_kernel(const f16* __restrict__ in,
                                     f16* __restrict__ out, int Kd, int Nd)
{
    __shared__ f16 t[32][34];
    const int n0 = blockIdx.x * 32, k0 = blockIdx.y * 32;
    const int tx = threadIdx.x, ty = threadIdx.y;
    #pragma unroll
    for (int i = 0; i < 4; i++)
        t[ty + 8*i][tx] = in[(size_t)(k0 + ty + 8*i) * Nd + n0 + tx];
    __syncthreads();
    #pragma unroll
    for (int i = 0; i < 4; i++)
        out[(size_t)(n0 + ty + 8*i) * Kd + k0 + tx] = t[tx][ty + 8*i];
}

// out_f16 = f16(a0+a1+a2+a3)
__global__ void add4_f16_kernel(const float* __restrict__ a0, const float* __restrict__ a1,
                                const float* __restrict__ a2, const float* __restrict__ a3,
                                f16* __restrict__ out, int n)
{
    int i = (blockIdx.x * blockDim.x + threadIdx.x) * 4;
    if (i >= n) return;
    float4 v0 = *(const float4*)(a0 + i);
    float4 v1 = *(const float4*)(a1 + i);
    float4 v2 = *(const float4*)(a2 + i);
    float4 v3 = *(const float4*)(a3 + i);
    f162 o[2];
    o[0] = __floats2half2_rn(v0.x + v1.x + v2.x + v3.x, v0.y + v1.y + v2.y + v3.y);
    o[1] = __floats2half2_rn(v0.z + v1.z + v2.z + v3.z, v0.w + v1.w + v2.w + v3.w);
    *(uint2*)(out + i) = *(const uint2*)o;
}

struct HP { const f16* B; const float* bias; float* C; f16* Ch; };

// ------------------------- unified fp16 GEMM -------------------------------
// C = alpha * A @ B^T + bias.  A [M,K] fp16; B [N,K] fp16; fp32 accumulate.
// Grid: (M/128, N/128, z).
// MODE 0: z selects batch {p0,p1,p2} (full K).
// MODE 1: causal block-skip (n0 > m0 -> return), p0 only.
// MODE 2: K bounded at m0+128, split over z (C = pz.C).
// MODE 3: split-K over z (C = pz.C).
// STATS: emit per-(row,n-block) softmax partials.
template<int MODE, int STATS>
__global__ void __launch_bounds__(256, 2)
gemm_fp16(const f16* __restrict__ A, HP p0, HP p1, HP p2, HP p3,
          float* __restrict__ smax, float* __restrict__ ssum,
          int M, int N, int K, float alpha)
{
    constexpr int BM = 128, BN = 128, BK = 32, ST = 3;
    constexpr int ASTR = 40;               // halves; 80B row stride (16B aligned)
    constexpr int A_PART = BM * ASTR;      // 5120 halves
    constexpr int BSTR = 40;
    constexpr int B_PART = BN * BSTR;
    constexpr int STAGE = A_PART + B_PART; // 10240 halves = 20480 B
    constexpr int MT = 2;
    constexpr int NT = 8;

    extern __shared__ f16 smem[];

    const int m0 = blockIdx.x * BM;
    const int n0 = blockIdx.y * BN;
    if (MODE == 1 && n0 > m0) return;

    HP P = p0;
    if (MODE == 0)
        P = (blockIdx.z == 0) ? p0 : ((blockIdx.z == 1) ? p1 : p2);
    float* C  = P.C;
    f16*  Ch = P.Ch;
    if (MODE >= 2) {
        C = (blockIdx.z == 0) ? p0.C : (blockIdx.z == 1) ? p1.C
          : (blockIdx.z == 2) ? p2.C : p3.C;
        Ch = nullptr;
    }
    const float* bias = P.bias;
    if (MODE >= 2 && blockIdx.z != 0) bias = nullptr;

    int Keff = K, kOff = 0;
    if (MODE == 2) { int kt = min(K, m0 + BM); Keff = kt / gridDim.z; kOff = blockIdx.z * Keff; }
    if (MODE == 3) { Keff = K / gridDim.z; kOff = blockIdx.z * Keff; }
    const int T = Keff / BK;

    const int tid  = threadIdx.x;
    const int lane = tid & 31;
    const int warp = tid >> 5;
    const int wm = warp & 3;
    const int wn = warp >> 2;
    const int l7 = lane & 7, q1 = (lane >> 3) & 1, q2 = lane >> 4;

    auto load_tile = [&](int t, int s) {
        const int k0 = kOff + t * BK;
        f16* sb = smem + s * STAGE;
        #pragma unroll
        for (int i = 0; i < 2; i++) {      // A: 128 rows x 4 16B-chunks
            int f = tid + 256 * i;
            int r = f >> 2;
            int c = f & 3;
            cpa16((uint32_t)__cvta_generic_to_shared(sb + r*ASTR + c*8),
                  A + (size_t)(m0 + r) * K + k0 + c*8);
        }
        #pragma unroll
        for (int i = 0; i < 2; i++) {      // B: 128 n-rows x 4 chunks
            int f = tid + 256 * i;
            int r = f >> 2;
            int c = f & 3;
            cpa16((uint32_t)__cvta_generic_to_shared(sb + A_PART + r*BSTR + c*8),
                  P.B + (size_t)(n0 + r) * K + k0 + c*8);
        }
    };

    float acc[MT][NT][4];
    #pragma unroll
    for (int mt = 0; mt < MT; mt++)
        #pragma unroll
        for (int nt = 0; nt < NT; nt++)
            #pragma unroll
            for (int i = 0; i < 4; i++) acc[mt][nt][i] = 0.f;

    const uint32_t smemBase = (uint32_t)__cvta_generic_to_shared(smem);
    const uint32_t aoff = (uint32_t)(((wm*MT*16 + l7 + q1*8) * ASTR + q2*8) * 2);
    const uint32_t boff = (uint32_t)((A_PART + (wn*64 + l7 + q2*8) * BSTR + q1*8) * 2);

    load_tile(0, 0); cpcommit();
    if (T > 1) load_tile(1, 1);
    cpcommit();

    for (int t = 0; t < T; t++) {
        cpwait<1>();
        __syncthreads();
        if (t + 2 < T) { load_tile(t + 2, (t + 2) % ST); }
        cpcommit();

        const uint32_t sbase = smemBase + (uint32_t)((t % ST) * STAGE * 2);

        #pragma unroll
        for (int ks = 0; ks < 2; ks++) {
            uint32_t a[MT][4], b[NT][2];
            #pragma unroll
            for (int mt = 0; mt < MT; mt++)
                ldsm4(a[mt], sbase + aoff + (uint32_t)(mt*16*ASTR*2 + ks*32));
            #pragma unroll
            for (int p = 0; p < 4; p++) {
                uint32_t r4[4];
                ldsm4(r4, sbase + boff + (uint32_t)(p*16*BSTR*2 + ks*32));
                b[2*p][0]   = r4[0]; b[2*p][1]   = r4[1];
                b[2*p+1][0] = r4[2]; b[2*p+1][1] = r4[3];
            }
            #pragma unroll
            for (int nt = 0; nt < NT; nt++)
                #pragma unroll
                for (int mt = 0; mt < MT; mt++)
                    mma16816h(acc[mt][nt], a[mt], b[nt]);
        }
    }

    // fold alpha + bias
    #pragma unroll
    for (int mt = 0; mt < MT; mt++)
        #pragma unroll
        for (int nt = 0; nt < NT; nt++) {
            int col = n0 + wn*64 + nt*8 + ((lane & 3) << 1);
            float b0 = 0.f, b1 = 0.f;
            if (bias) { b0 = bias[col]; b1 = bias[col + 1]; }
            acc[mt][nt][0] = acc[mt][nt][0] * alpha + b0;
            acc[mt][nt][1] = acc[mt][nt][1] * alpha + b1;
            acc[mt][nt][2] = acc[mt][nt][2] * alpha + b0;
            acc[mt][nt][3] = acc[mt][nt][3] * alpha + b1;
        }

    #pragma unroll
    for (int mt = 0; mt < MT; mt++) {
        int row0 = m0 + wm*MT*16 + mt*16 + (lane >> 2);
        #pragma unroll
        for (int nt = 0; nt < NT; nt++) {
            int col = n0 + wn*64 + nt*8 + ((lane & 3) << 1);
            if (C) {
                *(float2*)(C + (size_t)row0 * N + col)       = float2{acc[mt][nt][0], acc[mt][nt][1]};
                *(float2*)(C + (size_t)(row0 + 8) * N + col) = float2{acc[mt][nt][2], acc[mt][nt][3]};
            }
            if (Ch) {
                *(f162*)(Ch + (size_t)row0 * N + col) =
                    __floats2half2_rn(acc[mt][nt][0], acc[mt][nt][1]);
                *(f162*)(Ch + (size_t)(row0 + 8) * N + col) =
                    __floats2half2_rn(acc[mt][nt][2], acc[mt][nt][3]);
            }
        }
    }

    if (STATS) {
        __syncthreads();
        float* sm_m = (float*)smem;
        float* sm_s = sm_m + 256;
        #pragma unroll
        for (int mt = 0; mt < MT; mt++) {
            float mA = -1e30f, mB = -1e30f;
            #pragma unroll
            for (int nt = 0; nt < NT; nt++) {
                mA = fmaxf(mA, fmaxf(acc[mt][nt][0], acc[mt][nt][1]));
                mB = fmaxf(mB, fmaxf(acc[mt][nt][2], acc[mt][nt][3]));
            }
            mA = fmaxf(mA, __shfl_xor_sync(0xffffffffu, mA, 1));
            mA = fmaxf(mA, __shfl_xor_sync(0xffffffffu, mA, 2));
            mB = fmaxf(mB, __shfl_xor_sync(0xffffffffu, mB, 1));
            mB = fmaxf(mB, __shfl_xor_sync(0xffffffffu, mB, 2));
            float sA = 0.f, sB = 0.f;
            #pragma unroll
            for (int nt = 0; nt < NT; nt++) {
                sA += __expf(acc[mt][nt][0] - mA) + __expf(acc[mt][nt][1] - mA);
                sB += __expf(acc[mt][nt][2] - mB) + __expf(acc[mt][nt][3] - mB);
            }
            sA += __shfl_xor_sync(0xffffffffu, sA, 1);
            sA += __shfl_xor_sync(0xffffffffu, sA, 2);
            sB += __shfl_xor_sync(0xffffffffu, sB, 1);
            sB += __shfl_xor_sync(0xffffffffu, sB, 2);
            if ((lane & 3) == 0) {
                int r = wm*32 + mt*16 + (lane >> 2);
                sm_m[r*2 + wn]     = mA;  sm_s[r*2 + wn]     = sA;
                sm_m[(r+8)*2 + wn] = mB;  sm_s[(r+8)*2 + wn] = sB;
            }
        }
        __syncthreads();
        if (tid < 128) {
            float m1 = sm_m[tid*2], m2 = sm_m[tid*2 + 1];
            float Mx = fmaxf(m1, m2);
            float S  = sm_s[tid*2] * __expf(m1 - Mx) + sm_s[tid*2 + 1] * __expf(m2 - Mx);
            int nb = N >> 7;
            smax[(size_t)(m0 + tid) * nb + (n0 >> 7)] = Mx;
            ssum[(size_t)(m0 + tid) * nb + (n0 >> 7)] = S;
        }
    }
}

// ------------------------- warp-per-row causal softmax (fp32 -> fp16) ------
__global__ void __launch_bounds__(256)
softmax_causal_warp(const float* __restrict__ att, f16* __restrict__ oh)
{
    const int warp = threadIdx.x >> 5;
    const int lane = threadIdx.x & 31;
    const int r = blockIdx.x * 8 + warp;
    const float* row = att + (size_t)r * SQ;
    f16* rh = oh + (size_t)r * SQ;
    const int n = r + 1;
    const int fillEnd = ((r >> 7) + 1) << 7;

    float m = -1e30f;
    for (int j = lane * 4; j < fillEnd; j += 128) {
        float4 v = *(const float4*)(row + j);
        if (j + 0 < n) m = fmaxf(m, v.x);
        if (j + 1 < n) m = fmaxf(m, v.y);
        if (j + 2 < n) m = fmaxf(m, v.z);
        if (j + 3 < n) m = fmaxf(m, v.w);
    }
    #pragma unroll
    for (int st = 16; st > 0; st >>= 1)
        m = fmaxf(m, __shfl_xor_sync(0xffffffffu, m, st));

    float s = 0.f;
    for (int j = lane * 4; j < fillEnd; j += 128) {
        float4 v = *(const float4*)(row + j);
        if (j + 0 < n) s += __expf(v.x - m);
        if (j + 1 < n) s += __expf(v.y - m);
        if (j + 2 < n) s += __expf(v.z - m);
        if (j + 3 < n) s += __expf(v.w - m);
    }
    #pragma unroll
    for (int st = 16; st > 0; st >>= 1)
        s += __shfl_xor_sync(0xffffffffu, s, st);
    const float inv = 1.f / s;

    for (int j = lane * 4; j < fillEnd; j += 128) {
        float4 v = *(const float4*)(row + j);
        float e0 = (j + 0 < n) ? __expf(v.x - m) * inv : 0.f;
        float e1 = (j + 1 < n) ? __expf(v.y - m) * inv : 0.f;
        float e2 = (j + 2 < n) ? __expf(v.z - m) * inv : 0.f;
        float e3 = (j + 3 < n) ? __expf(v.w - m) * inv : 0.f;
        f162 o[2];
        o[0] = __floats2half2_rn(e0, e1);
        o[1] = __floats2half2_rn(e2, e3);
        *(uint2*)(rh + j) = *(const uint2*)o;
    }
}

// ------------------------- warp-per-row 4-partial add + LN -----------------
// x = LN(a0+a1+a2+a3 + res); outputs fp32 residual + fp16 GEMM operand.
__global__ void __launch_bounds__(256)
add_ln_warp(const float* __restrict__ a0, const float* __restrict__ a1,
            const float* __restrict__ a2, const float* __restrict__ a3,
            const float* __restrict__ res,
            const float* __restrict__ g, const float* __restrict__ beta,
            float* __restrict__ out, f16* __restrict__ xh)
{
    const int warp = threadIdx.x >> 5;
    const int lane = threadIdx.x & 31;
    const int r = blockIdx.x * 8 + warp;
    const size_t base = (size_t)r * DM;

    float v[16];
    float sum = 0.f;
    #pragma unroll
    for (int k = 0; k < 4; k++) {
        int j = lane * 4 + k * 128;
        float4 va = *(const float4*)(a0 + base + j);
        float4 v1 = *(const float4*)(a1 + base + j);
        float4 v2 = *(const float4*)(a2 + base + j);
        float4 v3 = *(const float4*)(a3 + base + j);
        float4 vr = *(const float4*)(res + base + j);
        va.x += v1.x + v2.x + v3.x + vr.x;
        va.y += v1.y + v2.y + v3.y + vr.y;
        va.z += v1.z + v2.z + v3.z + vr.z;
        va.w += v1.w + v2.w + v3.w + vr.w;
        v[k*4+0] = va.x; v[k*4+1] = va.y; v[k*4+2] = va.z; v[k*4+3] = va.w;
        sum += va.x + va.y + va.z + va.w;
    }
    #pragma unroll
    for (int st = 16; st > 0; st >>= 1)
        sum += __shfl_xor_sync(0xffffffffu, sum, st);
    const float mu = sum * (1.0f / DM);

    float var = 0.f;
    #pragma unroll
    for (int k = 0; k < 16; k++) {
        float d = v[k] - mu;
        v[k] = d;
        var += d * d;
    }
    #pragma unroll
    for (int st = 16; st > 0; st >>= 1)
        var += __shfl_xor_sync(0xffffffffu, var, st);
    const float rstd = rsqrtf(var * (1.0f / DM) + LN_EPS);

    #pragma unroll
    for (int k = 0; k < 4; k++) {
        int j = lane * 4 + k * 128;
        float4 vg = *(const float4*)(g + j);
        float4 vb = *(const float4*)(beta + j);
        float o0 = v[k*4+0] * rstd * vg.x + vb.x;
        float o1 = v[k*4+1] * rstd * vg.y + vb.y;
        float o2 = v[k*4+2] * rstd * vg.z + vb.z;
        float o3 = v[k*4+3] * rstd * vg.w + vb.w;
        *(float4*)(out + base + j) = float4{o0, o1, o2, o3};
        f162 o[2];
        o[0] = __floats2half2_rn(o0, o1);
        o[1] = __floats2half2_rn(o2, o3);
        *(uint2*)(xh + base + j) = *(const uint2*)o;
    }
}

// ------------------------- vocab softmax via GEMM partials -----------------
__global__ void softmax_vocab_kernel(float* __restrict__ x,
                                     const float* __restrict__ smax,
                                     const float* __restrict__ ssum)
{
    const int i = blockIdx.x;
    float* row = x + (size_t)i * VOC;
    const int tid = threadIdx.x;

    __shared__ float mRed[256];
    __shared__ float sRed[256];

    float m = -1e30f, s = 0.f;
    if (tid < NBV) {
        m = smax[(size_t)i * NBV + tid];
        s = ssum[(size_t)i * NBV + tid];
    }
    mRed[tid] = m; sRed[tid] = s; __syncthreads();
    for (int st = 128; st > 0; st >>= 1) {
        if (tid < st) {
            float m1 = mRed[tid], m2 = mRed[tid + st];
            float Mx = fmaxf(m1, m2);
            sRed[tid] = sRed[tid] * __expf(m1 - Mx) + sRed[tid + st] * __expf(m2 - Mx);
            mRed[tid] = Mx;
        }
        __syncthreads();
    }
    const float M = mRed[0];
    const float inv = 1.f / sRed[0];

    for (int j = tid * 4; j < VOC; j += 1024) {
        float4 v = *(const float4*)(row + j);
        v.x = __expf(v.x - M) * inv;
        v.y = __expf(v.y - M) * inv;
        v.z = __expf(v.z - M) * inv;
        v.w = __expf(v.w - M) * inv;
        *(float4*)(row + j) = v;
    }
}

// ------------------------- host side ---------------------------------------
#define SMEM_H 61440   // 3 stages x 20480 B

extern "C" void kernel_launch(void* const* d_in, const int* in_sizes, int n_in,
                              void* d_out, int out_size)
{
    const float* x   = (const float*)d_in[0];
    const float* Wq  = (const float*)d_in[1];
    const float* bq  = (const float*)d_in[2];
    const float* Wk  = (const float*)d_in[3];
    const float* bk  = (const float*)d_in[4];
    const float* Wv  = (const float*)d_in[5];
    const float* bv  = (const float*)d_in[6];
    const float* Wp  = (const float*)d_in[7];
    const float* bp  = (const float*)d_in[8];
    const float* g1  = (const float*)d_in[9];
    const float* be1 = (const float*)d_in[10];
    const float* W1  = (const float*)d_in[11];
    const float* b1  = (const float*)d_in[12];
    const float* W2  = (const float*)d_in[13];
    const float* b2  = (const float*)d_in[14];
    const float* g2  = (const float*)d_in[15];
    const float* be2 = (const float*)d_in[16];
    const float* Wf  = (const float*)d_in[17];
    const float* bf  = (const float*)d_in[18];
    float* out = (float*)d_out;

    cudaFuncSetAttribute(gemm_fp16<0,0>, cudaFuncAttributeMaxDynamicSharedMemorySize, SMEM_H);
    cudaFuncSetAttribute(gemm_fp16<1,0>, cudaFuncAttributeMaxDynamicSharedMemorySize, SMEM_H);
    cudaFuncSetAttribute(gemm_fp16<2,0>, cudaFuncAttributeMaxDynamicSharedMemorySize, SMEM_H);
    cudaFuncSetAttribute(gemm_fp16<3,0>, cudaFuncAttributeMaxDynamicSharedMemorySize, SMEM_H);
    cudaFuncSetAttribute(gemm_fp16<0,1>, cudaFuncAttributeMaxDynamicSharedMemorySize, SMEM_H);

    float *px, *px2, *patt, *pc0, *pc1, *pc2, *pc3, *psmax, *pssum;
    cudaGetSymbolAddress((void**)&px,    g_x);
    cudaGetSymbolAddress((void**)&px2,   g_x2);
    cudaGetSymbolAddress((void**)&patt,  g_att);
    cudaGetSymbolAddress((void**)&pc0,   g_c0);
    cudaGetSymbolAddress((void**)&pc1,   g_c1);
    cudaGetSymbolAddress((void**)&pc2,   g_c2);
    cudaGetSymbolAddress((void**)&pc3,   g_c3);
    cudaGetSymbolAddress((void**)&psmax, g_smax);
    cudaGetSymbolAddress((void**)&pssum, g_ssum);

    f16 *pxh, *px2h, *pq, *pk, *pv, *pvt, *path, *pt, *ph;
    f16 *pwqt, *pwkt, *pwvt, *pwpt, *pw1t, *pw2t, *pwft;
    cudaGetSymbolAddress((void**)&pxh,  g_xh);
    cudaGetSymbolAddress((void**)&px2h, g_x2h);
    cudaGetSymbolAddress((void**)&pq,   g_q);
    cudaGetSymbolAddress((void**)&pk,   g_k);
    cudaGetSymbolAddress((void**)&pv,   g_v);
    cudaGetSymbolAddress((void**)&pvt,  g_vt);
    cudaGetSymbolAddress((void**)&path, g_ath);
    cudaGetSymbolAddress((void**)&pt,   g_t);
    cudaGetSymbolAddress((void**)&ph,   g_h);
    cudaGetSymbolAddress((void**)&pwqt, g_wqt);
    cudaGetSymbolAddress((void**)&pwkt, g_wkt);
    cudaGetSymbolAddress((void**)&pwvt, g_wvt);
    cudaGetSymbolAddress((void**)&pwpt, g_wpt);
    cudaGetSymbolAddress((void**)&pw1t, g_w1t);
    cudaGetSymbolAddress((void**)&pw2t, g_w2t);
    cudaGetSymbolAddress((void**)&pwft, g_wft);

    const float scale = 1.0f / sqrtf((float)FF);
    dim3 tb(32, 8);
    HP z{nullptr, nullptr, nullptr, nullptr};

    // preprocessing needed for first QKV
    f32_to_f16_kernel<<<(SQ*DM)/2048, 256>>>(x, pxh, SQ*DM);
    transpose_f16_kernel<<<dim3(FF/32, DM/32, NL), tb>>>(Wq, pwqt, DM, FF);
    transpose_f16_kernel<<<dim3(FF/32, DM/32, NL), tb>>>(Wk, pwkt, DM, FF);
    transpose_f16_kernel<<<dim3(FF/32, DM/32, NL), tb>>>(Wv, pwvt, DM, FF);

    bool firstLayer = true;
    for (int l = 0; l < NL; l++) {
        size_t wOff = (size_t)l * DM * FF;

        // QKV (batched over z) -> fp16 q,k,v
        {
            HP pQ{pwqt + wOff, bq + (size_t)l*FF, nullptr, pq};
            HP pK{pwkt + wOff, bk + (size_t)l*FF, nullptr, pk};
            HP pV{pwvt + wOff, bv + (size_t)l*FF, nullptr, pv};
            gemm_fp16<0,0><<<dim3(SQ/128, FF/128, 3), 256, SMEM_H>>>(
                pxh, pQ, pK, pV, z, nullptr, nullptr, SQ, FF, DM, 1.f);
        }
        // scores = q @ k^T * scale (causal skip) -> fp32
        {
            HP p{pk, nullptr, patt, nullptr};
            gemm_fp16<1,0><<<dim3(SQ/128, SQ/128, 1), 256, SMEM_H>>>(
                pq, p, z, z, z, nullptr, nullptr, SQ, SQ, FF, scale);
        }
        if (firstLayer) {   // deferred preprocessing (overlaps with above)
            transpose_f16_kernel<<<dim3(FF/32, FF/32, NL),  tb>>>(Wp, pwpt, FF,  FF);
            transpose_f16_kernel<<<dim3(HID/32, FF/32, NL), tb>>>(W1, pw1t, FF,  HID);
            transpose_f16_kernel<<<dim3(DM/32, HID/32, NL), tb>>>(W2, pw2t, HID, DM);
            transpose_f16_kernel<<<dim3(VOC/32, DM/32, 1),  tb>>>(Wf, pwft, DM,  VOC);
            firstLayer = false;
        }
        // V^T for att@V
        transpose_h2h_kernel<<<dim3(FF/32, SQ/32), tb>>>(pv, pvt, SQ, FF);
        // causal softmax -> fp16 probs
        softmax_causal_warp<<<SQ/8, 256>>>(patt, path);
        // t = att @ V  (K bounded at m0+128, split-K=4)
        {
            HP pA{pvt, nullptr, pc0, nullptr};
            HP pB{nullptr, nullptr, pc1, nullptr};
            HP pC{nullptr, nullptr, pc2, nullptr};
            HP pD{nullptr, nullptr, pc3, nullptr};
            gemm_fp16<2,0><<<dim3(SQ/128, FF/128, 4), 256, SMEM_H>>>(
                path, pA, pB, pC, pD, nullptr, nullptr, SQ, FF, SQ, 1.f);
        }
        add4_f16_kernel<<<(SQ*FF)/1024, 256>>>(pc0, pc1, pc2, pc3, pt, SQ*FF);
        // z = t @ Wp + bp (split-K=4, partials -> LN1)
        {
            HP pA{pwpt + (size_t)l*FF*FF, bp + (size_t)l*FF, pc0, nullptr};
            HP pB{nullptr, nullptr, pc1, nullptr};
            HP pC{nullptr, nullptr, pc2, nullptr};
            HP pD{nullptr, nullptr, pc3, nullptr};
            gemm_fp16<3,0><<<dim3(SQ/128, FF/128, 4), 256, SMEM_H>>>(
                pt, pA, pB, pC, pD, nullptr, nullptr, SQ, FF, FF, 1.f);
        }
        add_ln_warp<<<SQ/8, 256>>>(pc0, pc1, pc2, pc3, (l == 0) ? x : px,
                                   g1 + (size_t)l*FF, be1 + (size_t)l*FF,
                                   px2, px2h);
        // h = x2 @ W1 + b1 -> fp16
        {
            HP p{pw1t + (size_t)l*HID*FF, b1 + (size_t)l*HID, nullptr, ph};
            gemm_fp16<0,0><<<dim3(SQ/128, HID/128, 1), 256, SMEM_H>>>(
                px2h, p, z, z, z, nullptr, nullptr, SQ, HID, FF, 1.f);
        }
        // h2 = h @ W2 + b2 (split-K=4)
        {
            HP pA{pw2t + (size_t)l*DM*HID, b2 + (size_t)l*DM, pc0, nullptr};
            HP pB{nullptr, nullptr, pc1, nullptr};
            HP pC{nullptr, nullptr, pc2, nullptr};
            HP pD{nullptr, nullptr, pc3, nullptr};
            gemm_fp16<3,0><<<dim3(SQ/128, DM/128, 4), 256, SMEM_H>>>(
                ph, pA, pB, pC, pD, nullptr, nullptr, SQ, DM, HID, 1.f);
        }
        add_ln_warp<<<SQ/8, 256>>>(pc0, pc1, pc2, pc3, px2,
                                   g2 + (size_t)l*DM, be2 + (size_t)l*DM,
                                   px, pxh);
    }

    // logits (fused softmax partials) + 1-pass vocab softmax
    {
        HP p{pwft, bf, out, nullptr};
        gemm_fp16<0,1><<<dim3(SQ/128, VOC/128, 1), 256, SMEM_H>>>(
            pxh, p, z, z, z, psmax, pssum, SQ, VOC, DM, 1.f);
    }
    softmax_vocab_kernel<<<SQ, 256>>>(out, psmax, pssum);

    (void)in_sizes; (void)n_in; (void)out_size;
}

// round 14
// speedup vs baseline: 6.9520x; 1.0303x over previous
#include <cuda_runtime.h>
#include <cuda_fp16.h>
#include <cstdint>
#include <cmath>

#define SQ   2048
#define DM   512
#define FF   512
#define HID  2048
#define VOC  32000
#define NL   4
#define LN_EPS 1e-5f
#define NBV  (VOC/128)
#define NBS  (SQ/128)

typedef __half  f16;
typedef __half2 f162;

// ------------------------- fp32 scratch ------------------------------------
__device__ float g_x  [SQ * DM];
__device__ float g_x2 [SQ * DM];
__device__ float g_att[SQ * SQ];
__device__ float g_c0 [SQ * FF];
__device__ float g_c1 [SQ * FF];
__device__ float g_c2 [SQ * FF];
__device__ float g_c3 [SQ * FF];
__device__ float g_smax[SQ * NBV];    // reused for scores (stride 16) & logits (250)
__device__ float g_ssum[SQ * NBV];

// ------------------------- fp16 operands -----------------------------------
__device__ f16 g_xh [SQ*DM];
__device__ f16 g_x2h[SQ*DM];
__device__ f16 g_q  [SQ*FF];
__device__ f16 g_k  [SQ*FF];
__device__ f16 g_vt [FF*SQ];          // V^T, written directly by QKV epilogue
__device__ f16 g_ath[SQ*SQ];
__device__ f16 g_t  [SQ*FF];
__device__ f16 g_h  [SQ*HID];
__device__ f16 g_wqt[(size_t)NL * FF * DM];
__device__ f16 g_wkt[(size_t)NL * FF * DM];
__device__ f16 g_wvt[(size_t)NL * FF * DM];
__device__ f16 g_wpt[(size_t)NL * FF * FF];
__device__ f16 g_w1t[(size_t)NL * HID * FF];
__device__ f16 g_w2t[(size_t)NL * DM * HID];
__device__ f16 g_wft[(size_t)VOC * DM];

// ------------------------- PTX helpers -------------------------------------
__device__ __forceinline__ void ldsm4(uint32_t* r, uint32_t addr) {
    asm volatile("ldmatrix.sync.aligned.m8n8.x4.shared.b16 {%0,%1,%2,%3}, [%4];"
                 : "=r"(r[0]), "=r"(r[1]), "=r"(r[2]), "=r"(r[3]) : "r"(addr));
}
__device__ __forceinline__ void mma16816h(float* c, const uint32_t* a, const uint32_t* b) {
    asm volatile("mma.sync.aligned.m16n8k16.row.col.f32.f16.f16.f32 "
                 "{%0,%1,%2,%3}, {%4,%5,%6,%7}, {%8,%9}, {%0,%1,%2,%3};"
                 : "+f"(c[0]), "+f"(c[1]), "+f"(c[2]), "+f"(c[3])
                 : "r"(a[0]), "r"(a[1]), "r"(a[2]), "r"(a[3]),
                   "r"(b[0]), "r"(b[1]));
}
__device__ __forceinline__ void cpa16(uint32_t s, const void* g) {
    asm volatile("cp.async.cg.shared.global [%0], [%1], 16;\n" :: "r"(s), "l"(g));
}
__device__ __forceinline__ void cpcommit() { asm volatile("cp.async.commit_group;\n"); }
template<int N> __device__ __forceinline__ void cpwait() {
    asm volatile("cp.async.wait_group %0;\n" :: "n"(N));
}

// ------------------------- utility kernels ---------------------------------
__global__ void f32_to_f16_kernel(const float* __restrict__ in,
                                  f16* __restrict__ out, int n)
{
    int i = (blockIdx.x * blockDim.x + threadIdx.x) * 8;
    if (i >= n) return;
    float4 a = *(const float4*)(in + i);
    float4 b = *(const float4*)(in + i + 4);
    f162 o[4];
    o[0] = __floats2half2_rn(a.x, a.y);
    o[1] = __floats2half2_rn(a.z, a.w);
    o[2] = __floats2half2_rn(b.x, b.y);
    o[3] = __floats2half2_rn(b.z, b.w);
    *(uint4*)(out + i) = *(const uint4*)o;
}

__global__ void transpose_f16_kernel(const float* __restrict__ in,
                                     f16* __restrict__ out, int Kd, int Nd)
{
    __shared__ float t[32][33];
    const size_t off = (size_t)blockIdx.z * Kd * Nd;
    const int n0 = blockIdx.x * 32, k0 = blockIdx.y * 32;
    const int tx = threadIdx.x, ty = threadIdx.y;
    #pragma unroll
    for (int i = 0; i < 4; i++)
        t[ty + 8*i][tx] = in[off + (size_t)(k0 + ty + 8*i) * Nd + n0 + tx];
    __syncthreads();
    #pragma unroll
    for (int i = 0; i < 4; i++)
        out[off + (size_t)(n0 + ty + 8*i) * Kd + k0 + tx] = __float2half_rn(t[tx][ty + 8*i]);
}

__global__ void add4_f16_kernel(const float* __restrict__ a0, const float* __restrict__ a1,
                                const float* __restrict__ a2, const float* __restrict__ a3,
                                f16* __restrict__ out, int n)
{
    int i = (blockIdx.x * blockDim.x + threadIdx.x) * 4;
    if (i >= n) return;
    float4 v0 = *(const float4*)(a0 + i);
    float4 v1 = *(const float4*)(a1 + i);
    float4 v2 = *(const float4*)(a2 + i);
    float4 v3 = *(const float4*)(a3 + i);
    f162 o[2];
    o[0] = __floats2half2_rn(v0.x + v1.x + v2.x + v3.x, v0.y + v1.y + v2.y + v3.y);
    o[1] = __floats2half2_rn(v0.z + v1.z + v2.z + v3.z, v0.w + v1.w + v2.w + v3.w);
    *(uint2*)(out + i) = *(const uint2*)o;
}

struct HP { const f16* B; const float* bias; float* C; f16* Ch; int transC; };

// ------------------------- unified fp16 GEMM -------------------------------
// C = alpha * A @ B^T + bias.  A [M,K] fp16; B [N,K] fp16; fp32 accumulate.
// MODE 0: z batches {p0,p1,p2}.  MODE 1: causal block-skip.
// MODE 2: K bounded at m0+128, split over z.  MODE 3: split-K over z.
// STATS 0: none; 1: softmax partials (logits); 2: causal-masked partials.
template<int MODE, int STATS, int BK>
__global__ void __launch_bounds__(256, 2)
gemm_fp16(const f16* __restrict__ A, HP p0, HP p1, HP p2, HP p3,
          float* __restrict__ smax, float* __restrict__ ssum,
          int M, int N, int K, float alpha)
{
    constexpr int BM = 128, BN = 128, ST = 3;
    constexpr int ASTR = BK + 8;
    constexpr int A_PART = BM * ASTR;
    constexpr int BSTR = BK + 8;
    constexpr int B_PART = BN * BSTR;
    constexpr int STAGE = A_PART + B_PART;
    constexpr int MT = 2;
    constexpr int NT = 8;
    constexpr int CHUNKS = BK / 8;       // 16B chunks per row
    constexpr int LD_IT = (BM * CHUNKS) / 256;

    extern __shared__ f16 smem[];

    const int m0 = blockIdx.x * BM;
    const int n0 = blockIdx.y * BN;
    if (MODE == 1 && n0 > m0) return;

    HP P = p0;
    if (MODE == 0)
        P = (blockIdx.z == 0) ? p0 : ((blockIdx.z == 1) ? p1 : p2);
    float* C  = P.C;
    f16*   Ch = P.Ch;
    if (MODE >= 2) {
        C = (blockIdx.z == 0) ? p0.C : (blockIdx.z == 1) ? p1.C
          : (blockIdx.z == 2) ? p2.C : p3.C;
        Ch = nullptr;
    }
    const float* bias = P.bias;
    if (MODE >= 2 && blockIdx.z != 0) bias = nullptr;

    int Keff = K, kOff = 0;
    if (MODE == 2) { int kt = min(K, m0 + BM); Keff = kt / gridDim.z; kOff = blockIdx.z * Keff; }
    if (MODE == 3) { Keff = K / gridDim.z; kOff = blockIdx.z * Keff; }
    const int T = Keff / BK;

    const int tid  = threadIdx.x;
    const int lane = tid & 31;
    const int warp = tid >> 5;
    const int wm = warp & 3;
    const int wn = warp >> 2;
    const int l7 = lane & 7, q1 = (lane >> 3) & 1, q2 = lane >> 4;

    auto load_tile = [&](int t, int s) {
        const int k0 = kOff + t * BK;
        f16* sb = smem + s * STAGE;
        #pragma unroll
        for (int i = 0; i < LD_IT; i++) {
            int f = tid + 256 * i;
            int r = f / CHUNKS;
            int c = f % CHUNKS;
            cpa16((uint32_t)__cvta_generic_to_shared(sb + r*ASTR + c*8),
                  A + (size_t)(m0 + r) * K + k0 + c*8);
        }
        #pragma unroll
        for (int i = 0; i < LD_IT; i++) {
            int f = tid + 256 * i;
            int r = f / CHUNKS;
            int c = f % CHUNKS;
            cpa16((uint32_t)__cvta_generic_to_shared(sb + A_PART + r*BSTR + c*8),
                  P.B + (size_t)(n0 + r) * K + k0 + c*8);
        }
    };

    float acc[MT][NT][4];
    #pragma unroll
    for (int mt = 0; mt < MT; mt++)
        #pragma unroll
        for (int nt = 0; nt < NT; nt++)
            #pragma unroll
            for (int i = 0; i < 4; i++) acc[mt][nt][i] = 0.f;

    const uint32_t smemBase = (uint32_t)__cvta_generic_to_shared(smem);
    const uint32_t aoff = (uint32_t)(((wm*MT*16 + l7 + q1*8) * ASTR + q2*8) * 2);
    const uint32_t boff = (uint32_t)((A_PART + (wn*64 + l7 + q2*8) * BSTR + q1*8) * 2);

    load_tile(0, 0); cpcommit();
    if (T > 1) load_tile(1, 1);
    cpcommit();

    for (int t = 0; t < T; t++) {
        cpwait<1>();
        __syncthreads();
        if (t + 2 < T) { load_tile(t + 2, (t + 2) % ST); }
        cpcommit();

        const uint32_t sbase = smemBase + (uint32_t)((t % ST) * STAGE * 2);

        #pragma unroll
        for (int ks = 0; ks < BK/16; ks++) {
            uint32_t a[MT][4], b[NT][2];
            #pragma unroll
            for (int mt = 0; mt < MT; mt++)
                ldsm4(a[mt], sbase + aoff + (uint32_t)(mt*16*ASTR*2 + ks*32));
            #pragma unroll
            for (int p = 0; p < 4; p++) {
                uint32_t r4[4];
                ldsm4(r4, sbase + boff + (uint32_t)(p*16*BSTR*2 + ks*32));
                b[2*p][0]   = r4[0]; b[2*p][1]   = r4[1];
                b[2*p+1][0] = r4[2]; b[2*p+1][1] = r4[3];
            }
            #pragma unroll
            for (int nt = 0; nt < NT; nt++)
                #pragma unroll
                for (int mt = 0; mt < MT; mt++)
                    mma16816h(acc[mt][nt], a[mt], b[nt]);
        }
    }

    // fold alpha + bias
    #pragma unroll
    for (int mt = 0; mt < MT; mt++)
        #pragma unroll
        for (int nt = 0; nt < NT; nt++) {
            int col = n0 + wn*64 + nt*8 + ((lane & 3) << 1);
            float b0 = 0.f, b1 = 0.f;
            if (bias) { b0 = bias[col]; b1 = bias[col + 1]; }
            acc[mt][nt][0] = acc[mt][nt][0] * alpha + b0;
            acc[mt][nt][1] = acc[mt][nt][1] * alpha + b1;
            acc[mt][nt][2] = acc[mt][nt][2] * alpha + b0;
            acc[mt][nt][3] = acc[mt][nt][3] * alpha + b1;
        }

    #pragma unroll
    for (int mt = 0; mt < MT; mt++) {
        int row0 = m0 + wm*MT*16 + mt*16 + (lane >> 2);
        #pragma unroll
        for (int nt = 0; nt < NT; nt++) {
            int col = n0 + wn*64 + nt*8 + ((lane & 3) << 1);
            if (C) {
                *(float2*)(C + (size_t)row0 * N + col)       = float2{acc[mt][nt][0], acc[mt][nt][1]};
                *(float2*)(C + (size_t)(row0 + 8) * N + col) = float2{acc[mt][nt][2], acc[mt][nt][3]};
            }
            if (Ch) {
                if (!P.transC) {
                    *(f162*)(Ch + (size_t)row0 * N + col) =
                        __floats2half2_rn(acc[mt][nt][0], acc[mt][nt][1]);
                    *(f162*)(Ch + (size_t)(row0 + 8) * N + col) =
                        __floats2half2_rn(acc[mt][nt][2], acc[mt][nt][3]);
                } else {   // transposed [N, M]
                    Ch[(size_t)col       * M + row0]     = __float2half_rn(acc[mt][nt][0]);
                    Ch[(size_t)(col + 1) * M + row0]     = __float2half_rn(acc[mt][nt][1]);
                    Ch[(size_t)col       * M + row0 + 8] = __float2half_rn(acc[mt][nt][2]);
                    Ch[(size_t)(col + 1) * M + row0 + 8] = __float2half_rn(acc[mt][nt][3]);
                }
            }
        }
    }

    if (STATS) {
        const bool diag = (STATS == 2) && (n0 == m0);
        __syncthreads();
        float* sm_m = (float*)smem;
        float* sm_s = sm_m + 256;
        #pragma unroll
        for (int mt = 0; mt < MT; mt++) {
            int rA = m0 + wm*32 + mt*16 + (lane >> 2);
            int rB = rA + 8;
            float mA = -1e30f, mB = -1e30f;
            #pragma unroll
            for (int nt = 0; nt < NT; nt++) {
                int col = n0 + wn*64 + nt*8 + ((lane & 3) << 1);
                float vA0 = acc[mt][nt][0], vA1 = acc[mt][nt][1];
                float vB0 = acc[mt][nt][2], vB1 = acc[mt][nt][3];
                if (diag) {
                    if (col     > rA) vA0 = -1e30f;
                    if (col + 1 > rA) vA1 = -1e30f;
                    if (col     > rB) vB0 = -1e30f;
                    if (col + 1 > rB) vB1 = -1e30f;
                }
                mA = fmaxf(mA, fmaxf(vA0, vA1));
                mB = fmaxf(mB, fmaxf(vB0, vB1));
            }
            mA = fmaxf(mA, __shfl_xor_sync(0xffffffffu, mA, 1));
            mA = fmaxf(mA, __shfl_xor_sync(0xffffffffu, mA, 2));
            mB = fmaxf(mB, __shfl_xor_sync(0xffffffffu, mB, 1));
            mB = fmaxf(mB, __shfl_xor_sync(0xffffffffu, mB, 2));
            float sA = 0.f, sB = 0.f;
            #pragma unroll
            for (int nt = 0; nt < NT; nt++) {
                int col = n0 + wn*64 + nt*8 + ((lane & 3) << 1);
                if (!diag || col     <= rA) sA += __expf(acc[mt][nt][0] - mA);
                if (!diag || col + 1 <= rA) sA += __expf(acc[mt][nt][1] - mA);
                if (!diag || col     <= rB) sB += __expf(acc[mt][nt][2] - mB);
                if (!diag || col + 1 <= rB) sB += __expf(acc[mt][nt][3] - mB);
            }
            sA += __shfl_xor_sync(0xffffffffu, sA, 1);
            sA += __shfl_xor_sync(0xffffffffu, sA, 2);
            sB += __shfl_xor_sync(0xffffffffu, sB, 1);
            sB += __shfl_xor_sync(0xffffffffu, sB, 2);
            if ((lane & 3) == 0) {
                int r = wm*32 + mt*16 + (lane >> 2);
                sm_m[r*2 + wn]     = mA;  sm_s[r*2 + wn]     = sA;
                sm_m[(r+8)*2 + wn] = mB;  sm_s[(r+8)*2 + wn] = sB;
            }
        }
        __syncthreads();
        if (tid < 128) {
            float m1 = sm_m[tid*2], m2 = sm_m[tid*2 + 1];
            float Mx = fmaxf(m1, m2);
            float S  = sm_s[tid*2] * __expf(m1 - Mx) + sm_s[tid*2 + 1] * __expf(m2 - Mx);
            int nb = N >> 7;
            smax[(size_t)(m0 + tid) * nb + (n0 >> 7)] = Mx;
            ssum[(size_t)(m0 + tid) * nb + (n0 >> 7)] = S;
        }
    }
}

// ------------------------- causal softmax: combine partials + 1 pass -------
__global__ void __launch_bounds__(256)
softmax_causal_warp(const float* __restrict__ att, f16* __restrict__ oh,
                    const float* __restrict__ smax, const float* __restrict__ ssum)
{
    const int warp = threadIdx.x >> 5;
    const int lane = threadIdx.x & 31;
    const int r = blockIdx.x * 8 + warp;
    const float* row = att + (size_t)r * SQ;
    f16* rh = oh + (size_t)r * SQ;
    const int n = r + 1;
    const int nb = (r >> 7) + 1;
    const int fillEnd = nb << 7;

    // combine partials (<=16) across first nb lanes, then warp-reduce
    float m = -1e30f, s = 0.f;
    if (lane < nb) {
        m = smax[(size_t)r * NBS + lane];
        s = ssum[(size_t)r * NBS + lane];
    }
    #pragma unroll
    for (int st = 16; st > 0; st >>= 1) {
        float mo = __shfl_xor_sync(0xffffffffu, m, st);
        float so = __shfl_xor_sync(0xffffffffu, s, st);
        float Mx = fmaxf(m, mo);
        s = s * __expf(m - Mx) + so * __expf(mo - Mx);
        m = Mx;
    }
    const float inv = 1.f / s;

    for (int j = lane * 4; j < fillEnd; j += 128) {
        float4 v = *(const float4*)(row + j);
        float e0 = (j + 0 < n) ? __expf(v.x - m) * inv : 0.f;
        float e1 = (j + 1 < n) ? __expf(v.y - m) * inv : 0.f;
        float e2 = (j + 2 < n) ? __expf(v.z - m) * inv : 0.f;
        float e3 = (j + 3 < n) ? __expf(v.w - m) * inv : 0.f;
        f162 o[2];
        o[0] = __floats2half2_rn(e0, e1);
        o[1] = __floats2half2_rn(e2, e3);
        *(uint2*)(rh + j) = *(const uint2*)o;
    }
}

// ------------------------- warp-per-row 4-partial add + LN -----------------
__global__ void __launch_bounds__(256)
add_ln_warp(const float* __restrict__ a0, const float* __restrict__ a1,
            const float* __restrict__ a2, const float* __restrict__ a3,
            const float* __restrict__ res,
            const float* __restrict__ g, const float* __restrict__ beta,
            float* __restrict__ out, f16* __restrict__ xh)
{
    const int warp = threadIdx.x >> 5;
    const int lane = threadIdx.x & 31;
    const int r = blockIdx.x * 8 + warp;
    const size_t base = (size_t)r * DM;

    float v[16];
    float sum = 0.f;
    #pragma unroll
    for (int k = 0; k < 4; k++) {
        int j = lane * 4 + k * 128;
        float4 va = *(const float4*)(a0 + base + j);
        float4 v1 = *(const float4*)(a1 + base + j);
        float4 v2 = *(const float4*)(a2 + base + j);
        float4 v3 = *(const float4*)(a3 + base + j);
        float4 vr = *(const float4*)(res + base + j);
        va.x += v1.x + v2.x + v3.x + vr.x;
        va.y += v1.y + v2.y + v3.y + vr.y;
        va.z += v1.z + v2.z + v3.z + vr.z;
        va.w += v1.w + v2.w + v3.w + vr.w;
        v[k*4+0] = va.x; v[k*4+1] = va.y; v[k*4+2] = va.z; v[k*4+3] = va.w;
        sum += va.x + va.y + va.z + va.w;
    }
    #pragma unroll
    for (int st = 16; st > 0; st >>= 1)
        sum += __shfl_xor_sync(0xffffffffu, sum, st);
    const float mu = sum * (1.0f / DM);

    float var = 0.f;
    #pragma unroll
    for (int k = 0; k < 16; k++) {
        float d = v[k] - mu;
        v[k] = d;
        var += d * d;
    }
    #pragma unroll
    for (int st = 16; st > 0; st >>= 1)
        var += __shfl_xor_sync(0xffffffffu, var, st);
    const float rstd = rsqrtf(var * (1.0f / DM) + LN_EPS);

    #pragma unroll
    for (int k = 0; k < 4; k++) {
        int j = lane * 4 + k * 128;
        float4 vg = *(const float4*)(g + j);
        float4 vb = *(const float4*)(beta + j);
        float o0 = v[k*4+0] * rstd * vg.x + vb.x;
        float o1 = v[k*4+1] * rstd * vg.y + vb.y;
        float o2 = v[k*4+2] * rstd * vg.z + vb.z;
        float o3 = v[k*4+3] * rstd * vg.w + vb.w;
        *(float4*)(out + base + j) = float4{o0, o1, o2, o3};
        f162 o[2];
        o[0] = __floats2half2_rn(o0, o1);
        o[1] = __floats2half2_rn(o2, o3);
        *(uint2*)(xh + base + j) = *(const uint2*)o;
    }
}

// ------------------------- vocab softmax via GEMM partials -----------------
__global__ void softmax_vocab_kernel(float* __restrict__ x,
                                     const float* __restrict__ smax,
                                     const float* __restrict__ ssum)
{
    const int i = blockIdx.x;
    float* row = x + (size_t)i * VOC;
    const int tid = threadIdx.x;

    __shared__ float mRed[256];
    __shared__ float sRed[256];

    float m = -1e30f, s = 0.f;
    if (tid < NBV) {
        m = smax[(size_t)i * NBV + tid];
        s = ssum[(size_t)i * NBV + tid];
    }
    mRed[tid] = m; sRed[tid] = s; __syncthreads();
    for (int st = 128; st > 0; st >>= 1) {
        if (tid < st) {
            float m1 = mRed[tid], m2 = mRed[tid + st];
            float Mx = fmaxf(m1, m2);
            sRed[tid] = sRed[tid] * __expf(m1 - Mx) + sRed[tid + st] * __expf(m2 - Mx);
            mRed[tid] = Mx;
        }
        __syncthreads();
    }
    const float M = mRed[0];
    const float inv = 1.f / sRed[0];

    for (int j = tid * 4; j < VOC; j += 1024) {
        float4 v = *(const float4*)(row + j);
        v.x = __expf(v.x - M) * inv;
        v.y = __expf(v.y - M) * inv;
        v.z = __expf(v.z - M) * inv;
        v.w = __expf(v.w - M) * inv;
        *(float4*)(row + j) = v;
    }
}

// ------------------------- host side ---------------------------------------
#define SMEM_H32  61440    // BK=32: 3 x 20480
#define SMEM_H64 110592    // BK=64: 3 x 36864

extern "C" void kernel_launch(void* const* d_in, const int* in_sizes, int n_in,
                              void* d_out, int out_size)
{
    const float* x   = (const float*)d_in[0];
    const float* Wq  = (const float*)d_in[1];
    const float* bq  = (const float*)d_in[2];
    const float* Wk  = (const float*)d_in[3];
    const float* bk  = (const float*)d_in[4];
    const float* Wv  = (const float*)d_in[5];
    const float* bv  = (const float*)d_in[6];
    const float* Wp  = (const float*)d_in[7];
    const float* bp  = (const float*)d_in[8];
    const float* g1  = (const float*)d_in[9];
    const float* be1 = (const float*)d_in[10];
    const float* W1  = (const float*)d_in[11];
    const float* b1  = (const float*)d_in[12];
    const float* W2  = (const float*)d_in[13];
    const float* b2  = (const float*)d_in[14];
    const float* g2  = (const float*)d_in[15];
    const float* be2 = (const float*)d_in[16];
    const float* Wf  = (const float*)d_in[17];
    const float* bf  = (const float*)d_in[18];
    float* out = (float*)d_out;

    cudaFuncSetAttribute(gemm_fp16<0,0,64>, cudaFuncAttributeMaxDynamicSharedMemorySize, SMEM_H64);
    cudaFuncSetAttribute(gemm_fp16<1,2,64>, cudaFuncAttributeMaxDynamicSharedMemorySize, SMEM_H64);
    cudaFuncSetAttribute(gemm_fp16<2,0,32>, cudaFuncAttributeMaxDynamicSharedMemorySize, SMEM_H32);
    cudaFuncSetAttribute(gemm_fp16<3,0,64>, cudaFuncAttributeMaxDynamicSharedMemorySize, SMEM_H64);
    cudaFuncSetAttribute(gemm_fp16<0,1,64>, cudaFuncAttributeMaxDynamicSharedMemorySize, SMEM_H64);

    float *px, *px2, *patt, *pc0, *pc1, *pc2, *pc3, *psmax, *pssum;
    cudaGetSymbolAddress((void**)&px,    g_x);
    cudaGetSymbolAddress((void**)&px2,   g_x2);
    cudaGetSymbolAddress((void**)&patt,  g_att);
    cudaGetSymbolAddress((void**)&pc0,   g_c0);
    cudaGetSymbolAddress((void**)&pc1,   g_c1);
    cudaGetSymbolAddress((void**)&pc2,   g_c2);
    cudaGetSymbolAddress((void**)&pc3,   g_c3);
    cudaGetSymbolAddress((void**)&psmax, g_smax);
    cudaGetSymbolAddress((void**)&pssum, g_ssum);

    f16 *pxh, *px2h, *pq, *pk, *pvt, *path, *pt, *ph;
    f16 *pwqt, *pwkt, *pwvt, *pwpt, *pw1t, *pw2t, *pwft;
    cudaGetSymbolAddress((void**)&pxh,  g_xh);
    cudaGetSymbolAddress((void**)&px2h, g_x2h);
    cudaGetSymbolAddress((void**)&pq,   g_q);
    cudaGetSymbolAddress((void**)&pk,   g_k);
    cudaGetSymbolAddress((void**)&pvt,  g_vt);
    cudaGetSymbolAddress((void**)&path, g_ath);
    cudaGetSymbolAddress((void**)&pt,   g_t);
    cudaGetSymbolAddress((void**)&ph,   g_h);
    cudaGetSymbolAddress((void**)&pwqt, g_wqt);
    cudaGetSymbolAddress((void**)&pwkt, g_wkt);
    cudaGetSymbolAddress((void**)&pwvt, g_wvt);
    cudaGetSymbolAddress((void**)&pwpt, g_wpt);
    cudaGetSymbolAddress((void**)&pw1t, g_w1t);
    cudaGetSymbolAddress((void**)&pw2t, g_w2t);
    cudaGetSymbolAddress((void**)&pwft, g_wft);

    const float scale = 1.0f / sqrtf((float)FF);
    dim3 tb(32, 8);
    HP z{nullptr, nullptr, nullptr, nullptr, 0};

    // preprocessing needed for first QKV (slots 0-3); QKV lands at 4-5
    transpose_f16_kernel<<<dim3(FF/32, DM/32, NL), tb>>>(Wq, pwqt, DM, FF);
    transpose_f16_kernel<<<dim3(FF/32, DM/32, NL), tb>>>(Wk, pwkt, DM, FF);
    transpose_f16_kernel<<<dim3(FF/32, DM/32, NL), tb>>>(Wv, pwvt, DM, FF);
    f32_to_f16_kernel<<<(SQ*DM)/2048, 256>>>(x, pxh, SQ*DM);

    bool firstLayer = true;
    for (int l = 0; l < NL; l++) {
        size_t wOff = (size_t)l * DM * FF;

        // QKV (batched over z); V written transposed [F,S]
        {
            HP pQ{pwqt + wOff, bq + (size_t)l*FF, nullptr, pq, 0};
            HP pK{pwkt + wOff, bk + (size_t)l*FF, nullptr, pk, 0};
            HP pV{pwvt + wOff, bv + (size_t)l*FF, nullptr, pvt, 1};
            gemm_fp16<0,0,64><<<dim3(SQ/128, FF/128, 3), 256, SMEM_H64>>>(
                pxh, pQ, pK, pV, z, nullptr, nullptr, SQ, FF, DM, 1.f);
        }
        // scores = q @ k^T * scale (causal skip) + causal softmax partials
        {
            HP p{pk, nullptr, patt, nullptr, 0};
            gemm_fp16<1,2,64><<<dim3(SQ/128, SQ/128, 1), 256, SMEM_H64>>>(
                pq, p, z, z, z, psmax, pssum, SQ, SQ, FF, scale);
        }
        if (firstLayer) {
            transpose_f16_kernel<<<dim3(FF/32, FF/32, NL),  tb>>>(Wp, pwpt, FF,  FF);
            transpose_f16_kernel<<<dim3(HID/32, FF/32, NL), tb>>>(W1, pw1t, FF,  HID);
            transpose_f16_kernel<<<dim3(DM/32, HID/32, NL), tb>>>(W2, pw2t, HID, DM);
            transpose_f16_kernel<<<dim3(VOC/32, DM/32, 1),  tb>>>(Wf, pwft, DM,  VOC);
            firstLayer = false;
        }
        // causal softmax: combine partials + one pass -> fp16 probs
        softmax_causal_warp<<<SQ/8, 256>>>(patt, path, psmax, pssum);
        // t = att @ V (K bounded at m0+128, split-K=4, BK=32)
        {
            HP pA{pvt, nullptr, pc0, nullptr, 0};
            HP pB{nullptr, nullptr, pc1, nullptr, 0};
            HP pC{nullptr, nullptr, pc2, nullptr, 0};
            HP pD{nullptr, nullptr, pc3, nullptr, 0};
            gemm_fp16<2,0,32><<<dim3(SQ/128, FF/128, 4), 256, SMEM_H32>>>(
                path, pA, pB, pC, pD, nullptr, nullptr, SQ, FF, SQ, 1.f);
        }
        add4_f16_kernel<<<(SQ*FF)/1024, 256>>>(pc0, pc1, pc2, pc3, pt, SQ*FF);
        // z = t @ Wp + bp (split-K=4)
        {
            HP pA{pwpt + (size_t)l*FF*FF, bp + (size_t)l*FF, pc0, nullptr, 0};
            HP pB{nullptr, nullptr, pc1, nullptr, 0};
            HP pC{nullptr, nullptr, pc2, nullptr, 0};
            HP pD{nullptr, nullptr, pc3, nullptr, 0};
            gemm_fp16<3,0,64><<<dim3(SQ/128, FF/128, 4), 256, SMEM_H64>>>(
                pt, pA, pB, pC, pD, nullptr, nullptr, SQ, FF, FF, 1.f);
        }
        add_ln_warp<<<SQ/8, 256>>>(pc0, pc1, pc2, pc3, (l == 0) ? x : px,
                                   g1 + (size_t)l*FF, be1 + (size_t)l*FF,
                                   px2, px2h);
        // h = x2 @ W1 + b1
        {
            HP p{pw1t + (size_t)l*HID*FF, b1 + (size_t)l*HID, nullptr, ph, 0};
            gemm_fp16<0,0,64><<<dim3(SQ/128, HID/128, 1), 256, SMEM_H64>>>(
                px2h, p, z, z, z, nullptr, nullptr, SQ, HID, FF, 1.f);
        }
        // h2 = h @ W2 + b2 (split-K=4)
        {
            HP pA{pw2t + (size_t)l*DM*HID, b2 + (size_t)l*DM, pc0, nullptr, 0};
            HP pB{nullptr, nullptr, pc1, nullptr, 0};
            HP pC{nullptr, nullptr, pc2, nullptr, 0};
            HP pD{nullptr, nullptr, pc3, nullptr, 0};
            gemm_fp16<3,0,64><<<dim3(SQ/128, DM/128, 4), 256, SMEM_H64>>>(
                ph, pA, pB, pC, pD, nullptr, nullptr, SQ, DM, HID, 1.f);
        }
        add_ln_warp<<<SQ/8, 256>>>(pc0, pc1, pc2, pc3, px2,
                                   g2 + (size_t)l*DM, be2 + (size_t)l*DM,
                                   px, pxh);
    }

    // logits (fused softmax partials) + 1-pass vocab softmax
    {
        HP p{pwft, bf, out, nullptr, 0};
        gemm_fp16<0,1,64><<<dim3(SQ/128, VOC/128, 1), 256, SMEM_H64>>>(
            pxh, p, z, z, z, psmax, pssum, SQ, VOC, DM, 1.f);
    }
    softmax_vocab_kernel<<<SQ, 256>>>(out, psmax, pssum);

    (void)in_sizes; (void)n_in; (void)out_size;
}

// round 15
// speedup vs baseline: 6.9822x; 1.0043x over previous
#include <cuda_runtime.h>
#include <cuda_fp16.h>
#include <cstdint>
#include <cmath>

#define SQ   2048
#define DM   512
#define FF   512
#define HID  2048
#define VOC  32000
#define NL   4
#define LN_EPS 1e-5f
#define NBV  (VOC/128)
#define NBS  (SQ/128)

typedef __half  f16;
typedef __half2 f162;

// ------------------------- fp32 scratch ------------------------------------
__device__ float g_x  [SQ * DM];
__device__ float g_x2 [SQ * DM];
__device__ float g_c0 [SQ * FF];
__device__ float g_c1 [SQ * FF];
__device__ float g_c2 [SQ * FF];
__device__ float g_c3 [SQ * FF];
__device__ float g_smax[SQ * NBV];
__device__ float g_ssum[SQ * NBV];

// ------------------------- fp16 operands -----------------------------------
__device__ f16 g_xh  [SQ*DM];
__device__ f16 g_x2h [SQ*DM];
__device__ f16 g_q   [SQ*FF];
__device__ f16 g_k   [SQ*FF];
__device__ f16 g_v   [SQ*FF];         // V (A for V@Wp)
__device__ f16 g_vpt [FF*SQ];         // (V@Wp)^T
__device__ f16 g_sc  [SQ*SQ];         // fp16 scores -> (in place) probs
__device__ f16 g_h   [SQ*HID];
__device__ f16 g_wqt[(size_t)NL * FF * DM];
__device__ f16 g_wkt[(size_t)NL * FF * DM];
__device__ f16 g_wvt[(size_t)NL * FF * DM];
__device__ f16 g_wpt[(size_t)NL * FF * FF];
__device__ f16 g_w1t[(size_t)NL * HID * FF];
__device__ f16 g_w2t[(size_t)NL * DM * HID];
__device__ f16 g_wft[(size_t)VOC * DM];

// ------------------------- PTX helpers -------------------------------------
__device__ __forceinline__ void ldsm4(uint32_t* r, uint32_t addr) {
    asm volatile("ldmatrix.sync.aligned.m8n8.x4.shared.b16 {%0,%1,%2,%3}, [%4];"
                 : "=r"(r[0]), "=r"(r[1]), "=r"(r[2]), "=r"(r[3]) : "r"(addr));
}
__device__ __forceinline__ void mma16816h(float* c, const uint32_t* a, const uint32_t* b) {
    asm volatile("mma.sync.aligned.m16n8k16.row.col.f32.f16.f16.f32 "
                 "{%0,%1,%2,%3}, {%4,%5,%6,%7}, {%8,%9}, {%0,%1,%2,%3};"
                 : "+f"(c[0]), "+f"(c[1]), "+f"(c[2]), "+f"(c[3])
                 : "r"(a[0]), "r"(a[1]), "r"(a[2]), "r"(a[3]),
                   "r"(b[0]), "r"(b[1]));
}
__device__ __forceinline__ void cpa16(uint32_t s, const void* g) {
    asm volatile("cp.async.cg.shared.global [%0], [%1], 16;\n" :: "r"(s), "l"(g));
}
__device__ __forceinline__ void cpcommit() { asm volatile("cp.async.commit_group;\n"); }
template<int N> __device__ __forceinline__ void cpwait() {
    asm volatile("cp.async.wait_group %0;\n" :: "n"(N));
}

// ------------------------- utility kernels ---------------------------------
__global__ void f32_to_f16_kernel(const float* __restrict__ in,
                                  f16* __restrict__ out, int n)
{
    int i = (blockIdx.x * blockDim.x + threadIdx.x) * 8;
    if (i >= n) return;
    float4 a = *(const float4*)(in + i);
    float4 b = *(const float4*)(in + i + 4);
    f162 o[4];
    o[0] = __floats2half2_rn(a.x, a.y);
    o[1] = __floats2half2_rn(a.z, a.w);
    o[2] = __floats2half2_rn(b.x, b.y);
    o[3] = __floats2half2_rn(b.z, b.w);
    *(uint4*)(out + i) = *(const uint4*)o;
}

__global__ void transpose_f16_kernel(const float* __restrict__ in,
                                     f16* __restrict__ out, int Kd, int Nd)
{
    __shared__ float t[32][33];
    const size_t off = (size_t)blockIdx.z * Kd * Nd;
    const int n0 = blockIdx.x * 32, k0 = blockIdx.y * 32;
    const int tx = threadIdx.x, ty = threadIdx.y;
    #pragma unroll
    for (int i = 0; i < 4; i++)
        t[ty + 8*i][tx] = in[off + (size_t)(k0 + ty + 8*i) * Nd + n0 + tx];
    __syncthreads();
    #pragma unroll
    for (int i = 0; i < 4; i++)
        out[off + (size_t)(n0 + ty + 8*i) * Kd + k0 + tx] = __float2half_rn(t[tx][ty + 8*i]);
}

struct HP { const f16* B; const float* bias; float* C; f16* Ch; int transC; };

// ------------------------- unified fp16 GEMM -------------------------------
// C = alpha * A @ B^T + bias.  A [M,K] fp16; B [N,K] fp16; fp32 accumulate.
// MODE 0: z batches {p0,p1,p2}.  MODE 1: causal block-skip.
// MODE 2: K bounded at m0+128, split over z.  MODE 3: split-K over z.
// STATS 0: none; 1: softmax partials (logits); 2: causal-masked partials.
template<int MODE, int STATS, int BK>
__global__ void __launch_bounds__(256, 2)
gemm_fp16(const f16* __restrict__ A, HP p0, HP p1, HP p2, HP p3,
          float* __restrict__ smax, float* __restrict__ ssum,
          int M, int N, int K, float alpha)
{
    constexpr int BM = 128, BN = 128, ST = 3;
    constexpr int ASTR = BK + 8;
    constexpr int A_PART = BM * ASTR;
    constexpr int BSTR = BK + 8;
    constexpr int B_PART = BN * BSTR;
    constexpr int STAGE = A_PART + B_PART;
    constexpr int MT = 2;
    constexpr int NT = 8;
    constexpr int CHUNKS = BK / 8;
    constexpr int LD_IT = (BM * CHUNKS) / 256;

    extern __shared__ f16 smem[];

    const int m0 = blockIdx.x * BM;
    const int n0 = blockIdx.y * BN;
    if (MODE == 1 && n0 > m0) return;

    HP P = p0;
    if (MODE == 0)
        P = (blockIdx.z == 0) ? p0 : ((blockIdx.z == 1) ? p1 : p2);
    float* C  = P.C;
    f16*   Ch = P.Ch;
    if (MODE >= 2) {
        C = (blockIdx.z == 0) ? p0.C : (blockIdx.z == 1) ? p1.C
          : (blockIdx.z == 2) ? p2.C : p3.C;
        Ch = nullptr;
    }
    const float* bias = P.bias;
    if (MODE >= 2 && blockIdx.z != 0) bias = nullptr;

    int Keff = K, kOff = 0;
    if (MODE == 2) { int kt = min(K, m0 + BM); Keff = kt / gridDim.z; kOff = blockIdx.z * Keff; }
    if (MODE == 3) { Keff = K / gridDim.z; kOff = blockIdx.z * Keff; }
    const int T = Keff / BK;

    const int tid  = threadIdx.x;
    const int lane = tid & 31;
    const int warp = tid >> 5;
    const int wm = warp & 3;
    const int wn = warp >> 2;
    const int l7 = lane & 7, q1 = (lane >> 3) & 1, q2 = lane >> 4;

    auto load_tile = [&](int t, int s) {
        const int k0 = kOff + t * BK;
        f16* sb = smem + s * STAGE;
        #pragma unroll
        for (int i = 0; i < LD_IT; i++) {
            int f = tid + 256 * i;
            int r = f / CHUNKS;
            int c = f % CHUNKS;
            cpa16((uint32_t)__cvta_generic_to_shared(sb + r*ASTR + c*8),
                  A + (size_t)(m0 + r) * K + k0 + c*8);
        }
        #pragma unroll
        for (int i = 0; i < LD_IT; i++) {
            int f = tid + 256 * i;
            int r = f / CHUNKS;
            int c = f % CHUNKS;
            cpa16((uint32_t)__cvta_generic_to_shared(sb + A_PART + r*BSTR + c*8),
                  P.B + (size_t)(n0 + r) * K + k0 + c*8);
        }
    };

    float acc[MT][NT][4];
    #pragma unroll
    for (int mt = 0; mt < MT; mt++)
        #pragma unroll
        for (int nt = 0; nt < NT; nt++)
            #pragma unroll
            for (int i = 0; i < 4; i++) acc[mt][nt][i] = 0.f;

    const uint32_t smemBase = (uint32_t)__cvta_generic_to_shared(smem);
    const uint32_t aoff = (uint32_t)(((wm*MT*16 + l7 + q1*8) * ASTR + q2*8) * 2);
    const uint32_t boff = (uint32_t)((A_PART + (wn*64 + l7 + q2*8) * BSTR + q1*8) * 2);

    load_tile(0, 0); cpcommit();
    if (T > 1) load_tile(1, 1);
    cpcommit();

    for (int t = 0; t < T; t++) {
        cpwait<1>();
        __syncthreads();
        if (t + 2 < T) { load_tile(t + 2, (t + 2) % ST); }
        cpcommit();

        const uint32_t sbase = smemBase + (uint32_t)((t % ST) * STAGE * 2);

        #pragma unroll
        for (int ks = 0; ks < BK/16; ks++) {
            uint32_t a[MT][4], b[NT][2];
            #pragma unroll
            for (int mt = 0; mt < MT; mt++)
                ldsm4(a[mt], sbase + aoff + (uint32_t)(mt*16*ASTR*2 + ks*32));
            #pragma unroll
            for (int p = 0; p < 4; p++) {
                uint32_t r4[4];
                ldsm4(r4, sbase + boff + (uint32_t)(p*16*BSTR*2 + ks*32));
                b[2*p][0]   = r4[0]; b[2*p][1]   = r4[1];
                b[2*p+1][0] = r4[2]; b[2*p+1][1] = r4[3];
            }
            #pragma unroll
            for (int nt = 0; nt < NT; nt++)
                #pragma unroll
                for (int mt = 0; mt < MT; mt++)
                    mma16816h(acc[mt][nt], a[mt], b[nt]);
        }
    }

    // fold alpha + bias
    #pragma unroll
    for (int mt = 0; mt < MT; mt++)
        #pragma unroll
        for (int nt = 0; nt < NT; nt++) {
            int col = n0 + wn*64 + nt*8 + ((lane & 3) << 1);
            float b0 = 0.f, b1 = 0.f;
            if (bias) { b0 = bias[col]; b1 = bias[col + 1]; }
            acc[mt][nt][0] = acc[mt][nt][0] * alpha + b0;
            acc[mt][nt][1] = acc[mt][nt][1] * alpha + b1;
            acc[mt][nt][2] = acc[mt][nt][2] * alpha + b0;
            acc[mt][nt][3] = acc[mt][nt][3] * alpha + b1;
        }

    #pragma unroll
    for (int mt = 0; mt < MT; mt++) {
        int row0 = m0 + wm*MT*16 + mt*16 + (lane >> 2);
        #pragma unroll
        for (int nt = 0; nt < NT; nt++) {
            int col = n0 + wn*64 + nt*8 + ((lane & 3) << 1);
            if (C) {
                *(float2*)(C + (size_t)row0 * N + col)       = float2{acc[mt][nt][0], acc[mt][nt][1]};
                *(float2*)(C + (size_t)(row0 + 8) * N + col) = float2{acc[mt][nt][2], acc[mt][nt][3]};
            }
            if (Ch) {
                if (!P.transC) {
                    *(f162*)(Ch + (size_t)row0 * N + col) =
                        __floats2half2_rn(acc[mt][nt][0], acc[mt][nt][1]);
                    *(f162*)(Ch + (size_t)(row0 + 8) * N + col) =
                        __floats2half2_rn(acc[mt][nt][2], acc[mt][nt][3]);
                } else {
                    Ch[(size_t)col       * M + row0]     = __float2half_rn(acc[mt][nt][0]);
                    Ch[(size_t)(col + 1) * M + row0]     = __float2half_rn(acc[mt][nt][1]);
                    Ch[(size_t)col       * M + row0 + 8] = __float2half_rn(acc[mt][nt][2]);
                    Ch[(size_t)(col + 1) * M + row0 + 8] = __float2half_rn(acc[mt][nt][3]);
                }
            }
        }
    }

    if (STATS) {
        const bool diag = (STATS == 2) && (n0 == m0);
        __syncthreads();
        float* sm_m = (float*)smem;
        float* sm_s = sm_m + 256;
        #pragma unroll
        for (int mt = 0; mt < MT; mt++) {
            int rA = m0 + wm*32 + mt*16 + (lane >> 2);
            int rB = rA + 8;
            float mA = -1e30f, mB = -1e30f;
            #pragma unroll
            for (int nt = 0; nt < NT; nt++) {
                int col = n0 + wn*64 + nt*8 + ((lane & 3) << 1);
                float vA0 = acc[mt][nt][0], vA1 = acc[mt][nt][1];
                float vB0 = acc[mt][nt][2], vB1 = acc[mt][nt][3];
                if (diag) {
                    if (col     > rA) vA0 = -1e30f;
                    if (col + 1 > rA) vA1 = -1e30f;
                    if (col     > rB) vB0 = -1e30f;
                    if (col + 1 > rB) vB1 = -1e30f;
                }
                mA = fmaxf(mA, fmaxf(vA0, vA1));
                mB = fmaxf(mB, fmaxf(vB0, vB1));
            }
            mA = fmaxf(mA, __shfl_xor_sync(0xffffffffu, mA, 1));
            mA = fmaxf(mA, __shfl_xor_sync(0xffffffffu, mA, 2));
            mB = fmaxf(mB, __shfl_xor_sync(0xffffffffu, mB, 1));
            mB = fmaxf(mB, __shfl_xor_sync(0xffffffffu, mB, 2));
            float sA = 0.f, sB = 0.f;
            #pragma unroll
            for (int nt = 0; nt < NT; nt++) {
                int col = n0 + wn*64 + nt*8 + ((lane & 3) << 1);
                if (!diag || col     <= rA) sA += __expf(acc[mt][nt][0] - mA);
                if (!diag || col + 1 <= rA) sA += __expf(acc[mt][nt][1] - mA);
                if (!diag || col     <= rB) sB += __expf(acc[mt][nt][2] - mB);
                if (!diag || col + 1 <= rB) sB += __expf(acc[mt][nt][3] - mB);
            }
            sA += __shfl_xor_sync(0xffffffffu, sA, 1);
            sA += __shfl_xor_sync(0xffffffffu, sA, 2);
            sB += __shfl_xor_sync(0xffffffffu, sB, 1);
            sB += __shfl_xor_sync(0xffffffffu, sB, 2);
            if ((lane & 3) == 0) {
                int r = wm*32 + mt*16 + (lane >> 2);
                sm_m[r*2 + wn]     = mA;  sm_s[r*2 + wn]     = sA;
                sm_m[(r+8)*2 + wn] = mB;  sm_s[(r+8)*2 + wn] = sB;
            }
        }
        __syncthreads();
        if (tid < 128) {
            float m1 = sm_m[tid*2], m2 = sm_m[tid*2 + 1];
            float Mx = fmaxf(m1, m2);
            float S  = sm_s[tid*2] * __expf(m1 - Mx) + sm_s[tid*2 + 1] * __expf(m2 - Mx);
            int nb = N >> 7;
            smax[(size_t)(m0 + tid) * nb + (n0 >> 7)] = Mx;
            ssum[(size_t)(m0 + tid) * nb + (n0 >> 7)] = S;
        }
    }
}

// ------------------------- causal softmax: partials + 1 pass (in place) ----
__global__ void __launch_bounds__(256)
softmax_causal_warp(f16* __restrict__ sc,
                    const float* __restrict__ smax, const float* __restrict__ ssum)
{
    const int warp = threadIdx.x >> 5;
    const int lane = threadIdx.x & 31;
    const int r = blockIdx.x * 8 + warp;
    f16* row = sc + (size_t)r * SQ;
    const int n = r + 1;
    const int nb = (r >> 7) + 1;
    const int fillEnd = nb << 7;

    float m = -1e30f, s = 0.f;
    if (lane < nb) {
        m = smax[(size_t)r * NBS + lane];
        s = ssum[(size_t)r * NBS + lane];
    }
    #pragma unroll
    for (int st = 16; st > 0; st >>= 1) {
        float mo = __shfl_xor_sync(0xffffffffu, m, st);
        float so = __shfl_xor_sync(0xffffffffu, s, st);
        float Mx = fmaxf(m, mo);
        s = s * __expf(m - Mx) + so * __expf(mo - Mx);
        m = Mx;
    }
    const float inv = 1.f / s;

    for (int j = lane * 8; j < fillEnd; j += 256) {
        uint4 raw = *(const uint4*)(row + j);
        const f162* pv = (const f162*)&raw;
        f162 o[4];
        #pragma unroll
        for (int q = 0; q < 4; q++) {
            float2 v = __half22float2(pv[q]);
            float e0 = (j + 2*q     < n) ? __expf(v.x - m) * inv : 0.f;
            float e1 = (j + 2*q + 1 < n) ? __expf(v.y - m) * inv : 0.f;
            o[q] = __floats2half2_rn(e0, e1);
        }
        *(uint4*)(row + j) = *(const uint4*)o;
    }
}

// ------------------------- warp-per-row 4-partial add + LN -----------------
__global__ void __launch_bounds__(256)
add_ln_warp(const float* __restrict__ a0, const float* __restrict__ a1,
            const float* __restrict__ a2, const float* __restrict__ a3,
            const float* __restrict__ res,
            const float* __restrict__ g, const float* __restrict__ beta,
            float* __restrict__ out, f16* __restrict__ xh)
{
    const int warp = threadIdx.x >> 5;
    const int lane = threadIdx.x & 31;
    const int r = blockIdx.x * 8 + warp;
    const size_t base = (size_t)r * DM;

    float v[16];
    float sum = 0.f;
    #pragma unroll
    for (int k = 0; k < 4; k++) {
        int j = lane * 4 + k * 128;
        float4 va = *(const float4*)(a0 + base + j);
        float4 v1 = *(const float4*)(a1 + base + j);
        float4 v2 = *(const float4*)(a2 + base + j);
        float4 v3 = *(const float4*)(a3 + base + j);
        float4 vr = *(const float4*)(res + base + j);
        va.x += v1.x + v2.x + v3.x + vr.x;
        va.y += v1.y + v2.y + v3.y + vr.y;
        va.z += v1.z + v2.z + v3.z + vr.z;
        va.w += v1.w + v2.w + v3.w + vr.w;
        v[k*4+0] = va.x; v[k*4+1] = va.y; v[k*4+2] = va.z; v[k*4+3] = va.w;
        sum += va.x + va.y + va.z + va.w;
    }
    #pragma unroll
    for (int st = 16; st > 0; st >>= 1)
        sum += __shfl_xor_sync(0xffffffffu, sum, st);
    const float mu = sum * (1.0f / DM);

    float var = 0.f;
    #pragma unroll
    for (int k = 0; k < 16; k++) {
        float d = v[k] - mu;
        v[k] = d;
        var += d * d;
    }
    #pragma unroll
    for (int st = 16; st > 0; st >>= 1)
        var += __shfl_xor_sync(0xffffffffu, var, st);
    const float rstd = rsqrtf(var * (1.0f / DM) + LN_EPS);

    #pragma unroll
    for (int k = 0; k < 4; k++) {
        int j = lane * 4 + k * 128;
        float4 vg = *(const float4*)(g + j);
        float4 vb = *(const float4*)(beta + j);
        float o0 = v[k*4+0] * rstd * vg.x + vb.x;
        float o1 = v[k*4+1] * rstd * vg.y + vb.y;
        float o2 = v[k*4+2] * rstd * vg.z + vb.z;
        float o3 = v[k*4+3] * rstd * vg.w + vb.w;
        *(float4*)(out + base + j) = float4{o0, o1, o2, o3};
        f162 o[2];
        o[0] = __floats2half2_rn(o0, o1);
        o[1] = __floats2half2_rn(o2, o3);
        *(uint2*)(xh + base + j) = *(const uint2*)o;
    }
}

// ------------------------- vocab softmax via GEMM partials -----------------
__global__ void softmax_vocab_kernel(float* __restrict__ x,
                                     const float* __restrict__ smax,
                                     const float* __restrict__ ssum)
{
    const int i = blockIdx.x;
    float* row = x + (size_t)i * VOC;
    const int tid = threadIdx.x;

    __shared__ float mRed[256];
    __shared__ float sRed[256];

    float m = -1e30f, s = 0.f;
    if (tid < NBV) {
        m = smax[(size_t)i * NBV + tid];
        s = ssum[(size_t)i * NBV + tid];
    }
    mRed[tid] = m; sRed[tid] = s; __syncthreads();
    for (int st = 128; st > 0; st >>= 1) {
        if (tid < st) {
            float m1 = mRed[tid], m2 = mRed[tid + st];
            float Mx = fmaxf(m1, m2);
            sRed[tid] = sRed[tid] * __expf(m1 - Mx) + sRed[tid + st] * __expf(m2 - Mx);
            mRed[tid] = Mx;
        }
        __syncthreads();
    }
    const float M = mRed[0];
    const float inv = 1.f / sRed[0];

    for (int j = tid * 4; j < VOC; j += 1024) {
        float4 v = *(const float4*)(row + j);
        v.x = __expf(v.x - M) * inv;
        v.y = __expf(v.y - M) * inv;
        v.z = __expf(v.z - M) * inv;
        v.w = __expf(v.w - M) * inv;
        *(float4*)(row + j) = v;
    }
}

// ------------------------- host side ---------------------------------------
#define SMEM_H32  61440
#define SMEM_H64 110592

extern "C" void kernel_launch(void* const* d_in, const int* in_sizes, int n_in,
                              void* d_out, int out_size)
{
    const float* x   = (const float*)d_in[0];
    const float* Wq  = (const float*)d_in[1];
    const float* bq  = (const float*)d_in[2];
    const float* Wk  = (const float*)d_in[3];
    const float* bk  = (const float*)d_in[4];
    const float* Wv  = (const float*)d_in[5];
    const float* bv  = (const float*)d_in[6];
    const float* Wp  = (const float*)d_in[7];
    const float* bp  = (const float*)d_in[8];
    const float* g1  = (const float*)d_in[9];
    const float* be1 = (const float*)d_in[10];
    const float* W1  = (const float*)d_in[11];
    const float* b1  = (const float*)d_in[12];
    const float* W2  = (const float*)d_in[13];
    const float* b2  = (const float*)d_in[14];
    const float* g2  = (const float*)d_in[15];
    const float* be2 = (const float*)d_in[16];
    const float* Wf  = (const float*)d_in[17];
    const float* bf  = (const float*)d_in[18];
    float* out = (float*)d_out;

    cudaFuncSetAttribute(gemm_fp16<0,0,64>, cudaFuncAttributeMaxDynamicSharedMemorySize, SMEM_H64);
    cudaFuncSetAttribute(gemm_fp16<1,2,64>, cudaFuncAttributeMaxDynamicSharedMemorySize, SMEM_H64);
    cudaFuncSetAttribute(gemm_fp16<2,0,32>, cudaFuncAttributeMaxDynamicSharedMemorySize, SMEM_H32);
    cudaFuncSetAttribute(gemm_fp16<3,0,64>, cudaFuncAttributeMaxDynamicSharedMemorySize, SMEM_H64);
    cudaFuncSetAttribute(gemm_fp16<0,1,64>, cudaFuncAttributeMaxDynamicSharedMemorySize, SMEM_H64);

    float *px, *px2, *pc0, *pc1, *pc2, *pc3, *psmax, *pssum;
    cudaGetSymbolAddress((void**)&px,    g_x);
    cudaGetSymbolAddress((void**)&px2,   g_x2);
    cudaGetSymbolAddress((void**)&pc0,   g_c0);
    cudaGetSymbolAddress((void**)&pc1,   g_c1);
    cudaGetSymbolAddress((void**)&pc2,   g_c2);
    cudaGetSymbolAddress((void**)&pc3,   g_c3);
    cudaGetSymbolAddress((void**)&psmax, g_smax);
    cudaGetSymbolAddress((void**)&pssum, g_ssum);

    f16 *pxh, *px2h, *pq, *pk, *pv, *pvpt, *psc, *ph;
    f16 *pwqt, *pwkt, *pwvt, *pwpt, *pw1t, *pw2t, *pwft;
    cudaGetSymbolAddress((void**)&pxh,  g_xh);
    cudaGetSymbolAddress((void**)&px2h, g_x2h);
    cudaGetSymbolAddress((void**)&pq,   g_q);
    cudaGetSymbolAddress((void**)&pk,   g_k);
    cudaGetSymbolAddress((void**)&pv,   g_v);
    cudaGetSymbolAddress((void**)&pvpt, g_vpt);
    cudaGetSymbolAddress((void**)&psc,  g_sc);
    cudaGetSymbolAddress((void**)&ph,   g_h);
    cudaGetSymbolAddress((void**)&pwqt, g_wqt);
    cudaGetSymbolAddress((void**)&pwkt, g_wkt);
    cudaGetSymbolAddress((void**)&pwvt, g_wvt);
    cudaGetSymbolAddress((void**)&pwpt, g_wpt);
    cudaGetSymbolAddress((void**)&pw1t, g_w1t);
    cudaGetSymbolAddress((void**)&pw2t, g_w2t);
    cudaGetSymbolAddress((void**)&pwft, g_wft);

    const float scale = 1.0f / sqrtf((float)FF);
    dim3 tb(32, 8);
    HP z{nullptr, nullptr, nullptr, nullptr, 0};

    // preprocessing needed for first QKV (slots 0-3); QKV lands at 4-5
    transpose_f16_kernel<<<dim3(FF/32, DM/32, NL), tb>>>(Wq, pwqt, DM, FF);
    transpose_f16_kernel<<<dim3(FF/32, DM/32, NL), tb>>>(Wk, pwkt, DM, FF);
    transpose_f16_kernel<<<dim3(FF/32, DM/32, NL), tb>>>(Wv, pwvt, DM, FF);
    f32_to_f16_kernel<<<(SQ*DM)/2048, 256>>>(x, pxh, SQ*DM);

    bool firstLayer = true;
    for (int l = 0; l < NL; l++) {
        size_t wOff = (size_t)l * DM * FF;

        // QKV (batched over z); V written normal [S,F]
        {
            HP pQ{pwqt + wOff, bq + (size_t)l*FF, nullptr, pq, 0};
            HP pK{pwkt + wOff, bk + (size_t)l*FF, nullptr, pk, 0};
            HP pV{pwvt + wOff, bv + (size_t)l*FF, nullptr, pv, 0};
            gemm_fp16<0,0,64><<<dim3(SQ/128, FF/128, 3), 256, SMEM_H64>>>(
                pxh, pQ, pK, pV, z, nullptr, nullptr, SQ, FF, DM, 1.f);
        }
        // scores = q @ k^T * scale (causal skip) -> fp16 + causal partials
        {
            HP p{pk, nullptr, nullptr, psc, 0};
            gemm_fp16<1,2,64><<<dim3(SQ/128, SQ/128, 1), 256, SMEM_H64>>>(
                pq, p, z, z, z, psmax, pssum, SQ, SQ, FF, scale);
        }
        if (firstLayer) {
            transpose_f16_kernel<<<dim3(FF/32, FF/32, NL),  tb>>>(Wp, pwpt, FF,  FF);
            transpose_f16_kernel<<<dim3(HID/32, FF/32, NL), tb>>>(W1, pw1t, FF,  HID);
            transpose_f16_kernel<<<dim3(DM/32, HID/32, NL), tb>>>(W2, pw2t, HID, DM);
            transpose_f16_kernel<<<dim3(VOC/32, DM/32, 1),  tb>>>(Wf, pwft, DM,  VOC);
            firstLayer = false;
        }
        // Vp = V @ Wp  -> (V@Wp)^T [F,S]   (independent of softmax; overlaps)
        {
            HP p{pwpt + (size_t)l*FF*FF, nullptr, nullptr, pvpt, 1};
            gemm_fp16<0,0,64><<<dim3(SQ/128, FF/128, 1), 256, SMEM_H64>>>(
                pv, p, z, z, z, nullptr, nullptr, SQ, FF, FF, 1.f);
        }
        // causal softmax: combine partials + one pass (in place, fp16)
        softmax_causal_warp<<<SQ/8, 256>>>(psc, psmax, pssum);
        // z = att @ Vp + bp  (K bounded at m0+128, split-K=4 -> LN1 partials)
        {
            HP pA{pvpt, bp + (size_t)l*FF, pc0, nullptr, 0};
            HP pB{nullptr, nullptr, pc1, nullptr, 0};
            HP pC{nullptr, nullptr, pc2, nullptr, 0};
            HP pD{nullptr, nullptr, pc3, nullptr, 0};
            gemm_fp16<2,0,32><<<dim3(SQ/128, FF/128, 4), 256, SMEM_H32>>>(
                psc, pA, pB, pC, pD, nullptr, nullptr, SQ, FF, SQ, 1.f);
        }
        add_ln_warp<<<SQ/8, 256>>>(pc0, pc1, pc2, pc3, (l == 0) ? x : px,
                                   g1 + (size_t)l*FF, be1 + (size_t)l*FF,
                                   px2, px2h);
        // h = x2 @ W1 + b1
        {
            HP p{pw1t + (size_t)l*HID*FF, b1 + (size_t)l*HID, nullptr, ph, 0};
            gemm_fp16<0,0,64><<<dim3(SQ/128, HID/128, 1), 256, SMEM_H64>>>(
                px2h, p, z, z, z, nullptr, nullptr, SQ, HID, FF, 1.f);
        }
        // h2 = h @ W2 + b2 (split-K=4)
        {
            HP pA{pw2t + (size_t)l*DM*HID, b2 + (size_t)l*DM, pc0, nullptr, 0};
            HP pB{nullptr, nullptr, pc1, nullptr, 0};
            HP pC{nullptr, nullptr, pc2, nullptr, 0};
            HP pD{nullptr, nullptr, pc3, nullptr, 0};
            gemm_fp16<3,0,64><<<dim3(SQ/128, DM/128, 4), 256, SMEM_H64>>>(
                ph, pA, pB, pC, pD, nullptr, nullptr, SQ, DM, HID, 1.f);
        }
        add_ln_warp<<<SQ/8, 256>>>(pc0, pc1, pc2, pc3, px2,
                                   g2 + (size_t)l*DM, be2 + (size_t)l*DM,
                                   px, pxh);
    }

    // logits (fused softmax partials) + 1-pass vocab softmax
    {
        HP p{pwft, bf, out, nullptr, 0};
        gemm_fp16<0,1,64><<<dim3(SQ/128, VOC/128, 1), 256, SMEM_H64>>>(
            pxh, p, z, z, z, psmax, pssum, SQ, VOC, DM, 1.f);
    }
    softmax_vocab_kernel<<<SQ, 256>>>(out, psmax, pssum);

    (void)in_sizes; (void)n_in; (void)out_size;
}

// round 16
// speedup vs baseline: 7.3570x; 1.0537x over previous
#include <cuda_runtime.h>
#include <cuda_fp16.h>
#include <cstdint>
#include <cmath>

#define SQ   2048
#define DM   512
#define FF   512
#define HID  2048
#define VOC  32000
#define NL   4
#define LN_EPS 1e-5f
#define NBV  (VOC/128)
#define NBS  (SQ/128)

typedef __half  f16;
typedef __half2 f162;

// ------------------------- fp32 scratch ------------------------------------
__device__ float g_x  [SQ * DM];
__device__ float g_x2 [SQ * DM];
__device__ float g_c0 [SQ * FF];
__device__ float g_c1 [SQ * FF];
__device__ float g_c2 [SQ * FF];
__device__ float g_c3 [SQ * FF];
__device__ float g_smax[SQ * NBV];
__device__ float g_ssum[SQ * NBV];

// ------------------------- fp16 operands -----------------------------------
__device__ f16 g_xh  [SQ*DM];
__device__ f16 g_x2h [SQ*DM];
__device__ f16 g_q   [SQ*FF];
__device__ f16 g_k   [SQ*FF];
__device__ f16 g_v   [SQ*FF];
__device__ f16 g_vpt [FF*SQ];         // (V@Wp)^T
__device__ f16 g_sc  [SQ*SQ];         // fp16 scores -> (in place) probs
__device__ f16 g_h   [SQ*HID];
__device__ f16 g_wqt[(size_t)NL * FF * DM];
__device__ f16 g_wkt[(size_t)NL * FF * DM];
__device__ f16 g_wvt[(size_t)NL * FF * DM];
__device__ f16 g_wpt[(size_t)NL * FF * FF];
__device__ f16 g_w1t[(size_t)NL * HID * FF];
__device__ f16 g_w2t[(size_t)NL * DM * HID];
__device__ f16 g_wft[(size_t)VOC * DM];

// ------------------------- PTX helpers -------------------------------------
__device__ __forceinline__ void ldsm4(uint32_t* r, uint32_t addr) {
    asm volatile("ldmatrix.sync.aligned.m8n8.x4.shared.b16 {%0,%1,%2,%3}, [%4];"
                 : "=r"(r[0]), "=r"(r[1]), "=r"(r[2]), "=r"(r[3]) : "r"(addr));
}
__device__ __forceinline__ void mma16816h(float* c, const uint32_t* a, const uint32_t* b) {
    asm volatile("mma.sync.aligned.m16n8k16.row.col.f32.f16.f16.f32 "
                 "{%0,%1,%2,%3}, {%4,%5,%6,%7}, {%8,%9}, {%0,%1,%2,%3};"
                 : "+f"(c[0]), "+f"(c[1]), "+f"(c[2]), "+f"(c[3])
                 : "r"(a[0]), "r"(a[1]), "r"(a[2]), "r"(a[3]),
                   "r"(b[0]), "r"(b[1]));
}
__device__ __forceinline__ void cpa16(uint32_t s, const void* g) {
    asm volatile("cp.async.cg.shared.global [%0], [%1], 16;\n" :: "r"(s), "l"(g));
}
__device__ __forceinline__ void cpcommit() { asm volatile("cp.async.commit_group;\n"); }
template<int N> __device__ __forceinline__ void cpwait() {
    asm volatile("cp.async.wait_group %0;\n" :: "n"(N));
}

// ------------------------- utility kernels ---------------------------------
__global__ void f32_to_f16_kernel(const float* __restrict__ in,
                                  f16* __restrict__ out, int n)
{
    int i = (blockIdx.x * blockDim.x + threadIdx.x) * 8;
    if (i >= n) return;
    float4 a = *(const float4*)(in + i);
    float4 b = *(const float4*)(in + i + 4);
    f162 o[4];
    o[0] = __floats2half2_rn(a.x, a.y);
    o[1] = __floats2half2_rn(a.z, a.w);
    o[2] = __floats2half2_rn(b.x, b.y);
    o[3] = __floats2half2_rn(b.z, b.w);
    *(uint4*)(out + i) = *(const uint4*)o;
}

__global__ void transpose_f16_kernel(const float* __restrict__ in,
                                     f16* __restrict__ out, int Kd, int Nd)
{
    __shared__ float t[32][33];
    const size_t off = (size_t)blockIdx.z * Kd * Nd;
    const int n0 = blockIdx.x * 32, k0 = blockIdx.y * 32;
    const int tx = threadIdx.x, ty = threadIdx.y;
    #pragma unroll
    for (int i = 0; i < 4; i++)
        t[ty + 8*i][tx] = in[off + (size_t)(k0 + ty + 8*i) * Nd + n0 + tx];
    __syncthreads();
    #pragma unroll
    for (int i = 0; i < 4; i++)
        out[off + (size_t)(n0 + ty + 8*i) * Kd + k0 + tx] = __float2half_rn(t[tx][ty + 8*i]);
}

struct HP { const f16* B; const float* bias; float* C; f16* Ch; int transC; };

// ------------------------- unified fp16 GEMM -------------------------------
// C = alpha * A @ B^T + bias.  A [M,K] fp16; B [N,K] fp16; fp32 accumulate.
// MODE 0: z batches {p0,p1,p2}.  MODE 1: causal block-skip.
// MODE 2: K bounded at m0+128, split over z.  MODE 3: split-K over z.
// MODE 4: fused scores+Vp: blockIdx.y < M/128 -> causal scores (p0, STATS);
//         blockIdx.y >= M/128 -> Vp job (A=A2, B=p1, N=K, alpha=1, no stats).
// STATS 0: none; 1: softmax partials (logits); 2: causal-masked partials.
template<int MODE, int STATS, int BK>
__global__ void __launch_bounds__(256, 2)
gemm_fp16(const f16* __restrict__ A, const f16* __restrict__ A2,
          HP p0, HP p1, HP p2, HP p3,
          float* __restrict__ smax, float* __restrict__ ssum,
          int M, int N, int K, float alpha)
{
    constexpr int BM = 128, BN = 128, ST = 3;
    constexpr int ASTR = BK + 8;
    constexpr int A_PART = BM * ASTR;
    constexpr int BSTR = BK + 8;
    constexpr int B_PART = BN * BSTR;
    constexpr int STAGE = A_PART + B_PART;
    constexpr int MT = 2;
    constexpr int NT = 8;
    constexpr int CHUNKS = BK / 8;
    constexpr int LD_IT = (BM * CHUNKS) / 256;

    extern __shared__ f16 smem[];

    const int m0 = blockIdx.x * BM;
    bool vpJob = false;
    int n0;
    if (MODE == 4) {
        const int nbS = M >> 7;
        if ((int)blockIdx.y < nbS) {
            n0 = blockIdx.y * BN;
            if (n0 > m0) return;
        } else {
            vpJob = true;
            n0 = ((int)blockIdx.y - nbS) * BN;
        }
    } else {
        n0 = blockIdx.y * BN;
        if (MODE == 1 && n0 > m0) return;
    }

    HP P = p0;
    if (MODE == 0)
        P = (blockIdx.z == 0) ? p0 : ((blockIdx.z == 1) ? p1 : p2);
    if (MODE == 4 && vpJob) P = p1;

    const f16* Aop = (MODE == 4 && vpJob) ? A2 : A;
    const int  Nop = (MODE == 4 && vpJob) ? K : N;
    const float alphaOp = (MODE == 4 && vpJob) ? 1.f : alpha;

    float* C  = P.C;
    f16*   Ch = P.Ch;
    if (MODE == 2 || MODE == 3) {
        C = (blockIdx.z == 0) ? p0.C : (blockIdx.z == 1) ? p1.C
          : (blockIdx.z == 2) ? p2.C : p3.C;
        Ch = nullptr;
    }
    const float* bias = P.bias;
    if ((MODE == 2 || MODE == 3) && blockIdx.z != 0) bias = nullptr;

    int Keff = K, kOff = 0;
    if (MODE == 2) { int kt = min(K, m0 + BM); Keff = kt / gridDim.z; kOff = blockIdx.z * Keff; }
    if (MODE == 3) { Keff = K / gridDim.z; kOff = blockIdx.z * Keff; }
    const int T = Keff / BK;

    const int tid  = threadIdx.x;
    const int lane = tid & 31;
    const int warp = tid >> 5;
    const int wm = warp & 3;
    const int wn = warp >> 2;
    const int l7 = lane & 7, q1 = (lane >> 3) & 1, q2 = lane >> 4;

    auto load_tile = [&](int t, int s) {
        const int k0 = kOff + t * BK;
        f16* sb = smem + s * STAGE;
        #pragma unroll
        for (int i = 0; i < LD_IT; i++) {
            int f = tid + 256 * i;
            int r = f / CHUNKS;
            int c = f % CHUNKS;
            cpa16((uint32_t)__cvta_generic_to_shared(sb + r*ASTR + c*8),
                  Aop + (size_t)(m0 + r) * K + k0 + c*8);
        }
        #pragma unroll
        for (int i = 0; i < LD_IT; i++) {
            int f = tid + 256 * i;
            int r = f / CHUNKS;
            int c = f % CHUNKS;
            cpa16((uint32_t)__cvta_generic_to_shared(sb + A_PART + r*BSTR + c*8),
                  P.B + (size_t)(n0 + r) * K + k0 + c*8);
        }
    };

    float acc[MT][NT][4];
    #pragma unroll
    for (int mt = 0; mt < MT; mt++)
        #pragma unroll
        for (int nt = 0; nt < NT; nt++)
            #pragma unroll
            for (int i = 0; i < 4; i++) acc[mt][nt][i] = 0.f;

    const uint32_t smemBase = (uint32_t)__cvta_generic_to_shared(smem);
    const uint32_t aoff = (uint32_t)(((wm*MT*16 + l7 + q1*8) * ASTR + q2*8) * 2);
    const uint32_t boff = (uint32_t)((A_PART + (wn*64 + l7 + q2*8) * BSTR + q1*8) * 2);

    load_tile(0, 0); cpcommit();
    if (T > 1) load_tile(1, 1);
    cpcommit();

    for (int t = 0; t < T; t++) {
        cpwait<1>();
        __syncthreads();
        if (t + 2 < T) { load_tile(t + 2, (t + 2) % ST); }
        cpcommit();

        const uint32_t sbase = smemBase + (uint32_t)((t % ST) * STAGE * 2);

        #pragma unroll
        for (int ks = 0; ks < BK/16; ks++) {
            uint32_t a[MT][4], b[NT][2];
            #pragma unroll
            for (int mt = 0; mt < MT; mt++)
                ldsm4(a[mt], sbase + aoff + (uint32_t)(mt*16*ASTR*2 + ks*32));
            #pragma unroll
            for (int p = 0; p < 4; p++) {
                uint32_t r4[4];
                ldsm4(r4, sbase + boff + (uint32_t)(p*16*BSTR*2 + ks*32));
                b[2*p][0]   = r4[0]; b[2*p][1]   = r4[1];
                b[2*p+1][0] = r4[2]; b[2*p+1][1] = r4[3];
            }
            #pragma unroll
            for (int nt = 0; nt < NT; nt++)
                #pragma unroll
                for (int mt = 0; mt < MT; mt++)
                    mma16816h(acc[mt][nt], a[mt], b[nt]);
        }
    }

    // fold alpha + bias
    #pragma unroll
    for (int mt = 0; mt < MT; mt++)
        #pragma unroll
        for (int nt = 0; nt < NT; nt++) {
            int col = n0 + wn*64 + nt*8 + ((lane & 3) << 1);
            float b0 = 0.f, b1 = 0.f;
            if (bias) { b0 = bias[col]; b1 = bias[col + 1]; }
            acc[mt][nt][0] = acc[mt][nt][0] * alphaOp + b0;
            acc[mt][nt][1] = acc[mt][nt][1] * alphaOp + b1;
            acc[mt][nt][2] = acc[mt][nt][2] * alphaOp + b0;
            acc[mt][nt][3] = acc[mt][nt][3] * alphaOp + b1;
        }

    #pragma unroll
    for (int mt = 0; mt < MT; mt++) {
        int row0 = m0 + wm*MT*16 + mt*16 + (lane >> 2);
        #pragma unroll
        for (int nt = 0; nt < NT; nt++) {
            int col = n0 + wn*64 + nt*8 + ((lane & 3) << 1);
            if (C) {
                *(float2*)(C + (size_t)row0 * Nop + col)       = float2{acc[mt][nt][0], acc[mt][nt][1]};
                *(float2*)(C + (size_t)(row0 + 8) * Nop + col) = float2{acc[mt][nt][2], acc[mt][nt][3]};
            }
            if (Ch) {
                if (!P.transC) {
                    *(f162*)(Ch + (size_t)row0 * Nop + col) =
                        __floats2half2_rn(acc[mt][nt][0], acc[mt][nt][1]);
                    *(f162*)(Ch + (size_t)(row0 + 8) * Nop + col) =
                        __floats2half2_rn(acc[mt][nt][2], acc[mt][nt][3]);
                } else {
                    Ch[(size_t)col       * M + row0]     = __float2half_rn(acc[mt][nt][0]);
                    Ch[(size_t)(col + 1) * M + row0]     = __float2half_rn(acc[mt][nt][1]);
                    Ch[(size_t)col       * M + row0 + 8] = __float2half_rn(acc[mt][nt][2]);
                    Ch[(size_t)(col + 1) * M + row0 + 8] = __float2half_rn(acc[mt][nt][3]);
                }
            }
        }
    }

    if (STATS && !(MODE == 4 && vpJob)) {
        const bool diag = (STATS == 2) && (n0 == m0);
        __syncthreads();
        float* sm_m = (float*)smem;
        float* sm_s = sm_m + 256;
        #pragma unroll
        for (int mt = 0; mt < MT; mt++) {
            int rA = m0 + wm*32 + mt*16 + (lane >> 2);
            int rB = rA + 8;
            float mA = -1e30f, mB = -1e30f;
            #pragma unroll
            for (int nt = 0; nt < NT; nt++) {
                int col = n0 + wn*64 + nt*8 + ((lane & 3) << 1);
                float vA0 = acc[mt][nt][0], vA1 = acc[mt][nt][1];
                float vB0 = acc[mt][nt][2], vB1 = acc[mt][nt][3];
                if (diag) {
                    if (col     > rA) vA0 = -1e30f;
                    if (col + 1 > rA) vA1 = -1e30f;
                    if (col     > rB) vB0 = -1e30f;
                    if (col + 1 > rB) vB1 = -1e30f;
                }
                mA = fmaxf(mA, fmaxf(vA0, vA1));
                mB = fmaxf(mB, fmaxf(vB0, vB1));
            }
            mA = fmaxf(mA, __shfl_xor_sync(0xffffffffu, mA, 1));
            mA = fmaxf(mA, __shfl_xor_sync(0xffffffffu, mA, 2));
            mB = fmaxf(mB, __shfl_xor_sync(0xffffffffu, mB, 1));
            mB = fmaxf(mB, __shfl_xor_sync(0xffffffffu, mB, 2));
            float sA = 0.f, sB = 0.f;
            #pragma unroll
            for (int nt = 0; nt < NT; nt++) {
                int col = n0 + wn*64 + nt*8 + ((lane & 3) << 1);
                if (!diag || col     <= rA) sA += __expf(acc[mt][nt][0] - mA);
                if (!diag || col + 1 <= rA) sA += __expf(acc[mt][nt][1] - mA);
                if (!diag || col     <= rB) sB += __expf(acc[mt][nt][2] - mB);
                if (!diag || col + 1 <= rB) sB += __expf(acc[mt][nt][3] - mB);
            }
            sA += __shfl_xor_sync(0xffffffffu, sA, 1);
            sA += __shfl_xor_sync(0xffffffffu, sA, 2);
            sB += __shfl_xor_sync(0xffffffffu, sB, 1);
            sB += __shfl_xor_sync(0xffffffffu, sB, 2);
            if ((lane & 3) == 0) {
                int r = wm*32 + mt*16 + (lane >> 2);
                sm_m[r*2 + wn]     = mA;  sm_s[r*2 + wn]     = sA;
                sm_m[(r+8)*2 + wn] = mB;  sm_s[(r+8)*2 + wn] = sB;
            }
        }
        __syncthreads();
        if (tid < 128) {
            float m1 = sm_m[tid*2], m2 = sm_m[tid*2 + 1];
            float Mx = fmaxf(m1, m2);
            float S  = sm_s[tid*2] * __expf(m1 - Mx) + sm_s[tid*2 + 1] * __expf(m2 - Mx);
            int nb = Nop >> 7;
            smax[(size_t)(m0 + tid) * nb + (n0 >> 7)] = Mx;
            ssum[(size_t)(m0 + tid) * nb + (n0 >> 7)] = S;
        }
    }
}

// ------------------------- causal softmax: partials + 1 pass (in place) ----
__global__ void __launch_bounds__(256)
softmax_causal_warp(f16* __restrict__ sc,
                    const float* __restrict__ smax, const float* __restrict__ ssum)
{
    const int warp = threadIdx.x >> 5;
    const int lane = threadIdx.x & 31;
    const int r = blockIdx.x * 8 + warp;
    f16* row = sc + (size_t)r * SQ;
    const int n = r + 1;
    const int nb = (r >> 7) + 1;
    const int fillEnd = nb << 7;

    float m = -1e30f, s = 0.f;
    if (lane < nb) {
        m = smax[(size_t)r * NBS + lane];
        s = ssum[(size_t)r * NBS + lane];
    }
    #pragma unroll
    for (int st = 16; st > 0; st >>= 1) {
        float mo = __shfl_xor_sync(0xffffffffu, m, st);
        float so = __shfl_xor_sync(0xffffffffu, s, st);
        float Mx = fmaxf(m, mo);
        s = s * __expf(m - Mx) + so * __expf(mo - Mx);
        m = Mx;
    }
    const float inv = 1.f / s;

    for (int j = lane * 8; j < fillEnd; j += 256) {
        uint4 raw = *(const uint4*)(row + j);
        const f162* pv = (const f162*)&raw;
        f162 o[4];
        #pragma unroll
        for (int q = 0; q < 4; q++) {
            float2 v = __half22float2(pv[q]);
            float e0 = (j + 2*q     < n) ? __expf(v.x - m) * inv : 0.f;
            float e1 = (j + 2*q + 1 < n) ? __expf(v.y - m) * inv : 0.f;
            o[q] = __floats2half2_rn(e0, e1);
        }
        *(uint4*)(row + j) = *(const uint4*)o;
    }
}

// ------------------------- warp-per-row 4-partial add + LN -----------------
__global__ void __launch_bounds__(256)
add_ln_warp(const float* __restrict__ a0, const float* __restrict__ a1,
            const float* __restrict__ a2, const float* __restrict__ a3,
            const float* __restrict__ res,
            const float* __restrict__ g, const float* __restrict__ beta,
            float* __restrict__ out, f16* __restrict__ xh)
{
    const int warp = threadIdx.x >> 5;
    const int lane = threadIdx.x & 31;
    const int r = blockIdx.x * 8 + warp;
    const size_t base = (size_t)r * DM;

    float v[16];
    float sum = 0.f;
    #pragma unroll
    for (int k = 0; k < 4; k++) {
        int j = lane * 4 + k * 128;
        float4 va = *(const float4*)(a0 + base + j);
        float4 v1 = *(const float4*)(a1 + base + j);
        float4 v2 = *(const float4*)(a2 + base + j);
        float4 v3 = *(const float4*)(a3 + base + j);
        float4 vr = *(const float4*)(res + base + j);
        va.x += v1.x + v2.x + v3.x + vr.x;
        va.y += v1.y + v2.y + v3.y + vr.y;
        va.z += v1.z + v2.z + v3.z + vr.z;
        va.w += v1.w + v2.w + v3.w + vr.w;
        v[k*4+0] = va.x; v[k*4+1] = va.y; v[k*4+2] = va.z; v[k*4+3] = va.w;
        sum += va.x + va.y + va.z + va.w;
    }
    #pragma unroll
    for (int st = 16; st > 0; st >>= 1)
        sum += __shfl_xor_sync(0xffffffffu, sum, st);
    const float mu = sum * (1.0f / DM);

    float var = 0.f;
    #pragma unroll
    for (int k = 0; k < 16; k++) {
        float d = v[k] - mu;
        v[k] = d;
        var += d * d;
    }
    #pragma unroll
    for (int st = 16; st > 0; st >>= 1)
        var += __shfl_xor_sync(0xffffffffu, var, st);
    const float rstd = rsqrtf(var * (1.0f / DM) + LN_EPS);

    #pragma unroll
    for (int k = 0; k < 4; k++) {
        int j = lane * 4 + k * 128;
        float4 vg = *(const float4*)(g + j);
        float4 vb = *(const float4*)(beta + j);
        float o0 = v[k*4+0] * rstd * vg.x + vb.x;
        float o1 = v[k*4+1] * rstd * vg.y + vb.y;
        float o2 = v[k*4+2] * rstd * vg.z + vb.z;
        float o3 = v[k*4+3] * rstd * vg.w + vb.w;
        *(float4*)(out + base + j) = float4{o0, o1, o2, o3};
        f162 o[2];
        o[0] = __floats2half2_rn(o0, o1);
        o[1] = __floats2half2_rn(o2, o3);
        *(uint2*)(xh + base + j) = *(const uint2*)o;
    }
}

// ------------------------- vocab softmax via GEMM partials -----------------
__global__ void softmax_vocab_kernel(float* __restrict__ x,
                                     const float* __restrict__ smax,
                                     const float* __restrict__ ssum)
{
    const int i = blockIdx.x;
    float* row = x + (size_t)i * VOC;
    const int tid = threadIdx.x;

    __shared__ float mRed[256];
    __shared__ float sRed[256];

    float m = -1e30f, s = 0.f;
    if (tid < NBV) {
        m = smax[(size_t)i * NBV + tid];
        s = ssum[(size_t)i * NBV + tid];
    }
    mRed[tid] = m; sRed[tid] = s; __syncthreads();
    for (int st = 128; st > 0; st >>= 1) {
        if (tid < st) {
            float m1 = mRed[tid], m2 = mRed[tid + st];
            float Mx = fmaxf(m1, m2);
            sRed[tid] = sRed[tid] * __expf(m1 - Mx) + sRed[tid + st] * __expf(m2 - Mx);
            mRed[tid] = Mx;
        }
        __syncthreads();
    }
    const float M = mRed[0];
    const float inv = 1.f / sRed[0];

    for (int j = tid * 4; j < VOC; j += 1024) {
        float4 v = *(const float4*)(row + j);
        v.x = __expf(v.x - M) * inv;
        v.y = __expf(v.y - M) * inv;
        v.z = __expf(v.z - M) * inv;
        v.w = __expf(v.w - M) * inv;
        *(float4*)(row + j) = v;
    }
}

// ------------------------- host side ---------------------------------------
#define SMEM_H32  61440
#define SMEM_H64 110592

extern "C" void kernel_launch(void* const* d_in, const int* in_sizes, int n_in,
                              void* d_out, int out_size)
{
    const float* x   = (const float*)d_in[0];
    const float* Wq  = (const float*)d_in[1];
    const float* bq  = (const float*)d_in[2];
    const float* Wk  = (const float*)d_in[3];
    const float* bk  = (const float*)d_in[4];
    const float* Wv  = (const float*)d_in[5];
    const float* bv  = (const float*)d_in[6];
    const float* Wp  = (const float*)d_in[7];
    const float* bp  = (const float*)d_in[8];
    const float* g1  = (const float*)d_in[9];
    const float* be1 = (const float*)d_in[10];
    const float* W1  = (const float*)d_in[11];
    const float* b1  = (const float*)d_in[12];
    const float* W2  = (const float*)d_in[13];
    const float* b2  = (const float*)d_in[14];
    const float* g2  = (const float*)d_in[15];
    const float* be2 = (const float*)d_in[16];
    const float* Wf  = (const float*)d_in[17];
    const float* bf  = (const float*)d_in[18];
    float* out = (float*)d_out;

    cudaFuncSetAttribute(gemm_fp16<0,0,64>, cudaFuncAttributeMaxDynamicSharedMemorySize, SMEM_H64);
    cudaFuncSetAttribute(gemm_fp16<4,2,64>, cudaFuncAttributeMaxDynamicSharedMemorySize, SMEM_H64);
    cudaFuncSetAttribute(gemm_fp16<2,0,32>, cudaFuncAttributeMaxDynamicSharedMemorySize, SMEM_H32);
    cudaFuncSetAttribute(gemm_fp16<3,0,64>, cudaFuncAttributeMaxDynamicSharedMemorySize, SMEM_H64);
    cudaFuncSetAttribute(gemm_fp16<0,1,64>, cudaFuncAttributeMaxDynamicSharedMemorySize, SMEM_H64);

    float *px, *px2, *pc0, *pc1, *pc2, *pc3, *psmax, *pssum;
    cudaGetSymbolAddress((void**)&px,    g_x);
    cudaGetSymbolAddress((void**)&px2,   g_x2);
    cudaGetSymbolAddress((void**)&pc0,   g_c0);
    cudaGetSymbolAddress((void**)&pc1,   g_c1);
    cudaGetSymbolAddress((void**)&pc2,   g_c2);
    cudaGetSymbolAddress((void**)&pc3,   g_c3);
    cudaGetSymbolAddress((void**)&psmax, g_smax);
    cudaGetSymbolAddress((void**)&pssum, g_ssum);

    f16 *pxh, *px2h, *pq, *pk, *pv, *pvpt, *psc, *ph;
    f16 *pwqt, *pwkt, *pwvt, *pwpt, *pw1t, *pw2t, *pwft;
    cudaGetSymbolAddress((void**)&pxh,  g_xh);
    cudaGetSymbolAddress((void**)&px2h, g_x2h);
    cudaGetSymbolAddress((void**)&pq,   g_q);
    cudaGetSymbolAddress((void**)&pk,   g_k);
    cudaGetSymbolAddress((void**)&pv,   g_v);
    cudaGetSymbolAddress((void**)&pvpt, g_vpt);
    cudaGetSymbolAddress((void**)&psc,  g_sc);
    cudaGetSymbolAddress((void**)&ph,   g_h);
    cudaGetSymbolAddress((void**)&pwqt, g_wqt);
    cudaGetSymbolAddress((void**)&pwkt, g_wkt);
    cudaGetSymbolAddress((void**)&pwvt, g_wvt);
    cudaGetSymbolAddress((void**)&pwpt, g_wpt);
    cudaGetSymbolAddress((void**)&pw1t, g_w1t);
    cudaGetSymbolAddress((void**)&pw2t, g_w2t);
    cudaGetSymbolAddress((void**)&pwft, g_wft);

    const float scale = 1.0f / sqrtf((float)FF);
    dim3 tb(32, 8);
    HP z{nullptr, nullptr, nullptr, nullptr, 0};

    // preprocessing needed for first layer (slots 0-4)
    transpose_f16_kernel<<<dim3(FF/32, DM/32, NL), tb>>>(Wq, pwqt, DM, FF);
    transpose_f16_kernel<<<dim3(FF/32, DM/32, NL), tb>>>(Wk, pwkt, DM, FF);
    transpose_f16_kernel<<<dim3(FF/32, DM/32, NL), tb>>>(Wv, pwvt, DM, FF);
    transpose_f16_kernel<<<dim3(FF/32, FF/32, NL), tb>>>(Wp, pwpt, FF, FF);
    f32_to_f16_kernel<<<(SQ*DM)/2048, 256>>>(x, pxh, SQ*DM);

    bool firstLayer = true;
    for (int l = 0; l < NL; l++) {
        size_t wOff = (size_t)l * DM * FF;

        // QKV (batched over z)
        {
            HP pQ{pwqt + wOff, bq + (size_t)l*FF, nullptr, pq, 0};
            HP pK{pwkt + wOff, bk + (size_t)l*FF, nullptr, pk, 0};
            HP pV{pwvt + wOff, bv + (size_t)l*FF, nullptr, pv, 0};
            gemm_fp16<0,0,64><<<dim3(SQ/128, FF/128, 3), 256, SMEM_H64>>>(
                pxh, nullptr, pQ, pK, pV, z, nullptr, nullptr, SQ, FF, DM, 1.f);
        }
        // fused: scores (causal, fp16 + partials)  ||  Vp = V @ Wp^T -> [F,S]
        {
            HP pS{pk, nullptr, nullptr, psc, 0};
            HP pVp{pwpt + (size_t)l*FF*FF, nullptr, nullptr, pvpt, 1};
            gemm_fp16<4,2,64><<<dim3(SQ/128, SQ/128 + FF/128, 1), 256, SMEM_H64>>>(
                pq, pv, pS, pVp, z, z, psmax, pssum, SQ, SQ, FF, scale);
        }
        if (firstLayer) {
            transpose_f16_kernel<<<dim3(HID/32, FF/32, NL), tb>>>(W1, pw1t, FF,  HID);
            transpose_f16_kernel<<<dim3(DM/32, HID/32, NL), tb>>>(W2, pw2t, HID, DM);
            transpose_f16_kernel<<<dim3(VOC/32, DM/32, 1),  tb>>>(Wf, pwft, DM,  VOC);
            firstLayer = false;
        }
        // causal softmax: combine partials + one pass (in place, fp16)
        softmax_causal_warp<<<SQ/8, 256>>>(psc, psmax, pssum);
        // z = att @ Vp + bp  (K bounded at m0+128, split-K=4 -> LN1 partials)
        {
            HP pA{pvpt, bp + (size_t)l*FF, pc0, nullptr, 0};
            HP pB{nullptr, nullptr, pc1, nullptr, 0};
            HP pC{nullptr, nullptr, pc2, nullptr, 0};
            HP pD{nullptr, nullptr, pc3, nullptr, 0};
            gemm_fp16<2,0,32><<<dim3(SQ/128, FF/128, 4), 256, SMEM_H32>>>(
                psc, nullptr, pA, pB, pC, pD, nullptr, nullptr, SQ, FF, SQ, 1.f);
        }
        add_ln_warp<<<SQ/8, 256>>>(pc0, pc1, pc2, pc3, (l == 0) ? x : px,
                                   g1 + (size_t)l*FF, be1 + (size_t)l*FF,
                                   px2, px2h);
        // h = x2 @ W1 + b1
        {
            HP p{pw1t + (size_t)l*HID*FF, b1 + (size_t)l*HID, nullptr, ph, 0};
            gemm_fp16<0,0,64><<<dim3(SQ/128, HID/128, 1), 256, SMEM_H64>>>(
                px2h, nullptr, p, z, z, z, nullptr, nullptr, SQ, HID, FF, 1.f);
        }
        // h2 = h @ W2 + b2 (split-K=4)
        {
            HP pA{pw2t + (size_t)l*DM*HID, b2 + (size_t)l*DM, pc0, nullptr, 0};
            HP pB{nullptr, nullptr, pc1, nullptr, 0};
            HP pC{nullptr, nullptr, pc2, nullptr, 0};
            HP pD{nullptr, nullptr, pc3, nullptr, 0};
            gemm_fp16<3,0,64><<<dim3(SQ/128, DM/128, 4), 256, SMEM_H64>>>(
                ph, nullptr, pA, pB, pC, pD, nullptr, nullptr, SQ, DM, HID, 1.f);
        }
        add_ln_warp<<<SQ/8, 256>>>(pc0, pc1, pc2, pc3, px2,
                                   g2 + (size_t)l*DM, be2 + (size_t)l*DM,
                                   px, pxh);
    }

    // logits (fused softmax partials) + 1-pass vocab softmax
    {
        HP p{pwft, bf, out, nullptr, 0};
        gemm_fp16<0,1,64><<<dim3(SQ/128, VOC/128, 1), 256, SMEM_H64>>>(
            pxh, nullptr, p, z, z, z, psmax, pssum, SQ, VOC, DM, 1.f);
    }
    softmax_vocab_kernel<<<SQ, 256>>>(out, psmax, pssum);

    (void)in_sizes; (void)n_in; (void)out_size;
}